// round 6
// baseline (speedup 1.0000x reference)
#include <cuda_runtime.h>
#include <cuda_bf16.h>
#include <cstdint>
#include <math.h>

// Problem dims
#define BB   256
#define LL   128
#define VOC  4096
#define EENC 1024
#define DDEC 1024
#define EEMB 512

// ======================= scratch (module-load allocated) ==================
#define OFF_ENC   0ull
#define OFF_W1    (OFF_ENC + 33554432ull)
#define OFF_W2    (OFF_W1  + 1048576ull)
#define OFF_O2E   (OFF_W2  + 1048576ull)
#define OFF_GWI   (OFF_O2E + 2097152ull)
#define OFF_GWH   (OFF_GWI + 4718592ull)
#define OFF_F1    (OFF_GWH + 3145728ull)
#define OFF_F2    (OFF_F1  + 524288ull)
#define OFF_X     (OFF_F2  + 2097152ull)
#define OFF_HID   (OFF_X   + 1048576ull)
#define OFF_RNN   (OFF_HID + 262144ull)
#define OFF_HNEW  (OFF_RNN + 393216ull)
#define OFF_T     (OFF_HNEW+ 262144ull)
#define BF_TOTAL  (OFF_T   + 131072ull)

__device__ __nv_bfloat16 g_bh[BF_TOTAL];
__device__ __nv_bfloat16 g_bl[BF_TOTAL];

#define F_G1    0ull
#define F_RNN   (F_G1   + 262144ull)
#define F_GI    (F_RNN  + 393216ull)
#define F_GH    (F_GI   + 786432ull)
#define F_T     (F_GH   + 786432ull)
#define F_PART  (F_T    + 131072ull)
#define F_TOTAL (F_PART + 524288ull)

__device__ float g_f32[F_TOTAL];

// ======================= small helpers ====================================
__device__ __forceinline__ void cp16(uint32_t s, const void* g) {
    asm volatile("cp.async.cg.shared.global [%0], [%1], 16;"
                 :: "r"(s), "l"(__cvta_generic_to_global(g)));
}
__device__ __forceinline__ void ldm4(uint32_t* r, uint32_t addr) {
    asm volatile("ldmatrix.sync.aligned.m8n8.x4.shared.b16 {%0,%1,%2,%3}, [%4];"
        : "=r"(r[0]), "=r"(r[1]), "=r"(r[2]), "=r"(r[3]) : "r"(addr));
}
__device__ __forceinline__ void mma16816(float* c, const uint32_t* a, const uint32_t* b) {
    asm volatile("mma.sync.aligned.m16n8k16.row.col.f32.bf16.bf16.f32 "
        "{%0,%1,%2,%3}, {%4,%5,%6,%7}, {%8,%9}, {%0,%1,%2,%3};"
        : "+f"(c[0]), "+f"(c[1]), "+f"(c[2]), "+f"(c[3])
        : "r"(a[0]), "r"(a[1]), "r"(a[2]), "r"(a[3]), "r"(b[0]), "r"(b[1]));
}
__device__ __forceinline__ void do_split(const float* src, int local,
                                         unsigned long long dst) {
    float2 v = ((const float2*)src)[local];
    __nv_bfloat16 h0 = __float2bfloat16(v.x);
    __nv_bfloat16 h1 = __float2bfloat16(v.y);
    __nv_bfloat162 hp; hp.x = h0; hp.y = h1;
    __nv_bfloat162 lp;
    lp.x = __float2bfloat16(v.x - __bfloat162float(h0));
    lp.y = __float2bfloat16(v.y - __bfloat162float(h1));
    ((__nv_bfloat162*)(g_bh + dst))[local] = hp;
    ((__nv_bfloat162*)(g_bl + dst))[local] = lp;
}

// ======================= fused split kernels ==============================
#define WN1 524288
#define WN2 1048576
#define WN3 2097152
#define WN4 4456448
#define WN5 6029312
#define WN6 6291456
#define WN7 7340032
__global__ __launch_bounds__(256)
void split_weights(const float* __restrict__ W1, const float* __restrict__ W2,
                   const float* __restrict__ o2e, const float* __restrict__ gwi,
                   const float* __restrict__ gwh, const float* __restrict__ f1,
                   const float* __restrict__ f2)
{
    int i = blockIdx.x * blockDim.x + threadIdx.x;
    if (i < WN1)      do_split(W1,  i,       OFF_W1);
    else if (i < WN2) do_split(W2,  i - WN1, OFF_W2);
    else if (i < WN3) do_split(o2e, i - WN2, OFF_O2E);
    else if (i < WN4) do_split(gwi, i - WN3, OFF_GWI);
    else if (i < WN5) do_split(gwh, i - WN4, OFF_GWH);
    else if (i < WN6) do_split(f1,  i - WN5, OFF_F1);
    else if (i < WN7) do_split(f2,  i - WN6, OFF_F2);
}
#define AN1 16777216
#define AN2 17301504
#define AN3 17432576
__global__ __launch_bounds__(256)
void split_acts(const float* __restrict__ enc, const float* __restrict__ x,
                const float* __restrict__ hid)
{
    int i = blockIdx.x * blockDim.x + threadIdx.x;
    if (i < AN1)      do_split(enc, i,       OFF_ENC);
    else if (i < AN2) do_split(x,   i - AN1, OFF_X);
    else if (i < AN3) do_split(hid, i - AN2, OFF_HID);
}
__global__ __launch_bounds__(256)
void f32_split(const float* __restrict__ in, __nv_bfloat16* __restrict__ hi,
               __nv_bfloat16* __restrict__ lo, int n2)
{
    int i = blockIdx.x * blockDim.x + threadIdx.x;
    if (i >= n2) return;
    float2 v = ((const float2*)in)[i];
    __nv_bfloat16 h0 = __float2bfloat16(v.x);
    __nv_bfloat16 h1 = __float2bfloat16(v.y);
    __nv_bfloat162 hp; hp.x = h0; hp.y = h1;
    __nv_bfloat162 lp;
    lp.x = __float2bfloat16(v.x - __bfloat162float(h0));
    lp.y = __float2bfloat16(v.y - __bfloat162float(h1));
    ((__nv_bfloat162*)hi)[i] = hp;
    ((__nv_bfloat162*)lo)[i] = lp;
}
__global__ __launch_bounds__(256)
void f32_split_tanh(const float* __restrict__ in, __nv_bfloat16* __restrict__ hi,
                    __nv_bfloat16* __restrict__ lo, int n2)
{
    int i = blockIdx.x * blockDim.x + threadIdx.x;
    if (i >= n2) return;
    float2 v = ((const float2*)in)[i];
    v.x = tanhf(v.x); v.y = tanhf(v.y);
    __nv_bfloat16 h0 = __float2bfloat16(v.x);
    __nv_bfloat16 h1 = __float2bfloat16(v.y);
    __nv_bfloat162 hp; hp.x = h0; hp.y = h1;
    __nv_bfloat162 lp;
    lp.x = __float2bfloat16(v.x - __bfloat162float(h0));
    lp.y = __float2bfloat16(v.y - __bfloat162float(h1));
    ((__nv_bfloat162*)hi)[i] = hp;
    ((__nv_bfloat162*)lo)[i] = lp;
}

// ================= bias pre-init (resets ALL atomic targets every call) ===
__global__ __launch_bounds__(256)
void bias_init(float* __restrict__ g1, float* __restrict__ rnn,
               float* __restrict__ gi, float* __restrict__ gh,
               float* __restrict__ tbuf, float* __restrict__ out,
               const float* __restrict__ w1b, const float* __restrict__ w2b,
               const float* __restrict__ o2eb, const float* __restrict__ gbi,
               const float* __restrict__ gbh, const float* __restrict__ f1b,
               const float* __restrict__ f2b)
{
    int i = blockIdx.x * blockDim.x + threadIdx.x;
    if (i < 262144) {
        g1[i] = w1b[i & 1023] + w2b[i & 1023];
    } else if (i < 393216) {
        int j = i - 262144;
        rnn[(j >> 9) * 1536 + 1024 + (j & 511)] = o2eb[j & 511];
    } else if (i < 1179648) {
        int j = i - 393216;
        gi[j] = gbi[j % 3072];
    } else if (i < 1966080) {
        int j = i - 1179648;
        gh[j] = gbh[j % 3072];
    } else if (i < 2097152) {
        int j = i - 1966080;
        tbuf[j] = f1b[j & 511];
    } else {
        int j = i - 2097152;
        out[j] = f2b[j & 4095];
    }
}
#define BIAS_TOTAL 3145728

// ======================= small split-K mma GEMM (unchanged from R5) =======
enum { EPI_ATOMIC = 0 };

#define ROWB      80
#define TILE_A_SB (128 * ROWB)
#define TILE_W_SB (64 * ROWB)
#define STAGE_SB  (2 * TILE_A_SB + 2 * TILE_W_SB)
#define SM_PART   (2 * STAGE_SB)
#define GEMM_SMEM (SM_PART + 512 + 32)

__global__ __launch_bounds__(256, 2)
void gemm64(const __nv_bfloat16* __restrict__ Ah, const __nv_bfloat16* __restrict__ Al,
            const __nv_bfloat16* __restrict__ Wh, const __nv_bfloat16* __restrict__ Wl,
            int K, int Kchunk, float* __restrict__ C, int ldc)
{
    extern __shared__ __align__(128) char smem[];
    const uint32_t sbase = (uint32_t)__cvta_generic_to_shared(smem);

    const int tid  = threadIdx.x;
    const int wid  = tid >> 5;
    const int lane = tid & 31;
    const int brow = blockIdx.y * 128;
    const int bcol = blockIdx.x * 64;
    const int k0   = blockIdx.z * Kchunk;
    const int m32  = (wid >> 1) * 32;
    const int n32w = (wid & 1) * 32;

    const int lrA = tid >> 1;
    const int cA  = (tid & 1) * 2;
    const int lrW = tid >> 2;
    const int cW  = tid & 3;
    const size_t aoff = (size_t)(brow + lrA) * K + k0;
    const size_t woff = (size_t)(bcol + lrW) * K + k0;

    auto load_stage = [&](int stage, int kk0) {
        const uint32_t sA = sbase + stage * STAGE_SB + lrA * ROWB;
        const uint32_t sW = sbase + stage * STAGE_SB + 2 * TILE_A_SB + lrW * ROWB;
        const char* pAh = (const char*)(Ah + aoff + kk0);
        const char* pAl = (const char*)(Al + aoff + kk0);
        const char* pWh = (const char*)(Wh + woff + kk0);
        const char* pWl = (const char*)(Wl + woff + kk0);
        #pragma unroll
        for (int c = cA; c < cA + 2; c++) {
            cp16(sA + c * 16, pAh + c * 16);
            cp16(sA + TILE_A_SB + c * 16, pAl + c * 16);
        }
        cp16(sW + cW * 16, pWh + cW * 16);
        cp16(sW + TILE_W_SB + cW * 16, pWl + cW * 16);
    };

    const int nk = Kchunk >> 5;

    load_stage(0, 0);
    asm volatile("cp.async.commit_group;");
    if (nk > 1) load_stage(1, 32);
    asm volatile("cp.async.commit_group;");

    float acc[2][4][4];
    #pragma unroll
    for (int i = 0; i < 2; i++)
        #pragma unroll
        for (int j = 0; j < 4; j++)
            #pragma unroll
            for (int q = 0; q < 4; q++) acc[i][j][q] = 0.f;

    const int arow_l = m32 + (lane & 15);
    const uint32_t akb = ((lane >> 4) & 1) * 16;
    const int nrow_l = n32w + (lane & 7) + ((lane >> 4) & 1) * 8;
    const uint32_t bkb = ((lane >> 3) & 1) * 16;

    for (int c = 0; c < nk; c++) {
        asm volatile("cp.async.wait_group %0;" :: "n"(1));
        __syncthreads();

        const uint32_t sb = sbase + (c & 1) * STAGE_SB;
        #pragma unroll
        for (int kk = 0; kk < 2; kk++) {
            const uint32_t kbyte = kk * 32;
            uint32_t afh[2][4], afl[2][4], bfh[4][2], bfl[4][2];
            #pragma unroll
            for (int mt = 0; mt < 2; mt++) {
                uint32_t ra = (uint32_t)((arow_l + mt * 16) * ROWB) + akb + kbyte;
                ldm4(afh[mt], sb + ra);
                ldm4(afl[mt], sb + TILE_A_SB + ra);
            }
            #pragma unroll
            for (int np = 0; np < 2; np++) {
                uint32_t rb = (uint32_t)((nrow_l + np * 16) * ROWB) + bkb + kbyte;
                uint32_t th[4], tl[4];
                ldm4(th, sb + 2 * TILE_A_SB + rb);
                ldm4(tl, sb + 2 * TILE_A_SB + TILE_W_SB + rb);
                bfh[2 * np][0] = th[0]; bfh[2 * np][1] = th[1];
                bfh[2 * np + 1][0] = th[2]; bfh[2 * np + 1][1] = th[3];
                bfl[2 * np][0] = tl[0]; bfl[2 * np][1] = tl[1];
                bfl[2 * np + 1][0] = tl[2]; bfl[2 * np + 1][1] = tl[3];
            }
            #pragma unroll
            for (int mt = 0; mt < 2; mt++)
                #pragma unroll
                for (int nt = 0; nt < 4; nt++) {
                    mma16816(acc[mt][nt], afh[mt], bfh[nt]);
                    mma16816(acc[mt][nt], afl[mt], bfh[nt]);
                    mma16816(acc[mt][nt], afh[mt], bfl[nt]);
                }
        }
        __syncthreads();

        if (c + 2 < nk) load_stage(c & 1, (c + 2) * 32);
        asm volatile("cp.async.commit_group;");
    }

    const int rloc0 = m32 + (lane >> 2);
    const int cloc0 = n32w + (lane & 3) * 2;
    #pragma unroll
    for (int mt = 0; mt < 2; mt++) {
        const int r0 = brow + rloc0 + mt * 16;
        #pragma unroll
        for (int nt = 0; nt < 4; nt++) {
            const int col = bcol + cloc0 + nt * 8;
            float* c0 = C + (size_t)r0 * ldc + col;
            float* c1 = C + (size_t)(r0 + 8) * ldc + col;
            atomicAdd(c0,     acc[mt][nt][0]);
            atomicAdd(c0 + 1, acc[mt][nt][1]);
            atomicAdd(c1,     acc[mt][nt][2]);
            atomicAdd(c1 + 1, acc[mt][nt][3]);
        }
    }
}

// ======================= score GEMM: 128x128, SW64, 3-stage ===============
// A(32768x1024) @ W1^T(1024x1024); epilogue: sum_col tanh(acc+g1)*vw -> partials.
// SW64 rows: 64 bytes (32 bf16 = BK), chunk' = chunk ^ ((row>>1)&3).
#define S_TILE   8192                    // 128 rows x 64B (one matrix, hi or lo)
#define S_REG    (2 * S_TILE)            // hi+lo region (A or W)
#define S_STAGE  (2 * S_REG)             // A hi/lo + W hi/lo = 32768
#define S_NST    3
#define S_SMEM   (S_NST * S_STAGE + 512 + 32)

__global__ __launch_bounds__(256, 2)
void score128(const __nv_bfloat16* __restrict__ Ah, const __nv_bfloat16* __restrict__ Al,
              const __nv_bfloat16* __restrict__ Wh, const __nv_bfloat16* __restrict__ Wl,
              const float* __restrict__ g1, const float* __restrict__ vw,
              float* __restrict__ partial)
{
    extern __shared__ __align__(128) char smem[];
    const uint32_t sbase = (uint32_t)__cvta_generic_to_shared(smem);
    float* part_sm = (float*)(smem + S_NST * S_STAGE);

    const int tid  = threadIdx.x;
    const int wid  = tid >> 5;
    const int lane = tid & 31;
    const int brow = blockIdx.y * 128;
    const int bcol = blockIdx.x * 128;
    const int m64  = (wid >> 2) * 64;    // 2 m-groups
    const int n32  = (wid & 3) * 32;     // 4 n-groups

    if (tid < 128) part_sm[tid] = 0.f;

    // loader: threads 0-127 -> A rows, 128-255 -> W rows; 8 cp16 each
    const int lhalf = tid >> 7;
    const int lrow  = tid & 127;
    const __nv_bfloat16* ph = lhalf ? (Wh + (size_t)(bcol + lrow) * 1024)
                                    : (Ah + (size_t)(brow + lrow) * 1024);
    const __nv_bfloat16* pl = lhalf ? (Wl + (size_t)(bcol + lrow) * 1024)
                                    : (Al + (size_t)(brow + lrow) * 1024);
    const uint32_t lkey  = ((uint32_t)(lrow >> 1) & 3) << 4;
    const uint32_t lbase = (uint32_t)(lhalf * S_REG + lrow * 64);

    auto load_stage = [&](int stage, int k0) {
        const uint32_t sb = sbase + stage * S_STAGE + lbase;
        const char* gh_ = (const char*)(ph + k0);
        const char* gl_ = (const char*)(pl + k0);
        #pragma unroll
        for (int c = 0; c < 4; c++) {
            uint32_t so = ((uint32_t)(c << 4)) ^ lkey;
            cp16(sb + so, gh_ + c * 16);
            cp16(sb + S_TILE + so, gl_ + c * 16);
        }
    };

    const int nk = 32;                   // K=1024 / 32

    load_stage(0, 0);
    asm volatile("cp.async.commit_group;");
    load_stage(1, 32);
    asm volatile("cp.async.commit_group;");

    float acc[4][4][4];
    #pragma unroll
    for (int i = 0; i < 4; i++)
        #pragma unroll
        for (int j = 0; j < 4; j++)
            #pragma unroll
            for (int q = 0; q < 4; q++) acc[i][j][q] = 0.f;

    const int arow_l = m64 + (lane & 7) + ((lane >> 3) & 1) * 8;
    const uint32_t acb = (lane >> 4) & 1;          // A chunk base (16B units)
    const int nrow_l = n32 + (lane & 7) + ((lane >> 4) & 1) * 8;
    const uint32_t bcb = (lane >> 3) & 1;          // B chunk base

    int stage = 0;
    for (int c = 0; c < nk; c++) {
        asm volatile("cp.async.wait_group %0;" :: "n"(1));
        __syncthreads();

        if (c + 2 < nk) {
            int s2 = stage + 2; if (s2 >= S_NST) s2 -= S_NST;
            load_stage(s2, (c + 2) * 32);
        }
        asm volatile("cp.async.commit_group;");

        const uint32_t sb = sbase + stage * S_STAGE;
        #pragma unroll
        for (int kk = 0; kk < 2; kk++) {
            const uint32_t kc = kk * 2;            // chunk offset of this k16
            uint32_t bfh[4][2], bfl[4][2];
            #pragma unroll
            for (int np = 0; np < 2; np++) {
                const uint32_t row = (uint32_t)(nrow_l + np * 16);
                const uint32_t ch  = (bcb + kc) ^ ((row >> 1) & 3);
                const uint32_t rb  = sb + S_REG + row * 64 + ch * 16;
                uint32_t th[4], tl[4];
                ldm4(th, rb);
                ldm4(tl, rb + S_TILE);
                bfh[2 * np][0] = th[0]; bfh[2 * np][1] = th[1];
                bfh[2 * np + 1][0] = th[2]; bfh[2 * np + 1][1] = th[3];
                bfl[2 * np][0] = tl[0]; bfl[2 * np][1] = tl[1];
                bfl[2 * np + 1][0] = tl[2]; bfl[2 * np + 1][1] = tl[3];
            }
            #pragma unroll
            for (int mt = 0; mt < 4; mt++) {
                const uint32_t row = (uint32_t)(arow_l + mt * 16);
                const uint32_t ch  = (acb + kc) ^ ((row >> 1) & 3);
                const uint32_t ra  = sb + row * 64 + ch * 16;
                uint32_t afh[4], afl[4];
                ldm4(afh, ra);
                ldm4(afl, ra + S_TILE);
                #pragma unroll
                for (int nt = 0; nt < 4; nt++) {
                    mma16816(acc[mt][nt], afh, bfh[nt]);
                    mma16816(acc[mt][nt], afl, bfh[nt]);
                    mma16816(acc[mt][nt], afh, bfl[nt]);
                }
            }
        }
        if (++stage >= S_NST) stage = 0;
    }

    // ---- epilogue: weighted-tanh row partial sums ----
    const int rloc0 = m64 + (lane >> 2);
    const int cloc0 = n32 + (lane & 3) * 2;
    const float* g1r = g1 + (size_t)blockIdx.y * 1024;
    #pragma unroll
    for (int mt = 0; mt < 4; mt++) {
        float s0 = 0.f, s1 = 0.f;
        #pragma unroll
        for (int nt = 0; nt < 4; nt++) {
            int col = bcol + cloc0 + nt * 8;
            float gw0 = g1r[col],     vw0 = vw[col];
            float gw1 = g1r[col + 1], vw1 = vw[col + 1];
            s0 += tanhf(acc[mt][nt][0] + gw0) * vw0;
            s0 += tanhf(acc[mt][nt][1] + gw1) * vw1;
            s1 += tanhf(acc[mt][nt][2] + gw0) * vw0;
            s1 += tanhf(acc[mt][nt][3] + gw1) * vw1;
        }
        atomicAdd(&part_sm[rloc0 + mt * 16], s0);
        atomicAdd(&part_sm[rloc0 + mt * 16 + 8], s1);
    }
    __syncthreads();
    if (tid < 128)
        partial[(size_t)(brow + tid) * gridDim.x + blockIdx.x] = part_sm[tid];
}

// ============== softmax + context (one block per batch element) ===========
__global__ __launch_bounds__(256)
void attn_softmax_context(const float* __restrict__ part, int npart,
                          const float* __restrict__ enc,
                          const float* __restrict__ Vb,
                          float* __restrict__ attn_out,
                          float* __restrict__ rnn)
{
    const int b   = blockIdx.x;
    const int tid = threadIdx.x;
    __shared__ float logit[LL];

    if (tid < LL) {
        const float* pr = part + (size_t)(b * LL + tid) * npart;
        float s = Vb[0];
        for (int j = 0; j < npart; j++) s += pr[j];
        logit[tid] = s;
    }
    __syncthreads();

    if (tid < 32) {
        const int lane = tid;
        float m = -1e30f;
        for (int l = lane; l < LL; l += 32) m = fmaxf(m, logit[l]);
        #pragma unroll
        for (int o = 16; o; o >>= 1) m = fmaxf(m, __shfl_xor_sync(0xffffffffu, m, o));
        float s = 0.f;
        for (int l = lane; l < LL; l += 32) {
            float e = expf(logit[l] - m);
            logit[l] = e;
            s += e;
        }
        #pragma unroll
        for (int o = 16; o; o >>= 1) s += __shfl_xor_sync(0xffffffffu, s, o);
        float inv = 1.f / s;
        for (int l = lane; l < LL; l += 32) logit[l] *= inv;
    }
    __syncthreads();

    if (tid < LL) attn_out[b * LL + tid] = logit[tid];

    float4 acc = make_float4(0.f, 0.f, 0.f, 0.f);
    const float* encb = enc + (size_t)b * LL * EENC;
    const int e4 = tid * 4;
    #pragma unroll 4
    for (int l = 0; l < LL; l++) {
        float a = logit[l];
        float4 v = *(const float4*)(encb + (size_t)l * EENC + e4);
        acc.x += a * v.x; acc.y += a * v.y; acc.z += a * v.z; acc.w += a * v.w;
    }
    *(float4*)(rnn + (size_t)b * 1536 + e4) = acc;
}

// ============================ GRU gates ===================================
__global__ __launch_bounds__(256)
void gru_gate(const float* __restrict__ gi, const float* __restrict__ gh,
              const float* __restrict__ h0, float* __restrict__ hnew)
{
    const int idx = blockIdx.x * blockDim.x + threadIdx.x;
    const int b = idx >> 10;
    const int d = idx & 1023;
    const float* gib = gi + (size_t)b * 3072;
    const float* ghb = gh + (size_t)b * 3072;
    float r = 1.f / (1.f + expf(-(gib[d] + ghb[d])));
    float z = 1.f / (1.f + expf(-(gib[1024 + d] + ghb[1024 + d])));
    float n = tanhf(gib[2048 + d] + r * ghb[2048 + d]);
    hnew[idx] = (1.f - z) * n + z * h0[idx];
}

// ============================ launch ======================================
extern "C" void kernel_launch(void* const* d_in, const int* in_sizes, int n_in,
                              void* d_out, int out_size)
{
    (void)in_sizes; (void)n_in; (void)out_size;

    const float* x      = (const float*)d_in[0];
    const float* hidden = (const float*)d_in[1];
    const float* enc    = (const float*)d_in[2];
    const float* W1_w   = (const float*)d_in[3];
    const float* W1_b   = (const float*)d_in[4];
    const float* W2_w   = (const float*)d_in[5];
    const float* W2_b   = (const float*)d_in[6];
    const float* V_w    = (const float*)d_in[7];
    const float* V_b    = (const float*)d_in[8];
    const float* o2e_w  = (const float*)d_in[9];
    const float* o2e_b  = (const float*)d_in[10];
    const float* gwi    = (const float*)d_in[11];
    const float* gwh    = (const float*)d_in[12];
    const float* gbi    = (const float*)d_in[13];
    const float* gbh    = (const float*)d_in[14];
    const float* f1w    = (const float*)d_in[15];
    const float* f1b    = (const float*)d_in[16];
    const float* f2w    = (const float*)d_in[17];
    const float* f2b    = (const float*)d_in[18];

    float* out  = (float*)d_out;
    float* hnew = out + (size_t)BB * VOC;
    float* attn = hnew + (size_t)BB * DDEC;

    __nv_bfloat16* bh = nullptr;
    __nv_bfloat16* bl = nullptr;
    float* fs = nullptr;
    cudaGetSymbolAddress((void**)&bh, g_bh);
    cudaGetSymbolAddress((void**)&bl, g_bl);
    cudaGetSymbolAddress((void**)&fs, g_f32);

    float* g1   = fs + F_G1;
    float* rnn  = fs + F_RNN;
    float* gi   = fs + F_GI;
    float* gh   = fs + F_GH;
    float* tbuf = fs + F_T;
    float* part = fs + F_PART;

    cudaFuncSetAttribute(gemm64,   cudaFuncAttributeMaxDynamicSharedMemorySize, GEMM_SMEM);
    cudaFuncSetAttribute(score128, cudaFuncAttributeMaxDynamicSharedMemorySize, S_SMEM);

    dim3 blk(256);

    // 0) weight splits
    split_weights<<<WN7 / 256, 256>>>(W1_w, W2_w, o2e_w, gwi, gwh, f1w, f2w);
    // 1) activation splits
    split_acts<<<AN3 / 256, 256>>>(enc, x, hidden);
    // 2) bias preinit
    bias_init<<<BIAS_TOTAL / 256, 256>>>(g1, rnn, gi, gh, tbuf, out,
                                         W1_b, W2_b, o2e_b, gbi, gbh, f1b, f2b);

    // 3) g1 += h0 @ W2^T            (256x1024, K=1024, splitK=4)
    gemm64<<<dim3(16, 2, 4), blk, GEMM_SMEM>>>(
        bh + OFF_HID, bl + OFF_HID, bh + OFF_W2, bl + OFF_W2,
        1024, 256, g1, 1024);

    // 4) score GEMM -> weighted-tanh row partials   (32768x1024, K=1024)
    score128<<<dim3(8, 256), blk, S_SMEM>>>(
        bh + OFF_ENC, bl + OFF_ENC, bh + OFF_W1, bl + OFF_W1, g1, V_w, part);

    // 5) softmax + attn out + context -> rnn[:, 0:1024]
    attn_softmax_context<<<BB, 256>>>(part, 8, enc, V_b, attn, rnn);

    // 6) x_emb += x @ out2emb^T     (256x512, K=4096, splitK=8)
    gemm64<<<dim3(8, 2, 8), blk, GEMM_SMEM>>>(
        bh + OFF_X, bl + OFF_X, bh + OFF_O2E, bl + OFF_O2E,
        4096, 512, rnn + 1024, 1536);

    // 7) gh += h0 @ gru_wh^T        (256x3072, K=1024, splitK=2)
    gemm64<<<dim3(48, 2, 2), blk, GEMM_SMEM>>>(
        bh + OFF_HID, bl + OFF_HID, bh + OFF_GWH, bl + OFF_GWH,
        1024, 512, gh, 3072);

    // 8) rnn -> bf16
    f32_split<<<(393216 / 2) / 256, 256>>>(rnn, bh + OFF_RNN, bl + OFF_RNN, 393216 / 2);

    // 9) gi += rnn_in @ gru_wi^T    (256x3072, K=1536, splitK=2)
    gemm64<<<dim3(48, 2, 2), blk, GEMM_SMEM>>>(
        bh + OFF_RNN, bl + OFF_RNN, bh + OFF_GWI, bl + OFF_GWI,
        1536, 768, gi, 3072);

    // 10) GRU gates -> h_new (output)
    gru_gate<<<(BB * DDEC) / 256, 256>>>(gi, gh, hidden, hnew);

    // 11) h_new -> bf16
    f32_split<<<(262144 / 2) / 256, 256>>>(hnew, bh + OFF_HNEW, bl + OFF_HNEW, 262144 / 2);

    // 12) tbuf += h_new @ fc1^T     (256x512, K=1024, splitK=8)
    gemm64<<<dim3(8, 2, 8), blk, GEMM_SMEM>>>(
        bh + OFF_HNEW, bl + OFF_HNEW, bh + OFF_F1, bl + OFF_F1,
        1024, 128, tbuf, 512);

    // 13) t = tanh(tbuf) -> bf16
    f32_split_tanh<<<(131072 / 2) / 256, 256>>>(tbuf, bh + OFF_T, bl + OFF_T, 131072 / 2);

    // 14) out += t @ fc2^T          (256x4096, K=512, splitK=2)
    gemm64<<<dim3(64, 2, 2), blk, GEMM_SMEM>>>(
        bh + OFF_T, bl + OFF_T, bh + OFF_F2, bl + OFF_F2,
        512, 256, out, 4096);
}

// round 7
// speedup vs baseline: 1.1684x; 1.1684x over previous
#include <cuda_runtime.h>
#include <cuda_fp16.h>
#include <cstdint>
#include <math.h>

// Problem dims
#define BB   256
#define LL   128
#define VOC  4096
#define EENC 1024
#define DDEC 1024
#define EEMB 512

// ======================= scratch (module-load allocated) ==================
#define OFF_ENC   0ull
#define OFF_W1    (OFF_ENC + 33554432ull)
#define OFF_W2    (OFF_W1  + 1048576ull)
#define OFF_O2E   (OFF_W2  + 1048576ull)
#define OFF_GWI   (OFF_O2E + 2097152ull)
#define OFF_GWH   (OFF_GWI + 4718592ull)
#define OFF_F1    (OFF_GWH + 3145728ull)
#define OFF_F2    (OFF_F1  + 524288ull)
#define OFF_X     (OFF_F2  + 2097152ull)
#define OFF_HID   (OFF_X   + 1048576ull)
#define OFF_RNN   (OFF_HID + 262144ull)
#define OFF_HNEW  (OFF_RNN + 393216ull)
#define OFF_T     (OFF_HNEW+ 262144ull)
#define BF_TOTAL  (OFF_T   + 131072ull)

__device__ __half g_bh[BF_TOTAL];
__device__ __half g_bl[BF_TOTAL];

#define F_G1    0ull
#define F_RNN   (F_G1   + 262144ull)
#define F_GI    (F_RNN  + 393216ull)
#define F_GH    (F_GI   + 786432ull)
#define F_T     (F_GH   + 786432ull)
#define F_PART  (F_T    + 131072ull)
#define F_TOTAL (F_PART + 524288ull)

__device__ float g_f32[F_TOTAL];

// ======================= small helpers ====================================
__device__ __forceinline__ void cp16(uint32_t s, const void* g) {
    asm volatile("cp.async.cg.shared.global [%0], [%1], 16;"
                 :: "r"(s), "l"(__cvta_generic_to_global(g)));
}
__device__ __forceinline__ void ldm4(uint32_t* r, uint32_t addr) {
    asm volatile("ldmatrix.sync.aligned.m8n8.x4.shared.b16 {%0,%1,%2,%3}, [%4];"
        : "=r"(r[0]), "=r"(r[1]), "=r"(r[2]), "=r"(r[3]) : "r"(addr));
}
__device__ __forceinline__ void mma16816(float* c, const uint32_t* a, const uint32_t* b) {
    asm volatile("mma.sync.aligned.m16n8k16.row.col.f32.f16.f16.f32 "
        "{%0,%1,%2,%3}, {%4,%5,%6,%7}, {%8,%9}, {%0,%1,%2,%3};"
        : "+f"(c[0]), "+f"(c[1]), "+f"(c[2]), "+f"(c[3])
        : "r"(a[0]), "r"(a[1]), "r"(a[2]), "r"(a[3]), "r"(b[0]), "r"(b[1]));
}
__device__ __forceinline__ void do_split(const float* src, int local,
                                         unsigned long long dst) {
    float2 v = ((const float2*)src)[local];
    __half h0 = __float2half_rn(v.x);
    __half h1 = __float2half_rn(v.y);
    __half2 hp; hp.x = h0; hp.y = h1;
    __half2 lp;
    lp.x = __float2half_rn(v.x - __half2float(h0));
    lp.y = __float2half_rn(v.y - __half2float(h1));
    ((__half2*)(g_bh + dst))[local] = hp;
    ((__half2*)(g_bl + dst))[local] = lp;
}

// ======================= fused split kernels ==============================
#define WN1 524288
#define WN2 1048576
#define WN3 2097152
#define WN4 4456448
#define WN5 6029312
#define WN6 6291456
#define WN7 7340032
__global__ __launch_bounds__(256)
void split_weights(const float* __restrict__ W1, const float* __restrict__ W2,
                   const float* __restrict__ o2e, const float* __restrict__ gwi,
                   const float* __restrict__ gwh, const float* __restrict__ f1,
                   const float* __restrict__ f2)
{
    int i = blockIdx.x * blockDim.x + threadIdx.x;
    if (i < WN1)      do_split(W1,  i,       OFF_W1);
    else if (i < WN2) do_split(W2,  i - WN1, OFF_W2);
    else if (i < WN3) do_split(o2e, i - WN2, OFF_O2E);
    else if (i < WN4) do_split(gwi, i - WN3, OFF_GWI);
    else if (i < WN5) do_split(gwh, i - WN4, OFF_GWH);
    else if (i < WN6) do_split(f1,  i - WN5, OFF_F1);
    else if (i < WN7) do_split(f2,  i - WN6, OFF_F2);
}
#define AN1 16777216
#define AN2 17301504
#define AN3 17432576
__global__ __launch_bounds__(256)
void split_acts(const float* __restrict__ enc, const float* __restrict__ x,
                const float* __restrict__ hid)
{
    int i = blockIdx.x * blockDim.x + threadIdx.x;
    if (i < AN1)      do_split(enc, i,       OFF_ENC);
    else if (i < AN2) do_split(x,   i - AN1, OFF_X);
    else if (i < AN3) do_split(hid, i - AN2, OFF_HID);
}
__global__ __launch_bounds__(256)
void f32_split(const float* __restrict__ in, __half* __restrict__ hi,
               __half* __restrict__ lo, int n2)
{
    int i = blockIdx.x * blockDim.x + threadIdx.x;
    if (i >= n2) return;
    float2 v = ((const float2*)in)[i];
    __half h0 = __float2half_rn(v.x);
    __half h1 = __float2half_rn(v.y);
    __half2 hp; hp.x = h0; hp.y = h1;
    __half2 lp;
    lp.x = __float2half_rn(v.x - __half2float(h0));
    lp.y = __float2half_rn(v.y - __half2float(h1));
    ((__half2*)hi)[i] = hp;
    ((__half2*)lo)[i] = lp;
}
__global__ __launch_bounds__(256)
void f32_split_tanh(const float* __restrict__ in, __half* __restrict__ hi,
                    __half* __restrict__ lo, int n2)
{
    int i = blockIdx.x * blockDim.x + threadIdx.x;
    if (i >= n2) return;
    float2 v = ((const float2*)in)[i];
    v.x = tanhf(v.x); v.y = tanhf(v.y);
    __half h0 = __float2half_rn(v.x);
    __half h1 = __float2half_rn(v.y);
    __half2 hp; hp.x = h0; hp.y = h1;
    __half2 lp;
    lp.x = __float2half_rn(v.x - __half2float(h0));
    lp.y = __float2half_rn(v.y - __half2float(h1));
    ((__half2*)hi)[i] = hp;
    ((__half2*)lo)[i] = lp;
}

// ================= bias pre-init (resets ALL atomic targets every call) ===
__global__ __launch_bounds__(256)
void bias_init(float* __restrict__ g1, float* __restrict__ rnn,
               float* __restrict__ gi, float* __restrict__ gh,
               float* __restrict__ tbuf, float* __restrict__ out,
               const float* __restrict__ w1b, const float* __restrict__ w2b,
               const float* __restrict__ o2eb, const float* __restrict__ gbi,
               const float* __restrict__ gbh, const float* __restrict__ f1b,
               const float* __restrict__ f2b)
{
    int i = blockIdx.x * blockDim.x + threadIdx.x;
    if (i < 262144) {
        g1[i] = w1b[i & 1023] + w2b[i & 1023];
    } else if (i < 393216) {
        int j = i - 262144;
        rnn[(j >> 9) * 1536 + 1024 + (j & 511)] = o2eb[j & 511];
    } else if (i < 1179648) {
        int j = i - 393216;
        gi[j] = gbi[j % 3072];
    } else if (i < 1966080) {
        int j = i - 1179648;
        gh[j] = gbh[j % 3072];
    } else if (i < 2097152) {
        int j = i - 1966080;
        tbuf[j] = f1b[j & 511];
    } else {
        int j = i - 2097152;
        out[j] = f2b[j & 4095];
    }
}
#define BIAS_TOTAL 3145728

// ======================= small split-K mma GEMM (R5-proven, fp16) =========
#define ROWB      80
#define TILE_A_SB (128 * ROWB)
#define TILE_W_SB (64 * ROWB)
#define STAGE_SB  (2 * TILE_A_SB + 2 * TILE_W_SB)
#define SM_PART   (2 * STAGE_SB)
#define GEMM_SMEM (SM_PART + 512 + 32)

__global__ __launch_bounds__(256, 2)
void gemm64(const __half* __restrict__ Ah, const __half* __restrict__ Al,
            const __half* __restrict__ Wh, const __half* __restrict__ Wl,
            int K, int Kchunk, float* __restrict__ C, int ldc)
{
    extern __shared__ __align__(128) char smem[];
    const uint32_t sbase = (uint32_t)__cvta_generic_to_shared(smem);

    const int tid  = threadIdx.x;
    const int wid  = tid >> 5;
    const int lane = tid & 31;
    const int brow = blockIdx.y * 128;
    const int bcol = blockIdx.x * 64;
    const int k0   = blockIdx.z * Kchunk;
    const int m32  = (wid >> 1) * 32;
    const int n32w = (wid & 1) * 32;

    const int lrA = tid >> 1;
    const int cA  = (tid & 1) * 2;
    const int lrW = tid >> 2;
    const int cW  = tid & 3;
    const size_t aoff = (size_t)(brow + lrA) * K + k0;
    const size_t woff = (size_t)(bcol + lrW) * K + k0;

    auto load_stage = [&](int stage, int kk0) {
        const uint32_t sA = sbase + stage * STAGE_SB + lrA * ROWB;
        const uint32_t sW = sbase + stage * STAGE_SB + 2 * TILE_A_SB + lrW * ROWB;
        const char* pAh = (const char*)(Ah + aoff + kk0);
        const char* pAl = (const char*)(Al + aoff + kk0);
        const char* pWh = (const char*)(Wh + woff + kk0);
        const char* pWl = (const char*)(Wl + woff + kk0);
        #pragma unroll
        for (int c = cA; c < cA + 2; c++) {
            cp16(sA + c * 16, pAh + c * 16);
            cp16(sA + TILE_A_SB + c * 16, pAl + c * 16);
        }
        cp16(sW + cW * 16, pWh + cW * 16);
        cp16(sW + TILE_W_SB + cW * 16, pWl + cW * 16);
    };

    const int nk = Kchunk >> 5;

    load_stage(0, 0);
    asm volatile("cp.async.commit_group;");
    if (nk > 1) load_stage(1, 32);
    asm volatile("cp.async.commit_group;");

    float acc[2][4][4];
    #pragma unroll
    for (int i = 0; i < 2; i++)
        #pragma unroll
        for (int j = 0; j < 4; j++)
            #pragma unroll
            for (int q = 0; q < 4; q++) acc[i][j][q] = 0.f;

    const int arow_l = m32 + (lane & 15);
    const uint32_t akb = ((lane >> 4) & 1) * 16;
    const int nrow_l = n32w + (lane & 7) + ((lane >> 4) & 1) * 8;
    const uint32_t bkb = ((lane >> 3) & 1) * 16;

    for (int c = 0; c < nk; c++) {
        asm volatile("cp.async.wait_group %0;" :: "n"(1));
        __syncthreads();

        const uint32_t sb = sbase + (c & 1) * STAGE_SB;
        #pragma unroll
        for (int kk = 0; kk < 2; kk++) {
            const uint32_t kbyte = kk * 32;
            uint32_t afh[2][4], afl[2][4], bfh[4][2], bfl[4][2];
            #pragma unroll
            for (int mt = 0; mt < 2; mt++) {
                uint32_t ra = (uint32_t)((arow_l + mt * 16) * ROWB) + akb + kbyte;
                ldm4(afh[mt], sb + ra);
                ldm4(afl[mt], sb + TILE_A_SB + ra);
            }
            #pragma unroll
            for (int np = 0; np < 2; np++) {
                uint32_t rb = (uint32_t)((nrow_l + np * 16) * ROWB) + bkb + kbyte;
                uint32_t th[4], tl[4];
                ldm4(th, sb + 2 * TILE_A_SB + rb);
                ldm4(tl, sb + 2 * TILE_A_SB + TILE_W_SB + rb);
                bfh[2 * np][0] = th[0]; bfh[2 * np][1] = th[1];
                bfh[2 * np + 1][0] = th[2]; bfh[2 * np + 1][1] = th[3];
                bfl[2 * np][0] = tl[0]; bfl[2 * np][1] = tl[1];
                bfl[2 * np + 1][0] = tl[2]; bfl[2 * np + 1][1] = tl[3];
            }
            #pragma unroll
            for (int mt = 0; mt < 2; mt++)
                #pragma unroll
                for (int nt = 0; nt < 4; nt++) {
                    mma16816(acc[mt][nt], afh[mt], bfh[nt]);
                    mma16816(acc[mt][nt], afl[mt], bfh[nt]);
                    mma16816(acc[mt][nt], afh[mt], bfl[nt]);
                }
        }
        __syncthreads();

        if (c + 2 < nk) load_stage(c & 1, (c + 2) * 32);
        asm volatile("cp.async.commit_group;");
    }

    const int rloc0 = m32 + (lane >> 2);
    const int cloc0 = n32w + (lane & 3) * 2;
    #pragma unroll
    for (int mt = 0; mt < 2; mt++) {
        const int r0 = brow + rloc0 + mt * 16;
        #pragma unroll
        for (int nt = 0; nt < 4; nt++) {
            const int col = bcol + cloc0 + nt * 8;
            float* c0 = C + (size_t)r0 * ldc + col;
            float* c1 = C + (size_t)(r0 + 8) * ldc + col;
            atomicAdd(c0,     acc[mt][nt][0]);
            atomicAdd(c0 + 1, acc[mt][nt][1]);
            atomicAdd(c1,     acc[mt][nt][2]);
            atomicAdd(c1 + 1, acc[mt][nt][3]);
        }
    }
}

// ======= score GEMM: R5 shape (128x64), fp16 2-term Ah*Wh + Ah*Wl =========
// smem per stage: Ah(128 rows) + Wh(64) + Wl(64), ROWB-strided.
#define SC_STAGE (TILE_A_SB + 2 * TILE_W_SB)     // 20480
#define SC_PART  (2 * SC_STAGE)                  // 40960
#define SC_SMEM  (SC_PART + 512 + 32)

__global__ __launch_bounds__(256, 2)
void score_gemm(const __half* __restrict__ Ah,
                const __half* __restrict__ Wh, const __half* __restrict__ Wl,
                const float* __restrict__ g1, const float* __restrict__ vw,
                float* __restrict__ partial)
{
    extern __shared__ __align__(128) char smem[];
    const uint32_t sbase = (uint32_t)__cvta_generic_to_shared(smem);
    float* part_sm = (float*)(smem + SC_PART);

    const int tid  = threadIdx.x;
    const int wid  = tid >> 5;
    const int lane = tid & 31;
    const int brow = blockIdx.y * 128;
    const int bcol = blockIdx.x * 64;
    const int m32  = (wid >> 1) * 32;
    const int n32w = (wid & 1) * 32;
    const int K    = 1024;

    if (tid < 128) part_sm[tid] = 0.f;

    // loader: tid<128 -> Ah row tid (4 cp16); 128-191 -> Wh; 192-255 -> Wl
    const int sel  = tid >> 6;                   // 0,1 -> A; 2 -> Wh; 3 -> Wl
    const int lrow = (sel < 2) ? tid : (tid & 63);
    const __half* gsrc = (sel < 2) ? (Ah + (size_t)(brow + lrow) * K)
                       : (sel == 2) ? (Wh + (size_t)(bcol + lrow) * K)
                                    : (Wl + (size_t)(bcol + lrow) * K);
    const uint32_t sdst = (sel < 2) ? (uint32_t)(lrow * ROWB)
                        : (sel == 2) ? (uint32_t)(TILE_A_SB + lrow * ROWB)
                                     : (uint32_t)(TILE_A_SB + TILE_W_SB + lrow * ROWB);

    auto load_stage = [&](int stage, int kk0) {
        const uint32_t sb = sbase + stage * SC_STAGE + sdst;
        const char* g = (const char*)(gsrc + kk0);
        #pragma unroll
        for (int c = 0; c < 4; c++) cp16(sb + c * 16, g + c * 16);
    };

    const int nk = 32;                           // 1024/32

    load_stage(0, 0);
    asm volatile("cp.async.commit_group;");
    load_stage(1, 32);
    asm volatile("cp.async.commit_group;");

    float acc[2][4][4];
    #pragma unroll
    for (int i = 0; i < 2; i++)
        #pragma unroll
        for (int j = 0; j < 4; j++)
            #pragma unroll
            for (int q = 0; q < 4; q++) acc[i][j][q] = 0.f;

    const int arow_l = m32 + (lane & 15);
    const uint32_t akb = ((lane >> 4) & 1) * 16;
    const int nrow_l = n32w + (lane & 7) + ((lane >> 4) & 1) * 8;
    const uint32_t bkb = ((lane >> 3) & 1) * 16;

    for (int c = 0; c < nk; c++) {
        asm volatile("cp.async.wait_group %0;" :: "n"(1));
        __syncthreads();

        const uint32_t sb = sbase + (c & 1) * SC_STAGE;
        #pragma unroll
        for (int kk = 0; kk < 2; kk++) {
            const uint32_t kbyte = kk * 32;
            uint32_t afh[2][4], bfh[4][2], bfl[4][2];
            #pragma unroll
            for (int mt = 0; mt < 2; mt++) {
                uint32_t ra = (uint32_t)((arow_l + mt * 16) * ROWB) + akb + kbyte;
                ldm4(afh[mt], sb + ra);
            }
            #pragma unroll
            for (int np = 0; np < 2; np++) {
                uint32_t rb = (uint32_t)((nrow_l + np * 16) * ROWB) + bkb + kbyte;
                uint32_t th[4], tl[4];
                ldm4(th, sb + TILE_A_SB + rb);
                ldm4(tl, sb + TILE_A_SB + TILE_W_SB + rb);
                bfh[2 * np][0] = th[0]; bfh[2 * np][1] = th[1];
                bfh[2 * np + 1][0] = th[2]; bfh[2 * np + 1][1] = th[3];
                bfl[2 * np][0] = tl[0]; bfl[2 * np][1] = tl[1];
                bfl[2 * np + 1][0] = tl[2]; bfl[2 * np + 1][1] = tl[3];
            }
            #pragma unroll
            for (int mt = 0; mt < 2; mt++)
                #pragma unroll
                for (int nt = 0; nt < 4; nt++) {
                    mma16816(acc[mt][nt], afh[mt], bfh[nt]);
                    mma16816(acc[mt][nt], afh[mt], bfl[nt]);
                }
        }
        __syncthreads();

        if (c + 2 < nk) load_stage(c & 1, (c + 2) * 32);
        asm volatile("cp.async.commit_group;");
    }

    // ---- epilogue: weighted-tanh row partial sums ----
    const int rloc0 = m32 + (lane >> 2);
    const int cloc0 = n32w + (lane & 3) * 2;
    const float* g1r = g1 + (size_t)blockIdx.y * 1024;
    #pragma unroll
    for (int mt = 0; mt < 2; mt++) {
        float s0 = 0.f, s1 = 0.f;
        #pragma unroll
        for (int nt = 0; nt < 4; nt++) {
            int col = bcol + cloc0 + nt * 8;
            float gw0 = g1r[col],     vw0 = vw[col];
            float gw1 = g1r[col + 1], vw1 = vw[col + 1];
            s0 += tanhf(acc[mt][nt][0] + gw0) * vw0;
            s0 += tanhf(acc[mt][nt][1] + gw1) * vw1;
            s1 += tanhf(acc[mt][nt][2] + gw0) * vw0;
            s1 += tanhf(acc[mt][nt][3] + gw1) * vw1;
        }
        atomicAdd(&part_sm[rloc0 + mt * 16], s0);
        atomicAdd(&part_sm[rloc0 + mt * 16 + 8], s1);
    }
    __syncthreads();
    if (tid < 128)
        partial[(size_t)(brow + tid) * gridDim.x + blockIdx.x] = part_sm[tid];
}

// ============== softmax + context (one block per batch element) ===========
__global__ __launch_bounds__(256)
void attn_softmax_context(const float* __restrict__ part, int npart,
                          const float* __restrict__ enc,
                          const float* __restrict__ Vb,
                          float* __restrict__ attn_out,
                          float* __restrict__ rnn)
{
    const int b   = blockIdx.x;
    const int tid = threadIdx.x;
    __shared__ float logit[LL];

    if (tid < LL) {
        const float* pr = part + (size_t)(b * LL + tid) * npart;
        float s = Vb[0];
        for (int j = 0; j < npart; j++) s += pr[j];
        logit[tid] = s;
    }
    __syncthreads();

    if (tid < 32) {
        const int lane = tid;
        float m = -1e30f;
        for (int l = lane; l < LL; l += 32) m = fmaxf(m, logit[l]);
        #pragma unroll
        for (int o = 16; o; o >>= 1) m = fmaxf(m, __shfl_xor_sync(0xffffffffu, m, o));
        float s = 0.f;
        for (int l = lane; l < LL; l += 32) {
            float e = expf(logit[l] - m);
            logit[l] = e;
            s += e;
        }
        #pragma unroll
        for (int o = 16; o; o >>= 1) s += __shfl_xor_sync(0xffffffffu, s, o);
        float inv = 1.f / s;
        for (int l = lane; l < LL; l += 32) logit[l] *= inv;
    }
    __syncthreads();

    if (tid < LL) attn_out[b * LL + tid] = logit[tid];

    float4 acc = make_float4(0.f, 0.f, 0.f, 0.f);
    const float* encb = enc + (size_t)b * LL * EENC;
    const int e4 = tid * 4;
    #pragma unroll 4
    for (int l = 0; l < LL; l++) {
        float a = logit[l];
        float4 v = *(const float4*)(encb + (size_t)l * EENC + e4);
        acc.x += a * v.x; acc.y += a * v.y; acc.z += a * v.z; acc.w += a * v.w;
    }
    *(float4*)(rnn + (size_t)b * 1536 + e4) = acc;
}

// ============================ GRU gates ===================================
__global__ __launch_bounds__(256)
void gru_gate(const float* __restrict__ gi, const float* __restrict__ gh,
              const float* __restrict__ h0, float* __restrict__ hnew)
{
    const int idx = blockIdx.x * blockDim.x + threadIdx.x;
    const int b = idx >> 10;
    const int d = idx & 1023;
    const float* gib = gi + (size_t)b * 3072;
    const float* ghb = gh + (size_t)b * 3072;
    float r = 1.f / (1.f + expf(-(gib[d] + ghb[d])));
    float z = 1.f / (1.f + expf(-(gib[1024 + d] + ghb[1024 + d])));
    float n = tanhf(gib[2048 + d] + r * ghb[2048 + d]);
    hnew[idx] = (1.f - z) * n + z * h0[idx];
}

// ============================ launch ======================================
extern "C" void kernel_launch(void* const* d_in, const int* in_sizes, int n_in,
                              void* d_out, int out_size)
{
    (void)in_sizes; (void)n_in; (void)out_size;

    const float* x      = (const float*)d_in[0];
    const float* hidden = (const float*)d_in[1];
    const float* enc    = (const float*)d_in[2];
    const float* W1_w   = (const float*)d_in[3];
    const float* W1_b   = (const float*)d_in[4];
    const float* W2_w   = (const float*)d_in[5];
    const float* W2_b   = (const float*)d_in[6];
    const float* V_w    = (const float*)d_in[7];
    const float* V_b    = (const float*)d_in[8];
    const float* o2e_w  = (const float*)d_in[9];
    const float* o2e_b  = (const float*)d_in[10];
    const float* gwi    = (const float*)d_in[11];
    const float* gwh    = (const float*)d_in[12];
    const float* gbi    = (const float*)d_in[13];
    const float* gbh    = (const float*)d_in[14];
    const float* f1w    = (const float*)d_in[15];
    const float* f1b    = (const float*)d_in[16];
    const float* f2w    = (const float*)d_in[17];
    const float* f2b    = (const float*)d_in[18];

    float* out  = (float*)d_out;
    float* hnew = out + (size_t)BB * VOC;
    float* attn = hnew + (size_t)BB * DDEC;

    __half* bh = nullptr;
    __half* bl = nullptr;
    float* fs = nullptr;
    cudaGetSymbolAddress((void**)&bh, g_bh);
    cudaGetSymbolAddress((void**)&bl, g_bl);
    cudaGetSymbolAddress((void**)&fs, g_f32);

    float* g1   = fs + F_G1;
    float* rnn  = fs + F_RNN;
    float* gi   = fs + F_GI;
    float* gh   = fs + F_GH;
    float* tbuf = fs + F_T;
    float* part = fs + F_PART;

    cudaFuncSetAttribute(gemm64,     cudaFuncAttributeMaxDynamicSharedMemorySize, GEMM_SMEM);
    cudaFuncSetAttribute(score_gemm, cudaFuncAttributeMaxDynamicSharedMemorySize, SC_SMEM);

    dim3 blk(256);

    // 0) weight splits
    split_weights<<<WN7 / 256, 256>>>(W1_w, W2_w, o2e_w, gwi, gwh, f1w, f2w);
    // 1) activation splits
    split_acts<<<AN3 / 256, 256>>>(enc, x, hidden);
    // 2) bias preinit
    bias_init<<<BIAS_TOTAL / 256, 256>>>(g1, rnn, gi, gh, tbuf, out,
                                         W1_b, W2_b, o2e_b, gbi, gbh, f1b, f2b);

    // 3) g1 += h0 @ W2^T            (256x1024, K=1024, splitK=4)
    gemm64<<<dim3(16, 2, 4), blk, GEMM_SMEM>>>(
        bh + OFF_HID, bl + OFF_HID, bh + OFF_W2, bl + OFF_W2,
        1024, 256, g1, 1024);

    // 4) score GEMM -> weighted-tanh row partials   (32768x1024, K=1024)
    score_gemm<<<dim3(16, 256), blk, SC_SMEM>>>(
        bh + OFF_ENC, bh + OFF_W1, bl + OFF_W1, g1, V_w, part);

    // 5) softmax + attn out + context -> rnn[:, 0:1024]
    attn_softmax_context<<<BB, 256>>>(part, 16, enc, V_b, attn, rnn);

    // 6) x_emb += x @ out2emb^T     (256x512, K=4096, splitK=8)
    gemm64<<<dim3(8, 2, 8), blk, GEMM_SMEM>>>(
        bh + OFF_X, bl + OFF_X, bh + OFF_O2E, bl + OFF_O2E,
        4096, 512, rnn + 1024, 1536);

    // 7) gh += h0 @ gru_wh^T        (256x3072, K=1024, splitK=2)
    gemm64<<<dim3(48, 2, 2), blk, GEMM_SMEM>>>(
        bh + OFF_HID, bl + OFF_HID, bh + OFF_GWH, bl + OFF_GWH,
        1024, 512, gh, 3072);

    // 8) rnn -> fp16
    f32_split<<<(393216 / 2) / 256, 256>>>(rnn, bh + OFF_RNN, bl + OFF_RNN, 393216 / 2);

    // 9) gi += rnn_in @ gru_wi^T    (256x3072, K=1536, splitK=2)
    gemm64<<<dim3(48, 2, 2), blk, GEMM_SMEM>>>(
        bh + OFF_RNN, bl + OFF_RNN, bh + OFF_GWI, bl + OFF_GWI,
        1536, 768, gi, 3072);

    // 10) GRU gates -> h_new (output)
    gru_gate<<<(BB * DDEC) / 256, 256>>>(gi, gh, hidden, hnew);

    // 11) h_new -> fp16
    f32_split<<<(262144 / 2) / 256, 256>>>(hnew, bh + OFF_HNEW, bl + OFF_HNEW, 262144 / 2);

    // 12) tbuf += h_new @ fc1^T     (256x512, K=1024, splitK=8)
    gemm64<<<dim3(8, 2, 8), blk, GEMM_SMEM>>>(
        bh + OFF_HNEW, bl + OFF_HNEW, bh + OFF_F1, bl + OFF_F1,
        1024, 128, tbuf, 512);

    // 13) t = tanh(tbuf) -> fp16
    f32_split_tanh<<<(131072 / 2) / 256, 256>>>(tbuf, bh + OFF_T, bl + OFF_T, 131072 / 2);

    // 14) out += t @ fc2^T          (256x4096, K=512, splitK=2)
    gemm64<<<dim3(64, 2, 2), blk, GEMM_SMEM>>>(
        bh + OFF_T, bl + OFF_T, bh + OFF_F2, bl + OFF_F2,
        512, 256, out, 4096);
}

// round 8
// speedup vs baseline: 1.3950x; 1.1939x over previous
#include <cuda_runtime.h>
#include <cuda_fp16.h>
#include <cstdint>
#include <math.h>

// Problem dims
#define BB   256
#define LL   128
#define VOC  4096
#define EENC 1024
#define DDEC 1024
#define EEMB 512

// ======================= scratch (module-load allocated) ==================
#define OFF_ENC   0ull
#define OFF_W1    (OFF_ENC + 33554432ull)
#define OFF_W2    (OFF_W1  + 1048576ull)
#define OFF_O2E   (OFF_W2  + 1048576ull)
#define OFF_GWI   (OFF_O2E + 2097152ull)
#define OFF_GWH   (OFF_GWI + 4718592ull)
#define OFF_F1    (OFF_GWH + 3145728ull)
#define OFF_F2    (OFF_F1  + 524288ull)
#define OFF_X     (OFF_F2  + 2097152ull)
#define OFF_HID   (OFF_X   + 1048576ull)
#define OFF_RNN   (OFF_HID + 262144ull)
#define OFF_HNEW  (OFF_RNN + 393216ull)
#define OFF_T     (OFF_HNEW+ 262144ull)
#define BF_TOTAL  (OFF_T   + 131072ull)

__device__ __half g_bh[BF_TOTAL];
__device__ __half g_bl[BF_TOTAL];

#define F_G1    0ull
#define F_RNN   (F_G1   + 262144ull)
#define F_GI    (F_RNN  + 393216ull)
#define F_GH    (F_GI   + 786432ull)
#define F_T     (F_GH   + 786432ull)
#define F_PART  (F_T    + 131072ull)
#define F_TOTAL (F_PART + 524288ull)

__device__ float g_f32[F_TOTAL];

// ======================= small helpers ====================================
__device__ __forceinline__ void cp16(uint32_t s, const void* g) {
    asm volatile("cp.async.cg.shared.global [%0], [%1], 16;"
                 :: "r"(s), "l"(__cvta_generic_to_global(g)));
}
__device__ __forceinline__ void ldm4(uint32_t* r, uint32_t addr) {
    asm volatile("ldmatrix.sync.aligned.m8n8.x4.shared.b16 {%0,%1,%2,%3}, [%4];"
        : "=r"(r[0]), "=r"(r[1]), "=r"(r[2]), "=r"(r[3]) : "r"(addr));
}
__device__ __forceinline__ void mma16816(float* c, const uint32_t* a, const uint32_t* b) {
    asm volatile("mma.sync.aligned.m16n8k16.row.col.f32.f16.f16.f32 "
        "{%0,%1,%2,%3}, {%4,%5,%6,%7}, {%8,%9}, {%0,%1,%2,%3};"
        : "+f"(c[0]), "+f"(c[1]), "+f"(c[2]), "+f"(c[3])
        : "r"(a[0]), "r"(a[1]), "r"(a[2]), "r"(a[3]), "r"(b[0]), "r"(b[1]));
}
__device__ __forceinline__ void do_split(const float* src, int local,
                                         unsigned long long dst) {
    float2 v = ((const float2*)src)[local];
    __half h0 = __float2half_rn(v.x);
    __half h1 = __float2half_rn(v.y);
    __half2 hp; hp.x = h0; hp.y = h1;
    __half2 lp;
    lp.x = __float2half_rn(v.x - __half2float(h0));
    lp.y = __float2half_rn(v.y - __half2float(h1));
    ((__half2*)(g_bh + dst))[local] = hp;
    ((__half2*)(g_bl + dst))[local] = lp;
}

// ======================= fused split kernels ==============================
#define WN1 524288
#define WN2 1048576
#define WN3 2097152
#define WN4 4456448
#define WN5 6029312
#define WN6 6291456
#define WN7 7340032
__global__ __launch_bounds__(256)
void split_weights(const float* __restrict__ W1, const float* __restrict__ W2,
                   const float* __restrict__ o2e, const float* __restrict__ gwi,
                   const float* __restrict__ gwh, const float* __restrict__ f1,
                   const float* __restrict__ f2)
{
    int i = blockIdx.x * blockDim.x + threadIdx.x;
    if (i < WN1)      do_split(W1,  i,       OFF_W1);
    else if (i < WN2) do_split(W2,  i - WN1, OFF_W2);
    else if (i < WN3) do_split(o2e, i - WN2, OFF_O2E);
    else if (i < WN4) do_split(gwi, i - WN3, OFF_GWI);
    else if (i < WN5) do_split(gwh, i - WN4, OFF_GWH);
    else if (i < WN6) do_split(f1,  i - WN5, OFF_F1);
    else if (i < WN7) do_split(f2,  i - WN6, OFF_F2);
}
#define AN1 16777216
#define AN2 17301504
#define AN3 17432576
__global__ __launch_bounds__(256)
void split_acts(const float* __restrict__ enc, const float* __restrict__ x,
                const float* __restrict__ hid)
{
    int i = blockIdx.x * blockDim.x + threadIdx.x;
    if (i < AN1)      do_split(enc, i,       OFF_ENC);
    else if (i < AN2) do_split(x,   i - AN1, OFF_X);
    else if (i < AN3) do_split(hid, i - AN2, OFF_HID);
}
__global__ __launch_bounds__(256)
void f32_split(const float* __restrict__ in, __half* __restrict__ hi,
               __half* __restrict__ lo, int n2)
{
    int i = blockIdx.x * blockDim.x + threadIdx.x;
    if (i >= n2) return;
    float2 v = ((const float2*)in)[i];
    __half h0 = __float2half_rn(v.x);
    __half h1 = __float2half_rn(v.y);
    __half2 hp; hp.x = h0; hp.y = h1;
    __half2 lp;
    lp.x = __float2half_rn(v.x - __half2float(h0));
    lp.y = __float2half_rn(v.y - __half2float(h1));
    ((__half2*)hi)[i] = hp;
    ((__half2*)lo)[i] = lp;
}
__global__ __launch_bounds__(256)
void f32_split_tanh(const float* __restrict__ in, __half* __restrict__ hi,
                    __half* __restrict__ lo, int n2)
{
    int i = blockIdx.x * blockDim.x + threadIdx.x;
    if (i >= n2) return;
    float2 v = ((const float2*)in)[i];
    v.x = tanhf(v.x); v.y = tanhf(v.y);
    __half h0 = __float2half_rn(v.x);
    __half h1 = __float2half_rn(v.y);
    __half2 hp; hp.x = h0; hp.y = h1;
    __half2 lp;
    lp.x = __float2half_rn(v.x - __half2float(h0));
    lp.y = __float2half_rn(v.y - __half2float(h1));
    ((__half2*)hi)[i] = hp;
    ((__half2*)lo)[i] = lp;
}

// ================= bias pre-init (g1 removed; rest unchanged) =============
__global__ __launch_bounds__(256)
void bias_init(float* __restrict__ rnn,
               float* __restrict__ gi, float* __restrict__ gh,
               float* __restrict__ tbuf, float* __restrict__ out,
               const float* __restrict__ o2eb, const float* __restrict__ gbi,
               const float* __restrict__ gbh, const float* __restrict__ f1b,
               const float* __restrict__ f2b)
{
    int i = blockIdx.x * blockDim.x + threadIdx.x;
    if (i < 131072) {
        rnn[(i >> 9) * 1536 + 1024 + (i & 511)] = o2eb[i & 511];
    } else if (i < 917504) {
        int j = i - 131072;
        gi[j] = gbi[j % 3072];
    } else if (i < 1703936) {
        int j = i - 917504;
        gh[j] = gbh[j % 3072];
    } else if (i < 1835008) {
        int j = i - 1703936;
        tbuf[j] = f1b[j & 511];
    } else {
        int j = i - 1835008;
        out[j] = f2b[j & 4095];
    }
}
#define BIAS_TOTAL 2883584

// ======================= small split-K mma GEMM (R5-proven, fp16) =========
#define ROWB      80
#define TILE_A_SB (128 * ROWB)
#define TILE_W_SB (64 * ROWB)
#define STAGE_SB  (2 * TILE_A_SB + 2 * TILE_W_SB)
#define SM_PART   (2 * STAGE_SB)
#define GEMM_SMEM (SM_PART + 512 + 32)

__global__ __launch_bounds__(256, 2)
void gemm64(const __half* __restrict__ Ah, const __half* __restrict__ Al,
            const __half* __restrict__ Wh, const __half* __restrict__ Wl,
            int K, int Kchunk, float* __restrict__ C, int ldc)
{
    extern __shared__ __align__(128) char smem[];
    const uint32_t sbase = (uint32_t)__cvta_generic_to_shared(smem);

    const int tid  = threadIdx.x;
    const int wid  = tid >> 5;
    const int lane = tid & 31;
    const int brow = blockIdx.y * 128;
    const int bcol = blockIdx.x * 64;
    const int k0   = blockIdx.z * Kchunk;
    const int m32  = (wid >> 1) * 32;
    const int n32w = (wid & 1) * 32;

    const int lrA = tid >> 1;
    const int cA  = (tid & 1) * 2;
    const int lrW = tid >> 2;
    const int cW  = tid & 3;
    const size_t aoff = (size_t)(brow + lrA) * K + k0;
    const size_t woff = (size_t)(bcol + lrW) * K + k0;

    auto load_stage = [&](int stage, int kk0) {
        const uint32_t sA = sbase + stage * STAGE_SB + lrA * ROWB;
        const uint32_t sW = sbase + stage * STAGE_SB + 2 * TILE_A_SB + lrW * ROWB;
        const char* pAh = (const char*)(Ah + aoff + kk0);
        const char* pAl = (const char*)(Al + aoff + kk0);
        const char* pWh = (const char*)(Wh + woff + kk0);
        const char* pWl = (const char*)(Wl + woff + kk0);
        #pragma unroll
        for (int c = cA; c < cA + 2; c++) {
            cp16(sA + c * 16, pAh + c * 16);
            cp16(sA + TILE_A_SB + c * 16, pAl + c * 16);
        }
        cp16(sW + cW * 16, pWh + cW * 16);
        cp16(sW + TILE_W_SB + cW * 16, pWl + cW * 16);
    };

    const int nk = Kchunk >> 5;

    load_stage(0, 0);
    asm volatile("cp.async.commit_group;");
    if (nk > 1) load_stage(1, 32);
    asm volatile("cp.async.commit_group;");

    float acc[2][4][4];
    #pragma unroll
    for (int i = 0; i < 2; i++)
        #pragma unroll
        for (int j = 0; j < 4; j++)
            #pragma unroll
            for (int q = 0; q < 4; q++) acc[i][j][q] = 0.f;

    const int arow_l = m32 + (lane & 15);
    const uint32_t akb = ((lane >> 4) & 1) * 16;
    const int nrow_l = n32w + (lane & 7) + ((lane >> 4) & 1) * 8;
    const uint32_t bkb = ((lane >> 3) & 1) * 16;

    for (int c = 0; c < nk; c++) {
        asm volatile("cp.async.wait_group %0;" :: "n"(1));
        __syncthreads();

        const uint32_t sb = sbase + (c & 1) * STAGE_SB;
        #pragma unroll
        for (int kk = 0; kk < 2; kk++) {
            const uint32_t kbyte = kk * 32;
            uint32_t afh[2][4], afl[2][4], bfh[4][2], bfl[4][2];
            #pragma unroll
            for (int mt = 0; mt < 2; mt++) {
                uint32_t ra = (uint32_t)((arow_l + mt * 16) * ROWB) + akb + kbyte;
                ldm4(afh[mt], sb + ra);
                ldm4(afl[mt], sb + TILE_A_SB + ra);
            }
            #pragma unroll
            for (int np = 0; np < 2; np++) {
                uint32_t rb = (uint32_t)((nrow_l + np * 16) * ROWB) + bkb + kbyte;
                uint32_t th[4], tl[4];
                ldm4(th, sb + 2 * TILE_A_SB + rb);
                ldm4(tl, sb + 2 * TILE_A_SB + TILE_W_SB + rb);
                bfh[2 * np][0] = th[0]; bfh[2 * np][1] = th[1];
                bfh[2 * np + 1][0] = th[2]; bfh[2 * np + 1][1] = th[3];
                bfl[2 * np][0] = tl[0]; bfl[2 * np][1] = tl[1];
                bfl[2 * np + 1][0] = tl[2]; bfl[2 * np + 1][1] = tl[3];
            }
            #pragma unroll
            for (int mt = 0; mt < 2; mt++)
                #pragma unroll
                for (int nt = 0; nt < 4; nt++) {
                    mma16816(acc[mt][nt], afh[mt], bfh[nt]);
                    mma16816(acc[mt][nt], afl[mt], bfh[nt]);
                    mma16816(acc[mt][nt], afh[mt], bfl[nt]);
                }
        }
        __syncthreads();

        if (c + 2 < nk) load_stage(c & 1, (c + 2) * 32);
        asm volatile("cp.async.commit_group;");
    }

    const int rloc0 = m32 + (lane >> 2);
    const int cloc0 = n32w + (lane & 3) * 2;
    #pragma unroll
    for (int mt = 0; mt < 2; mt++) {
        const int r0 = brow + rloc0 + mt * 16;
        #pragma unroll
        for (int nt = 0; nt < 4; nt++) {
            const int col = bcol + cloc0 + nt * 8;
            float* c0 = C + (size_t)r0 * ldc + col;
            float* c1 = C + (size_t)(r0 + 8) * ldc + col;
            atomicAdd(c0,     acc[mt][nt][0]);
            atomicAdd(c0 + 1, acc[mt][nt][1]);
            atomicAdd(c1,     acc[mt][nt][2]);
            atomicAdd(c1 + 1, acc[mt][nt][3]);
        }
    }
}

// ========== gemm64_bias: direct-store variant with 2-bias epilogue ========
// Full-K (no split), C = A@W^T + b1 + b2. Used for g1 so score can be idx 3.
__global__ __launch_bounds__(256, 2)
void gemm64_bias(const __half* __restrict__ Ah, const __half* __restrict__ Al,
                 const __half* __restrict__ Wh, const __half* __restrict__ Wl,
                 int K, float* __restrict__ C, int ldc,
                 const float* __restrict__ b1, const float* __restrict__ b2)
{
    extern __shared__ __align__(128) char smem[];
    const uint32_t sbase = (uint32_t)__cvta_generic_to_shared(smem);

    const int tid  = threadIdx.x;
    const int wid  = tid >> 5;
    const int lane = tid & 31;
    const int brow = blockIdx.y * 128;
    const int bcol = blockIdx.x * 64;
    const int m32  = (wid >> 1) * 32;
    const int n32w = (wid & 1) * 32;

    const int lrA = tid >> 1;
    const int cA  = (tid & 1) * 2;
    const int lrW = tid >> 2;
    const int cW  = tid & 3;
    const size_t aoff = (size_t)(brow + lrA) * K;
    const size_t woff = (size_t)(bcol + lrW) * K;

    auto load_stage = [&](int stage, int kk0) {
        const uint32_t sA = sbase + stage * STAGE_SB + lrA * ROWB;
        const uint32_t sW = sbase + stage * STAGE_SB + 2 * TILE_A_SB + lrW * ROWB;
        const char* pAh = (const char*)(Ah + aoff + kk0);
        const char* pAl = (const char*)(Al + aoff + kk0);
        const char* pWh = (const char*)(Wh + woff + kk0);
        const char* pWl = (const char*)(Wl + woff + kk0);
        #pragma unroll
        for (int c = cA; c < cA + 2; c++) {
            cp16(sA + c * 16, pAh + c * 16);
            cp16(sA + TILE_A_SB + c * 16, pAl + c * 16);
        }
        cp16(sW + cW * 16, pWh + cW * 16);
        cp16(sW + TILE_W_SB + cW * 16, pWl + cW * 16);
    };

    const int nk = K >> 5;

    load_stage(0, 0);
    asm volatile("cp.async.commit_group;");
    load_stage(1, 32);
    asm volatile("cp.async.commit_group;");

    float acc[2][4][4];
    #pragma unroll
    for (int i = 0; i < 2; i++)
        #pragma unroll
        for (int j = 0; j < 4; j++)
            #pragma unroll
            for (int q = 0; q < 4; q++) acc[i][j][q] = 0.f;

    const int arow_l = m32 + (lane & 15);
    const uint32_t akb = ((lane >> 4) & 1) * 16;
    const int nrow_l = n32w + (lane & 7) + ((lane >> 4) & 1) * 8;
    const uint32_t bkb = ((lane >> 3) & 1) * 16;

    for (int c = 0; c < nk; c++) {
        asm volatile("cp.async.wait_group %0;" :: "n"(1));
        __syncthreads();

        const uint32_t sb = sbase + (c & 1) * STAGE_SB;
        #pragma unroll
        for (int kk = 0; kk < 2; kk++) {
            const uint32_t kbyte = kk * 32;
            uint32_t afh[2][4], afl[2][4], bfh[4][2], bfl[4][2];
            #pragma unroll
            for (int mt = 0; mt < 2; mt++) {
                uint32_t ra = (uint32_t)((arow_l + mt * 16) * ROWB) + akb + kbyte;
                ldm4(afh[mt], sb + ra);
                ldm4(afl[mt], sb + TILE_A_SB + ra);
            }
            #pragma unroll
            for (int np = 0; np < 2; np++) {
                uint32_t rb = (uint32_t)((nrow_l + np * 16) * ROWB) + bkb + kbyte;
                uint32_t th[4], tl[4];
                ldm4(th, sb + 2 * TILE_A_SB + rb);
                ldm4(tl, sb + 2 * TILE_A_SB + TILE_W_SB + rb);
                bfh[2 * np][0] = th[0]; bfh[2 * np][1] = th[1];
                bfh[2 * np + 1][0] = th[2]; bfh[2 * np + 1][1] = th[3];
                bfl[2 * np][0] = tl[0]; bfl[2 * np][1] = tl[1];
                bfl[2 * np + 1][0] = tl[2]; bfl[2 * np + 1][1] = tl[3];
            }
            #pragma unroll
            for (int mt = 0; mt < 2; mt++)
                #pragma unroll
                for (int nt = 0; nt < 4; nt++) {
                    mma16816(acc[mt][nt], afh[mt], bfh[nt]);
                    mma16816(acc[mt][nt], afl[mt], bfh[nt]);
                    mma16816(acc[mt][nt], afh[mt], bfl[nt]);
                }
        }
        __syncthreads();

        if (c + 2 < nk) load_stage(c & 1, (c + 2) * 32);
        asm volatile("cp.async.commit_group;");
    }

    const int rloc0 = m32 + (lane >> 2);
    const int cloc0 = n32w + (lane & 3) * 2;
    #pragma unroll
    for (int mt = 0; mt < 2; mt++) {
        const int r0 = brow + rloc0 + mt * 16;
        #pragma unroll
        for (int nt = 0; nt < 4; nt++) {
            const int col = bcol + cloc0 + nt * 8;
            float2 bb = make_float2(b1[col] + b2[col], b1[col + 1] + b2[col + 1]);
            *(float2*)(C + (size_t)r0 * ldc + col) =
                make_float2(acc[mt][nt][0] + bb.x, acc[mt][nt][1] + bb.y);
            *(float2*)(C + (size_t)(r0 + 8) * ldc + col) =
                make_float2(acc[mt][nt][2] + bb.x, acc[mt][nt][3] + bb.y);
        }
    }
}

// ======= score GEMM: 128x64, fp16 1-term Ah*Wh, fused weighted-tanh =======
#define SC_STAGE (TILE_A_SB + TILE_W_SB)         // 15360
#define SC_PART  (2 * SC_STAGE)                  // 30720
#define SC_SMEM  (SC_PART + 512 + 32)

__global__ __launch_bounds__(256, 2)
void score_gemm(const __half* __restrict__ Ah, const __half* __restrict__ Wh,
                const float* __restrict__ g1, const float* __restrict__ vw,
                float* __restrict__ partial)
{
    extern __shared__ __align__(128) char smem[];
    const uint32_t sbase = (uint32_t)__cvta_generic_to_shared(smem);
    float* part_sm = (float*)(smem + SC_PART);

    const int tid  = threadIdx.x;
    const int wid  = tid >> 5;
    const int lane = tid & 31;
    const int brow = blockIdx.y * 128;
    const int bcol = blockIdx.x * 64;
    const int m32  = (wid >> 1) * 32;
    const int n32w = (wid & 1) * 32;
    const int K    = 1024;

    if (tid < 128) part_sm[tid] = 0.f;

    // loader: tid<128 -> A row tid; tid 128-191 -> Wh row; rest idle
    const int sel  = tid >> 7;
    const int lrow = sel ? (tid & 63) : tid;
    const bool active = (tid < 192);
    const __half* gsrc = sel ? (Wh + (size_t)(bcol + lrow) * K)
                             : (Ah + (size_t)(brow + lrow) * K);
    const uint32_t sdst = sel ? (uint32_t)(TILE_A_SB + lrow * ROWB)
                              : (uint32_t)(lrow * ROWB);

    auto load_stage = [&](int stage, int kk0) {
        if (!active) return;
        const uint32_t sb = sbase + stage * SC_STAGE + sdst;
        const char* g = (const char*)(gsrc + kk0);
        #pragma unroll
        for (int c = 0; c < 4; c++) cp16(sb + c * 16, g + c * 16);
    };

    const int nk = 32;

    load_stage(0, 0);
    asm volatile("cp.async.commit_group;");
    load_stage(1, 32);
    asm volatile("cp.async.commit_group;");

    float acc[2][4][4];
    #pragma unroll
    for (int i = 0; i < 2; i++)
        #pragma unroll
        for (int j = 0; j < 4; j++)
            #pragma unroll
            for (int q = 0; q < 4; q++) acc[i][j][q] = 0.f;

    const int arow_l = m32 + (lane & 15);
    const uint32_t akb = ((lane >> 4) & 1) * 16;
    const int nrow_l = n32w + (lane & 7) + ((lane >> 4) & 1) * 8;
    const uint32_t bkb = ((lane >> 3) & 1) * 16;

    for (int c = 0; c < nk; c++) {
        asm volatile("cp.async.wait_group %0;" :: "n"(1));
        __syncthreads();

        const uint32_t sb = sbase + (c & 1) * SC_STAGE;
        #pragma unroll
        for (int kk = 0; kk < 2; kk++) {
            const uint32_t kbyte = kk * 32;
            uint32_t afh[2][4], bfh[4][2];
            #pragma unroll
            for (int mt = 0; mt < 2; mt++) {
                uint32_t ra = (uint32_t)((arow_l + mt * 16) * ROWB) + akb + kbyte;
                ldm4(afh[mt], sb + ra);
            }
            #pragma unroll
            for (int np = 0; np < 2; np++) {
                uint32_t rb = (uint32_t)((nrow_l + np * 16) * ROWB) + bkb + kbyte;
                uint32_t th[4];
                ldm4(th, sb + TILE_A_SB + rb);
                bfh[2 * np][0] = th[0]; bfh[2 * np][1] = th[1];
                bfh[2 * np + 1][0] = th[2]; bfh[2 * np + 1][1] = th[3];
            }
            #pragma unroll
            for (int mt = 0; mt < 2; mt++)
                #pragma unroll
                for (int nt = 0; nt < 4; nt++)
                    mma16816(acc[mt][nt], afh[mt], bfh[nt]);
        }
        __syncthreads();

        if (c + 2 < nk) load_stage(c & 1, (c + 2) * 32);
        asm volatile("cp.async.commit_group;");
    }

    // ---- epilogue: weighted-tanh row partial sums ----
    const int rloc0 = m32 + (lane >> 2);
    const int cloc0 = n32w + (lane & 3) * 2;
    const float* g1r = g1 + (size_t)blockIdx.y * 1024;
    #pragma unroll
    for (int mt = 0; mt < 2; mt++) {
        float s0 = 0.f, s1 = 0.f;
        #pragma unroll
        for (int nt = 0; nt < 4; nt++) {
            int col = bcol + cloc0 + nt * 8;
            float gw0 = g1r[col],     vw0 = vw[col];
            float gw1 = g1r[col + 1], vw1 = vw[col + 1];
            s0 += tanhf(acc[mt][nt][0] + gw0) * vw0;
            s0 += tanhf(acc[mt][nt][1] + gw1) * vw1;
            s1 += tanhf(acc[mt][nt][2] + gw0) * vw0;
            s1 += tanhf(acc[mt][nt][3] + gw1) * vw1;
        }
        atomicAdd(&part_sm[rloc0 + mt * 16], s0);
        atomicAdd(&part_sm[rloc0 + mt * 16 + 8], s1);
    }
    __syncthreads();
    if (tid < 128)
        partial[(size_t)(brow + tid) * gridDim.x + blockIdx.x] = part_sm[tid];
}

// ============== softmax + context (one block per batch element) ===========
__global__ __launch_bounds__(256)
void attn_softmax_context(const float* __restrict__ part, int npart,
                          const float* __restrict__ enc,
                          const float* __restrict__ Vb,
                          float* __restrict__ attn_out,
                          float* __restrict__ rnn)
{
    const int b   = blockIdx.x;
    const int tid = threadIdx.x;
    __shared__ float logit[LL];

    if (tid < LL) {
        const float* pr = part + (size_t)(b * LL + tid) * npart;
        float s = Vb[0];
        for (int j = 0; j < npart; j++) s += pr[j];
        logit[tid] = s;
    }
    __syncthreads();

    if (tid < 32) {
        const int lane = tid;
        float m = -1e30f;
        for (int l = lane; l < LL; l += 32) m = fmaxf(m, logit[l]);
        #pragma unroll
        for (int o = 16; o; o >>= 1) m = fmaxf(m, __shfl_xor_sync(0xffffffffu, m, o));
        float s = 0.f;
        for (int l = lane; l < LL; l += 32) {
            float e = expf(logit[l] - m);
            logit[l] = e;
            s += e;
        }
        #pragma unroll
        for (int o = 16; o; o >>= 1) s += __shfl_xor_sync(0xffffffffu, s, o);
        float inv = 1.f / s;
        for (int l = lane; l < LL; l += 32) logit[l] *= inv;
    }
    __syncthreads();

    if (tid < LL) attn_out[b * LL + tid] = logit[tid];

    float4 acc = make_float4(0.f, 0.f, 0.f, 0.f);
    const float* encb = enc + (size_t)b * LL * EENC;
    const int e4 = tid * 4;
    #pragma unroll 4
    for (int l = 0; l < LL; l++) {
        float a = logit[l];
        float4 v = *(const float4*)(encb + (size_t)l * EENC + e4);
        acc.x += a * v.x; acc.y += a * v.y; acc.z += a * v.z; acc.w += a * v.w;
    }
    *(float4*)(rnn + (size_t)b * 1536 + e4) = acc;
}

// ============================ GRU gates ===================================
__global__ __launch_bounds__(256)
void gru_gate(const float* __restrict__ gi, const float* __restrict__ gh,
              const float* __restrict__ h0, float* __restrict__ hnew)
{
    const int idx = blockIdx.x * blockDim.x + threadIdx.x;
    const int b = idx >> 10;
    const int d = idx & 1023;
    const float* gib = gi + (size_t)b * 3072;
    const float* ghb = gh + (size_t)b * 3072;
    float r = 1.f / (1.f + expf(-(gib[d] + ghb[d])));
    float z = 1.f / (1.f + expf(-(gib[1024 + d] + ghb[1024 + d])));
    float n = tanhf(gib[2048 + d] + r * ghb[2048 + d]);
    hnew[idx] = (1.f - z) * n + z * h0[idx];
}

// ============================ launch ======================================
extern "C" void kernel_launch(void* const* d_in, const int* in_sizes, int n_in,
                              void* d_out, int out_size)
{
    (void)in_sizes; (void)n_in; (void)out_size;

    const float* x      = (const float*)d_in[0];
    const float* hidden = (const float*)d_in[1];
    const float* enc    = (const float*)d_in[2];
    const float* W1_w   = (const float*)d_in[3];
    const float* W1_b   = (const float*)d_in[4];
    const float* W2_w   = (const float*)d_in[5];
    const float* W2_b   = (const float*)d_in[6];
    const float* V_w    = (const float*)d_in[7];
    const float* V_b    = (const float*)d_in[8];
    const float* o2e_w  = (const float*)d_in[9];
    const float* o2e_b  = (const float*)d_in[10];
    const float* gwi    = (const float*)d_in[11];
    const float* gwh    = (const float*)d_in[12];
    const float* gbi    = (const float*)d_in[13];
    const float* gbh    = (const float*)d_in[14];
    const float* f1w    = (const float*)d_in[15];
    const float* f1b    = (const float*)d_in[16];
    const float* f2w    = (const float*)d_in[17];
    const float* f2b    = (const float*)d_in[18];

    float* out  = (float*)d_out;
    float* hnew = out + (size_t)BB * VOC;
    float* attn = hnew + (size_t)BB * DDEC;

    __half* bh = nullptr;
    __half* bl = nullptr;
    float* fs = nullptr;
    cudaGetSymbolAddress((void**)&bh, g_bh);
    cudaGetSymbolAddress((void**)&bl, g_bl);
    cudaGetSymbolAddress((void**)&fs, g_f32);

    float* g1   = fs + F_G1;
    float* rnn  = fs + F_RNN;
    float* gi   = fs + F_GI;
    float* gh   = fs + F_GH;
    float* tbuf = fs + F_T;
    float* part = fs + F_PART;

    cudaFuncSetAttribute(gemm64,      cudaFuncAttributeMaxDynamicSharedMemorySize, GEMM_SMEM);
    cudaFuncSetAttribute(gemm64_bias, cudaFuncAttributeMaxDynamicSharedMemorySize, GEMM_SMEM);
    cudaFuncSetAttribute(score_gemm,  cudaFuncAttributeMaxDynamicSharedMemorySize, SC_SMEM);

    dim3 blk(256);

    // 0) weight splits
    split_weights<<<WN7 / 256, 256>>>(W1_w, W2_w, o2e_w, gwi, gwh, f1w, f2w);
    // 1) activation splits
    split_acts<<<AN3 / 256, 256>>>(enc, x, hidden);

    // 2) g1 = h0 @ W2^T + W2_b + W1_b  (direct store; 256x1024, K=1024)
    gemm64_bias<<<dim3(16, 2), blk, GEMM_SMEM>>>(
        bh + OFF_HID, bl + OFF_HID, bh + OFF_W2, bl + OFF_W2,
        1024, g1, 1024, W2_b, W1_b);

    // 3) score GEMM (launch index 3 -> ncu profiles THIS)
    score_gemm<<<dim3(16, 256), blk, SC_SMEM>>>(
        bh + OFF_ENC, bh + OFF_W1, g1, V_w, part);

    // 4) bias preinit for remaining atomic targets
    bias_init<<<BIAS_TOTAL / 256, 256>>>(rnn, gi, gh, tbuf, out,
                                         o2e_b, gbi, gbh, f1b, f2b);

    // 5) softmax + attn out + context -> rnn[:, 0:1024]
    attn_softmax_context<<<BB, 256>>>(part, 16, enc, V_b, attn, rnn);

    // 6) x_emb += x @ out2emb^T     (256x512, K=4096, splitK=8)
    gemm64<<<dim3(8, 2, 8), blk, GEMM_SMEM>>>(
        bh + OFF_X, bl + OFF_X, bh + OFF_O2E, bl + OFF_O2E,
        4096, 512, rnn + 1024, 1536);

    // 7) gh += h0 @ gru_wh^T        (256x3072, K=1024, splitK=2)
    gemm64<<<dim3(48, 2, 2), blk, GEMM_SMEM>>>(
        bh + OFF_HID, bl + OFF_HID, bh + OFF_GWH, bl + OFF_GWH,
        1024, 512, gh, 3072);

    // 8) rnn -> fp16
    f32_split<<<(393216 / 2) / 256, 256>>>(rnn, bh + OFF_RNN, bl + OFF_RNN, 393216 / 2);

    // 9) gi += rnn_in @ gru_wi^T    (256x3072, K=1536, splitK=2)
    gemm64<<<dim3(48, 2, 2), blk, GEMM_SMEM>>>(
        bh + OFF_RNN, bl + OFF_RNN, bh + OFF_GWI, bl + OFF_GWI,
        1536, 768, gi, 3072);

    // 10) GRU gates -> h_new (output)
    gru_gate<<<(BB * DDEC) / 256, 256>>>(gi, gh, hidden, hnew);

    // 11) h_new -> fp16
    f32_split<<<(262144 / 2) / 256, 256>>>(hnew, bh + OFF_HNEW, bl + OFF_HNEW, 262144 / 2);

    // 12) tbuf += h_new @ fc1^T     (256x512, K=1024, splitK=8)
    gemm64<<<dim3(8, 2, 8), blk, GEMM_SMEM>>>(
        bh + OFF_HNEW, bl + OFF_HNEW, bh + OFF_F1, bl + OFF_F1,
        1024, 128, tbuf, 512);

    // 13) t = tanh(tbuf) -> fp16
    f32_split_tanh<<<(131072 / 2) / 256, 256>>>(tbuf, bh + OFF_T, bl + OFF_T, 131072 / 2);

    // 14) out += t @ fc2^T          (256x4096, K=512, splitK=2)
    gemm64<<<dim3(64, 2, 2), blk, GEMM_SMEM>>>(
        bh + OFF_T, bl + OFF_T, bh + OFF_F2, bl + OFF_F2,
        512, 256, out, 4096);
}

// round 9
// speedup vs baseline: 1.6179x; 1.1598x over previous
#include <cuda_runtime.h>
#include <cuda_fp16.h>
#include <cstdint>
#include <math.h>

// Problem dims
#define BB   256
#define LL   128
#define VOC  4096
#define EENC 1024
#define DDEC 1024
#define EEMB 512

// ======================= scratch (module-load allocated) ==================
#define OFF_ENC   0ull
#define OFF_W1    (OFF_ENC + 33554432ull)
#define OFF_W2    (OFF_W1  + 1048576ull)
#define OFF_O2E   (OFF_W2  + 1048576ull)
#define OFF_GWI   (OFF_O2E + 2097152ull)
#define OFF_GWH   (OFF_GWI + 4718592ull)
#define OFF_F1    (OFF_GWH + 3145728ull)
#define OFF_F2    (OFF_F1  + 524288ull)
#define OFF_X     (OFF_F2  + 2097152ull)
#define OFF_HID   (OFF_X   + 1048576ull)
#define OFF_RNN   (OFF_HID + 262144ull)
#define OFF_HNEW  (OFF_RNN + 393216ull)
#define OFF_T     (OFF_HNEW+ 262144ull)
#define BF_TOTAL  (OFF_T   + 131072ull)

__device__ __half g_bh[BF_TOTAL];
__device__ __half g_bl[BF_TOTAL];

#define F_G1    0ull
#define F_RNN   (F_G1   + 262144ull)
#define F_GI    (F_RNN  + 393216ull)
#define F_GH    (F_GI   + 786432ull)
#define F_T     (F_GH   + 786432ull)
#define F_PART  (F_T    + 131072ull)
#define F_TOTAL (F_PART + 524288ull)

__device__ float g_f32[F_TOTAL];

// ======================= small helpers ====================================
__device__ __forceinline__ void cp16(uint32_t s, const void* g) {
    asm volatile("cp.async.cg.shared.global [%0], [%1], 16;"
                 :: "r"(s), "l"(__cvta_generic_to_global(g)));
}
__device__ __forceinline__ void ldm4(uint32_t* r, uint32_t addr) {
    asm volatile("ldmatrix.sync.aligned.m8n8.x4.shared.b16 {%0,%1,%2,%3}, [%4];"
        : "=r"(r[0]), "=r"(r[1]), "=r"(r[2]), "=r"(r[3]) : "r"(addr));
}
__device__ __forceinline__ void mma16816(float* c, const uint32_t* a, const uint32_t* b) {
    asm volatile("mma.sync.aligned.m16n8k16.row.col.f32.f16.f16.f32 "
        "{%0,%1,%2,%3}, {%4,%5,%6,%7}, {%8,%9}, {%0,%1,%2,%3};"
        : "+f"(c[0]), "+f"(c[1]), "+f"(c[2]), "+f"(c[3])
        : "r"(a[0]), "r"(a[1]), "r"(a[2]), "r"(a[3]), "r"(b[0]), "r"(b[1]));
}
__device__ __forceinline__ void do_split(const float* src, int local,
                                         unsigned long long dst) {
    float2 v = ((const float2*)src)[local];
    __half h0 = __float2half_rn(v.x);
    __half h1 = __float2half_rn(v.y);
    __half2 hp; hp.x = h0; hp.y = h1;
    __half2 lp;
    lp.x = __float2half_rn(v.x - __half2float(h0));
    lp.y = __float2half_rn(v.y - __half2float(h1));
    ((__half2*)(g_bh + dst))[local] = hp;
    ((__half2*)(g_bl + dst))[local] = lp;
}

// ======================= fused split kernels ==============================
#define WN1 524288
#define WN2 1048576
#define WN3 2097152
#define WN4 4456448
#define WN5 6029312
#define WN6 6291456
#define WN7 7340032
__global__ __launch_bounds__(256)
void split_weights(const float* __restrict__ W1, const float* __restrict__ W2,
                   const float* __restrict__ o2e, const float* __restrict__ gwi,
                   const float* __restrict__ gwh, const float* __restrict__ f1,
                   const float* __restrict__ f2)
{
    int i = blockIdx.x * blockDim.x + threadIdx.x;
    if (i < WN1)      do_split(W1,  i,       OFF_W1);
    else if (i < WN2) do_split(W2,  i - WN1, OFF_W2);
    else if (i < WN3) do_split(o2e, i - WN2, OFF_O2E);
    else if (i < WN4) do_split(gwi, i - WN3, OFF_GWI);
    else if (i < WN5) do_split(gwh, i - WN4, OFF_GWH);
    else if (i < WN6) do_split(f1,  i - WN5, OFF_F1);
    else if (i < WN7) do_split(f2,  i - WN6, OFF_F2);
}
#define AN1 16777216
#define AN2 17301504
#define AN3 17432576
__global__ __launch_bounds__(256)
void split_acts(const float* __restrict__ enc, const float* __restrict__ x,
                const float* __restrict__ hid)
{
    int i = blockIdx.x * blockDim.x + threadIdx.x;
    if (i < AN1)      do_split(enc, i,       OFF_ENC);
    else if (i < AN2) do_split(x,   i - AN1, OFF_X);
    else if (i < AN3) do_split(hid, i - AN2, OFF_HID);
}
__global__ __launch_bounds__(256)
void f32_split(const float* __restrict__ in, __half* __restrict__ hi,
               __half* __restrict__ lo, int n2)
{
    int i = blockIdx.x * blockDim.x + threadIdx.x;
    if (i >= n2) return;
    float2 v = ((const float2*)in)[i];
    __half h0 = __float2half_rn(v.x);
    __half h1 = __float2half_rn(v.y);
    __half2 hp; hp.x = h0; hp.y = h1;
    __half2 lp;
    lp.x = __float2half_rn(v.x - __half2float(h0));
    lp.y = __float2half_rn(v.y - __half2float(h1));
    ((__half2*)hi)[i] = hp;
    ((__half2*)lo)[i] = lp;
}
__global__ __launch_bounds__(256)
void f32_split_tanh(const float* __restrict__ in, __half* __restrict__ hi,
                    __half* __restrict__ lo, int n2)
{
    int i = blockIdx.x * blockDim.x + threadIdx.x;
    if (i >= n2) return;
    float2 v = ((const float2*)in)[i];
    v.x = tanhf(v.x); v.y = tanhf(v.y);
    __half h0 = __float2half_rn(v.x);
    __half h1 = __float2half_rn(v.y);
    __half2 hp; hp.x = h0; hp.y = h1;
    __half2 lp;
    lp.x = __float2half_rn(v.x - __half2float(h0));
    lp.y = __float2half_rn(v.y - __half2float(h1));
    ((__half2*)hi)[i] = hp;
    ((__half2*)lo)[i] = lp;
}

// ================= bias pre-init (resets atomic targets every call) =======
__global__ __launch_bounds__(256)
void bias_init(float* __restrict__ rnn,
               float* __restrict__ gi, float* __restrict__ gh,
               float* __restrict__ tbuf, float* __restrict__ out,
               const float* __restrict__ o2eb, const float* __restrict__ gbi,
               const float* __restrict__ gbh, const float* __restrict__ f1b,
               const float* __restrict__ f2b)
{
    int i = blockIdx.x * blockDim.x + threadIdx.x;
    if (i < 131072) {
        rnn[(i >> 9) * 1536 + 1024 + (i & 511)] = o2eb[i & 511];
    } else if (i < 917504) {
        int j = i - 131072;
        gi[j] = gbi[j % 3072];
    } else if (i < 1703936) {
        int j = i - 917504;
        gh[j] = gbh[j % 3072];
    } else if (i < 1835008) {
        int j = i - 1703936;
        tbuf[j] = f1b[j & 511];
    } else {
        int j = i - 1835008;
        out[j] = f2b[j & 4095];
    }
}
#define BIAS_TOTAL 2883584

// ======================= small split-K mma GEMM (R5-proven, fp16) =========
#define ROWB      80
#define TILE_A_SB (128 * ROWB)
#define TILE_W_SB (64 * ROWB)
#define STAGE_SB  (2 * TILE_A_SB + 2 * TILE_W_SB)
#define SM_PART   (2 * STAGE_SB)
#define GEMM_SMEM (SM_PART + 512 + 32)

__global__ __launch_bounds__(256, 2)
void gemm64(const __half* __restrict__ Ah, const __half* __restrict__ Al,
            const __half* __restrict__ Wh, const __half* __restrict__ Wl,
            int K, int Kchunk, float* __restrict__ C, int ldc)
{
    extern __shared__ __align__(128) char smem[];
    const uint32_t sbase = (uint32_t)__cvta_generic_to_shared(smem);

    const int tid  = threadIdx.x;
    const int wid  = tid >> 5;
    const int lane = tid & 31;
    const int brow = blockIdx.y * 128;
    const int bcol = blockIdx.x * 64;
    const int k0   = blockIdx.z * Kchunk;
    const int m32  = (wid >> 1) * 32;
    const int n32w = (wid & 1) * 32;

    const int lrA = tid >> 1;
    const int cA  = (tid & 1) * 2;
    const int lrW = tid >> 2;
    const int cW  = tid & 3;
    const size_t aoff = (size_t)(brow + lrA) * K + k0;
    const size_t woff = (size_t)(bcol + lrW) * K + k0;

    auto load_stage = [&](int stage, int kk0) {
        const uint32_t sA = sbase + stage * STAGE_SB + lrA * ROWB;
        const uint32_t sW = sbase + stage * STAGE_SB + 2 * TILE_A_SB + lrW * ROWB;
        const char* pAh = (const char*)(Ah + aoff + kk0);
        const char* pAl = (const char*)(Al + aoff + kk0);
        const char* pWh = (const char*)(Wh + woff + kk0);
        const char* pWl = (const char*)(Wl + woff + kk0);
        #pragma unroll
        for (int c = cA; c < cA + 2; c++) {
            cp16(sA + c * 16, pAh + c * 16);
            cp16(sA + TILE_A_SB + c * 16, pAl + c * 16);
        }
        cp16(sW + cW * 16, pWh + cW * 16);
        cp16(sW + TILE_W_SB + cW * 16, pWl + cW * 16);
    };

    const int nk = Kchunk >> 5;

    load_stage(0, 0);
    asm volatile("cp.async.commit_group;");
    if (nk > 1) load_stage(1, 32);
    asm volatile("cp.async.commit_group;");

    float acc[2][4][4];
    #pragma unroll
    for (int i = 0; i < 2; i++)
        #pragma unroll
        for (int j = 0; j < 4; j++)
            #pragma unroll
            for (int q = 0; q < 4; q++) acc[i][j][q] = 0.f;

    const int arow_l = m32 + (lane & 15);
    const uint32_t akb = ((lane >> 4) & 1) * 16;
    const int nrow_l = n32w + (lane & 7) + ((lane >> 4) & 1) * 8;
    const uint32_t bkb = ((lane >> 3) & 1) * 16;

    for (int c = 0; c < nk; c++) {
        asm volatile("cp.async.wait_group %0;" :: "n"(1));
        __syncthreads();

        const uint32_t sb = sbase + (c & 1) * STAGE_SB;
        #pragma unroll
        for (int kk = 0; kk < 2; kk++) {
            const uint32_t kbyte = kk * 32;
            uint32_t afh[2][4], afl[2][4], bfh[4][2], bfl[4][2];
            #pragma unroll
            for (int mt = 0; mt < 2; mt++) {
                uint32_t ra = (uint32_t)((arow_l + mt * 16) * ROWB) + akb + kbyte;
                ldm4(afh[mt], sb + ra);
                ldm4(afl[mt], sb + TILE_A_SB + ra);
            }
            #pragma unroll
            for (int np = 0; np < 2; np++) {
                uint32_t rb = (uint32_t)((nrow_l + np * 16) * ROWB) + bkb + kbyte;
                uint32_t th[4], tl[4];
                ldm4(th, sb + 2 * TILE_A_SB + rb);
                ldm4(tl, sb + 2 * TILE_A_SB + TILE_W_SB + rb);
                bfh[2 * np][0] = th[0]; bfh[2 * np][1] = th[1];
                bfh[2 * np + 1][0] = th[2]; bfh[2 * np + 1][1] = th[3];
                bfl[2 * np][0] = tl[0]; bfl[2 * np][1] = tl[1];
                bfl[2 * np + 1][0] = tl[2]; bfl[2 * np + 1][1] = tl[3];
            }
            #pragma unroll
            for (int mt = 0; mt < 2; mt++)
                #pragma unroll
                for (int nt = 0; nt < 4; nt++) {
                    mma16816(acc[mt][nt], afh[mt], bfh[nt]);
                    mma16816(acc[mt][nt], afl[mt], bfh[nt]);
                    mma16816(acc[mt][nt], afh[mt], bfl[nt]);
                }
        }
        __syncthreads();

        if (c + 2 < nk) load_stage(c & 1, (c + 2) * 32);
        asm volatile("cp.async.commit_group;");
    }

    const int rloc0 = m32 + (lane >> 2);
    const int cloc0 = n32w + (lane & 3) * 2;
    #pragma unroll
    for (int mt = 0; mt < 2; mt++) {
        const int r0 = brow + rloc0 + mt * 16;
        #pragma unroll
        for (int nt = 0; nt < 4; nt++) {
            const int col = bcol + cloc0 + nt * 8;
            float* c0 = C + (size_t)r0 * ldc + col;
            float* c1 = C + (size_t)(r0 + 8) * ldc + col;
            atomicAdd(c0,     acc[mt][nt][0]);
            atomicAdd(c0 + 1, acc[mt][nt][1]);
            atomicAdd(c1,     acc[mt][nt][2]);
            atomicAdd(c1 + 1, acc[mt][nt][3]);
        }
    }
}

// ========== gemm64_bias: direct-store variant with 2-bias epilogue ========
__global__ __launch_bounds__(256, 2)
void gemm64_bias(const __half* __restrict__ Ah, const __half* __restrict__ Al,
                 const __half* __restrict__ Wh, const __half* __restrict__ Wl,
                 int K, float* __restrict__ C, int ldc,
                 const float* __restrict__ b1, const float* __restrict__ b2)
{
    extern __shared__ __align__(128) char smem[];
    const uint32_t sbase = (uint32_t)__cvta_generic_to_shared(smem);

    const int tid  = threadIdx.x;
    const int wid  = tid >> 5;
    const int lane = tid & 31;
    const int brow = blockIdx.y * 128;
    const int bcol = blockIdx.x * 64;
    const int m32  = (wid >> 1) * 32;
    const int n32w = (wid & 1) * 32;

    const int lrA = tid >> 1;
    const int cA  = (tid & 1) * 2;
    const int lrW = tid >> 2;
    const int cW  = tid & 3;
    const size_t aoff = (size_t)(brow + lrA) * K;
    const size_t woff = (size_t)(bcol + lrW) * K;

    auto load_stage = [&](int stage, int kk0) {
        const uint32_t sA = sbase + stage * STAGE_SB + lrA * ROWB;
        const uint32_t sW = sbase + stage * STAGE_SB + 2 * TILE_A_SB + lrW * ROWB;
        const char* pAh = (const char*)(Ah + aoff + kk0);
        const char* pAl = (const char*)(Al + aoff + kk0);
        const char* pWh = (const char*)(Wh + woff + kk0);
        const char* pWl = (const char*)(Wl + woff + kk0);
        #pragma unroll
        for (int c = cA; c < cA + 2; c++) {
            cp16(sA + c * 16, pAh + c * 16);
            cp16(sA + TILE_A_SB + c * 16, pAl + c * 16);
        }
        cp16(sW + cW * 16, pWh + cW * 16);
        cp16(sW + TILE_W_SB + cW * 16, pWl + cW * 16);
    };

    const int nk = K >> 5;

    load_stage(0, 0);
    asm volatile("cp.async.commit_group;");
    load_stage(1, 32);
    asm volatile("cp.async.commit_group;");

    float acc[2][4][4];
    #pragma unroll
    for (int i = 0; i < 2; i++)
        #pragma unroll
        for (int j = 0; j < 4; j++)
            #pragma unroll
            for (int q = 0; q < 4; q++) acc[i][j][q] = 0.f;

    const int arow_l = m32 + (lane & 15);
    const uint32_t akb = ((lane >> 4) & 1) * 16;
    const int nrow_l = n32w + (lane & 7) + ((lane >> 4) & 1) * 8;
    const uint32_t bkb = ((lane >> 3) & 1) * 16;

    for (int c = 0; c < nk; c++) {
        asm volatile("cp.async.wait_group %0;" :: "n"(1));
        __syncthreads();

        const uint32_t sb = sbase + (c & 1) * STAGE_SB;
        #pragma unroll
        for (int kk = 0; kk < 2; kk++) {
            const uint32_t kbyte = kk * 32;
            uint32_t afh[2][4], afl[2][4], bfh[4][2], bfl[4][2];
            #pragma unroll
            for (int mt = 0; mt < 2; mt++) {
                uint32_t ra = (uint32_t)((arow_l + mt * 16) * ROWB) + akb + kbyte;
                ldm4(afh[mt], sb + ra);
                ldm4(afl[mt], sb + TILE_A_SB + ra);
            }
            #pragma unroll
            for (int np = 0; np < 2; np++) {
                uint32_t rb = (uint32_t)((nrow_l + np * 16) * ROWB) + bkb + kbyte;
                uint32_t th[4], tl[4];
                ldm4(th, sb + 2 * TILE_A_SB + rb);
                ldm4(tl, sb + 2 * TILE_A_SB + TILE_W_SB + rb);
                bfh[2 * np][0] = th[0]; bfh[2 * np][1] = th[1];
                bfh[2 * np + 1][0] = th[2]; bfh[2 * np + 1][1] = th[3];
                bfl[2 * np][0] = tl[0]; bfl[2 * np][1] = tl[1];
                bfl[2 * np + 1][0] = tl[2]; bfl[2 * np + 1][1] = tl[3];
            }
            #pragma unroll
            for (int mt = 0; mt < 2; mt++)
                #pragma unroll
                for (int nt = 0; nt < 4; nt++) {
                    mma16816(acc[mt][nt], afh[mt], bfh[nt]);
                    mma16816(acc[mt][nt], afl[mt], bfh[nt]);
                    mma16816(acc[mt][nt], afh[mt], bfl[nt]);
                }
        }
        __syncthreads();

        if (c + 2 < nk) load_stage(c & 1, (c + 2) * 32);
        asm volatile("cp.async.commit_group;");
    }

    const int rloc0 = m32 + (lane >> 2);
    const int cloc0 = n32w + (lane & 3) * 2;
    #pragma unroll
    for (int mt = 0; mt < 2; mt++) {
        const int r0 = brow + rloc0 + mt * 16;
        #pragma unroll
        for (int nt = 0; nt < 4; nt++) {
            const int col = bcol + cloc0 + nt * 8;
            float2 bb = make_float2(b1[col] + b2[col], b1[col + 1] + b2[col + 1]);
            *(float2*)(C + (size_t)r0 * ldc + col) =
                make_float2(acc[mt][nt][0] + bb.x, acc[mt][nt][1] + bb.y);
            *(float2*)(C + (size_t)(r0 + 8) * ldc + col) =
                make_float2(acc[mt][nt][2] + bb.x, acc[mt][nt][3] + bb.y);
        }
    }
}

// ======= score GEMM v2: 128x64, BK=64, 3 stages, 1 sync per chunk =========
// fp16 1-term Ah*Wh, fused weighted-tanh row-partial epilogue.
// Rows padded to 144B: bank granule (9r + c) mod 8 is a permutation -> no
// ldmatrix or cp.async conflicts.
#define SC_ROWB   144
#define SC_A_SB   (128 * SC_ROWB)        // 18432
#define SC_W_SB   (64 * SC_ROWB)         // 9216
#define SC_STAGE  (SC_A_SB + SC_W_SB)    // 27648
#define SC_NST    3
#define SC_SMEM   (SC_NST * SC_STAGE + 512 + 32)

__global__ __launch_bounds__(256, 2)
void score_gemm(const __half* __restrict__ Ah, const __half* __restrict__ Wh,
                const float* __restrict__ g1, const float* __restrict__ vw,
                float* __restrict__ partial)
{
    extern __shared__ __align__(128) char smem[];
    const uint32_t sbase = (uint32_t)__cvta_generic_to_shared(smem);
    float* part_sm = (float*)(smem + SC_NST * SC_STAGE);

    const int tid  = threadIdx.x;
    const int wid  = tid >> 5;
    const int lane = tid & 31;
    const int brow = blockIdx.y * 128;
    const int bcol = blockIdx.x * 64;
    const int m32  = (wid >> 1) * 32;
    const int n32w = (wid & 1) * 32;
    const int K    = 1024;

    if (tid < 128) part_sm[tid] = 0.f;

    // loaders: A: 2 threads/row x 4 chunks; W: 4 threads/row x 2 chunks
    const int arow = tid >> 1;
    const int acb_ld = (tid & 1) * 4;
    const int wrow = tid >> 2;
    const int wcb_ld = (tid & 3) * 2;
    const __half* gA = Ah + (size_t)(brow + arow) * K;
    const __half* gW = Wh + (size_t)(bcol + wrow) * K;
    const uint32_t sA_ld = (uint32_t)(arow * SC_ROWB + acb_ld * 16);
    const uint32_t sW_ld = (uint32_t)(SC_A_SB + wrow * SC_ROWB + wcb_ld * 16);

    auto load_stage = [&](int stage, int k0) {
        const uint32_t sb = sbase + stage * SC_STAGE;
        const char* pA = (const char*)(gA + k0) + acb_ld * 16;
        const char* pW = (const char*)(gW + k0) + wcb_ld * 16;
        #pragma unroll
        for (int c = 0; c < 4; c++) cp16(sb + sA_ld + c * 16, pA + c * 16);
        #pragma unroll
        for (int c = 0; c < 2; c++) cp16(sb + sW_ld + c * 16, pW + c * 16);
    };

    const int nk = 16;                   // K=1024 / 64

    load_stage(0, 0);
    asm volatile("cp.async.commit_group;");
    load_stage(1, 64);
    asm volatile("cp.async.commit_group;");

    float acc[2][4][4];
    #pragma unroll
    for (int i = 0; i < 2; i++)
        #pragma unroll
        for (int j = 0; j < 4; j++)
            #pragma unroll
            for (int q = 0; q < 4; q++) acc[i][j][q] = 0.f;

    const int arow_l = m32 + (lane & 15);
    const uint32_t akb = ((lane >> 4) & 1) * 16;
    const int nrow_l = n32w + (lane & 7) + ((lane >> 4) & 1) * 8;
    const uint32_t bkb = ((lane >> 3) & 1) * 16;

    int stage = 0;
    for (int c = 0; c < nk; c++) {
        asm volatile("cp.async.wait_group %0;" :: "n"(1));
        __syncthreads();

        // prefetch chunk c+2 into stage+2 (not read this iter or next)
        if (c + 2 < nk) {
            int s2 = stage + 2; if (s2 >= SC_NST) s2 -= SC_NST;
            load_stage(s2, (c + 2) * 64);
        }
        asm volatile("cp.async.commit_group;");

        const uint32_t sb = sbase + stage * SC_STAGE;
        #pragma unroll
        for (int kk = 0; kk < 4; kk++) {
            const uint32_t kbyte = kk * 32;
            uint32_t afh[2][4], bfh[4][2];
            #pragma unroll
            for (int mt = 0; mt < 2; mt++) {
                uint32_t ra = (uint32_t)((arow_l + mt * 16) * SC_ROWB) + akb + kbyte;
                ldm4(afh[mt], sb + ra);
            }
            #pragma unroll
            for (int np = 0; np < 2; np++) {
                uint32_t rb = (uint32_t)((nrow_l + np * 16) * SC_ROWB) + bkb + kbyte;
                uint32_t th[4];
                ldm4(th, sb + SC_A_SB + rb);
                bfh[2 * np][0] = th[0]; bfh[2 * np][1] = th[1];
                bfh[2 * np + 1][0] = th[2]; bfh[2 * np + 1][1] = th[3];
            }
            #pragma unroll
            for (int mt = 0; mt < 2; mt++)
                #pragma unroll
                for (int nt = 0; nt < 4; nt++)
                    mma16816(acc[mt][nt], afh[mt], bfh[nt]);
        }
        if (++stage >= SC_NST) stage = 0;
    }

    // ---- epilogue: weighted-tanh row partial sums ----
    const int rloc0 = m32 + (lane >> 2);
    const int cloc0 = n32w + (lane & 3) * 2;
    const float* g1r = g1 + (size_t)blockIdx.y * 1024;
    #pragma unroll
    for (int mt = 0; mt < 2; mt++) {
        float s0 = 0.f, s1 = 0.f;
        #pragma unroll
        for (int nt = 0; nt < 4; nt++) {
            int col = bcol + cloc0 + nt * 8;
            float gw0 = g1r[col],     vw0 = vw[col];
            float gw1 = g1r[col + 1], vw1 = vw[col + 1];
            s0 += tanhf(acc[mt][nt][0] + gw0) * vw0;
            s0 += tanhf(acc[mt][nt][1] + gw1) * vw1;
            s1 += tanhf(acc[mt][nt][2] + gw0) * vw0;
            s1 += tanhf(acc[mt][nt][3] + gw1) * vw1;
        }
        atomicAdd(&part_sm[rloc0 + mt * 16], s0);
        atomicAdd(&part_sm[rloc0 + mt * 16 + 8], s1);
    }
    __syncthreads();
    if (tid < 128)
        partial[(size_t)(brow + tid) * gridDim.x + blockIdx.x] = part_sm[tid];
}

// ============== softmax + context (one block per batch element) ===========
__global__ __launch_bounds__(256)
void attn_softmax_context(const float* __restrict__ part, int npart,
                          const float* __restrict__ enc,
                          const float* __restrict__ Vb,
                          float* __restrict__ attn_out,
                          float* __restrict__ rnn)
{
    const int b   = blockIdx.x;
    const int tid = threadIdx.x;
    __shared__ float logit[LL];

    if (tid < LL) {
        const float* pr = part + (size_t)(b * LL + tid) * npart;
        float s = Vb[0];
        for (int j = 0; j < npart; j++) s += pr[j];
        logit[tid] = s;
    }
    __syncthreads();

    if (tid < 32) {
        const int lane = tid;
        float m = -1e30f;
        for (int l = lane; l < LL; l += 32) m = fmaxf(m, logit[l]);
        #pragma unroll
        for (int o = 16; o; o >>= 1) m = fmaxf(m, __shfl_xor_sync(0xffffffffu, m, o));
        float s = 0.f;
        for (int l = lane; l < LL; l += 32) {
            float e = expf(logit[l] - m);
            logit[l] = e;
            s += e;
        }
        #pragma unroll
        for (int o = 16; o; o >>= 1) s += __shfl_xor_sync(0xffffffffu, s, o);
        float inv = 1.f / s;
        for (int l = lane; l < LL; l += 32) logit[l] *= inv;
    }
    __syncthreads();

    if (tid < LL) attn_out[b * LL + tid] = logit[tid];

    float4 acc = make_float4(0.f, 0.f, 0.f, 0.f);
    const float* encb = enc + (size_t)b * LL * EENC;
    const int e4 = tid * 4;
    #pragma unroll 4
    for (int l = 0; l < LL; l++) {
        float a = logit[l];
        float4 v = *(const float4*)(encb + (size_t)l * EENC + e4);
        acc.x += a * v.x; acc.y += a * v.y; acc.z += a * v.z; acc.w += a * v.w;
    }
    *(float4*)(rnn + (size_t)b * 1536 + e4) = acc;
}

// ============================ GRU gates ===================================
__global__ __launch_bounds__(256)
void gru_gate(const float* __restrict__ gi, const float* __restrict__ gh,
              const float* __restrict__ h0, float* __restrict__ hnew)
{
    const int idx = blockIdx.x * blockDim.x + threadIdx.x;
    const int b = idx >> 10;
    const int d = idx & 1023;
    const float* gib = gi + (size_t)b * 3072;
    const float* ghb = gh + (size_t)b * 3072;
    float r = 1.f / (1.f + expf(-(gib[d] + ghb[d])));
    float z = 1.f / (1.f + expf(-(gib[1024 + d] + ghb[1024 + d])));
    float n = tanhf(gib[2048 + d] + r * ghb[2048 + d]);
    hnew[idx] = (1.f - z) * n + z * h0[idx];
}

// ============================ launch ======================================
extern "C" void kernel_launch(void* const* d_in, const int* in_sizes, int n_in,
                              void* d_out, int out_size)
{
    (void)in_sizes; (void)n_in; (void)out_size;

    const float* x      = (const float*)d_in[0];
    const float* hidden = (const float*)d_in[1];
    const float* enc    = (const float*)d_in[2];
    const float* W1_w   = (const float*)d_in[3];
    const float* W1_b   = (const float*)d_in[4];
    const float* W2_w   = (const float*)d_in[5];
    const float* W2_b   = (const float*)d_in[6];
    const float* V_w    = (const float*)d_in[7];
    const float* V_b    = (const float*)d_in[8];
    const float* o2e_w  = (const float*)d_in[9];
    const float* o2e_b  = (const float*)d_in[10];
    const float* gwi    = (const float*)d_in[11];
    const float* gwh    = (const float*)d_in[12];
    const float* gbi    = (const float*)d_in[13];
    const float* gbh    = (const float*)d_in[14];
    const float* f1w    = (const float*)d_in[15];
    const float* f1b    = (const float*)d_in[16];
    const float* f2w    = (const float*)d_in[17];
    const float* f2b    = (const float*)d_in[18];

    float* out  = (float*)d_out;
    float* hnew = out + (size_t)BB * VOC;
    float* attn = hnew + (size_t)BB * DDEC;

    __half* bh = nullptr;
    __half* bl = nullptr;
    float* fs = nullptr;
    cudaGetSymbolAddress((void**)&bh, g_bh);
    cudaGetSymbolAddress((void**)&bl, g_bl);
    cudaGetSymbolAddress((void**)&fs, g_f32);

    float* g1   = fs + F_G1;
    float* rnn  = fs + F_RNN;
    float* gi   = fs + F_GI;
    float* gh   = fs + F_GH;
    float* tbuf = fs + F_T;
    float* part = fs + F_PART;

    cudaFuncSetAttribute(gemm64,      cudaFuncAttributeMaxDynamicSharedMemorySize, GEMM_SMEM);
    cudaFuncSetAttribute(gemm64_bias, cudaFuncAttributeMaxDynamicSharedMemorySize, GEMM_SMEM);
    cudaFuncSetAttribute(score_gemm,  cudaFuncAttributeMaxDynamicSharedMemorySize, SC_SMEM);

    dim3 blk(256);

    // 0) weight splits
    split_weights<<<WN7 / 256, 256>>>(W1_w, W2_w, o2e_w, gwi, gwh, f1w, f2w);
    // 1) activation splits
    split_acts<<<AN3 / 256, 256>>>(enc, x, hidden);

    // 2) g1 = h0 @ W2^T + W2_b + W1_b  (direct store; 256x1024, K=1024)
    gemm64_bias<<<dim3(16, 2), blk, GEMM_SMEM>>>(
        bh + OFF_HID, bl + OFF_HID, bh + OFF_W2, bl + OFF_W2,
        1024, g1, 1024, W2_b, W1_b);

    // 3) score GEMM (launch index 3 -> ncu profiles THIS)
    score_gemm<<<dim3(16, 256), blk, SC_SMEM>>>(
        bh + OFF_ENC, bh + OFF_W1, g1, V_w, part);

    // 4) bias preinit for remaining atomic targets
    bias_init<<<BIAS_TOTAL / 256, 256>>>(rnn, gi, gh, tbuf, out,
                                         o2e_b, gbi, gbh, f1b, f2b);

    // 5) softmax + attn out + context -> rnn[:, 0:1024]
    attn_softmax_context<<<BB, 256>>>(part, 16, enc, V_b, attn, rnn);

    // 6) x_emb += x @ out2emb^T     (256x512, K=4096, splitK=8)
    gemm64<<<dim3(8, 2, 8), blk, GEMM_SMEM>>>(
        bh + OFF_X, bl + OFF_X, bh + OFF_O2E, bl + OFF_O2E,
        4096, 512, rnn + 1024, 1536);

    // 7) gh += h0 @ gru_wh^T        (256x3072, K=1024, splitK=2)
    gemm64<<<dim3(48, 2, 2), blk, GEMM_SMEM>>>(
        bh + OFF_HID, bl + OFF_HID, bh + OFF_GWH, bl + OFF_GWH,
        1024, 512, gh, 3072);

    // 8) rnn -> fp16
    f32_split<<<(393216 / 2) / 256, 256>>>(rnn, bh + OFF_RNN, bl + OFF_RNN, 393216 / 2);

    // 9) gi += rnn_in @ gru_wi^T    (256x3072, K=1536, splitK=2)
    gemm64<<<dim3(48, 2, 2), blk, GEMM_SMEM>>>(
        bh + OFF_RNN, bl + OFF_RNN, bh + OFF_GWI, bl + OFF_GWI,
        1536, 768, gi, 3072);

    // 10) GRU gates -> h_new (output)
    gru_gate<<<(BB * DDEC) / 256, 256>>>(gi, gh, hidden, hnew);

    // 11) h_new -> fp16
    f32_split<<<(262144 / 2) / 256, 256>>>(hnew, bh + OFF_HNEW, bl + OFF_HNEW, 262144 / 2);

    // 12) tbuf += h_new @ fc1^T     (256x512, K=1024, splitK=8)
    gemm64<<<dim3(8, 2, 8), blk, GEMM_SMEM>>>(
        bh + OFF_HNEW, bl + OFF_HNEW, bh + OFF_F1, bl + OFF_F1,
        1024, 128, tbuf, 512);

    // 13) t = tanh(tbuf) -> fp16
    f32_split_tanh<<<(131072 / 2) / 256, 256>>>(tbuf, bh + OFF_T, bl + OFF_T, 131072 / 2);

    // 14) out += t @ fc2^T          (256x4096, K=512, splitK=2)
    gemm64<<<dim3(64, 2, 2), blk, GEMM_SMEM>>>(
        bh + OFF_T, bl + OFF_T, bh + OFF_F2, bl + OFF_F2,
        512, 256, out, 4096);
}

// round 10
// speedup vs baseline: 1.7916x; 1.1074x over previous
#include <cuda_runtime.h>
#include <cuda_fp16.h>
#include <cstdint>
#include <math.h>

// Problem dims
#define BB   256
#define LL   128
#define VOC  4096
#define EENC 1024
#define DDEC 1024
#define EEMB 512

// ======================= scratch (module-load allocated) ==================
#define OFF_ENC   0ull
#define OFF_W1    (OFF_ENC + 33554432ull)
#define OFF_W2    (OFF_W1  + 1048576ull)
#define OFF_O2E   (OFF_W2  + 1048576ull)
#define OFF_GWI   (OFF_O2E + 2097152ull)
#define OFF_GWH   (OFF_GWI + 4718592ull)
#define OFF_F1    (OFF_GWH + 3145728ull)
#define OFF_F2    (OFF_F1  + 524288ull)
#define OFF_X     (OFF_F2  + 2097152ull)
#define OFF_HID   (OFF_X   + 1048576ull)
#define OFF_RNN   (OFF_HID + 262144ull)
#define OFF_HNEW  (OFF_RNN + 393216ull)
#define OFF_T     (OFF_HNEW+ 262144ull)
#define BF_TOTAL  (OFF_T   + 131072ull)

__device__ __half g_bh[BF_TOTAL];
__device__ __half g_bl[BF_TOTAL];

#define F_G1    0ull
#define F_RNN   (F_G1   + 262144ull)
#define F_GI    (F_RNN  + 393216ull)
#define F_GH    (F_GI   + 786432ull)
#define F_T     (F_GH   + 786432ull)
#define F_PART  (F_T    + 131072ull)
#define F_TOTAL (F_PART + 524288ull)

__device__ float g_f32[F_TOTAL];

// ======================= small helpers ====================================
__device__ __forceinline__ void cp16(uint32_t s, const void* g) {
    asm volatile("cp.async.cg.shared.global [%0], [%1], 16;"
                 :: "r"(s), "l"(__cvta_generic_to_global(g)));
}
__device__ __forceinline__ void ldm4(uint32_t* r, uint32_t addr) {
    asm volatile("ldmatrix.sync.aligned.m8n8.x4.shared.b16 {%0,%1,%2,%3}, [%4];"
        : "=r"(r[0]), "=r"(r[1]), "=r"(r[2]), "=r"(r[3]) : "r"(addr));
}
__device__ __forceinline__ void mma16816(float* c, const uint32_t* a, const uint32_t* b) {
    asm volatile("mma.sync.aligned.m16n8k16.row.col.f32.f16.f16.f32 "
        "{%0,%1,%2,%3}, {%4,%5,%6,%7}, {%8,%9}, {%0,%1,%2,%3};"
        : "+f"(c[0]), "+f"(c[1]), "+f"(c[2]), "+f"(c[3])
        : "r"(a[0]), "r"(a[1]), "r"(a[2]), "r"(a[3]), "r"(b[0]), "r"(b[1]));
}
__device__ __forceinline__ void do_split(const float* src, int local,
                                         unsigned long long dst) {
    float2 v = ((const float2*)src)[local];
    __half h0 = __float2half_rn(v.x);
    __half h1 = __float2half_rn(v.y);
    __half2 hp; hp.x = h0; hp.y = h1;
    __half2 lp;
    lp.x = __float2half_rn(v.x - __half2float(h0));
    lp.y = __float2half_rn(v.y - __half2float(h1));
    ((__half2*)(g_bh + dst))[local] = hp;
    ((__half2*)(g_bl + dst))[local] = lp;
}

// ======================= fused split kernels ==============================
#define WN1 524288
#define WN2 1048576
#define WN3 2097152
#define WN4 4456448
#define WN5 6029312
#define WN6 6291456
#define WN7 7340032
__global__ __launch_bounds__(256)
void split_weights(const float* __restrict__ W1, const float* __restrict__ W2,
                   const float* __restrict__ o2e, const float* __restrict__ gwi,
                   const float* __restrict__ gwh, const float* __restrict__ f1,
                   const float* __restrict__ f2)
{
    int i = blockIdx.x * blockDim.x + threadIdx.x;
    if (i < WN1)      do_split(W1,  i,       OFF_W1);
    else if (i < WN2) do_split(W2,  i - WN1, OFF_W2);
    else if (i < WN3) do_split(o2e, i - WN2, OFF_O2E);
    else if (i < WN4) do_split(gwi, i - WN3, OFF_GWI);
    else if (i < WN5) do_split(gwh, i - WN4, OFF_GWH);
    else if (i < WN6) do_split(f1,  i - WN5, OFF_F1);
    else if (i < WN7) do_split(f2,  i - WN6, OFF_F2);
}
#define AN1 16777216
#define AN2 17301504
#define AN3 17432576
__global__ __launch_bounds__(256)
void split_acts(const float* __restrict__ enc, const float* __restrict__ x,
                const float* __restrict__ hid)
{
    int i = blockIdx.x * blockDim.x + threadIdx.x;
    if (i < AN1)      do_split(enc, i,       OFF_ENC);
    else if (i < AN2) do_split(x,   i - AN1, OFF_X);
    else if (i < AN3) do_split(hid, i - AN2, OFF_HID);
}
__global__ __launch_bounds__(256)
void f32_split(const float* __restrict__ in, __half* __restrict__ hi,
               __half* __restrict__ lo, int n2)
{
    int i = blockIdx.x * blockDim.x + threadIdx.x;
    if (i >= n2) return;
    float2 v = ((const float2*)in)[i];
    __half h0 = __float2half_rn(v.x);
    __half h1 = __float2half_rn(v.y);
    __half2 hp; hp.x = h0; hp.y = h1;
    __half2 lp;
    lp.x = __float2half_rn(v.x - __half2float(h0));
    lp.y = __float2half_rn(v.y - __half2float(h1));
    ((__half2*)hi)[i] = hp;
    ((__half2*)lo)[i] = lp;
}
__global__ __launch_bounds__(256)
void f32_split_tanh(const float* __restrict__ in, __half* __restrict__ hi,
                    __half* __restrict__ lo, int n2)
{
    int i = blockIdx.x * blockDim.x + threadIdx.x;
    if (i >= n2) return;
    float2 v = ((const float2*)in)[i];
    v.x = tanhf(v.x); v.y = tanhf(v.y);
    __half h0 = __float2half_rn(v.x);
    __half h1 = __float2half_rn(v.y);
    __half2 hp; hp.x = h0; hp.y = h1;
    __half2 lp;
    lp.x = __float2half_rn(v.x - __half2float(h0));
    lp.y = __float2half_rn(v.y - __half2float(h1));
    ((__half2*)hi)[i] = hp;
    ((__half2*)lo)[i] = lp;
}

// ================= bias pre-init (resets atomic targets every call) =======
__global__ __launch_bounds__(256)
void bias_init(float* __restrict__ rnn,
               float* __restrict__ gi, float* __restrict__ gh,
               float* __restrict__ tbuf, float* __restrict__ out,
               const float* __restrict__ o2eb, const float* __restrict__ gbi,
               const float* __restrict__ gbh, const float* __restrict__ f1b,
               const float* __restrict__ f2b)
{
    int i = blockIdx.x * blockDim.x + threadIdx.x;
    if (i < 131072) {
        rnn[(i >> 9) * 1536 + 1024 + (i & 511)] = o2eb[i & 511];
    } else if (i < 917504) {
        int j = i - 131072;
        gi[j] = gbi[j % 3072];
    } else if (i < 1703936) {
        int j = i - 917504;
        gh[j] = gbh[j % 3072];
    } else if (i < 1835008) {
        int j = i - 1703936;
        tbuf[j] = f1b[j & 511];
    } else {
        int j = i - 1835008;
        out[j] = f2b[j & 4095];
    }
}
#define BIAS_TOTAL 2883584

// ======================= small split-K mma GEMM (R5-proven, fp16) =========
#define ROWB      80
#define TILE_A_SB (128 * ROWB)
#define TILE_W_SB (64 * ROWB)
#define STAGE_SB  (2 * TILE_A_SB + 2 * TILE_W_SB)
#define SM_PART   (2 * STAGE_SB)
#define GEMM_SMEM (SM_PART + 512 + 32)

__global__ __launch_bounds__(256, 2)
void gemm64(const __half* __restrict__ Ah, const __half* __restrict__ Al,
            const __half* __restrict__ Wh, const __half* __restrict__ Wl,
            int K, int Kchunk, float* __restrict__ C, int ldc)
{
    extern __shared__ __align__(128) char smem[];
    const uint32_t sbase = (uint32_t)__cvta_generic_to_shared(smem);

    const int tid  = threadIdx.x;
    const int wid  = tid >> 5;
    const int lane = tid & 31;
    const int brow = blockIdx.y * 128;
    const int bcol = blockIdx.x * 64;
    const int k0   = blockIdx.z * Kchunk;
    const int m32  = (wid >> 1) * 32;
    const int n32w = (wid & 1) * 32;

    const int lrA = tid >> 1;
    const int cA  = (tid & 1) * 2;
    const int lrW = tid >> 2;
    const int cW  = tid & 3;
    const size_t aoff = (size_t)(brow + lrA) * K + k0;
    const size_t woff = (size_t)(bcol + lrW) * K + k0;

    auto load_stage = [&](int stage, int kk0) {
        const uint32_t sA = sbase + stage * STAGE_SB + lrA * ROWB;
        const uint32_t sW = sbase + stage * STAGE_SB + 2 * TILE_A_SB + lrW * ROWB;
        const char* pAh = (const char*)(Ah + aoff + kk0);
        const char* pAl = (const char*)(Al + aoff + kk0);
        const char* pWh = (const char*)(Wh + woff + kk0);
        const char* pWl = (const char*)(Wl + woff + kk0);
        #pragma unroll
        for (int c = cA; c < cA + 2; c++) {
            cp16(sA + c * 16, pAh + c * 16);
            cp16(sA + TILE_A_SB + c * 16, pAl + c * 16);
        }
        cp16(sW + cW * 16, pWh + cW * 16);
        cp16(sW + TILE_W_SB + cW * 16, pWl + cW * 16);
    };

    const int nk = Kchunk >> 5;

    load_stage(0, 0);
    asm volatile("cp.async.commit_group;");
    if (nk > 1) load_stage(1, 32);
    asm volatile("cp.async.commit_group;");

    float acc[2][4][4];
    #pragma unroll
    for (int i = 0; i < 2; i++)
        #pragma unroll
        for (int j = 0; j < 4; j++)
            #pragma unroll
            for (int q = 0; q < 4; q++) acc[i][j][q] = 0.f;

    const int arow_l = m32 + (lane & 15);
    const uint32_t akb = ((lane >> 4) & 1) * 16;
    const int nrow_l = n32w + (lane & 7) + ((lane >> 4) & 1) * 8;
    const uint32_t bkb = ((lane >> 3) & 1) * 16;

    for (int c = 0; c < nk; c++) {
        asm volatile("cp.async.wait_group %0;" :: "n"(1));
        __syncthreads();

        const uint32_t sb = sbase + (c & 1) * STAGE_SB;
        #pragma unroll
        for (int kk = 0; kk < 2; kk++) {
            const uint32_t kbyte = kk * 32;
            uint32_t afh[2][4], afl[2][4], bfh[4][2], bfl[4][2];
            #pragma unroll
            for (int mt = 0; mt < 2; mt++) {
                uint32_t ra = (uint32_t)((arow_l + mt * 16) * ROWB) + akb + kbyte;
                ldm4(afh[mt], sb + ra);
                ldm4(afl[mt], sb + TILE_A_SB + ra);
            }
            #pragma unroll
            for (int np = 0; np < 2; np++) {
                uint32_t rb = (uint32_t)((nrow_l + np * 16) * ROWB) + bkb + kbyte;
                uint32_t th[4], tl[4];
                ldm4(th, sb + 2 * TILE_A_SB + rb);
                ldm4(tl, sb + 2 * TILE_A_SB + TILE_W_SB + rb);
                bfh[2 * np][0] = th[0]; bfh[2 * np][1] = th[1];
                bfh[2 * np + 1][0] = th[2]; bfh[2 * np + 1][1] = th[3];
                bfl[2 * np][0] = tl[0]; bfl[2 * np][1] = tl[1];
                bfl[2 * np + 1][0] = tl[2]; bfl[2 * np + 1][1] = tl[3];
            }
            #pragma unroll
            for (int mt = 0; mt < 2; mt++)
                #pragma unroll
                for (int nt = 0; nt < 4; nt++) {
                    mma16816(acc[mt][nt], afh[mt], bfh[nt]);
                    mma16816(acc[mt][nt], afl[mt], bfh[nt]);
                    mma16816(acc[mt][nt], afh[mt], bfl[nt]);
                }
        }
        __syncthreads();

        if (c + 2 < nk) load_stage(c & 1, (c + 2) * 32);
        asm volatile("cp.async.commit_group;");
    }

    const int rloc0 = m32 + (lane >> 2);
    const int cloc0 = n32w + (lane & 3) * 2;
    #pragma unroll
    for (int mt = 0; mt < 2; mt++) {
        const int r0 = brow + rloc0 + mt * 16;
        #pragma unroll
        for (int nt = 0; nt < 4; nt++) {
            const int col = bcol + cloc0 + nt * 8;
            float* c0 = C + (size_t)r0 * ldc + col;
            float* c1 = C + (size_t)(r0 + 8) * ldc + col;
            atomicAdd(c0,     acc[mt][nt][0]);
            atomicAdd(c0 + 1, acc[mt][nt][1]);
            atomicAdd(c1,     acc[mt][nt][2]);
            atomicAdd(c1 + 1, acc[mt][nt][3]);
        }
    }
}

// ========== gemm64_bias: direct-store variant with 2-bias epilogue ========
__global__ __launch_bounds__(256, 2)
void gemm64_bias(const __half* __restrict__ Ah, const __half* __restrict__ Al,
                 const __half* __restrict__ Wh, const __half* __restrict__ Wl,
                 int K, float* __restrict__ C, int ldc,
                 const float* __restrict__ b1, const float* __restrict__ b2)
{
    extern __shared__ __align__(128) char smem[];
    const uint32_t sbase = (uint32_t)__cvta_generic_to_shared(smem);

    const int tid  = threadIdx.x;
    const int wid  = tid >> 5;
    const int lane = tid & 31;
    const int brow = blockIdx.y * 128;
    const int bcol = blockIdx.x * 64;
    const int m32  = (wid >> 1) * 32;
    const int n32w = (wid & 1) * 32;

    const int lrA = tid >> 1;
    const int cA  = (tid & 1) * 2;
    const int lrW = tid >> 2;
    const int cW  = tid & 3;
    const size_t aoff = (size_t)(brow + lrA) * K;
    const size_t woff = (size_t)(bcol + lrW) * K;

    auto load_stage = [&](int stage, int kk0) {
        const uint32_t sA = sbase + stage * STAGE_SB + lrA * ROWB;
        const uint32_t sW = sbase + stage * STAGE_SB + 2 * TILE_A_SB + lrW * ROWB;
        const char* pAh = (const char*)(Ah + aoff + kk0);
        const char* pAl = (const char*)(Al + aoff + kk0);
        const char* pWh = (const char*)(Wh + woff + kk0);
        const char* pWl = (const char*)(Wl + woff + kk0);
        #pragma unroll
        for (int c = cA; c < cA + 2; c++) {
            cp16(sA + c * 16, pAh + c * 16);
            cp16(sA + TILE_A_SB + c * 16, pAl + c * 16);
        }
        cp16(sW + cW * 16, pWh + cW * 16);
        cp16(sW + TILE_W_SB + cW * 16, pWl + cW * 16);
    };

    const int nk = K >> 5;

    load_stage(0, 0);
    asm volatile("cp.async.commit_group;");
    load_stage(1, 32);
    asm volatile("cp.async.commit_group;");

    float acc[2][4][4];
    #pragma unroll
    for (int i = 0; i < 2; i++)
        #pragma unroll
        for (int j = 0; j < 4; j++)
            #pragma unroll
            for (int q = 0; q < 4; q++) acc[i][j][q] = 0.f;

    const int arow_l = m32 + (lane & 15);
    const uint32_t akb = ((lane >> 4) & 1) * 16;
    const int nrow_l = n32w + (lane & 7) + ((lane >> 4) & 1) * 8;
    const uint32_t bkb = ((lane >> 3) & 1) * 16;

    for (int c = 0; c < nk; c++) {
        asm volatile("cp.async.wait_group %0;" :: "n"(1));
        __syncthreads();

        const uint32_t sb = sbase + (c & 1) * STAGE_SB;
        #pragma unroll
        for (int kk = 0; kk < 2; kk++) {
            const uint32_t kbyte = kk * 32;
            uint32_t afh[2][4], afl[2][4], bfh[4][2], bfl[4][2];
            #pragma unroll
            for (int mt = 0; mt < 2; mt++) {
                uint32_t ra = (uint32_t)((arow_l + mt * 16) * ROWB) + akb + kbyte;
                ldm4(afh[mt], sb + ra);
                ldm4(afl[mt], sb + TILE_A_SB + ra);
            }
            #pragma unroll
            for (int np = 0; np < 2; np++) {
                uint32_t rb = (uint32_t)((nrow_l + np * 16) * ROWB) + bkb + kbyte;
                uint32_t th[4], tl[4];
                ldm4(th, sb + 2 * TILE_A_SB + rb);
                ldm4(tl, sb + 2 * TILE_A_SB + TILE_W_SB + rb);
                bfh[2 * np][0] = th[0]; bfh[2 * np][1] = th[1];
                bfh[2 * np + 1][0] = th[2]; bfh[2 * np + 1][1] = th[3];
                bfl[2 * np][0] = tl[0]; bfl[2 * np][1] = tl[1];
                bfl[2 * np + 1][0] = tl[2]; bfl[2 * np + 1][1] = tl[3];
            }
            #pragma unroll
            for (int mt = 0; mt < 2; mt++)
                #pragma unroll
                for (int nt = 0; nt < 4; nt++) {
                    mma16816(acc[mt][nt], afh[mt], bfh[nt]);
                    mma16816(acc[mt][nt], afl[mt], bfh[nt]);
                    mma16816(acc[mt][nt], afh[mt], bfl[nt]);
                }
        }
        __syncthreads();

        if (c + 2 < nk) load_stage(c & 1, (c + 2) * 32);
        asm volatile("cp.async.commit_group;");
    }

    const int rloc0 = m32 + (lane >> 2);
    const int cloc0 = n32w + (lane & 3) * 2;
    #pragma unroll
    for (int mt = 0; mt < 2; mt++) {
        const int r0 = brow + rloc0 + mt * 16;
        #pragma unroll
        for (int nt = 0; nt < 4; nt++) {
            const int col = bcol + cloc0 + nt * 8;
            float2 bb = make_float2(b1[col] + b2[col], b1[col + 1] + b2[col + 1]);
            *(float2*)(C + (size_t)r0 * ldc + col) =
                make_float2(acc[mt][nt][0] + bb.x, acc[mt][nt][1] + bb.y);
            *(float2*)(C + (size_t)(r0 + 8) * ldc + col) =
                make_float2(acc[mt][nt][2] + bb.x, acc[mt][nt][3] + bb.y);
        }
    }
}

// ======= score GEMM v3: 128x128 tile, BK=64, 3 stages, warp 64x32 =========
// fp16 1-term Ah*Wh. 144B row padding; fused weighted-tanh row partials.
#define SC_ROWB   144
#define SC_A_SB   (128 * SC_ROWB)        // 18432
#define SC_W_SB   (128 * SC_ROWB)        // 18432
#define SC_STAGE  (SC_A_SB + SC_W_SB)    // 36864
#define SC_NST    3
#define SC_SMEM   (SC_NST * SC_STAGE + 512 + 32)

__global__ __launch_bounds__(256, 2)
void score_gemm(const __half* __restrict__ Ah, const __half* __restrict__ Wh,
                const float* __restrict__ g1, const float* __restrict__ vw,
                float* __restrict__ partial)
{
    extern __shared__ __align__(128) char smem[];
    const uint32_t sbase = (uint32_t)__cvta_generic_to_shared(smem);
    float* part_sm = (float*)(smem + SC_NST * SC_STAGE);

    const int tid  = threadIdx.x;
    const int wid  = tid >> 5;
    const int lane = tid & 31;
    const int brow = blockIdx.y * 128;
    const int bcol = blockIdx.x * 128;
    const int m64  = (wid >> 2) * 64;    // 2 m-groups, warp covers 64 rows
    const int n32  = (wid & 3) * 32;     // 4 n-groups, warp covers 32 cols
    const int K    = 1024;

    if (tid < 128) part_sm[tid] = 0.f;

    // loaders: A and W each 128 rows x 128B/stage; 2 threads/row, 4 cp16 each
    const int arow = tid >> 1;
    const int acb_ld = (tid & 1) * 4;
    const __half* gA = Ah + (size_t)(brow + arow) * K;
    const __half* gW = Wh + (size_t)(bcol + arow) * K;
    const uint32_t sA_ld = (uint32_t)(arow * SC_ROWB + acb_ld * 16);
    const uint32_t sW_ld = (uint32_t)(SC_A_SB + arow * SC_ROWB + acb_ld * 16);

    auto load_stage = [&](int stage, int k0) {
        const uint32_t sb = sbase + stage * SC_STAGE;
        const char* pA = (const char*)(gA + k0) + acb_ld * 16;
        const char* pW = (const char*)(gW + k0) + acb_ld * 16;
        #pragma unroll
        for (int c = 0; c < 4; c++) {
            cp16(sb + sA_ld + c * 16, pA + c * 16);
            cp16(sb + sW_ld + c * 16, pW + c * 16);
        }
    };

    const int nk = 16;                   // K=1024 / 64

    load_stage(0, 0);
    asm volatile("cp.async.commit_group;");
    load_stage(1, 64);
    asm volatile("cp.async.commit_group;");

    float acc[4][4][4];
    #pragma unroll
    for (int i = 0; i < 4; i++)
        #pragma unroll
        for (int j = 0; j < 4; j++)
            #pragma unroll
            for (int q = 0; q < 4; q++) acc[i][j][q] = 0.f;

    const int arow_l = m64 + (lane & 15);
    const uint32_t akb = ((lane >> 4) & 1) * 16;
    const int nrow_l = n32 + (lane & 7) + ((lane >> 4) & 1) * 8;
    const uint32_t bkb = ((lane >> 3) & 1) * 16;

    int stage = 0;
    for (int c = 0; c < nk; c++) {
        asm volatile("cp.async.wait_group %0;" :: "n"(1));
        __syncthreads();

        if (c + 2 < nk) {
            int s2 = stage + 2; if (s2 >= SC_NST) s2 -= SC_NST;
            load_stage(s2, (c + 2) * 64);
        }
        asm volatile("cp.async.commit_group;");

        const uint32_t sb = sbase + stage * SC_STAGE;
        #pragma unroll
        for (int kk = 0; kk < 4; kk++) {
            const uint32_t kbyte = kk * 32;
            uint32_t bfh[4][2];
            #pragma unroll
            for (int np = 0; np < 2; np++) {
                uint32_t rb = (uint32_t)((nrow_l + np * 16) * SC_ROWB) + bkb + kbyte;
                uint32_t th[4];
                ldm4(th, sb + SC_A_SB + rb);
                bfh[2 * np][0] = th[0]; bfh[2 * np][1] = th[1];
                bfh[2 * np + 1][0] = th[2]; bfh[2 * np + 1][1] = th[3];
            }
            #pragma unroll
            for (int mt = 0; mt < 4; mt++) {
                uint32_t afh[4];
                uint32_t ra = (uint32_t)((arow_l + mt * 16) * SC_ROWB) + akb + kbyte;
                ldm4(afh, sb + ra);
                #pragma unroll
                for (int nt = 0; nt < 4; nt++)
                    mma16816(acc[mt][nt], afh, bfh[nt]);
            }
        }
        if (++stage >= SC_NST) stage = 0;
    }

    // ---- epilogue: weighted-tanh row partial sums ----
    const int rloc0 = m64 + (lane >> 2);
    const int cloc0 = n32 + (lane & 3) * 2;
    const float* g1r = g1 + (size_t)blockIdx.y * 1024;
    #pragma unroll
    for (int mt = 0; mt < 4; mt++) {
        float s0 = 0.f, s1 = 0.f;
        #pragma unroll
        for (int nt = 0; nt < 4; nt++) {
            int col = bcol + cloc0 + nt * 8;
            float gw0 = g1r[col],     vw0 = vw[col];
            float gw1 = g1r[col + 1], vw1 = vw[col + 1];
            s0 += tanhf(acc[mt][nt][0] + gw0) * vw0;
            s0 += tanhf(acc[mt][nt][1] + gw1) * vw1;
            s1 += tanhf(acc[mt][nt][2] + gw0) * vw0;
            s1 += tanhf(acc[mt][nt][3] + gw1) * vw1;
        }
        atomicAdd(&part_sm[rloc0 + mt * 16], s0);
        atomicAdd(&part_sm[rloc0 + mt * 16 + 8], s1);
    }
    __syncthreads();
    if (tid < 128)
        partial[(size_t)(brow + tid) * gridDim.x + blockIdx.x] = part_sm[tid];
}

// ============== softmax + context (one block per batch element) ===========
__global__ __launch_bounds__(256)
void attn_softmax_context(const float* __restrict__ part, int npart,
                          const float* __restrict__ enc,
                          const float* __restrict__ Vb,
                          float* __restrict__ attn_out,
                          float* __restrict__ rnn)
{
    const int b   = blockIdx.x;
    const int tid = threadIdx.x;
    __shared__ float logit[LL];

    if (tid < LL) {
        const float* pr = part + (size_t)(b * LL + tid) * npart;
        float s = Vb[0];
        for (int j = 0; j < npart; j++) s += pr[j];
        logit[tid] = s;
    }
    __syncthreads();

    if (tid < 32) {
        const int lane = tid;
        float m = -1e30f;
        for (int l = lane; l < LL; l += 32) m = fmaxf(m, logit[l]);
        #pragma unroll
        for (int o = 16; o; o >>= 1) m = fmaxf(m, __shfl_xor_sync(0xffffffffu, m, o));
        float s = 0.f;
        for (int l = lane; l < LL; l += 32) {
            float e = expf(logit[l] - m);
            logit[l] = e;
            s += e;
        }
        #pragma unroll
        for (int o = 16; o; o >>= 1) s += __shfl_xor_sync(0xffffffffu, s, o);
        float inv = 1.f / s;
        for (int l = lane; l < LL; l += 32) logit[l] *= inv;
    }
    __syncthreads();

    if (tid < LL) attn_out[b * LL + tid] = logit[tid];

    float4 acc = make_float4(0.f, 0.f, 0.f, 0.f);
    const float* encb = enc + (size_t)b * LL * EENC;
    const int e4 = tid * 4;
    #pragma unroll 4
    for (int l = 0; l < LL; l++) {
        float a = logit[l];
        float4 v = *(const float4*)(encb + (size_t)l * EENC + e4);
        acc.x += a * v.x; acc.y += a * v.y; acc.z += a * v.z; acc.w += a * v.w;
    }
    *(float4*)(rnn + (size_t)b * 1536 + e4) = acc;
}

// ============================ GRU gates ===================================
__global__ __launch_bounds__(256)
void gru_gate(const float* __restrict__ gi, const float* __restrict__ gh,
              const float* __restrict__ h0, float* __restrict__ hnew)
{
    const int idx = blockIdx.x * blockDim.x + threadIdx.x;
    const int b = idx >> 10;
    const int d = idx & 1023;
    const float* gib = gi + (size_t)b * 3072;
    const float* ghb = gh + (size_t)b * 3072;
    float r = 1.f / (1.f + expf(-(gib[d] + ghb[d])));
    float z = 1.f / (1.f + expf(-(gib[1024 + d] + ghb[1024 + d])));
    float n = tanhf(gib[2048 + d] + r * ghb[2048 + d]);
    hnew[idx] = (1.f - z) * n + z * h0[idx];
}

// ============================ launch ======================================
extern "C" void kernel_launch(void* const* d_in, const int* in_sizes, int n_in,
                              void* d_out, int out_size)
{
    (void)in_sizes; (void)n_in; (void)out_size;

    const float* x      = (const float*)d_in[0];
    const float* hidden = (const float*)d_in[1];
    const float* enc    = (const float*)d_in[2];
    const float* W1_w   = (const float*)d_in[3];
    const float* W1_b   = (const float*)d_in[4];
    const float* W2_w   = (const float*)d_in[5];
    const float* W2_b   = (const float*)d_in[6];
    const float* V_w    = (const float*)d_in[7];
    const float* V_b    = (const float*)d_in[8];
    const float* o2e_w  = (const float*)d_in[9];
    const float* o2e_b  = (const float*)d_in[10];
    const float* gwi    = (const float*)d_in[11];
    const float* gwh    = (const float*)d_in[12];
    const float* gbi    = (const float*)d_in[13];
    const float* gbh    = (const float*)d_in[14];
    const float* f1w    = (const float*)d_in[15];
    const float* f1b    = (const float*)d_in[16];
    const float* f2w    = (const float*)d_in[17];
    const float* f2b    = (const float*)d_in[18];

    float* out  = (float*)d_out;
    float* hnew = out + (size_t)BB * VOC;
    float* attn = hnew + (size_t)BB * DDEC;

    __half* bh = nullptr;
    __half* bl = nullptr;
    float* fs = nullptr;
    cudaGetSymbolAddress((void**)&bh, g_bh);
    cudaGetSymbolAddress((void**)&bl, g_bl);
    cudaGetSymbolAddress((void**)&fs, g_f32);

    float* g1   = fs + F_G1;
    float* rnn  = fs + F_RNN;
    float* gi   = fs + F_GI;
    float* gh   = fs + F_GH;
    float* tbuf = fs + F_T;
    float* part = fs + F_PART;

    cudaFuncSetAttribute(gemm64,      cudaFuncAttributeMaxDynamicSharedMemorySize, GEMM_SMEM);
    cudaFuncSetAttribute(gemm64_bias, cudaFuncAttributeMaxDynamicSharedMemorySize, GEMM_SMEM);
    cudaFuncSetAttribute(score_gemm,  cudaFuncAttributeMaxDynamicSharedMemorySize, SC_SMEM);

    dim3 blk(256);

    // 0) weight splits
    split_weights<<<WN7 / 256, 256>>>(W1_w, W2_w, o2e_w, gwi, gwh, f1w, f2w);
    // 1) activation splits
    split_acts<<<AN3 / 256, 256>>>(enc, x, hidden);

    // 2) g1 = h0 @ W2^T + W2_b + W1_b  (direct store; 256x1024, K=1024)
    gemm64_bias<<<dim3(16, 2), blk, GEMM_SMEM>>>(
        bh + OFF_HID, bl + OFF_HID, bh + OFF_W2, bl + OFF_W2,
        1024, g1, 1024, W2_b, W1_b);

    // 3) score GEMM (launch index 3 -> ncu profiles THIS)
    score_gemm<<<dim3(8, 256), blk, SC_SMEM>>>(
        bh + OFF_ENC, bh + OFF_W1, g1, V_w, part);

    // 4) bias preinit for remaining atomic targets
    bias_init<<<BIAS_TOTAL / 256, 256>>>(rnn, gi, gh, tbuf, out,
                                         o2e_b, gbi, gbh, f1b, f2b);

    // 5) softmax + attn out + context -> rnn[:, 0:1024]
    attn_softmax_context<<<BB, 256>>>(part, 8, enc, V_b, attn, rnn);

    // 6) x_emb += x @ out2emb^T     (256x512, K=4096, splitK=8)
    gemm64<<<dim3(8, 2, 8), blk, GEMM_SMEM>>>(
        bh + OFF_X, bl + OFF_X, bh + OFF_O2E, bl + OFF_O2E,
        4096, 512, rnn + 1024, 1536);

    // 7) gh += h0 @ gru_wh^T        (256x3072, K=1024, splitK=2)
    gemm64<<<dim3(48, 2, 2), blk, GEMM_SMEM>>>(
        bh + OFF_HID, bl + OFF_HID, bh + OFF_GWH, bl + OFF_GWH,
        1024, 512, gh, 3072);

    // 8) rnn -> fp16
    f32_split<<<(393216 / 2) / 256, 256>>>(rnn, bh + OFF_RNN, bl + OFF_RNN, 393216 / 2);

    // 9) gi += rnn_in @ gru_wi^T    (256x3072, K=1536, splitK=2)
    gemm64<<<dim3(48, 2, 2), blk, GEMM_SMEM>>>(
        bh + OFF_RNN, bl + OFF_RNN, bh + OFF_GWI, bl + OFF_GWI,
        1536, 768, gi, 3072);

    // 10) GRU gates -> h_new (output)
    gru_gate<<<(BB * DDEC) / 256, 256>>>(gi, gh, hidden, hnew);

    // 11) h_new -> fp16
    f32_split<<<(262144 / 2) / 256, 256>>>(hnew, bh + OFF_HNEW, bl + OFF_HNEW, 262144 / 2);

    // 12) tbuf += h_new @ fc1^T     (256x512, K=1024, splitK=8)
    gemm64<<<dim3(8, 2, 8), blk, GEMM_SMEM>>>(
        bh + OFF_HNEW, bl + OFF_HNEW, bh + OFF_F1, bl + OFF_F1,
        1024, 128, tbuf, 512);

    // 13) t = tanh(tbuf) -> fp16
    f32_split_tanh<<<(131072 / 2) / 256, 256>>>(tbuf, bh + OFF_T, bl + OFF_T, 131072 / 2);

    // 14) out += t @ fc2^T          (256x4096, K=512, splitK=2)
    gemm64<<<dim3(64, 2, 2), blk, GEMM_SMEM>>>(
        bh + OFF_T, bl + OFF_T, bh + OFF_F2, bl + OFF_F2,
        512, 256, out, 4096);
}

// round 11
// speedup vs baseline: 1.9169x; 1.0699x over previous
#include <cuda_runtime.h>
#include <cuda_fp16.h>
#include <cstdint>
#include <math.h>

// Problem dims
#define BB   256
#define LL   128
#define VOC  4096
#define EENC 1024
#define DDEC 1024
#define EEMB 512

// ======================= scratch (module-load allocated) ==================
#define OFF_ENC   0ull
#define OFF_W1    (OFF_ENC + 33554432ull)
#define OFF_W2    (OFF_W1  + 1048576ull)
#define OFF_O2E   (OFF_W2  + 1048576ull)
#define OFF_GWI   (OFF_O2E + 2097152ull)
#define OFF_GWH   (OFF_GWI + 4718592ull)
#define OFF_F1    (OFF_GWH + 3145728ull)
#define OFF_F2    (OFF_F1  + 524288ull)
#define OFF_X     (OFF_F2  + 2097152ull)
#define OFF_HID   (OFF_X   + 1048576ull)
#define OFF_RNN   (OFF_HID + 262144ull)
#define OFF_HNEW  (OFF_RNN + 393216ull)
#define OFF_T     (OFF_HNEW+ 262144ull)
#define BF_TOTAL  (OFF_T   + 131072ull)

__device__ __half g_bh[BF_TOTAL];
__device__ __half g_bl[BF_TOTAL];

#define F_G1    0ull
#define F_RNN   (F_G1   + 262144ull)
#define F_GI    (F_RNN  + 393216ull)
#define F_GH    (F_GI   + 786432ull)
#define F_T     (F_GH   + 786432ull)
#define F_PART  (F_T    + 131072ull)
#define F_TOTAL (F_PART + 524288ull)

__device__ float g_f32[F_TOTAL];

// ======================= small helpers ====================================
__device__ __forceinline__ void cp16(uint32_t s, const void* g) {
    asm volatile("cp.async.cg.shared.global [%0], [%1], 16;"
                 :: "r"(s), "l"(__cvta_generic_to_global(g)));
}
__device__ __forceinline__ void ldm4(uint32_t* r, uint32_t addr) {
    asm volatile("ldmatrix.sync.aligned.m8n8.x4.shared.b16 {%0,%1,%2,%3}, [%4];"
        : "=r"(r[0]), "=r"(r[1]), "=r"(r[2]), "=r"(r[3]) : "r"(addr));
}
__device__ __forceinline__ void mma16816(float* c, const uint32_t* a, const uint32_t* b) {
    asm volatile("mma.sync.aligned.m16n8k16.row.col.f32.f16.f16.f32 "
        "{%0,%1,%2,%3}, {%4,%5,%6,%7}, {%8,%9}, {%0,%1,%2,%3};"
        : "+f"(c[0]), "+f"(c[1]), "+f"(c[2]), "+f"(c[3])
        : "r"(a[0]), "r"(a[1]), "r"(a[2]), "r"(a[3]), "r"(b[0]), "r"(b[1]));
}
// float4 (4-element) hi/lo split
__device__ __forceinline__ void do_split4(const float* __restrict__ src, int i,
                                          unsigned long long dst) {
    float4 v = ((const float4*)src)[i];
    __half h0 = __float2half_rn(v.x), h1 = __float2half_rn(v.y);
    __half h2 = __float2half_rn(v.z), h3 = __float2half_rn(v.w);
    __half2 hp0; hp0.x = h0; hp0.y = h1;
    __half2 hp1; hp1.x = h2; hp1.y = h3;
    __half2 lp0, lp1;
    lp0.x = __float2half_rn(v.x - __half2float(h0));
    lp0.y = __float2half_rn(v.y - __half2float(h1));
    lp1.x = __float2half_rn(v.z - __half2float(h2));
    lp1.y = __float2half_rn(v.w - __half2float(h3));
    ((__half2*)(g_bh + dst))[2 * i]     = hp0;
    ((__half2*)(g_bh + dst))[2 * i + 1] = hp1;
    ((__half2*)(g_bl + dst))[2 * i]     = lp0;
    ((__half2*)(g_bl + dst))[2 * i + 1] = lp1;
}
// hi-only variant (for enc; lo is never consumed)
__device__ __forceinline__ void do_split4_hi(const float* __restrict__ src, int i,
                                             unsigned long long dst) {
    float4 v = ((const float4*)src)[i];
    __half2 hp0, hp1;
    hp0.x = __float2half_rn(v.x); hp0.y = __float2half_rn(v.y);
    hp1.x = __float2half_rn(v.z); hp1.y = __float2half_rn(v.w);
    ((__half2*)(g_bh + dst))[2 * i]     = hp0;
    ((__half2*)(g_bh + dst))[2 * i + 1] = hp1;
}

// ======================= fused split kernels (float4 units) ===============
#define W4N1 262144
#define W4N2 524288
#define W4N3 1048576
#define W4N4 2228224
#define W4N5 3014656
#define W4N6 3145728
#define W4N7 3670016
__global__ __launch_bounds__(256)
void split_weights(const float* __restrict__ W1, const float* __restrict__ W2,
                   const float* __restrict__ o2e, const float* __restrict__ gwi,
                   const float* __restrict__ gwh, const float* __restrict__ f1,
                   const float* __restrict__ f2)
{
    int i = blockIdx.x * blockDim.x + threadIdx.x;
    if (i < W4N1)      do_split4(W1,  i,        OFF_W1);
    else if (i < W4N2) do_split4(W2,  i - W4N1, OFF_W2);
    else if (i < W4N3) do_split4(o2e, i - W4N2, OFF_O2E);
    else if (i < W4N4) do_split4(gwi, i - W4N3, OFF_GWI);
    else if (i < W4N5) do_split4(gwh, i - W4N4, OFF_GWH);
    else if (i < W4N6) do_split4(f1,  i - W4N5, OFF_F1);
    else if (i < W4N7) do_split4(f2,  i - W4N6, OFF_F2);
}
// acts: enc (hi-only) | x | hidden  (float4 units)
#define A4N1 8388608
#define A4N2 8650752
#define A4N3 8716288
__global__ __launch_bounds__(256)
void split_acts(const float* __restrict__ enc, const float* __restrict__ x,
                const float* __restrict__ hid)
{
    int i = blockIdx.x * blockDim.x + threadIdx.x;
    if (i < A4N1)      do_split4_hi(enc, i,        OFF_ENC);
    else if (i < A4N2) do_split4(x,   i - A4N1, OFF_X);
    else if (i < A4N3) do_split4(hid, i - A4N2, OFF_HID);
}
__global__ __launch_bounds__(256)
void f32_split(const float* __restrict__ in, __half* __restrict__ hi,
               __half* __restrict__ lo, int n4)
{
    int i = blockIdx.x * blockDim.x + threadIdx.x;
    if (i >= n4) return;
    float4 v = ((const float4*)in)[i];
    __half h0 = __float2half_rn(v.x), h1 = __float2half_rn(v.y);
    __half h2 = __float2half_rn(v.z), h3 = __float2half_rn(v.w);
    __half2 hp0; hp0.x = h0; hp0.y = h1;
    __half2 hp1; hp1.x = h2; hp1.y = h3;
    __half2 lp0, lp1;
    lp0.x = __float2half_rn(v.x - __half2float(h0));
    lp0.y = __float2half_rn(v.y - __half2float(h1));
    lp1.x = __float2half_rn(v.z - __half2float(h2));
    lp1.y = __float2half_rn(v.w - __half2float(h3));
    ((__half2*)hi)[2 * i]     = hp0;
    ((__half2*)hi)[2 * i + 1] = hp1;
    ((__half2*)lo)[2 * i]     = lp0;
    ((__half2*)lo)[2 * i + 1] = lp1;
}
__global__ __launch_bounds__(256)
void f32_split_tanh(const float* __restrict__ in, __half* __restrict__ hi,
                    __half* __restrict__ lo, int n4)
{
    int i = blockIdx.x * blockDim.x + threadIdx.x;
    if (i >= n4) return;
    float4 v = ((const float4*)in)[i];
    v.x = tanhf(v.x); v.y = tanhf(v.y); v.z = tanhf(v.z); v.w = tanhf(v.w);
    __half h0 = __float2half_rn(v.x), h1 = __float2half_rn(v.y);
    __half h2 = __float2half_rn(v.z), h3 = __float2half_rn(v.w);
    __half2 hp0; hp0.x = h0; hp0.y = h1;
    __half2 hp1; hp1.x = h2; hp1.y = h3;
    __half2 lp0, lp1;
    lp0.x = __float2half_rn(v.x - __half2float(h0));
    lp0.y = __float2half_rn(v.y - __half2float(h1));
    lp1.x = __float2half_rn(v.z - __half2float(h2));
    lp1.y = __float2half_rn(v.w - __half2float(h3));
    ((__half2*)hi)[2 * i]     = hp0;
    ((__half2*)hi)[2 * i + 1] = hp1;
    ((__half2*)lo)[2 * i]     = lp0;
    ((__half2*)lo)[2 * i + 1] = lp1;
}

// ================= bias pre-init (resets atomic targets every call) =======
__global__ __launch_bounds__(256)
void bias_init(float* __restrict__ rnn,
               float* __restrict__ gi, float* __restrict__ gh,
               float* __restrict__ tbuf, float* __restrict__ out,
               const float* __restrict__ o2eb, const float* __restrict__ gbi,
               const float* __restrict__ gbh, const float* __restrict__ f1b,
               const float* __restrict__ f2b)
{
    int i = blockIdx.x * blockDim.x + threadIdx.x;
    if (i < 131072) {
        rnn[(i >> 9) * 1536 + 1024 + (i & 511)] = o2eb[i & 511];
    } else if (i < 917504) {
        int j = i - 131072;
        gi[j] = gbi[j % 3072];
    } else if (i < 1703936) {
        int j = i - 917504;
        gh[j] = gbh[j % 3072];
    } else if (i < 1835008) {
        int j = i - 1703936;
        tbuf[j] = f1b[j & 511];
    } else {
        int j = i - 1835008;
        out[j] = f2b[j & 4095];
    }
}
#define BIAS_TOTAL 2883584

// ======================= small split-K mma GEMM (R5-proven, fp16) =========
#define ROWB      80
#define TILE_A_SB (128 * ROWB)
#define TILE_W_SB (64 * ROWB)
#define STAGE_SB  (2 * TILE_A_SB + 2 * TILE_W_SB)
#define SM_PART   (2 * STAGE_SB)
#define GEMM_SMEM (SM_PART + 512 + 32)

__global__ __launch_bounds__(256, 2)
void gemm64(const __half* __restrict__ Ah, const __half* __restrict__ Al,
            const __half* __restrict__ Wh, const __half* __restrict__ Wl,
            int K, int Kchunk, float* __restrict__ C, int ldc)
{
    extern __shared__ __align__(128) char smem[];
    const uint32_t sbase = (uint32_t)__cvta_generic_to_shared(smem);

    const int tid  = threadIdx.x;
    const int wid  = tid >> 5;
    const int lane = tid & 31;
    const int brow = blockIdx.y * 128;
    const int bcol = blockIdx.x * 64;
    const int k0   = blockIdx.z * Kchunk;
    const int m32  = (wid >> 1) * 32;
    const int n32w = (wid & 1) * 32;

    const int lrA = tid >> 1;
    const int cA  = (tid & 1) * 2;
    const int lrW = tid >> 2;
    const int cW  = tid & 3;
    const size_t aoff = (size_t)(brow + lrA) * K + k0;
    const size_t woff = (size_t)(bcol + lrW) * K + k0;

    auto load_stage = [&](int stage, int kk0) {
        const uint32_t sA = sbase + stage * STAGE_SB + lrA * ROWB;
        const uint32_t sW = sbase + stage * STAGE_SB + 2 * TILE_A_SB + lrW * ROWB;
        const char* pAh = (const char*)(Ah + aoff + kk0);
        const char* pAl = (const char*)(Al + aoff + kk0);
        const char* pWh = (const char*)(Wh + woff + kk0);
        const char* pWl = (const char*)(Wl + woff + kk0);
        #pragma unroll
        for (int c = cA; c < cA + 2; c++) {
            cp16(sA + c * 16, pAh + c * 16);
            cp16(sA + TILE_A_SB + c * 16, pAl + c * 16);
        }
        cp16(sW + cW * 16, pWh + cW * 16);
        cp16(sW + TILE_W_SB + cW * 16, pWl + cW * 16);
    };

    const int nk = Kchunk >> 5;

    load_stage(0, 0);
    asm volatile("cp.async.commit_group;");
    if (nk > 1) load_stage(1, 32);
    asm volatile("cp.async.commit_group;");

    float acc[2][4][4];
    #pragma unroll
    for (int i = 0; i < 2; i++)
        #pragma unroll
        for (int j = 0; j < 4; j++)
            #pragma unroll
            for (int q = 0; q < 4; q++) acc[i][j][q] = 0.f;

    const int arow_l = m32 + (lane & 15);
    const uint32_t akb = ((lane >> 4) & 1) * 16;
    const int nrow_l = n32w + (lane & 7) + ((lane >> 4) & 1) * 8;
    const uint32_t bkb = ((lane >> 3) & 1) * 16;

    for (int c = 0; c < nk; c++) {
        asm volatile("cp.async.wait_group %0;" :: "n"(1));
        __syncthreads();

        const uint32_t sb = sbase + (c & 1) * STAGE_SB;
        #pragma unroll
        for (int kk = 0; kk < 2; kk++) {
            const uint32_t kbyte = kk * 32;
            uint32_t afh[2][4], afl[2][4], bfh[4][2], bfl[4][2];
            #pragma unroll
            for (int mt = 0; mt < 2; mt++) {
                uint32_t ra = (uint32_t)((arow_l + mt * 16) * ROWB) + akb + kbyte;
                ldm4(afh[mt], sb + ra);
                ldm4(afl[mt], sb + TILE_A_SB + ra);
            }
            #pragma unroll
            for (int np = 0; np < 2; np++) {
                uint32_t rb = (uint32_t)((nrow_l + np * 16) * ROWB) + bkb + kbyte;
                uint32_t th[4], tl[4];
                ldm4(th, sb + 2 * TILE_A_SB + rb);
                ldm4(tl, sb + 2 * TILE_A_SB + TILE_W_SB + rb);
                bfh[2 * np][0] = th[0]; bfh[2 * np][1] = th[1];
                bfh[2 * np + 1][0] = th[2]; bfh[2 * np + 1][1] = th[3];
                bfl[2 * np][0] = tl[0]; bfl[2 * np][1] = tl[1];
                bfl[2 * np + 1][0] = tl[2]; bfl[2 * np + 1][1] = tl[3];
            }
            #pragma unroll
            for (int mt = 0; mt < 2; mt++)
                #pragma unroll
                for (int nt = 0; nt < 4; nt++) {
                    mma16816(acc[mt][nt], afh[mt], bfh[nt]);
                    mma16816(acc[mt][nt], afl[mt], bfh[nt]);
                    mma16816(acc[mt][nt], afh[mt], bfl[nt]);
                }
        }
        __syncthreads();

        if (c + 2 < nk) load_stage(c & 1, (c + 2) * 32);
        asm volatile("cp.async.commit_group;");
    }

    const int rloc0 = m32 + (lane >> 2);
    const int cloc0 = n32w + (lane & 3) * 2;
    #pragma unroll
    for (int mt = 0; mt < 2; mt++) {
        const int r0 = brow + rloc0 + mt * 16;
        #pragma unroll
        for (int nt = 0; nt < 4; nt++) {
            const int col = bcol + cloc0 + nt * 8;
            float* c0 = C + (size_t)r0 * ldc + col;
            float* c1 = C + (size_t)(r0 + 8) * ldc + col;
            atomicAdd(c0,     acc[mt][nt][0]);
            atomicAdd(c0 + 1, acc[mt][nt][1]);
            atomicAdd(c1,     acc[mt][nt][2]);
            atomicAdd(c1 + 1, acc[mt][nt][3]);
        }
    }
}

// ========== gemm64_bias: direct-store variant with 2-bias epilogue ========
__global__ __launch_bounds__(256, 2)
void gemm64_bias(const __half* __restrict__ Ah, const __half* __restrict__ Al,
                 const __half* __restrict__ Wh, const __half* __restrict__ Wl,
                 int K, float* __restrict__ C, int ldc,
                 const float* __restrict__ b1, const float* __restrict__ b2)
{
    extern __shared__ __align__(128) char smem[];
    const uint32_t sbase = (uint32_t)__cvta_generic_to_shared(smem);

    const int tid  = threadIdx.x;
    const int wid  = tid >> 5;
    const int lane = tid & 31;
    const int brow = blockIdx.y * 128;
    const int bcol = blockIdx.x * 64;
    const int m32  = (wid >> 1) * 32;
    const int n32w = (wid & 1) * 32;

    const int lrA = tid >> 1;
    const int cA  = (tid & 1) * 2;
    const int lrW = tid >> 2;
    const int cW  = tid & 3;
    const size_t aoff = (size_t)(brow + lrA) * K;
    const size_t woff = (size_t)(bcol + lrW) * K;

    auto load_stage = [&](int stage, int kk0) {
        const uint32_t sA = sbase + stage * STAGE_SB + lrA * ROWB;
        const uint32_t sW = sbase + stage * STAGE_SB + 2 * TILE_A_SB + lrW * ROWB;
        const char* pAh = (const char*)(Ah + aoff + kk0);
        const char* pAl = (const char*)(Al + aoff + kk0);
        const char* pWh = (const char*)(Wh + woff + kk0);
        const char* pWl = (const char*)(Wl + woff + kk0);
        #pragma unroll
        for (int c = cA; c < cA + 2; c++) {
            cp16(sA + c * 16, pAh + c * 16);
            cp16(sA + TILE_A_SB + c * 16, pAl + c * 16);
        }
        cp16(sW + cW * 16, pWh + cW * 16);
        cp16(sW + TILE_W_SB + cW * 16, pWl + cW * 16);
    };

    const int nk = K >> 5;

    load_stage(0, 0);
    asm volatile("cp.async.commit_group;");
    load_stage(1, 32);
    asm volatile("cp.async.commit_group;");

    float acc[2][4][4];
    #pragma unroll
    for (int i = 0; i < 2; i++)
        #pragma unroll
        for (int j = 0; j < 4; j++)
            #pragma unroll
            for (int q = 0; q < 4; q++) acc[i][j][q] = 0.f;

    const int arow_l = m32 + (lane & 15);
    const uint32_t akb = ((lane >> 4) & 1) * 16;
    const int nrow_l = n32w + (lane & 7) + ((lane >> 4) & 1) * 8;
    const uint32_t bkb = ((lane >> 3) & 1) * 16;

    for (int c = 0; c < nk; c++) {
        asm volatile("cp.async.wait_group %0;" :: "n"(1));
        __syncthreads();

        const uint32_t sb = sbase + (c & 1) * STAGE_SB;
        #pragma unroll
        for (int kk = 0; kk < 2; kk++) {
            const uint32_t kbyte = kk * 32;
            uint32_t afh[2][4], afl[2][4], bfh[4][2], bfl[4][2];
            #pragma unroll
            for (int mt = 0; mt < 2; mt++) {
                uint32_t ra = (uint32_t)((arow_l + mt * 16) * ROWB) + akb + kbyte;
                ldm4(afh[mt], sb + ra);
                ldm4(afl[mt], sb + TILE_A_SB + ra);
            }
            #pragma unroll
            for (int np = 0; np < 2; np++) {
                uint32_t rb = (uint32_t)((nrow_l + np * 16) * ROWB) + bkb + kbyte;
                uint32_t th[4], tl[4];
                ldm4(th, sb + 2 * TILE_A_SB + rb);
                ldm4(tl, sb + 2 * TILE_A_SB + TILE_W_SB + rb);
                bfh[2 * np][0] = th[0]; bfh[2 * np][1] = th[1];
                bfh[2 * np + 1][0] = th[2]; bfh[2 * np + 1][1] = th[3];
                bfl[2 * np][0] = tl[0]; bfl[2 * np][1] = tl[1];
                bfl[2 * np + 1][0] = tl[2]; bfl[2 * np + 1][1] = tl[3];
            }
            #pragma unroll
            for (int mt = 0; mt < 2; mt++)
                #pragma unroll
                for (int nt = 0; nt < 4; nt++) {
                    mma16816(acc[mt][nt], afh[mt], bfh[nt]);
                    mma16816(acc[mt][nt], afl[mt], bfh[nt]);
                    mma16816(acc[mt][nt], afh[mt], bfl[nt]);
                }
        }
        __syncthreads();

        if (c + 2 < nk) load_stage(c & 1, (c + 2) * 32);
        asm volatile("cp.async.commit_group;");
    }

    const int rloc0 = m32 + (lane >> 2);
    const int cloc0 = n32w + (lane & 3) * 2;
    #pragma unroll
    for (int mt = 0; mt < 2; mt++) {
        const int r0 = brow + rloc0 + mt * 16;
        #pragma unroll
        for (int nt = 0; nt < 4; nt++) {
            const int col = bcol + cloc0 + nt * 8;
            float2 bb = make_float2(b1[col] + b2[col], b1[col + 1] + b2[col + 1]);
            *(float2*)(C + (size_t)r0 * ldc + col) =
                make_float2(acc[mt][nt][0] + bb.x, acc[mt][nt][1] + bb.y);
            *(float2*)(C + (size_t)(r0 + 8) * ldc + col) =
                make_float2(acc[mt][nt][2] + bb.x, acc[mt][nt][3] + bb.y);
        }
    }
}

// ======= score GEMM v3: 128x128 tile, BK=64, 3 stages, warp 64x32 =========
#define SC_ROWB   144
#define SC_A_SB   (128 * SC_ROWB)
#define SC_W_SB   (128 * SC_ROWB)
#define SC_STAGE  (SC_A_SB + SC_W_SB)
#define SC_NST    3
#define SC_SMEM   (SC_NST * SC_STAGE + 512 + 32)

__global__ __launch_bounds__(256, 2)
void score_gemm(const __half* __restrict__ Ah, const __half* __restrict__ Wh,
                const float* __restrict__ g1, const float* __restrict__ vw,
                float* __restrict__ partial)
{
    extern __shared__ __align__(128) char smem[];
    const uint32_t sbase = (uint32_t)__cvta_generic_to_shared(smem);
    float* part_sm = (float*)(smem + SC_NST * SC_STAGE);

    const int tid  = threadIdx.x;
    const int wid  = tid >> 5;
    const int lane = tid & 31;
    const int brow = blockIdx.y * 128;
    const int bcol = blockIdx.x * 128;
    const int m64  = (wid >> 2) * 64;
    const int n32  = (wid & 3) * 32;
    const int K    = 1024;

    if (tid < 128) part_sm[tid] = 0.f;

    const int arow = tid >> 1;
    const int acb_ld = (tid & 1) * 4;
    const __half* gA = Ah + (size_t)(brow + arow) * K;
    const __half* gW = Wh + (size_t)(bcol + arow) * K;
    const uint32_t sA_ld = (uint32_t)(arow * SC_ROWB + acb_ld * 16);
    const uint32_t sW_ld = (uint32_t)(SC_A_SB + arow * SC_ROWB + acb_ld * 16);

    auto load_stage = [&](int stage, int k0) {
        const uint32_t sb = sbase + stage * SC_STAGE;
        const char* pA = (const char*)(gA + k0) + acb_ld * 16;
        const char* pW = (const char*)(gW + k0) + acb_ld * 16;
        #pragma unroll
        for (int c = 0; c < 4; c++) {
            cp16(sb + sA_ld + c * 16, pA + c * 16);
            cp16(sb + sW_ld + c * 16, pW + c * 16);
        }
    };

    const int nk = 16;

    load_stage(0, 0);
    asm volatile("cp.async.commit_group;");
    load_stage(1, 64);
    asm volatile("cp.async.commit_group;");

    float acc[4][4][4];
    #pragma unroll
    for (int i = 0; i < 4; i++)
        #pragma unroll
        for (int j = 0; j < 4; j++)
            #pragma unroll
            for (int q = 0; q < 4; q++) acc[i][j][q] = 0.f;

    const int arow_l = m64 + (lane & 15);
    const uint32_t akb = ((lane >> 4) & 1) * 16;
    const int nrow_l = n32 + (lane & 7) + ((lane >> 4) & 1) * 8;
    const uint32_t bkb = ((lane >> 3) & 1) * 16;

    int stage = 0;
    for (int c = 0; c < nk; c++) {
        asm volatile("cp.async.wait_group %0;" :: "n"(1));
        __syncthreads();

        if (c + 2 < nk) {
            int s2 = stage + 2; if (s2 >= SC_NST) s2 -= SC_NST;
            load_stage(s2, (c + 2) * 64);
        }
        asm volatile("cp.async.commit_group;");

        const uint32_t sb = sbase + stage * SC_STAGE;
        #pragma unroll
        for (int kk = 0; kk < 4; kk++) {
            const uint32_t kbyte = kk * 32;
            uint32_t bfh[4][2];
            #pragma unroll
            for (int np = 0; np < 2; np++) {
                uint32_t rb = (uint32_t)((nrow_l + np * 16) * SC_ROWB) + bkb + kbyte;
                uint32_t th[4];
                ldm4(th, sb + SC_A_SB + rb);
                bfh[2 * np][0] = th[0]; bfh[2 * np][1] = th[1];
                bfh[2 * np + 1][0] = th[2]; bfh[2 * np + 1][1] = th[3];
            }
            #pragma unroll
            for (int mt = 0; mt < 4; mt++) {
                uint32_t afh[4];
                uint32_t ra = (uint32_t)((arow_l + mt * 16) * SC_ROWB) + akb + kbyte;
                ldm4(afh, sb + ra);
                #pragma unroll
                for (int nt = 0; nt < 4; nt++)
                    mma16816(acc[mt][nt], afh, bfh[nt]);
            }
        }
        if (++stage >= SC_NST) stage = 0;
    }

    const int rloc0 = m64 + (lane >> 2);
    const int cloc0 = n32 + (lane & 3) * 2;
    const float* g1r = g1 + (size_t)blockIdx.y * 1024;
    #pragma unroll
    for (int mt = 0; mt < 4; mt++) {
        float s0 = 0.f, s1 = 0.f;
        #pragma unroll
        for (int nt = 0; nt < 4; nt++) {
            int col = bcol + cloc0 + nt * 8;
            float gw0 = g1r[col],     vw0 = vw[col];
            float gw1 = g1r[col + 1], vw1 = vw[col + 1];
            s0 += tanhf(acc[mt][nt][0] + gw0) * vw0;
            s0 += tanhf(acc[mt][nt][1] + gw1) * vw1;
            s1 += tanhf(acc[mt][nt][2] + gw0) * vw0;
            s1 += tanhf(acc[mt][nt][3] + gw1) * vw1;
        }
        atomicAdd(&part_sm[rloc0 + mt * 16], s0);
        atomicAdd(&part_sm[rloc0 + mt * 16 + 8], s1);
    }
    __syncthreads();
    if (tid < 128)
        partial[(size_t)(brow + tid) * gridDim.x + blockIdx.x] = part_sm[tid];
}

// ============== softmax + context (enc read as fp16 hi) ===================
__global__ __launch_bounds__(256)
void attn_softmax_context(const float* __restrict__ part, int npart,
                          const __half* __restrict__ ench,
                          const float* __restrict__ Vb,
                          float* __restrict__ attn_out,
                          float* __restrict__ rnn)
{
    const int b   = blockIdx.x;
    const int tid = threadIdx.x;
    __shared__ float logit[LL];

    if (tid < LL) {
        const float* pr = part + (size_t)(b * LL + tid) * npart;
        float s = Vb[0];
        for (int j = 0; j < npart; j++) s += pr[j];
        logit[tid] = s;
    }
    __syncthreads();

    if (tid < 32) {
        const int lane = tid;
        float m = -1e30f;
        for (int l = lane; l < LL; l += 32) m = fmaxf(m, logit[l]);
        #pragma unroll
        for (int o = 16; o; o >>= 1) m = fmaxf(m, __shfl_xor_sync(0xffffffffu, m, o));
        float s = 0.f;
        for (int l = lane; l < LL; l += 32) {
            float e = expf(logit[l] - m);
            logit[l] = e;
            s += e;
        }
        #pragma unroll
        for (int o = 16; o; o >>= 1) s += __shfl_xor_sync(0xffffffffu, s, o);
        float inv = 1.f / s;
        for (int l = lane; l < LL; l += 32) logit[l] *= inv;
    }
    __syncthreads();

    if (tid < LL) attn_out[b * LL + tid] = logit[tid];

    // context: 4 columns per thread, read enc as __half2 pairs
    float4 acc = make_float4(0.f, 0.f, 0.f, 0.f);
    const __half2* encb = (const __half2*)(ench + (size_t)b * LL * EENC) + tid * 2;
    #pragma unroll 4
    for (int l = 0; l < LL; l++) {
        float a = logit[l];
        __half2 v0 = encb[l * (EENC / 2)];
        __half2 v1 = encb[l * (EENC / 2) + 1];
        float2 f0 = __half22float2(v0);
        float2 f1 = __half22float2(v1);
        acc.x += a * f0.x; acc.y += a * f0.y;
        acc.z += a * f1.x; acc.w += a * f1.y;
    }
    *(float4*)(rnn + (size_t)b * 1536 + tid * 4) = acc;
}

// ============================ GRU gates ===================================
__global__ __launch_bounds__(256)
void gru_gate(const float* __restrict__ gi, const float* __restrict__ gh,
              const float* __restrict__ h0, float* __restrict__ hnew)
{
    const int idx = blockIdx.x * blockDim.x + threadIdx.x;
    const int b = idx >> 10;
    const int d = idx & 1023;
    const float* gib = gi + (size_t)b * 3072;
    const float* ghb = gh + (size_t)b * 3072;
    float r = 1.f / (1.f + expf(-(gib[d] + ghb[d])));
    float z = 1.f / (1.f + expf(-(gib[1024 + d] + ghb[1024 + d])));
    float n = tanhf(gib[2048 + d] + r * ghb[2048 + d]);
    hnew[idx] = (1.f - z) * n + z * h0[idx];
}

// ============================ launch ======================================
extern "C" void kernel_launch(void* const* d_in, const int* in_sizes, int n_in,
                              void* d_out, int out_size)
{
    (void)in_sizes; (void)n_in; (void)out_size;

    const float* x      = (const float*)d_in[0];
    const float* hidden = (const float*)d_in[1];
    const float* enc    = (const float*)d_in[2];
    const float* W1_w   = (const float*)d_in[3];
    const float* W1_b   = (const float*)d_in[4];
    const float* W2_w   = (const float*)d_in[5];
    const float* W2_b   = (const float*)d_in[6];
    const float* V_w    = (const float*)d_in[7];
    const float* V_b    = (const float*)d_in[8];
    const float* o2e_w  = (const float*)d_in[9];
    const float* o2e_b  = (const float*)d_in[10];
    const float* gwi    = (const float*)d_in[11];
    const float* gwh    = (const float*)d_in[12];
    const float* gbi    = (const float*)d_in[13];
    const float* gbh    = (const float*)d_in[14];
    const float* f1w    = (const float*)d_in[15];
    const float* f1b    = (const float*)d_in[16];
    const float* f2w    = (const float*)d_in[17];
    const float* f2b    = (const float*)d_in[18];

    float* out  = (float*)d_out;
    float* hnew = out + (size_t)BB * VOC;
    float* attn = hnew + (size_t)BB * DDEC;

    __half* bh = nullptr;
    __half* bl = nullptr;
    float* fs = nullptr;
    cudaGetSymbolAddress((void**)&bh, g_bh);
    cudaGetSymbolAddress((void**)&bl, g_bl);
    cudaGetSymbolAddress((void**)&fs, g_f32);

    float* g1   = fs + F_G1;
    float* rnn  = fs + F_RNN;
    float* gi   = fs + F_GI;
    float* gh   = fs + F_GH;
    float* tbuf = fs + F_T;
    float* part = fs + F_PART;

    cudaFuncSetAttribute(gemm64,      cudaFuncAttributeMaxDynamicSharedMemorySize, GEMM_SMEM);
    cudaFuncSetAttribute(gemm64_bias, cudaFuncAttributeMaxDynamicSharedMemorySize, GEMM_SMEM);
    cudaFuncSetAttribute(score_gemm,  cudaFuncAttributeMaxDynamicSharedMemorySize, SC_SMEM);

    dim3 blk(256);

    // 0) weight splits (float4)
    split_weights<<<W4N7 / 256, 256>>>(W1_w, W2_w, o2e_w, gwi, gwh, f1w, f2w);
    // 1) activation splits (float4, enc hi-only)
    split_acts<<<A4N3 / 256, 256>>>(enc, x, hidden);

    // 2) g1 = h0 @ W2^T + W2_b + W1_b  (direct store; 256x1024, K=1024)
    gemm64_bias<<<dim3(16, 2), blk, GEMM_SMEM>>>(
        bh + OFF_HID, bl + OFF_HID, bh + OFF_W2, bl + OFF_W2,
        1024, g1, 1024, W2_b, W1_b);

    // 3) score GEMM (launch index 3 -> ncu profiles THIS)
    score_gemm<<<dim3(8, 256), blk, SC_SMEM>>>(
        bh + OFF_ENC, bh + OFF_W1, g1, V_w, part);

    // 4) bias preinit for remaining atomic targets
    bias_init<<<BIAS_TOTAL / 256, 256>>>(rnn, gi, gh, tbuf, out,
                                         o2e_b, gbi, gbh, f1b, f2b);

    // 5) softmax + attn out + context (enc fp16) -> rnn[:, 0:1024]
    attn_softmax_context<<<BB, 256>>>(part, 8, bh + OFF_ENC, V_b, attn, rnn);

    // 6) x_emb += x @ out2emb^T     (256x512, K=4096, splitK=8)
    gemm64<<<dim3(8, 2, 8), blk, GEMM_SMEM>>>(
        bh + OFF_X, bl + OFF_X, bh + OFF_O2E, bl + OFF_O2E,
        4096, 512, rnn + 1024, 1536);

    // 7) gh += h0 @ gru_wh^T        (256x3072, K=1024, splitK=2)
    gemm64<<<dim3(48, 2, 2), blk, GEMM_SMEM>>>(
        bh + OFF_HID, bl + OFF_HID, bh + OFF_GWH, bl + OFF_GWH,
        1024, 512, gh, 3072);

    // 8) rnn -> fp16 (float4 units)
    f32_split<<<(393216 / 4) / 256, 256>>>(rnn, bh + OFF_RNN, bl + OFF_RNN, 393216 / 4);

    // 9) gi += rnn_in @ gru_wi^T    (256x3072, K=1536, splitK=2)
    gemm64<<<dim3(48, 2, 2), blk, GEMM_SMEM>>>(
        bh + OFF_RNN, bl + OFF_RNN, bh + OFF_GWI, bl + OFF_GWI,
        1536, 768, gi, 3072);

    // 10) GRU gates -> h_new (output)
    gru_gate<<<(BB * DDEC) / 256, 256>>>(gi, gh, hidden, hnew);

    // 11) h_new -> fp16
    f32_split<<<(262144 / 4) / 256, 256>>>(hnew, bh + OFF_HNEW, bl + OFF_HNEW, 262144 / 4);

    // 12) tbuf += h_new @ fc1^T     (256x512, K=1024, splitK=8)
    gemm64<<<dim3(8, 2, 8), blk, GEMM_SMEM>>>(
        bh + OFF_HNEW, bl + OFF_HNEW, bh + OFF_F1, bl + OFF_F1,
        1024, 128, tbuf, 512);

    // 13) t = tanh(tbuf) -> fp16
    f32_split_tanh<<<(131072 / 4) / 256, 256>>>(tbuf, bh + OFF_T, bl + OFF_T, 131072 / 4);

    // 14) out += t @ fc2^T          (256x4096, K=512, splitK=2)
    gemm64<<<dim3(64, 2, 2), blk, GEMM_SMEM>>>(
        bh + OFF_T, bl + OFF_T, bh + OFF_F2, bl + OFF_F2,
        512, 256, out, 4096);
}

// round 12
// speedup vs baseline: 2.0024x; 1.0446x over previous
#include <cuda_runtime.h>
#include <cuda_fp16.h>
#include <cstdint>
#include <math.h>

// Problem dims
#define BB   256
#define LL   128
#define VOC  4096
#define EENC 1024
#define DDEC 1024
#define EEMB 512

// ======================= scratch (module-load allocated) ==================
#define OFF_ENC   0ull
#define OFF_W1    (OFF_ENC + 33554432ull)
#define OFF_W2    (OFF_W1  + 1048576ull)
#define OFF_O2E   (OFF_W2  + 1048576ull)
#define OFF_GWI   (OFF_O2E + 2097152ull)
#define OFF_GWH   (OFF_GWI + 4718592ull)
#define OFF_F1    (OFF_GWH + 3145728ull)
#define OFF_F2    (OFF_F1  + 524288ull)
#define OFF_X     (OFF_F2  + 2097152ull)
#define OFF_HID   (OFF_X   + 1048576ull)
#define OFF_RNN   (OFF_HID + 262144ull)
#define OFF_HNEW  (OFF_RNN + 393216ull)
#define OFF_T     (OFF_HNEW+ 262144ull)
#define BF_TOTAL  (OFF_T   + 131072ull)

__device__ __half g_bh[BF_TOTAL];
__device__ __half g_bl[BF_TOTAL];

#define F_G1    0ull
#define F_RNN   (F_G1   + 262144ull)
#define F_GI    (F_RNN  + 393216ull)
#define F_GH    (F_GI   + 786432ull)
#define F_T     (F_GH   + 786432ull)
#define F_PART  (F_T    + 131072ull)
#define F_TOTAL (F_PART + 524288ull)

__device__ float g_f32[F_TOTAL];

// ======================= small helpers ====================================
__device__ __forceinline__ void cp16(uint32_t s, const void* g) {
    asm volatile("cp.async.cg.shared.global [%0], [%1], 16;"
                 :: "r"(s), "l"(__cvta_generic_to_global(g)));
}
__device__ __forceinline__ void ldm4(uint32_t* r, uint32_t addr) {
    asm volatile("ldmatrix.sync.aligned.m8n8.x4.shared.b16 {%0,%1,%2,%3}, [%4];"
        : "=r"(r[0]), "=r"(r[1]), "=r"(r[2]), "=r"(r[3]) : "r"(addr));
}
__device__ __forceinline__ void mma16816(float* c, const uint32_t* a, const uint32_t* b) {
    asm volatile("mma.sync.aligned.m16n8k16.row.col.f32.f16.f16.f32 "
        "{%0,%1,%2,%3}, {%4,%5,%6,%7}, {%8,%9}, {%0,%1,%2,%3};"
        : "+f"(c[0]), "+f"(c[1]), "+f"(c[2]), "+f"(c[3])
        : "r"(a[0]), "r"(a[1]), "r"(a[2]), "r"(a[3]), "r"(b[0]), "r"(b[1]));
}
__device__ __forceinline__ void do_split4(const float* __restrict__ src, int i,
                                          unsigned long long dst) {
    float4 v = ((const float4*)src)[i];
    __half h0 = __float2half_rn(v.x), h1 = __float2half_rn(v.y);
    __half h2 = __float2half_rn(v.z), h3 = __float2half_rn(v.w);
    __half2 hp0; hp0.x = h0; hp0.y = h1;
    __half2 hp1; hp1.x = h2; hp1.y = h3;
    __half2 lp0, lp1;
    lp0.x = __float2half_rn(v.x - __half2float(h0));
    lp0.y = __float2half_rn(v.y - __half2float(h1));
    lp1.x = __float2half_rn(v.z - __half2float(h2));
    lp1.y = __float2half_rn(v.w - __half2float(h3));
    ((__half2*)(g_bh + dst))[2 * i]     = hp0;
    ((__half2*)(g_bh + dst))[2 * i + 1] = hp1;
    ((__half2*)(g_bl + dst))[2 * i]     = lp0;
    ((__half2*)(g_bl + dst))[2 * i + 1] = lp1;
}
__device__ __forceinline__ void do_split4_hi(const float* __restrict__ src, int i,
                                             unsigned long long dst) {
    float4 v = ((const float4*)src)[i];
    __half2 hp0, hp1;
    hp0.x = __float2half_rn(v.x); hp0.y = __float2half_rn(v.y);
    hp1.x = __float2half_rn(v.z); hp1.y = __float2half_rn(v.w);
    ((__half2*)(g_bh + dst))[2 * i]     = hp0;
    ((__half2*)(g_bh + dst))[2 * i + 1] = hp1;
}

// ======================= fused split kernels (float4 units) ===============
// hi-only: W1, o2e, gwi, gwh, f1.  hi+lo: W2, f2.
#define W4N1 262144
#define W4N2 524288
#define W4N3 1048576
#define W4N4 2228224
#define W4N5 3014656
#define W4N6 3145728
#define W4N7 3670016
__global__ __launch_bounds__(256)
void split_weights(const float* __restrict__ W1, const float* __restrict__ W2,
                   const float* __restrict__ o2e, const float* __restrict__ gwi,
                   const float* __restrict__ gwh, const float* __restrict__ f1,
                   const float* __restrict__ f2)
{
    int i = blockIdx.x * blockDim.x + threadIdx.x;
    if (i < W4N1)      do_split4_hi(W1,  i,        OFF_W1);
    else if (i < W4N2) do_split4(W2,  i - W4N1, OFF_W2);
    else if (i < W4N3) do_split4_hi(o2e, i - W4N2, OFF_O2E);
    else if (i < W4N4) do_split4_hi(gwi, i - W4N3, OFF_GWI);
    else if (i < W4N5) do_split4_hi(gwh, i - W4N4, OFF_GWH);
    else if (i < W4N6) do_split4_hi(f1,  i - W4N5, OFF_F1);
    else if (i < W4N7) do_split4(f2,  i - W4N6, OFF_F2);
}
#define A4N1 8388608
#define A4N2 8650752
#define A4N3 8716288
__global__ __launch_bounds__(256)
void split_acts(const float* __restrict__ enc, const float* __restrict__ x,
                const float* __restrict__ hid)
{
    int i = blockIdx.x * blockDim.x + threadIdx.x;
    if (i < A4N1)      do_split4_hi(enc, i,        OFF_ENC);
    else if (i < A4N2) do_split4(x,   i - A4N1, OFF_X);
    else if (i < A4N3) do_split4(hid, i - A4N2, OFF_HID);
}
__global__ __launch_bounds__(256)
void f32_split(const float* __restrict__ in, __half* __restrict__ hi,
               __half* __restrict__ lo, int n4)
{
    int i = blockIdx.x * blockDim.x + threadIdx.x;
    if (i >= n4) return;
    float4 v = ((const float4*)in)[i];
    __half h0 = __float2half_rn(v.x), h1 = __float2half_rn(v.y);
    __half h2 = __float2half_rn(v.z), h3 = __float2half_rn(v.w);
    __half2 hp0; hp0.x = h0; hp0.y = h1;
    __half2 hp1; hp1.x = h2; hp1.y = h3;
    __half2 lp0, lp1;
    lp0.x = __float2half_rn(v.x - __half2float(h0));
    lp0.y = __float2half_rn(v.y - __half2float(h1));
    lp1.x = __float2half_rn(v.z - __half2float(h2));
    lp1.y = __float2half_rn(v.w - __half2float(h3));
    ((__half2*)hi)[2 * i]     = hp0;
    ((__half2*)hi)[2 * i + 1] = hp1;
    ((__half2*)lo)[2 * i]     = lp0;
    ((__half2*)lo)[2 * i + 1] = lp1;
}
__global__ __launch_bounds__(256)
void f32_split_tanh(const float* __restrict__ in, __half* __restrict__ hi,
                    __half* __restrict__ lo, int n4)
{
    int i = blockIdx.x * blockDim.x + threadIdx.x;
    if (i >= n4) return;
    float4 v = ((const float4*)in)[i];
    v.x = tanhf(v.x); v.y = tanhf(v.y); v.z = tanhf(v.z); v.w = tanhf(v.w);
    __half h0 = __float2half_rn(v.x), h1 = __float2half_rn(v.y);
    __half h2 = __float2half_rn(v.z), h3 = __float2half_rn(v.w);
    __half2 hp0; hp0.x = h0; hp0.y = h1;
    __half2 hp1; hp1.x = h2; hp1.y = h3;
    __half2 lp0, lp1;
    lp0.x = __float2half_rn(v.x - __half2float(h0));
    lp0.y = __float2half_rn(v.y - __half2float(h1));
    lp1.x = __float2half_rn(v.z - __half2float(h2));
    lp1.y = __float2half_rn(v.w - __half2float(h3));
    ((__half2*)hi)[2 * i]     = hp0;
    ((__half2*)hi)[2 * i + 1] = hp1;
    ((__half2*)lo)[2 * i]     = lp0;
    ((__half2*)lo)[2 * i + 1] = lp1;
}

// ================= bias pre-init (resets atomic targets every call) =======
__global__ __launch_bounds__(256)
void bias_init(float* __restrict__ rnn,
               float* __restrict__ gi, float* __restrict__ gh,
               float* __restrict__ tbuf, float* __restrict__ out,
               const float* __restrict__ o2eb, const float* __restrict__ gbi,
               const float* __restrict__ gbh, const float* __restrict__ f1b,
               const float* __restrict__ f2b)
{
    int i = blockIdx.x * blockDim.x + threadIdx.x;
    if (i < 131072) {
        rnn[(i >> 9) * 1536 + 1024 + (i & 511)] = o2eb[i & 511];
    } else if (i < 917504) {
        int j = i - 131072;
        gi[j] = gbi[j % 3072];
    } else if (i < 1703936) {
        int j = i - 917504;
        gh[j] = gbh[j % 3072];
    } else if (i < 1835008) {
        int j = i - 1703936;
        tbuf[j] = f1b[j & 511];
    } else {
        int j = i - 1835008;
        out[j] = f2b[j & 4095];
    }
}
#define BIAS_TOTAL 2883584

// ======================= 3-term split-K mma GEMM (fc2 / g1) ===============
#define ROWB      80
#define TILE_A_SB (128 * ROWB)
#define TILE_W_SB (64 * ROWB)
#define STAGE_SB  (2 * TILE_A_SB + 2 * TILE_W_SB)
#define SM_PART   (2 * STAGE_SB)
#define GEMM_SMEM (SM_PART + 512 + 32)

__global__ __launch_bounds__(256, 2)
void gemm64(const __half* __restrict__ Ah, const __half* __restrict__ Al,
            const __half* __restrict__ Wh, const __half* __restrict__ Wl,
            int K, int Kchunk, float* __restrict__ C, int ldc)
{
    extern __shared__ __align__(128) char smem[];
    const uint32_t sbase = (uint32_t)__cvta_generic_to_shared(smem);

    const int tid  = threadIdx.x;
    const int wid  = tid >> 5;
    const int lane = tid & 31;
    const int brow = blockIdx.y * 128;
    const int bcol = blockIdx.x * 64;
    const int k0   = blockIdx.z * Kchunk;
    const int m32  = (wid >> 1) * 32;
    const int n32w = (wid & 1) * 32;

    const int lrA = tid >> 1;
    const int cA  = (tid & 1) * 2;
    const int lrW = tid >> 2;
    const int cW  = tid & 3;
    const size_t aoff = (size_t)(brow + lrA) * K + k0;
    const size_t woff = (size_t)(bcol + lrW) * K + k0;

    auto load_stage = [&](int stage, int kk0) {
        const uint32_t sA = sbase + stage * STAGE_SB + lrA * ROWB;
        const uint32_t sW = sbase + stage * STAGE_SB + 2 * TILE_A_SB + lrW * ROWB;
        const char* pAh = (const char*)(Ah + aoff + kk0);
        const char* pAl = (const char*)(Al + aoff + kk0);
        const char* pWh = (const char*)(Wh + woff + kk0);
        const char* pWl = (const char*)(Wl + woff + kk0);
        #pragma unroll
        for (int c = cA; c < cA + 2; c++) {
            cp16(sA + c * 16, pAh + c * 16);
            cp16(sA + TILE_A_SB + c * 16, pAl + c * 16);
        }
        cp16(sW + cW * 16, pWh + cW * 16);
        cp16(sW + TILE_W_SB + cW * 16, pWl + cW * 16);
    };

    const int nk = Kchunk >> 5;

    load_stage(0, 0);
    asm volatile("cp.async.commit_group;");
    if (nk > 1) load_stage(1, 32);
    asm volatile("cp.async.commit_group;");

    float acc[2][4][4];
    #pragma unroll
    for (int i = 0; i < 2; i++)
        #pragma unroll
        for (int j = 0; j < 4; j++)
            #pragma unroll
            for (int q = 0; q < 4; q++) acc[i][j][q] = 0.f;

    const int arow_l = m32 + (lane & 15);
    const uint32_t akb = ((lane >> 4) & 1) * 16;
    const int nrow_l = n32w + (lane & 7) + ((lane >> 4) & 1) * 8;
    const uint32_t bkb = ((lane >> 3) & 1) * 16;

    for (int c = 0; c < nk; c++) {
        asm volatile("cp.async.wait_group %0;" :: "n"(1));
        __syncthreads();

        const uint32_t sb = sbase + (c & 1) * STAGE_SB;
        #pragma unroll
        for (int kk = 0; kk < 2; kk++) {
            const uint32_t kbyte = kk * 32;
            uint32_t afh[2][4], afl[2][4], bfh[4][2], bfl[4][2];
            #pragma unroll
            for (int mt = 0; mt < 2; mt++) {
                uint32_t ra = (uint32_t)((arow_l + mt * 16) * ROWB) + akb + kbyte;
                ldm4(afh[mt], sb + ra);
                ldm4(afl[mt], sb + TILE_A_SB + ra);
            }
            #pragma unroll
            for (int np = 0; np < 2; np++) {
                uint32_t rb = (uint32_t)((nrow_l + np * 16) * ROWB) + bkb + kbyte;
                uint32_t th[4], tl[4];
                ldm4(th, sb + 2 * TILE_A_SB + rb);
                ldm4(tl, sb + 2 * TILE_A_SB + TILE_W_SB + rb);
                bfh[2 * np][0] = th[0]; bfh[2 * np][1] = th[1];
                bfh[2 * np + 1][0] = th[2]; bfh[2 * np + 1][1] = th[3];
                bfl[2 * np][0] = tl[0]; bfl[2 * np][1] = tl[1];
                bfl[2 * np + 1][0] = tl[2]; bfl[2 * np + 1][1] = tl[3];
            }
            #pragma unroll
            for (int mt = 0; mt < 2; mt++)
                #pragma unroll
                for (int nt = 0; nt < 4; nt++) {
                    mma16816(acc[mt][nt], afh[mt], bfh[nt]);
                    mma16816(acc[mt][nt], afl[mt], bfh[nt]);
                    mma16816(acc[mt][nt], afh[mt], bfl[nt]);
                }
        }
        __syncthreads();

        if (c + 2 < nk) load_stage(c & 1, (c + 2) * 32);
        asm volatile("cp.async.commit_group;");
    }

    const int rloc0 = m32 + (lane >> 2);
    const int cloc0 = n32w + (lane & 3) * 2;
    #pragma unroll
    for (int mt = 0; mt < 2; mt++) {
        const int r0 = brow + rloc0 + mt * 16;
        #pragma unroll
        for (int nt = 0; nt < 4; nt++) {
            const int col = bcol + cloc0 + nt * 8;
            float* c0 = C + (size_t)r0 * ldc + col;
            float* c1 = C + (size_t)(r0 + 8) * ldc + col;
            atomicAdd(c0,     acc[mt][nt][0]);
            atomicAdd(c0 + 1, acc[mt][nt][1]);
            atomicAdd(c1,     acc[mt][nt][2]);
            atomicAdd(c1 + 1, acc[mt][nt][3]);
        }
    }
}

// ====== 2-term split-K GEMM: (Ah+Al)*Wh, Wl never loaded (gi/gh/xemb/fc1) =
#define STAGE2_SB (2 * TILE_A_SB + TILE_W_SB)     // 25600
#define GEMM2_SMEM (2 * STAGE2_SB + 512 + 32)

__global__ __launch_bounds__(256, 2)
void gemm64b(const __half* __restrict__ Ah, const __half* __restrict__ Al,
             const __half* __restrict__ Wh,
             int K, int Kchunk, float* __restrict__ C, int ldc)
{
    extern __shared__ __align__(128) char smem[];
    const uint32_t sbase = (uint32_t)__cvta_generic_to_shared(smem);

    const int tid  = threadIdx.x;
    const int wid  = tid >> 5;
    const int lane = tid & 31;
    const int brow = blockIdx.y * 128;
    const int bcol = blockIdx.x * 64;
    const int k0   = blockIdx.z * Kchunk;
    const int m32  = (wid >> 1) * 32;
    const int n32w = (wid & 1) * 32;

    const int lrA = tid >> 1;
    const int cA  = (tid & 1) * 2;
    const int lrW = tid >> 2;
    const int cW  = tid & 3;
    const size_t aoff = (size_t)(brow + lrA) * K + k0;
    const size_t woff = (size_t)(bcol + lrW) * K + k0;

    auto load_stage = [&](int stage, int kk0) {
        const uint32_t sA = sbase + stage * STAGE2_SB + lrA * ROWB;
        const uint32_t sW = sbase + stage * STAGE2_SB + 2 * TILE_A_SB + lrW * ROWB;
        const char* pAh = (const char*)(Ah + aoff + kk0);
        const char* pAl = (const char*)(Al + aoff + kk0);
        const char* pWh = (const char*)(Wh + woff + kk0);
        #pragma unroll
        for (int c = cA; c < cA + 2; c++) {
            cp16(sA + c * 16, pAh + c * 16);
            cp16(sA + TILE_A_SB + c * 16, pAl + c * 16);
        }
        cp16(sW + cW * 16, pWh + cW * 16);
    };

    const int nk = Kchunk >> 5;

    load_stage(0, 0);
    asm volatile("cp.async.commit_group;");
    if (nk > 1) load_stage(1, 32);
    asm volatile("cp.async.commit_group;");

    float acc[2][4][4];
    #pragma unroll
    for (int i = 0; i < 2; i++)
        #pragma unroll
        for (int j = 0; j < 4; j++)
            #pragma unroll
            for (int q = 0; q < 4; q++) acc[i][j][q] = 0.f;

    const int arow_l = m32 + (lane & 15);
    const uint32_t akb = ((lane >> 4) & 1) * 16;
    const int nrow_l = n32w + (lane & 7) + ((lane >> 4) & 1) * 8;
    const uint32_t bkb = ((lane >> 3) & 1) * 16;

    for (int c = 0; c < nk; c++) {
        asm volatile("cp.async.wait_group %0;" :: "n"(1));
        __syncthreads();

        const uint32_t sb = sbase + (c & 1) * STAGE2_SB;
        #pragma unroll
        for (int kk = 0; kk < 2; kk++) {
            const uint32_t kbyte = kk * 32;
            uint32_t afh[2][4], afl[2][4], bfh[4][2];
            #pragma unroll
            for (int mt = 0; mt < 2; mt++) {
                uint32_t ra = (uint32_t)((arow_l + mt * 16) * ROWB) + akb + kbyte;
                ldm4(afh[mt], sb + ra);
                ldm4(afl[mt], sb + TILE_A_SB + ra);
            }
            #pragma unroll
            for (int np = 0; np < 2; np++) {
                uint32_t rb = (uint32_t)((nrow_l + np * 16) * ROWB) + bkb + kbyte;
                uint32_t th[4];
                ldm4(th, sb + 2 * TILE_A_SB + rb);
                bfh[2 * np][0] = th[0]; bfh[2 * np][1] = th[1];
                bfh[2 * np + 1][0] = th[2]; bfh[2 * np + 1][1] = th[3];
            }
            #pragma unroll
            for (int mt = 0; mt < 2; mt++)
                #pragma unroll
                for (int nt = 0; nt < 4; nt++) {
                    mma16816(acc[mt][nt], afh[mt], bfh[nt]);
                    mma16816(acc[mt][nt], afl[mt], bfh[nt]);
                }
        }
        __syncthreads();

        if (c + 2 < nk) load_stage(c & 1, (c + 2) * 32);
        asm volatile("cp.async.commit_group;");
    }

    const int rloc0 = m32 + (lane >> 2);
    const int cloc0 = n32w + (lane & 3) * 2;
    #pragma unroll
    for (int mt = 0; mt < 2; mt++) {
        const int r0 = brow + rloc0 + mt * 16;
        #pragma unroll
        for (int nt = 0; nt < 4; nt++) {
            const int col = bcol + cloc0 + nt * 8;
            float* c0 = C + (size_t)r0 * ldc + col;
            float* c1 = C + (size_t)(r0 + 8) * ldc + col;
            atomicAdd(c0,     acc[mt][nt][0]);
            atomicAdd(c0 + 1, acc[mt][nt][1]);
            atomicAdd(c1,     acc[mt][nt][2]);
            atomicAdd(c1 + 1, acc[mt][nt][3]);
        }
    }
}

// ========== gemm64_bias: 3-term direct-store with 2-bias epilogue (g1) ====
__global__ __launch_bounds__(256, 2)
void gemm64_bias(const __half* __restrict__ Ah, const __half* __restrict__ Al,
                 const __half* __restrict__ Wh, const __half* __restrict__ Wl,
                 int K, float* __restrict__ C, int ldc,
                 const float* __restrict__ b1, const float* __restrict__ b2)
{
    extern __shared__ __align__(128) char smem[];
    const uint32_t sbase = (uint32_t)__cvta_generic_to_shared(smem);

    const int tid  = threadIdx.x;
    const int wid  = tid >> 5;
    const int lane = tid & 31;
    const int brow = blockIdx.y * 128;
    const int bcol = blockIdx.x * 64;
    const int m32  = (wid >> 1) * 32;
    const int n32w = (wid & 1) * 32;

    const int lrA = tid >> 1;
    const int cA  = (tid & 1) * 2;
    const int lrW = tid >> 2;
    const int cW  = tid & 3;
    const size_t aoff = (size_t)(brow + lrA) * K;
    const size_t woff = (size_t)(bcol + lrW) * K;

    auto load_stage = [&](int stage, int kk0) {
        const uint32_t sA = sbase + stage * STAGE_SB + lrA * ROWB;
        const uint32_t sW = sbase + stage * STAGE_SB + 2 * TILE_A_SB + lrW * ROWB;
        const char* pAh = (const char*)(Ah + aoff + kk0);
        const char* pAl = (const char*)(Al + aoff + kk0);
        const char* pWh = (const char*)(Wh + woff + kk0);
        const char* pWl = (const char*)(Wl + woff + kk0);
        #pragma unroll
        for (int c = cA; c < cA + 2; c++) {
            cp16(sA + c * 16, pAh + c * 16);
            cp16(sA + TILE_A_SB + c * 16, pAl + c * 16);
        }
        cp16(sW + cW * 16, pWh + cW * 16);
        cp16(sW + TILE_W_SB + cW * 16, pWl + cW * 16);
    };

    const int nk = K >> 5;

    load_stage(0, 0);
    asm volatile("cp.async.commit_group;");
    load_stage(1, 32);
    asm volatile("cp.async.commit_group;");

    float acc[2][4][4];
    #pragma unroll
    for (int i = 0; i < 2; i++)
        #pragma unroll
        for (int j = 0; j < 4; j++)
            #pragma unroll
            for (int q = 0; q < 4; q++) acc[i][j][q] = 0.f;

    const int arow_l = m32 + (lane & 15);
    const uint32_t akb = ((lane >> 4) & 1) * 16;
    const int nrow_l = n32w + (lane & 7) + ((lane >> 4) & 1) * 8;
    const uint32_t bkb = ((lane >> 3) & 1) * 16;

    for (int c = 0; c < nk; c++) {
        asm volatile("cp.async.wait_group %0;" :: "n"(1));
        __syncthreads();

        const uint32_t sb = sbase + (c & 1) * STAGE_SB;
        #pragma unroll
        for (int kk = 0; kk < 2; kk++) {
            const uint32_t kbyte = kk * 32;
            uint32_t afh[2][4], afl[2][4], bfh[4][2], bfl[4][2];
            #pragma unroll
            for (int mt = 0; mt < 2; mt++) {
                uint32_t ra = (uint32_t)((arow_l + mt * 16) * ROWB) + akb + kbyte;
                ldm4(afh[mt], sb + ra);
                ldm4(afl[mt], sb + TILE_A_SB + ra);
            }
            #pragma unroll
            for (int np = 0; np < 2; np++) {
                uint32_t rb = (uint32_t)((nrow_l + np * 16) * ROWB) + bkb + kbyte;
                uint32_t th[4], tl[4];
                ldm4(th, sb + 2 * TILE_A_SB + rb);
                ldm4(tl, sb + 2 * TILE_A_SB + TILE_W_SB + rb);
                bfh[2 * np][0] = th[0]; bfh[2 * np][1] = th[1];
                bfh[2 * np + 1][0] = th[2]; bfh[2 * np + 1][1] = th[3];
                bfl[2 * np][0] = tl[0]; bfl[2 * np][1] = tl[1];
                bfl[2 * np + 1][0] = tl[2]; bfl[2 * np + 1][1] = tl[3];
            }
            #pragma unroll
            for (int mt = 0; mt < 2; mt++)
                #pragma unroll
                for (int nt = 0; nt < 4; nt++) {
                    mma16816(acc[mt][nt], afh[mt], bfh[nt]);
                    mma16816(acc[mt][nt], afl[mt], bfh[nt]);
                    mma16816(acc[mt][nt], afh[mt], bfl[nt]);
                }
        }
        __syncthreads();

        if (c + 2 < nk) load_stage(c & 1, (c + 2) * 32);
        asm volatile("cp.async.commit_group;");
    }

    const int rloc0 = m32 + (lane >> 2);
    const int cloc0 = n32w + (lane & 3) * 2;
    #pragma unroll
    for (int mt = 0; mt < 2; mt++) {
        const int r0 = brow + rloc0 + mt * 16;
        #pragma unroll
        for (int nt = 0; nt < 4; nt++) {
            const int col = bcol + cloc0 + nt * 8;
            float2 bb = make_float2(b1[col] + b2[col], b1[col + 1] + b2[col + 1]);
            *(float2*)(C + (size_t)r0 * ldc + col) =
                make_float2(acc[mt][nt][0] + bb.x, acc[mt][nt][1] + bb.y);
            *(float2*)(C + (size_t)(r0 + 8) * ldc + col) =
                make_float2(acc[mt][nt][2] + bb.x, acc[mt][nt][3] + bb.y);
        }
    }
}

// ======= score GEMM v3: 128x128 tile, BK=64, 3 stages, warp 64x32 =========
#define SC_ROWB   144
#define SC_A_SB   (128 * SC_ROWB)
#define SC_W_SB   (128 * SC_ROWB)
#define SC_STAGE  (SC_A_SB + SC_W_SB)
#define SC_NST    3
#define SC_SMEM   (SC_NST * SC_STAGE + 512 + 32)

__global__ __launch_bounds__(256, 2)
void score_gemm(const __half* __restrict__ Ah, const __half* __restrict__ Wh,
                const float* __restrict__ g1, const float* __restrict__ vw,
                float* __restrict__ partial)
{
    extern __shared__ __align__(128) char smem[];
    const uint32_t sbase = (uint32_t)__cvta_generic_to_shared(smem);
    float* part_sm = (float*)(smem + SC_NST * SC_STAGE);

    const int tid  = threadIdx.x;
    const int wid  = tid >> 5;
    const int lane = tid & 31;
    const int brow = blockIdx.y * 128;
    const int bcol = blockIdx.x * 128;
    const int m64  = (wid >> 2) * 64;
    const int n32  = (wid & 3) * 32;
    const int K    = 1024;

    if (tid < 128) part_sm[tid] = 0.f;

    const int arow = tid >> 1;
    const int acb_ld = (tid & 1) * 4;
    const __half* gA = Ah + (size_t)(brow + arow) * K;
    const __half* gW = Wh + (size_t)(bcol + arow) * K;
    const uint32_t sA_ld = (uint32_t)(arow * SC_ROWB + acb_ld * 16);
    const uint32_t sW_ld = (uint32_t)(SC_A_SB + arow * SC_ROWB + acb_ld * 16);

    auto load_stage = [&](int stage, int k0) {
        const uint32_t sb = sbase + stage * SC_STAGE;
        const char* pA = (const char*)(gA + k0) + acb_ld * 16;
        const char* pW = (const char*)(gW + k0) + acb_ld * 16;
        #pragma unroll
        for (int c = 0; c < 4; c++) {
            cp16(sb + sA_ld + c * 16, pA + c * 16);
            cp16(sb + sW_ld + c * 16, pW + c * 16);
        }
    };

    const int nk = 16;

    load_stage(0, 0);
    asm volatile("cp.async.commit_group;");
    load_stage(1, 64);
    asm volatile("cp.async.commit_group;");

    float acc[4][4][4];
    #pragma unroll
    for (int i = 0; i < 4; i++)
        #pragma unroll
        for (int j = 0; j < 4; j++)
            #pragma unroll
            for (int q = 0; q < 4; q++) acc[i][j][q] = 0.f;

    const int arow_l = m64 + (lane & 15);
    const uint32_t akb = ((lane >> 4) & 1) * 16;
    const int nrow_l = n32 + (lane & 7) + ((lane >> 4) & 1) * 8;
    const uint32_t bkb = ((lane >> 3) & 1) * 16;

    int stage = 0;
    for (int c = 0; c < nk; c++) {
        asm volatile("cp.async.wait_group %0;" :: "n"(1));
        __syncthreads();

        if (c + 2 < nk) {
            int s2 = stage + 2; if (s2 >= SC_NST) s2 -= SC_NST;
            load_stage(s2, (c + 2) * 64);
        }
        asm volatile("cp.async.commit_group;");

        const uint32_t sb = sbase + stage * SC_STAGE;
        #pragma unroll
        for (int kk = 0; kk < 4; kk++) {
            const uint32_t kbyte = kk * 32;
            uint32_t bfh[4][2];
            #pragma unroll
            for (int np = 0; np < 2; np++) {
                uint32_t rb = (uint32_t)((nrow_l + np * 16) * SC_ROWB) + bkb + kbyte;
                uint32_t th[4];
                ldm4(th, sb + SC_A_SB + rb);
                bfh[2 * np][0] = th[0]; bfh[2 * np][1] = th[1];
                bfh[2 * np + 1][0] = th[2]; bfh[2 * np + 1][1] = th[3];
            }
            #pragma unroll
            for (int mt = 0; mt < 4; mt++) {
                uint32_t afh[4];
                uint32_t ra = (uint32_t)((arow_l + mt * 16) * SC_ROWB) + akb + kbyte;
                ldm4(afh, sb + ra);
                #pragma unroll
                for (int nt = 0; nt < 4; nt++)
                    mma16816(acc[mt][nt], afh, bfh[nt]);
            }
        }
        if (++stage >= SC_NST) stage = 0;
    }

    const int rloc0 = m64 + (lane >> 2);
    const int cloc0 = n32 + (lane & 3) * 2;
    const float* g1r = g1 + (size_t)blockIdx.y * 1024;
    #pragma unroll
    for (int mt = 0; mt < 4; mt++) {
        float s0 = 0.f, s1 = 0.f;
        #pragma unroll
        for (int nt = 0; nt < 4; nt++) {
            int col = bcol + cloc0 + nt * 8;
            float gw0 = g1r[col],     vw0 = vw[col];
            float gw1 = g1r[col + 1], vw1 = vw[col + 1];
            s0 += tanhf(acc[mt][nt][0] + gw0) * vw0;
            s0 += tanhf(acc[mt][nt][1] + gw1) * vw1;
            s1 += tanhf(acc[mt][nt][2] + gw0) * vw0;
            s1 += tanhf(acc[mt][nt][3] + gw1) * vw1;
        }
        atomicAdd(&part_sm[rloc0 + mt * 16], s0);
        atomicAdd(&part_sm[rloc0 + mt * 16 + 8], s1);
    }
    __syncthreads();
    if (tid < 128)
        partial[(size_t)(brow + tid) * gridDim.x + blockIdx.x] = part_sm[tid];
}

// ============== softmax + context (enc read as fp16 hi) ===================
__global__ __launch_bounds__(256)
void attn_softmax_context(const float* __restrict__ part, int npart,
                          const __half* __restrict__ ench,
                          const float* __restrict__ Vb,
                          float* __restrict__ attn_out,
                          float* __restrict__ rnn)
{
    const int b   = blockIdx.x;
    const int tid = threadIdx.x;
    __shared__ float logit[LL];

    if (tid < LL) {
        const float* pr = part + (size_t)(b * LL + tid) * npart;
        float s = Vb[0];
        for (int j = 0; j < npart; j++) s += pr[j];
        logit[tid] = s;
    }
    __syncthreads();

    if (tid < 32) {
        const int lane = tid;
        float m = -1e30f;
        for (int l = lane; l < LL; l += 32) m = fmaxf(m, logit[l]);
        #pragma unroll
        for (int o = 16; o; o >>= 1) m = fmaxf(m, __shfl_xor_sync(0xffffffffu, m, o));
        float s = 0.f;
        for (int l = lane; l < LL; l += 32) {
            float e = expf(logit[l] - m);
            logit[l] = e;
            s += e;
        }
        #pragma unroll
        for (int o = 16; o; o >>= 1) s += __shfl_xor_sync(0xffffffffu, s, o);
        float inv = 1.f / s;
        for (int l = lane; l < LL; l += 32) logit[l] *= inv;
    }
    __syncthreads();

    if (tid < LL) attn_out[b * LL + tid] = logit[tid];

    float4 acc = make_float4(0.f, 0.f, 0.f, 0.f);
    const __half2* encb = (const __half2*)(ench + (size_t)b * LL * EENC) + tid * 2;
    #pragma unroll 4
    for (int l = 0; l < LL; l++) {
        float a = logit[l];
        __half2 v0 = encb[l * (EENC / 2)];
        __half2 v1 = encb[l * (EENC / 2) + 1];
        float2 f0 = __half22float2(v0);
        float2 f1 = __half22float2(v1);
        acc.x += a * f0.x; acc.y += a * f0.y;
        acc.z += a * f1.x; acc.w += a * f1.y;
    }
    *(float4*)(rnn + (size_t)b * 1536 + tid * 4) = acc;
}

// ============================ GRU gates ===================================
__global__ __launch_bounds__(256)
void gru_gate(const float* __restrict__ gi, const float* __restrict__ gh,
              const float* __restrict__ h0, float* __restrict__ hnew)
{
    const int idx = blockIdx.x * blockDim.x + threadIdx.x;
    const int b = idx >> 10;
    const int d = idx & 1023;
    const float* gib = gi + (size_t)b * 3072;
    const float* ghb = gh + (size_t)b * 3072;
    float r = 1.f / (1.f + expf(-(gib[d] + ghb[d])));
    float z = 1.f / (1.f + expf(-(gib[1024 + d] + ghb[1024 + d])));
    float n = tanhf(gib[2048 + d] + r * ghb[2048 + d]);
    hnew[idx] = (1.f - z) * n + z * h0[idx];
}

// ============================ launch ======================================
extern "C" void kernel_launch(void* const* d_in, const int* in_sizes, int n_in,
                              void* d_out, int out_size)
{
    (void)in_sizes; (void)n_in; (void)out_size;

    const float* x      = (const float*)d_in[0];
    const float* hidden = (const float*)d_in[1];
    const float* enc    = (const float*)d_in[2];
    const float* W1_w   = (const float*)d_in[3];
    const float* W1_b   = (const float*)d_in[4];
    const float* W2_w   = (const float*)d_in[5];
    const float* W2_b   = (const float*)d_in[6];
    const float* V_w    = (const float*)d_in[7];
    const float* V_b    = (const float*)d_in[8];
    const float* o2e_w  = (const float*)d_in[9];
    const float* o2e_b  = (const float*)d_in[10];
    const float* gwi    = (const float*)d_in[11];
    const float* gwh    = (const float*)d_in[12];
    const float* gbi    = (const float*)d_in[13];
    const float* gbh    = (const float*)d_in[14];
    const float* f1w    = (const float*)d_in[15];
    const float* f1b    = (const float*)d_in[16];
    const float* f2w    = (const float*)d_in[17];
    const float* f2b    = (const float*)d_in[18];

    float* out  = (float*)d_out;
    float* hnew = out + (size_t)BB * VOC;
    float* attn = hnew + (size_t)BB * DDEC;

    __half* bh = nullptr;
    __half* bl = nullptr;
    float* fs = nullptr;
    cudaGetSymbolAddress((void**)&bh, g_bh);
    cudaGetSymbolAddress((void**)&bl, g_bl);
    cudaGetSymbolAddress((void**)&fs, g_f32);

    float* g1   = fs + F_G1;
    float* rnn  = fs + F_RNN;
    float* gi   = fs + F_GI;
    float* gh   = fs + F_GH;
    float* tbuf = fs + F_T;
    float* part = fs + F_PART;

    cudaFuncSetAttribute(gemm64,      cudaFuncAttributeMaxDynamicSharedMemorySize, GEMM_SMEM);
    cudaFuncSetAttribute(gemm64b,     cudaFuncAttributeMaxDynamicSharedMemorySize, GEMM2_SMEM);
    cudaFuncSetAttribute(gemm64_bias, cudaFuncAttributeMaxDynamicSharedMemorySize, GEMM_SMEM);
    cudaFuncSetAttribute(score_gemm,  cudaFuncAttributeMaxDynamicSharedMemorySize, SC_SMEM);

    dim3 blk(256);

    // 0) weight splits (hi-only except W2/f2)
    split_weights<<<W4N7 / 256, 256>>>(W1_w, W2_w, o2e_w, gwi, gwh, f1w, f2w);
    // 1) activation splits (enc hi-only)
    split_acts<<<A4N3 / 256, 256>>>(enc, x, hidden);

    // 2) g1 = h0 @ W2^T + W2_b + W1_b  (3-term direct store)
    gemm64_bias<<<dim3(16, 2), blk, GEMM_SMEM>>>(
        bh + OFF_HID, bl + OFF_HID, bh + OFF_W2, bl + OFF_W2,
        1024, g1, 1024, W2_b, W1_b);

    // 3) score GEMM (launch index 3 -> ncu profiles THIS)
    score_gemm<<<dim3(8, 256), blk, SC_SMEM>>>(
        bh + OFF_ENC, bh + OFF_W1, g1, V_w, part);

    // 4) bias preinit for remaining atomic targets
    bias_init<<<BIAS_TOTAL / 256, 256>>>(rnn, gi, gh, tbuf, out,
                                         o2e_b, gbi, gbh, f1b, f2b);

    // 5) softmax + attn out + context (enc fp16) -> rnn[:, 0:1024]
    attn_softmax_context<<<BB, 256>>>(part, 8, bh + OFF_ENC, V_b, attn, rnn);

    // 6) x_emb += x @ out2emb^T     (2-term, splitK=8)
    gemm64b<<<dim3(8, 2, 8), blk, GEMM2_SMEM>>>(
        bh + OFF_X, bl + OFF_X, bh + OFF_O2E,
        4096, 512, rnn + 1024, 1536);

    // 7) gh += h0 @ gru_wh^T        (2-term, splitK=2)
    gemm64b<<<dim3(48, 2, 2), blk, GEMM2_SMEM>>>(
        bh + OFF_HID, bl + OFF_HID, bh + OFF_GWH,
        1024, 512, gh, 3072);

    // 8) rnn -> fp16
    f32_split<<<(393216 / 4) / 256, 256>>>(rnn, bh + OFF_RNN, bl + OFF_RNN, 393216 / 4);

    // 9) gi += rnn_in @ gru_wi^T    (2-term, splitK=2)
    gemm64b<<<dim3(48, 2, 2), blk, GEMM2_SMEM>>>(
        bh + OFF_RNN, bl + OFF_RNN, bh + OFF_GWI,
        1536, 768, gi, 3072);

    // 10) GRU gates -> h_new (output)
    gru_gate<<<(BB * DDEC) / 256, 256>>>(gi, gh, hidden, hnew);

    // 11) h_new -> fp16
    f32_split<<<(262144 / 4) / 256, 256>>>(hnew, bh + OFF_HNEW, bl + OFF_HNEW, 262144 / 4);

    // 12) tbuf += h_new @ fc1^T     (2-term, splitK=8)
    gemm64b<<<dim3(8, 2, 8), blk, GEMM2_SMEM>>>(
        bh + OFF_HNEW, bl + OFF_HNEW, bh + OFF_F1,
        1024, 128, tbuf, 512);

    // 13) t = tanh(tbuf) -> fp16
    f32_split_tanh<<<(131072 / 4) / 256, 256>>>(tbuf, bh + OFF_T, bl + OFF_T, 131072 / 4);

    // 14) out += t @ fc2^T          (3-term, splitK=2; direct output path)
    gemm64<<<dim3(64, 2, 2), blk, GEMM_SMEM>>>(
        bh + OFF_T, bl + OFF_T, bh + OFF_F2, bl + OFF_F2,
        512, 256, out, 4096);
}

// round 13
// speedup vs baseline: 2.0390x; 1.0182x over previous
#include <cuda_runtime.h>
#include <cuda_fp16.h>
#include <cstdint>
#include <math.h>

// Problem dims
#define BB   256
#define LL   128
#define VOC  4096
#define EENC 1024
#define DDEC 1024
#define EEMB 512

// ======================= scratch (module-load allocated) ==================
#define OFF_ENC   0ull
#define OFF_W1    (OFF_ENC + 33554432ull)
#define OFF_W2    (OFF_W1  + 1048576ull)
#define OFF_O2E   (OFF_W2  + 1048576ull)
#define OFF_GWI   (OFF_O2E + 2097152ull)
#define OFF_GWH   (OFF_GWI + 4718592ull)
#define OFF_F1    (OFF_GWH + 3145728ull)
#define OFF_F2    (OFF_F1  + 524288ull)
#define OFF_X     (OFF_F2  + 2097152ull)
#define OFF_HID   (OFF_X   + 1048576ull)
#define OFF_RNN   (OFF_HID + 262144ull)
#define OFF_HNEW  (OFF_RNN + 393216ull)
#define OFF_T     (OFF_HNEW+ 262144ull)
#define BF_TOTAL  (OFF_T   + 131072ull)

__device__ __half g_bh[BF_TOTAL];
__device__ __half g_bl[BF_TOTAL];

#define F_G1    0ull
#define F_RNN   (F_G1   + 262144ull)
#define F_GI    (F_RNN  + 393216ull)
#define F_GH    (F_GI   + 786432ull)
#define F_T     (F_GH   + 786432ull)
#define F_PART  (F_T    + 131072ull)
#define F_TOTAL (F_PART + 524288ull)

__device__ float g_f32[F_TOTAL];

// ======================= small helpers ====================================
__device__ __forceinline__ void cp16(uint32_t s, const void* g) {
    asm volatile("cp.async.cg.shared.global [%0], [%1], 16;"
                 :: "r"(s), "l"(__cvta_generic_to_global(g)));
}
__device__ __forceinline__ void ldm4(uint32_t* r, uint32_t addr) {
    asm volatile("ldmatrix.sync.aligned.m8n8.x4.shared.b16 {%0,%1,%2,%3}, [%4];"
        : "=r"(r[0]), "=r"(r[1]), "=r"(r[2]), "=r"(r[3]) : "r"(addr));
}
__device__ __forceinline__ void mma16816(float* c, const uint32_t* a, const uint32_t* b) {
    asm volatile("mma.sync.aligned.m16n8k16.row.col.f32.f16.f16.f32 "
        "{%0,%1,%2,%3}, {%4,%5,%6,%7}, {%8,%9}, {%0,%1,%2,%3};"
        : "+f"(c[0]), "+f"(c[1]), "+f"(c[2]), "+f"(c[3])
        : "r"(a[0]), "r"(a[1]), "r"(a[2]), "r"(a[3]), "r"(b[0]), "r"(b[1]));
}
__device__ __forceinline__ void do_split4(const float* __restrict__ src, int i,
                                          unsigned long long dst) {
    float4 v = ((const float4*)src)[i];
    __half h0 = __float2half_rn(v.x), h1 = __float2half_rn(v.y);
    __half h2 = __float2half_rn(v.z), h3 = __float2half_rn(v.w);
    __half2 hp0; hp0.x = h0; hp0.y = h1;
    __half2 hp1; hp1.x = h2; hp1.y = h3;
    __half2 lp0, lp1;
    lp0.x = __float2half_rn(v.x - __half2float(h0));
    lp0.y = __float2half_rn(v.y - __half2float(h1));
    lp1.x = __float2half_rn(v.z - __half2float(h2));
    lp1.y = __float2half_rn(v.w - __half2float(h3));
    ((__half2*)(g_bh + dst))[2 * i]     = hp0;
    ((__half2*)(g_bh + dst))[2 * i + 1] = hp1;
    ((__half2*)(g_bl + dst))[2 * i]     = lp0;
    ((__half2*)(g_bl + dst))[2 * i + 1] = lp1;
}
__device__ __forceinline__ void do_split4_hi(const float* __restrict__ src, int i,
                                             unsigned long long dst) {
    float4 v = ((const float4*)src)[i];
    __half2 hp0, hp1;
    hp0.x = __float2half_rn(v.x); hp0.y = __float2half_rn(v.y);
    hp1.x = __float2half_rn(v.z); hp1.y = __float2half_rn(v.w);
    ((__half2*)(g_bh + dst))[2 * i]     = hp0;
    ((__half2*)(g_bh + dst))[2 * i + 1] = hp1;
}

// ======================= fused split kernels (float4 units) ===============
// hi-only: W1, W2, o2e, gwi, gwh, f1.  hi+lo: f2.
#define W4N1 262144
#define W4N2 524288
#define W4N3 1048576
#define W4N4 2228224
#define W4N5 3014656
#define W4N6 3145728
#define W4N7 3670016
__global__ __launch_bounds__(256)
void split_weights(const float* __restrict__ W1, const float* __restrict__ W2,
                   const float* __restrict__ o2e, const float* __restrict__ gwi,
                   const float* __restrict__ gwh, const float* __restrict__ f1,
                   const float* __restrict__ f2)
{
    int i = blockIdx.x * blockDim.x + threadIdx.x;
    if (i < W4N1)      do_split4_hi(W1,  i,        OFF_W1);
    else if (i < W4N2) do_split4_hi(W2,  i - W4N1, OFF_W2);
    else if (i < W4N3) do_split4_hi(o2e, i - W4N2, OFF_O2E);
    else if (i < W4N4) do_split4_hi(gwi, i - W4N3, OFF_GWI);
    else if (i < W4N5) do_split4_hi(gwh, i - W4N4, OFF_GWH);
    else if (i < W4N6) do_split4_hi(f1,  i - W4N5, OFF_F1);
    else if (i < W4N7) do_split4(f2,  i - W4N6, OFF_F2);
}
#define A4N1 8388608
#define A4N2 8650752
#define A4N3 8716288
__global__ __launch_bounds__(256)
void split_acts(const float* __restrict__ enc, const float* __restrict__ x,
                const float* __restrict__ hid)
{
    int i = blockIdx.x * blockDim.x + threadIdx.x;
    if (i < A4N1)      do_split4_hi(enc, i,        OFF_ENC);
    else if (i < A4N2) do_split4(x,   i - A4N1, OFF_X);
    else if (i < A4N3) do_split4(hid, i - A4N2, OFF_HID);
}
__global__ __launch_bounds__(256)
void f32_split(const float* __restrict__ in, __half* __restrict__ hi,
               __half* __restrict__ lo, int n4)
{
    int i = blockIdx.x * blockDim.x + threadIdx.x;
    if (i >= n4) return;
    float4 v = ((const float4*)in)[i];
    __half h0 = __float2half_rn(v.x), h1 = __float2half_rn(v.y);
    __half h2 = __float2half_rn(v.z), h3 = __float2half_rn(v.w);
    __half2 hp0; hp0.x = h0; hp0.y = h1;
    __half2 hp1; hp1.x = h2; hp1.y = h3;
    __half2 lp0, lp1;
    lp0.x = __float2half_rn(v.x - __half2float(h0));
    lp0.y = __float2half_rn(v.y - __half2float(h1));
    lp1.x = __float2half_rn(v.z - __half2float(h2));
    lp1.y = __float2half_rn(v.w - __half2float(h3));
    ((__half2*)hi)[2 * i]     = hp0;
    ((__half2*)hi)[2 * i + 1] = hp1;
    ((__half2*)lo)[2 * i]     = lp0;
    ((__half2*)lo)[2 * i + 1] = lp1;
}
__global__ __launch_bounds__(256)
void f32_split_tanh(const float* __restrict__ in, __half* __restrict__ hi,
                    __half* __restrict__ lo, int n4)
{
    int i = blockIdx.x * blockDim.x + threadIdx.x;
    if (i >= n4) return;
    float4 v = ((const float4*)in)[i];
    v.x = tanhf(v.x); v.y = tanhf(v.y); v.z = tanhf(v.z); v.w = tanhf(v.w);
    __half h0 = __float2half_rn(v.x), h1 = __float2half_rn(v.y);
    __half h2 = __float2half_rn(v.z), h3 = __float2half_rn(v.w);
    __half2 hp0; hp0.x = h0; hp0.y = h1;
    __half2 hp1; hp1.x = h2; hp1.y = h3;
    __half2 lp0, lp1;
    lp0.x = __float2half_rn(v.x - __half2float(h0));
    lp0.y = __float2half_rn(v.y - __half2float(h1));
    lp1.x = __float2half_rn(v.z - __half2float(h2));
    lp1.y = __float2half_rn(v.w - __half2float(h3));
    ((__half2*)hi)[2 * i]     = hp0;
    ((__half2*)hi)[2 * i + 1] = hp1;
    ((__half2*)lo)[2 * i]     = lp0;
    ((__half2*)lo)[2 * i + 1] = lp1;
}

// ================= bias pre-init (resets atomic targets every call) =======
__global__ __launch_bounds__(256)
void bias_init(float* __restrict__ rnn,
               float* __restrict__ gi, float* __restrict__ gh,
               float* __restrict__ tbuf, float* __restrict__ out,
               const float* __restrict__ o2eb, const float* __restrict__ gbi,
               const float* __restrict__ gbh, const float* __restrict__ f1b,
               const float* __restrict__ f2b)
{
    int i = blockIdx.x * blockDim.x + threadIdx.x;
    if (i < 131072) {
        rnn[(i >> 9) * 1536 + 1024 + (i & 511)] = o2eb[i & 511];
    } else if (i < 917504) {
        int j = i - 131072;
        gi[j] = gbi[j % 3072];
    } else if (i < 1703936) {
        int j = i - 917504;
        gh[j] = gbh[j % 3072];
    } else if (i < 1835008) {
        int j = i - 1703936;
        tbuf[j] = f1b[j & 511];
    } else {
        int j = i - 1835008;
        out[j] = f2b[j & 4095];
    }
}
#define BIAS_TOTAL 2883584

// ======================= 3-term split-K mma GEMM (fc2 only) ===============
#define ROWB      80
#define TILE_A_SB (128 * ROWB)
#define TILE_W_SB (64 * ROWB)
#define STAGE_SB  (2 * TILE_A_SB + 2 * TILE_W_SB)
#define GEMM_SMEM (2 * STAGE_SB + 512 + 32)

__global__ __launch_bounds__(256, 2)
void gemm64(const __half* __restrict__ Ah, const __half* __restrict__ Al,
            const __half* __restrict__ Wh, const __half* __restrict__ Wl,
            int K, int Kchunk, float* __restrict__ C, int ldc)
{
    extern __shared__ __align__(128) char smem[];
    const uint32_t sbase = (uint32_t)__cvta_generic_to_shared(smem);

    const int tid  = threadIdx.x;
    const int wid  = tid >> 5;
    const int lane = tid & 31;
    const int brow = blockIdx.y * 128;
    const int bcol = blockIdx.x * 64;
    const int k0   = blockIdx.z * Kchunk;
    const int m32  = (wid >> 1) * 32;
    const int n32w = (wid & 1) * 32;

    const int lrA = tid >> 1;
    const int cA  = (tid & 1) * 2;
    const int lrW = tid >> 2;
    const int cW  = tid & 3;
    const size_t aoff = (size_t)(brow + lrA) * K + k0;
    const size_t woff = (size_t)(bcol + lrW) * K + k0;

    auto load_stage = [&](int stage, int kk0) {
        const uint32_t sA = sbase + stage * STAGE_SB + lrA * ROWB;
        const uint32_t sW = sbase + stage * STAGE_SB + 2 * TILE_A_SB + lrW * ROWB;
        const char* pAh = (const char*)(Ah + aoff + kk0);
        const char* pAl = (const char*)(Al + aoff + kk0);
        const char* pWh = (const char*)(Wh + woff + kk0);
        const char* pWl = (const char*)(Wl + woff + kk0);
        #pragma unroll
        for (int c = cA; c < cA + 2; c++) {
            cp16(sA + c * 16, pAh + c * 16);
            cp16(sA + TILE_A_SB + c * 16, pAl + c * 16);
        }
        cp16(sW + cW * 16, pWh + cW * 16);
        cp16(sW + TILE_W_SB + cW * 16, pWl + cW * 16);
    };

    const int nk = Kchunk >> 5;

    load_stage(0, 0);
    asm volatile("cp.async.commit_group;");
    if (nk > 1) load_stage(1, 32);
    asm volatile("cp.async.commit_group;");

    float acc[2][4][4];
    #pragma unroll
    for (int i = 0; i < 2; i++)
        #pragma unroll
        for (int j = 0; j < 4; j++)
            #pragma unroll
            for (int q = 0; q < 4; q++) acc[i][j][q] = 0.f;

    const int arow_l = m32 + (lane & 15);
    const uint32_t akb = ((lane >> 4) & 1) * 16;
    const int nrow_l = n32w + (lane & 7) + ((lane >> 4) & 1) * 8;
    const uint32_t bkb = ((lane >> 3) & 1) * 16;

    for (int c = 0; c < nk; c++) {
        asm volatile("cp.async.wait_group %0;" :: "n"(1));
        __syncthreads();

        const uint32_t sb = sbase + (c & 1) * STAGE_SB;
        #pragma unroll
        for (int kk = 0; kk < 2; kk++) {
            const uint32_t kbyte = kk * 32;
            uint32_t afh[2][4], afl[2][4], bfh[4][2], bfl[4][2];
            #pragma unroll
            for (int mt = 0; mt < 2; mt++) {
                uint32_t ra = (uint32_t)((arow_l + mt * 16) * ROWB) + akb + kbyte;
                ldm4(afh[mt], sb + ra);
                ldm4(afl[mt], sb + TILE_A_SB + ra);
            }
            #pragma unroll
            for (int np = 0; np < 2; np++) {
                uint32_t rb = (uint32_t)((nrow_l + np * 16) * ROWB) + bkb + kbyte;
                uint32_t th[4], tl[4];
                ldm4(th, sb + 2 * TILE_A_SB + rb);
                ldm4(tl, sb + 2 * TILE_A_SB + TILE_W_SB + rb);
                bfh[2 * np][0] = th[0]; bfh[2 * np][1] = th[1];
                bfh[2 * np + 1][0] = th[2]; bfh[2 * np + 1][1] = th[3];
                bfl[2 * np][0] = tl[0]; bfl[2 * np][1] = tl[1];
                bfl[2 * np + 1][0] = tl[2]; bfl[2 * np + 1][1] = tl[3];
            }
            #pragma unroll
            for (int mt = 0; mt < 2; mt++)
                #pragma unroll
                for (int nt = 0; nt < 4; nt++) {
                    mma16816(acc[mt][nt], afh[mt], bfh[nt]);
                    mma16816(acc[mt][nt], afl[mt], bfh[nt]);
                    mma16816(acc[mt][nt], afh[mt], bfl[nt]);
                }
        }
        __syncthreads();

        if (c + 2 < nk) load_stage(c & 1, (c + 2) * 32);
        asm volatile("cp.async.commit_group;");
    }

    const int rloc0 = m32 + (lane >> 2);
    const int cloc0 = n32w + (lane & 3) * 2;
    #pragma unroll
    for (int mt = 0; mt < 2; mt++) {
        const int r0 = brow + rloc0 + mt * 16;
        #pragma unroll
        for (int nt = 0; nt < 4; nt++) {
            const int col = bcol + cloc0 + nt * 8;
            float* c0 = C + (size_t)r0 * ldc + col;
            float* c1 = C + (size_t)(r0 + 8) * ldc + col;
            atomicAdd(c0,     acc[mt][nt][0]);
            atomicAdd(c0 + 1, acc[mt][nt][1]);
            atomicAdd(c1,     acc[mt][nt][2]);
            atomicAdd(c1 + 1, acc[mt][nt][3]);
        }
    }
}

// ====== 2-term split-K GEMM v2: 3 stages, single sync per chunk ===========
#define STAGE2_SB (2 * TILE_A_SB + TILE_W_SB)     // 25600
#define GEMM2_SMEM (3 * STAGE2_SB + 512 + 32)

__global__ __launch_bounds__(256, 2)
void gemm64b(const __half* __restrict__ Ah, const __half* __restrict__ Al,
             const __half* __restrict__ Wh,
             int K, int Kchunk, float* __restrict__ C, int ldc)
{
    extern __shared__ __align__(128) char smem[];
    const uint32_t sbase = (uint32_t)__cvta_generic_to_shared(smem);

    const int tid  = threadIdx.x;
    const int wid  = tid >> 5;
    const int lane = tid & 31;
    const int brow = blockIdx.y * 128;
    const int bcol = blockIdx.x * 64;
    const int k0   = blockIdx.z * Kchunk;
    const int m32  = (wid >> 1) * 32;
    const int n32w = (wid & 1) * 32;

    const int lrA = tid >> 1;
    const int cA  = (tid & 1) * 2;
    const int lrW = tid >> 2;
    const int cW  = tid & 3;
    const size_t aoff = (size_t)(brow + lrA) * K + k0;
    const size_t woff = (size_t)(bcol + lrW) * K + k0;

    auto load_stage = [&](int stage, int kk0) {
        const uint32_t sA = sbase + stage * STAGE2_SB + lrA * ROWB;
        const uint32_t sW = sbase + stage * STAGE2_SB + 2 * TILE_A_SB + lrW * ROWB;
        const char* pAh = (const char*)(Ah + aoff + kk0);
        const char* pAl = (const char*)(Al + aoff + kk0);
        const char* pWh = (const char*)(Wh + woff + kk0);
        #pragma unroll
        for (int c = cA; c < cA + 2; c++) {
            cp16(sA + c * 16, pAh + c * 16);
            cp16(sA + TILE_A_SB + c * 16, pAl + c * 16);
        }
        cp16(sW + cW * 16, pWh + cW * 16);
    };

    const int nk = Kchunk >> 5;

    load_stage(0, 0);
    asm volatile("cp.async.commit_group;");
    if (nk > 1) load_stage(1, 32);
    asm volatile("cp.async.commit_group;");

    float acc[2][4][4];
    #pragma unroll
    for (int i = 0; i < 2; i++)
        #pragma unroll
        for (int j = 0; j < 4; j++)
            #pragma unroll
            for (int q = 0; q < 4; q++) acc[i][j][q] = 0.f;

    const int arow_l = m32 + (lane & 15);
    const uint32_t akb = ((lane >> 4) & 1) * 16;
    const int nrow_l = n32w + (lane & 7) + ((lane >> 4) & 1) * 8;
    const uint32_t bkb = ((lane >> 3) & 1) * 16;

    int stage = 0;
    for (int c = 0; c < nk; c++) {
        asm volatile("cp.async.wait_group %0;" :: "n"(1));
        __syncthreads();

        if (c + 2 < nk) {
            int s2 = stage + 2; if (s2 >= 3) s2 -= 3;
            load_stage(s2, (c + 2) * 32);
        }
        asm volatile("cp.async.commit_group;");

        const uint32_t sb = sbase + stage * STAGE2_SB;
        #pragma unroll
        for (int kk = 0; kk < 2; kk++) {
            const uint32_t kbyte = kk * 32;
            uint32_t afh[2][4], afl[2][4], bfh[4][2];
            #pragma unroll
            for (int mt = 0; mt < 2; mt++) {
                uint32_t ra = (uint32_t)((arow_l + mt * 16) * ROWB) + akb + kbyte;
                ldm4(afh[mt], sb + ra);
                ldm4(afl[mt], sb + TILE_A_SB + ra);
            }
            #pragma unroll
            for (int np = 0; np < 2; np++) {
                uint32_t rb = (uint32_t)((nrow_l + np * 16) * ROWB) + bkb + kbyte;
                uint32_t th[4];
                ldm4(th, sb + 2 * TILE_A_SB + rb);
                bfh[2 * np][0] = th[0]; bfh[2 * np][1] = th[1];
                bfh[2 * np + 1][0] = th[2]; bfh[2 * np + 1][1] = th[3];
            }
            #pragma unroll
            for (int mt = 0; mt < 2; mt++)
                #pragma unroll
                for (int nt = 0; nt < 4; nt++) {
                    mma16816(acc[mt][nt], afh[mt], bfh[nt]);
                    mma16816(acc[mt][nt], afl[mt], bfh[nt]);
                }
        }
        if (++stage >= 3) stage = 0;
    }

    const int rloc0 = m32 + (lane >> 2);
    const int cloc0 = n32w + (lane & 3) * 2;
    #pragma unroll
    for (int mt = 0; mt < 2; mt++) {
        const int r0 = brow + rloc0 + mt * 16;
        #pragma unroll
        for (int nt = 0; nt < 4; nt++) {
            const int col = bcol + cloc0 + nt * 8;
            float* c0 = C + (size_t)r0 * ldc + col;
            float* c1 = C + (size_t)(r0 + 8) * ldc + col;
            atomicAdd(c0,     acc[mt][nt][0]);
            atomicAdd(c0 + 1, acc[mt][nt][1]);
            atomicAdd(c1,     acc[mt][nt][2]);
            atomicAdd(c1 + 1, acc[mt][nt][3]);
        }
    }
}

// ====== 2-term direct-store GEMM with 2-bias epilogue (g1), 3 stages ======
__global__ __launch_bounds__(256, 2)
void gemm64b_bias(const __half* __restrict__ Ah, const __half* __restrict__ Al,
                  const __half* __restrict__ Wh,
                  int K, float* __restrict__ C, int ldc,
                  const float* __restrict__ b1, const float* __restrict__ b2)
{
    extern __shared__ __align__(128) char smem[];
    const uint32_t sbase = (uint32_t)__cvta_generic_to_shared(smem);

    const int tid  = threadIdx.x;
    const int wid  = tid >> 5;
    const int lane = tid & 31;
    const int brow = blockIdx.y * 128;
    const int bcol = blockIdx.x * 64;
    const int m32  = (wid >> 1) * 32;
    const int n32w = (wid & 1) * 32;

    const int lrA = tid >> 1;
    const int cA  = (tid & 1) * 2;
    const int lrW = tid >> 2;
    const int cW  = tid & 3;
    const size_t aoff = (size_t)(brow + lrA) * K;
    const size_t woff = (size_t)(bcol + lrW) * K;

    auto load_stage = [&](int stage, int kk0) {
        const uint32_t sA = sbase + stage * STAGE2_SB + lrA * ROWB;
        const uint32_t sW = sbase + stage * STAGE2_SB + 2 * TILE_A_SB + lrW * ROWB;
        const char* pAh = (const char*)(Ah + aoff + kk0);
        const char* pAl = (const char*)(Al + aoff + kk0);
        const char* pWh = (const char*)(Wh + woff + kk0);
        #pragma unroll
        for (int c = cA; c < cA + 2; c++) {
            cp16(sA + c * 16, pAh + c * 16);
            cp16(sA + TILE_A_SB + c * 16, pAl + c * 16);
        }
        cp16(sW + cW * 16, pWh + cW * 16);
    };

    const int nk = K >> 5;

    load_stage(0, 0);
    asm volatile("cp.async.commit_group;");
    load_stage(1, 32);
    asm volatile("cp.async.commit_group;");

    float acc[2][4][4];
    #pragma unroll
    for (int i = 0; i < 2; i++)
        #pragma unroll
        for (int j = 0; j < 4; j++)
            #pragma unroll
            for (int q = 0; q < 4; q++) acc[i][j][q] = 0.f;

    const int arow_l = m32 + (lane & 15);
    const uint32_t akb = ((lane >> 4) & 1) * 16;
    const int nrow_l = n32w + (lane & 7) + ((lane >> 4) & 1) * 8;
    const uint32_t bkb = ((lane >> 3) & 1) * 16;

    int stage = 0;
    for (int c = 0; c < nk; c++) {
        asm volatile("cp.async.wait_group %0;" :: "n"(1));
        __syncthreads();

        if (c + 2 < nk) {
            int s2 = stage + 2; if (s2 >= 3) s2 -= 3;
            load_stage(s2, (c + 2) * 32);
        }
        asm volatile("cp.async.commit_group;");

        const uint32_t sb = sbase + stage * STAGE2_SB;
        #pragma unroll
        for (int kk = 0; kk < 2; kk++) {
            const uint32_t kbyte = kk * 32;
            uint32_t afh[2][4], afl[2][4], bfh[4][2];
            #pragma unroll
            for (int mt = 0; mt < 2; mt++) {
                uint32_t ra = (uint32_t)((arow_l + mt * 16) * ROWB) + akb + kbyte;
                ldm4(afh[mt], sb + ra);
                ldm4(afl[mt], sb + TILE_A_SB + ra);
            }
            #pragma unroll
            for (int np = 0; np < 2; np++) {
                uint32_t rb = (uint32_t)((nrow_l + np * 16) * ROWB) + bkb + kbyte;
                uint32_t th[4];
                ldm4(th, sb + 2 * TILE_A_SB + rb);
                bfh[2 * np][0] = th[0]; bfh[2 * np][1] = th[1];
                bfh[2 * np + 1][0] = th[2]; bfh[2 * np + 1][1] = th[3];
            }
            #pragma unroll
            for (int mt = 0; mt < 2; mt++)
                #pragma unroll
                for (int nt = 0; nt < 4; nt++) {
                    mma16816(acc[mt][nt], afh[mt], bfh[nt]);
                    mma16816(acc[mt][nt], afl[mt], bfh[nt]);
                }
        }
        if (++stage >= 3) stage = 0;
    }

    const int rloc0 = m32 + (lane >> 2);
    const int cloc0 = n32w + (lane & 3) * 2;
    #pragma unroll
    for (int mt = 0; mt < 2; mt++) {
        const int r0 = brow + rloc0 + mt * 16;
        #pragma unroll
        for (int nt = 0; nt < 4; nt++) {
            const int col = bcol + cloc0 + nt * 8;
            float2 bb = make_float2(b1[col] + b2[col], b1[col + 1] + b2[col + 1]);
            *(float2*)(C + (size_t)r0 * ldc + col) =
                make_float2(acc[mt][nt][0] + bb.x, acc[mt][nt][1] + bb.y);
            *(float2*)(C + (size_t)(r0 + 8) * ldc + col) =
                make_float2(acc[mt][nt][2] + bb.x, acc[mt][nt][3] + bb.y);
        }
    }
}

// ======= score GEMM v3: 128x128 tile, BK=64, 3 stages, warp 64x32 =========
#define SC_ROWB   144
#define SC_A_SB   (128 * SC_ROWB)
#define SC_W_SB   (128 * SC_ROWB)
#define SC_STAGE  (SC_A_SB + SC_W_SB)
#define SC_NST    3
#define SC_SMEM   (SC_NST * SC_STAGE + 512 + 32)

__global__ __launch_bounds__(256, 2)
void score_gemm(const __half* __restrict__ Ah, const __half* __restrict__ Wh,
                const float* __restrict__ g1, const float* __restrict__ vw,
                float* __restrict__ partial)
{
    extern __shared__ __align__(128) char smem[];
    const uint32_t sbase = (uint32_t)__cvta_generic_to_shared(smem);
    float* part_sm = (float*)(smem + SC_NST * SC_STAGE);

    const int tid  = threadIdx.x;
    const int wid  = tid >> 5;
    const int lane = tid & 31;
    const int brow = blockIdx.y * 128;
    const int bcol = blockIdx.x * 128;
    const int m64  = (wid >> 2) * 64;
    const int n32  = (wid & 3) * 32;
    const int K    = 1024;

    if (tid < 128) part_sm[tid] = 0.f;

    const int arow = tid >> 1;
    const int acb_ld = (tid & 1) * 4;
    const __half* gA = Ah + (size_t)(brow + arow) * K;
    const __half* gW = Wh + (size_t)(bcol + arow) * K;
    const uint32_t sA_ld = (uint32_t)(arow * SC_ROWB + acb_ld * 16);
    const uint32_t sW_ld = (uint32_t)(SC_A_SB + arow * SC_ROWB + acb_ld * 16);

    auto load_stage = [&](int stage, int k0) {
        const uint32_t sb = sbase + stage * SC_STAGE;
        const char* pA = (const char*)(gA + k0) + acb_ld * 16;
        const char* pW = (const char*)(gW + k0) + acb_ld * 16;
        #pragma unroll
        for (int c = 0; c < 4; c++) {
            cp16(sb + sA_ld + c * 16, pA + c * 16);
            cp16(sb + sW_ld + c * 16, pW + c * 16);
        }
    };

    const int nk = 16;

    load_stage(0, 0);
    asm volatile("cp.async.commit_group;");
    load_stage(1, 64);
    asm volatile("cp.async.commit_group;");

    float acc[4][4][4];
    #pragma unroll
    for (int i = 0; i < 4; i++)
        #pragma unroll
        for (int j = 0; j < 4; j++)
            #pragma unroll
            for (int q = 0; q < 4; q++) acc[i][j][q] = 0.f;

    const int arow_l = m64 + (lane & 15);
    const uint32_t akb = ((lane >> 4) & 1) * 16;
    const int nrow_l = n32 + (lane & 7) + ((lane >> 4) & 1) * 8;
    const uint32_t bkb = ((lane >> 3) & 1) * 16;

    int stage = 0;
    for (int c = 0; c < nk; c++) {
        asm volatile("cp.async.wait_group %0;" :: "n"(1));
        __syncthreads();

        if (c + 2 < nk) {
            int s2 = stage + 2; if (s2 >= SC_NST) s2 -= SC_NST;
            load_stage(s2, (c + 2) * 64);
        }
        asm volatile("cp.async.commit_group;");

        const uint32_t sb = sbase + stage * SC_STAGE;
        #pragma unroll
        for (int kk = 0; kk < 4; kk++) {
            const uint32_t kbyte = kk * 32;
            uint32_t bfh[4][2];
            #pragma unroll
            for (int np = 0; np < 2; np++) {
                uint32_t rb = (uint32_t)((nrow_l + np * 16) * SC_ROWB) + bkb + kbyte;
                uint32_t th[4];
                ldm4(th, sb + SC_A_SB + rb);
                bfh[2 * np][0] = th[0]; bfh[2 * np][1] = th[1];
                bfh[2 * np + 1][0] = th[2]; bfh[2 * np + 1][1] = th[3];
            }
            #pragma unroll
            for (int mt = 0; mt < 4; mt++) {
                uint32_t afh[4];
                uint32_t ra = (uint32_t)((arow_l + mt * 16) * SC_ROWB) + akb + kbyte;
                ldm4(afh, sb + ra);
                #pragma unroll
                for (int nt = 0; nt < 4; nt++)
                    mma16816(acc[mt][nt], afh, bfh[nt]);
            }
        }
        if (++stage >= SC_NST) stage = 0;
    }

    const int rloc0 = m64 + (lane >> 2);
    const int cloc0 = n32 + (lane & 3) * 2;
    const float* g1r = g1 + (size_t)blockIdx.y * 1024;
    #pragma unroll
    for (int mt = 0; mt < 4; mt++) {
        float s0 = 0.f, s1 = 0.f;
        #pragma unroll
        for (int nt = 0; nt < 4; nt++) {
            int col = bcol + cloc0 + nt * 8;
            float gw0 = g1r[col],     vw0 = vw[col];
            float gw1 = g1r[col + 1], vw1 = vw[col + 1];
            s0 += tanhf(acc[mt][nt][0] + gw0) * vw0;
            s0 += tanhf(acc[mt][nt][1] + gw1) * vw1;
            s1 += tanhf(acc[mt][nt][2] + gw0) * vw0;
            s1 += tanhf(acc[mt][nt][3] + gw1) * vw1;
        }
        atomicAdd(&part_sm[rloc0 + mt * 16], s0);
        atomicAdd(&part_sm[rloc0 + mt * 16 + 8], s1);
    }
    __syncthreads();
    if (tid < 128)
        partial[(size_t)(brow + tid) * gridDim.x + blockIdx.x] = part_sm[tid];
}

// ============== softmax + context (enc read as fp16 hi) ===================
__global__ __launch_bounds__(256)
void attn_softmax_context(const float* __restrict__ part, int npart,
                          const __half* __restrict__ ench,
                          const float* __restrict__ Vb,
                          float* __restrict__ attn_out,
                          float* __restrict__ rnn)
{
    const int b   = blockIdx.x;
    const int tid = threadIdx.x;
    __shared__ float logit[LL];

    if (tid < LL) {
        const float* pr = part + (size_t)(b * LL + tid) * npart;
        float s = Vb[0];
        for (int j = 0; j < npart; j++) s += pr[j];
        logit[tid] = s;
    }
    __syncthreads();

    if (tid < 32) {
        const int lane = tid;
        float m = -1e30f;
        for (int l = lane; l < LL; l += 32) m = fmaxf(m, logit[l]);
        #pragma unroll
        for (int o = 16; o; o >>= 1) m = fmaxf(m, __shfl_xor_sync(0xffffffffu, m, o));
        float s = 0.f;
        for (int l = lane; l < LL; l += 32) {
            float e = expf(logit[l] - m);
            logit[l] = e;
            s += e;
        }
        #pragma unroll
        for (int o = 16; o; o >>= 1) s += __shfl_xor_sync(0xffffffffu, s, o);
        float inv = 1.f / s;
        for (int l = lane; l < LL; l += 32) logit[l] *= inv;
    }
    __syncthreads();

    if (tid < LL) attn_out[b * LL + tid] = logit[tid];

    float4 acc = make_float4(0.f, 0.f, 0.f, 0.f);
    const __half2* encb = (const __half2*)(ench + (size_t)b * LL * EENC) + tid * 2;
    #pragma unroll 4
    for (int l = 0; l < LL; l++) {
        float a = logit[l];
        __half2 v0 = encb[l * (EENC / 2)];
        __half2 v1 = encb[l * (EENC / 2) + 1];
        float2 f0 = __half22float2(v0);
        float2 f1 = __half22float2(v1);
        acc.x += a * f0.x; acc.y += a * f0.y;
        acc.z += a * f1.x; acc.w += a * f1.y;
    }
    *(float4*)(rnn + (size_t)b * 1536 + tid * 4) = acc;
}

// ============================ GRU gates ===================================
__global__ __launch_bounds__(256)
void gru_gate(const float* __restrict__ gi, const float* __restrict__ gh,
              const float* __restrict__ h0, float* __restrict__ hnew)
{
    const int idx = blockIdx.x * blockDim.x + threadIdx.x;
    const int b = idx >> 10;
    const int d = idx & 1023;
    const float* gib = gi + (size_t)b * 3072;
    const float* ghb = gh + (size_t)b * 3072;
    float r = 1.f / (1.f + expf(-(gib[d] + ghb[d])));
    float z = 1.f / (1.f + expf(-(gib[1024 + d] + ghb[1024 + d])));
    float n = tanhf(gib[2048 + d] + r * ghb[2048 + d]);
    hnew[idx] = (1.f - z) * n + z * h0[idx];
}

// ============================ launch ======================================
extern "C" void kernel_launch(void* const* d_in, const int* in_sizes, int n_in,
                              void* d_out, int out_size)
{
    (void)in_sizes; (void)n_in; (void)out_size;

    const float* x      = (const float*)d_in[0];
    const float* hidden = (const float*)d_in[1];
    const float* enc    = (const float*)d_in[2];
    const float* W1_w   = (const float*)d_in[3];
    const float* W1_b   = (const float*)d_in[4];
    const float* W2_w   = (const float*)d_in[5];
    const float* W2_b   = (const float*)d_in[6];
    const float* V_w    = (const float*)d_in[7];
    const float* V_b    = (const float*)d_in[8];
    const float* o2e_w  = (const float*)d_in[9];
    const float* o2e_b  = (const float*)d_in[10];
    const float* gwi    = (const float*)d_in[11];
    const float* gwh    = (const float*)d_in[12];
    const float* gbi    = (const float*)d_in[13];
    const float* gbh    = (const float*)d_in[14];
    const float* f1w    = (const float*)d_in[15];
    const float* f1b    = (const float*)d_in[16];
    const float* f2w    = (const float*)d_in[17];
    const float* f2b    = (const float*)d_in[18];

    float* out  = (float*)d_out;
    float* hnew = out + (size_t)BB * VOC;
    float* attn = hnew + (size_t)BB * DDEC;

    __half* bh = nullptr;
    __half* bl = nullptr;
    float* fs = nullptr;
    cudaGetSymbolAddress((void**)&bh, g_bh);
    cudaGetSymbolAddress((void**)&bl, g_bl);
    cudaGetSymbolAddress((void**)&fs, g_f32);

    float* g1   = fs + F_G1;
    float* rnn  = fs + F_RNN;
    float* gi   = fs + F_GI;
    float* gh   = fs + F_GH;
    float* tbuf = fs + F_T;
    float* part = fs + F_PART;

    cudaFuncSetAttribute(gemm64,       cudaFuncAttributeMaxDynamicSharedMemorySize, GEMM_SMEM);
    cudaFuncSetAttribute(gemm64b,      cudaFuncAttributeMaxDynamicSharedMemorySize, GEMM2_SMEM);
    cudaFuncSetAttribute(gemm64b_bias, cudaFuncAttributeMaxDynamicSharedMemorySize, GEMM2_SMEM);
    cudaFuncSetAttribute(score_gemm,   cudaFuncAttributeMaxDynamicSharedMemorySize, SC_SMEM);

    dim3 blk(256);

    // 0) weight splits (hi-only except f2)
    split_weights<<<W4N7 / 256, 256>>>(W1_w, W2_w, o2e_w, gwi, gwh, f1w, f2w);
    // 1) activation splits (enc hi-only)
    split_acts<<<A4N3 / 256, 256>>>(enc, x, hidden);

    // 2) g1 = h0 @ W2^T + W2_b + W1_b  (2-term direct store, 3-stage)
    gemm64b_bias<<<dim3(16, 2), blk, GEMM2_SMEM>>>(
        bh + OFF_HID, bl + OFF_HID, bh + OFF_W2,
        1024, g1, 1024, W2_b, W1_b);

    // 3) score GEMM (launch index 3 -> ncu profiles THIS)
    score_gemm<<<dim3(8, 256), blk, SC_SMEM>>>(
        bh + OFF_ENC, bh + OFF_W1, g1, V_w, part);

    // 4) bias preinit for remaining atomic targets
    bias_init<<<BIAS_TOTAL / 256, 256>>>(rnn, gi, gh, tbuf, out,
                                         o2e_b, gbi, gbh, f1b, f2b);

    // 5) softmax + attn out + context (enc fp16) -> rnn[:, 0:1024]
    attn_softmax_context<<<BB, 256>>>(part, 8, bh + OFF_ENC, V_b, attn, rnn);

    // 6) x_emb += x @ out2emb^T     (2-term v2, splitK=8)
    gemm64b<<<dim3(8, 2, 8), blk, GEMM2_SMEM>>>(
        bh + OFF_X, bl + OFF_X, bh + OFF_O2E,
        4096, 512, rnn + 1024, 1536);

    // 7) gh += h0 @ gru_wh^T        (2-term v2, splitK=2)
    gemm64b<<<dim3(48, 2, 2), blk, GEMM2_SMEM>>>(
        bh + OFF_HID, bl + OFF_HID, bh + OFF_GWH,
        1024, 512, gh, 3072);

    // 8) rnn -> fp16
    f32_split<<<(393216 / 4) / 256, 256>>>(rnn, bh + OFF_RNN, bl + OFF_RNN, 393216 / 4);

    // 9) gi += rnn_in @ gru_wi^T    (2-term v2, splitK=2)
    gemm64b<<<dim3(48, 2, 2), blk, GEMM2_SMEM>>>(
        bh + OFF_RNN, bl + OFF_RNN, bh + OFF_GWI,
        1536, 768, gi, 3072);

    // 10) GRU gates -> h_new (output)
    gru_gate<<<(BB * DDEC) / 256, 256>>>(gi, gh, hidden, hnew);

    // 11) h_new -> fp16
    f32_split<<<(262144 / 4) / 256, 256>>>(hnew, bh + OFF_HNEW, bl + OFF_HNEW, 262144 / 4);

    // 12) tbuf += h_new @ fc1^T     (2-term v2, splitK=8)
    gemm64b<<<dim3(8, 2, 8), blk, GEMM2_SMEM>>>(
        bh + OFF_HNEW, bl + OFF_HNEW, bh + OFF_F1,
        1024, 128, tbuf, 512);

    // 13) t = tanh(tbuf) -> fp16
    f32_split_tanh<<<(131072 / 4) / 256, 256>>>(tbuf, bh + OFF_T, bl + OFF_T, 131072 / 4);

    // 14) out += t @ fc2^T          (3-term, splitK=2; direct output path)
    gemm64<<<dim3(64, 2, 2), blk, GEMM_SMEM>>>(
        bh + OFF_T, bl + OFF_T, bh + OFF_F2, bl + OFF_F2,
        512, 256, out, 4096);
}

// round 14
// speedup vs baseline: 2.0646x; 1.0126x over previous
#include <cuda_runtime.h>
#include <cuda_fp16.h>
#include <cstdint>
#include <math.h>

// Problem dims
#define BB   256
#define LL   128
#define VOC  4096
#define EENC 1024
#define DDEC 1024
#define EEMB 512

// ======================= scratch (module-load allocated) ==================
#define OFF_ENC   0ull
#define OFF_W1    (OFF_ENC + 33554432ull)
#define OFF_W2    (OFF_W1  + 1048576ull)
#define OFF_O2E   (OFF_W2  + 1048576ull)
#define OFF_GWI   (OFF_O2E + 2097152ull)
#define OFF_GWH   (OFF_GWI + 4718592ull)
#define OFF_F1    (OFF_GWH + 3145728ull)
#define OFF_F2    (OFF_F1  + 524288ull)
#define OFF_X     (OFF_F2  + 2097152ull)
#define OFF_HID   (OFF_X   + 1048576ull)
#define OFF_RNN   (OFF_HID + 262144ull)
#define OFF_HNEW  (OFF_RNN + 393216ull)
#define OFF_T     (OFF_HNEW+ 262144ull)
#define BF_TOTAL  (OFF_T   + 131072ull)

__device__ __half g_bh[BF_TOTAL];
__device__ __half g_bl[BF_TOTAL];

#define F_G1    0ull
#define F_RNN   (F_G1   + 262144ull)
#define F_GI    (F_RNN  + 393216ull)
#define F_GH    (F_GI   + 786432ull)
#define F_T     (F_GH   + 786432ull)
#define F_PART  (F_T    + 131072ull)
#define F_TOTAL (F_PART + 524288ull)

__device__ float g_f32[F_TOTAL];

// ======================= small helpers ====================================
__device__ __forceinline__ void cp16(uint32_t s, const void* g) {
    asm volatile("cp.async.cg.shared.global [%0], [%1], 16;"
                 :: "r"(s), "l"(__cvta_generic_to_global(g)));
}
__device__ __forceinline__ void ldm4(uint32_t* r, uint32_t addr) {
    asm volatile("ldmatrix.sync.aligned.m8n8.x4.shared.b16 {%0,%1,%2,%3}, [%4];"
        : "=r"(r[0]), "=r"(r[1]), "=r"(r[2]), "=r"(r[3]) : "r"(addr));
}
__device__ __forceinline__ void mma16816(float* c, const uint32_t* a, const uint32_t* b) {
    asm volatile("mma.sync.aligned.m16n8k16.row.col.f32.f16.f16.f32 "
        "{%0,%1,%2,%3}, {%4,%5,%6,%7}, {%8,%9}, {%0,%1,%2,%3};"
        : "+f"(c[0]), "+f"(c[1]), "+f"(c[2]), "+f"(c[3])
        : "r"(a[0]), "r"(a[1]), "r"(a[2]), "r"(a[3]), "r"(b[0]), "r"(b[1]));
}
__device__ __forceinline__ void do_split4(const float* __restrict__ src, int i,
                                          unsigned long long dst) {
    float4 v = ((const float4*)src)[i];
    __half h0 = __float2half_rn(v.x), h1 = __float2half_rn(v.y);
    __half h2 = __float2half_rn(v.z), h3 = __float2half_rn(v.w);
    __half2 hp0; hp0.x = h0; hp0.y = h1;
    __half2 hp1; hp1.x = h2; hp1.y = h3;
    __half2 lp0, lp1;
    lp0.x = __float2half_rn(v.x - __half2float(h0));
    lp0.y = __float2half_rn(v.y - __half2float(h1));
    lp1.x = __float2half_rn(v.z - __half2float(h2));
    lp1.y = __float2half_rn(v.w - __half2float(h3));
    ((__half2*)(g_bh + dst))[2 * i]     = hp0;
    ((__half2*)(g_bh + dst))[2 * i + 1] = hp1;
    ((__half2*)(g_bl + dst))[2 * i]     = lp0;
    ((__half2*)(g_bl + dst))[2 * i + 1] = lp1;
}
__device__ __forceinline__ void do_split4_hi(const float* __restrict__ src, int i,
                                             unsigned long long dst) {
    float4 v = ((const float4*)src)[i];
    __half2 hp0, hp1;
    hp0.x = __float2half_rn(v.x); hp0.y = __float2half_rn(v.y);
    hp1.x = __float2half_rn(v.z); hp1.y = __float2half_rn(v.w);
    ((__half2*)(g_bh + dst))[2 * i]     = hp0;
    ((__half2*)(g_bh + dst))[2 * i + 1] = hp1;
}

// ================= prep: all input splits + bias pre-init, one kernel =====
// weights (hi-only except f2): [0, 3670016) float4 units
// acts (enc hi-only):          [3670016, 12386304)
// bias pre-init (scalar):      [12386304, 15269888)
#define W4N1 262144
#define W4N2 524288
#define W4N3 1048576
#define W4N4 2228224
#define W4N5 3014656
#define W4N6 3145728
#define W4N7 3670016
#define P_ACT0 3670016
#define PA1 (P_ACT0 + 8388608)
#define PA2 (P_ACT0 + 8650752)
#define PA3 (P_ACT0 + 8716288)
#define P_BIAS0 12386304
#define PB1 (P_BIAS0 + 131072)
#define PB2 (P_BIAS0 + 917504)
#define PB3 (P_BIAS0 + 1703936)
#define PB4 (P_BIAS0 + 1835008)
#define PB5 (P_BIAS0 + 2883584)
#define PREP_TOTAL PB5

__global__ __launch_bounds__(256)
void prep(const float* __restrict__ W1, const float* __restrict__ W2,
          const float* __restrict__ o2e, const float* __restrict__ gwi,
          const float* __restrict__ gwh, const float* __restrict__ f1,
          const float* __restrict__ f2,
          const float* __restrict__ enc, const float* __restrict__ x,
          const float* __restrict__ hid,
          float* __restrict__ rnn, float* __restrict__ gi, float* __restrict__ gh,
          float* __restrict__ tbuf, float* __restrict__ out,
          const float* __restrict__ o2eb, const float* __restrict__ gbi,
          const float* __restrict__ gbh, const float* __restrict__ f1b,
          const float* __restrict__ f2b)
{
    int i = blockIdx.x * blockDim.x + threadIdx.x;
    if (i < W4N7) {
        if (i < W4N1)      do_split4_hi(W1,  i,        OFF_W1);
        else if (i < W4N2) do_split4_hi(W2,  i - W4N1, OFF_W2);
        else if (i < W4N3) do_split4_hi(o2e, i - W4N2, OFF_O2E);
        else if (i < W4N4) do_split4_hi(gwi, i - W4N3, OFF_GWI);
        else if (i < W4N5) do_split4_hi(gwh, i - W4N4, OFF_GWH);
        else if (i < W4N6) do_split4_hi(f1,  i - W4N5, OFF_F1);
        else               do_split4(f2,  i - W4N6, OFF_F2);
    } else if (i < PA3) {
        if (i < PA1)       do_split4_hi(enc, i - P_ACT0, OFF_ENC);
        else if (i < PA2)  do_split4(x,   i - PA1, OFF_X);
        else               do_split4(hid, i - PA2, OFF_HID);
    } else if (i < PB5) {
        int j = i - P_BIAS0;
        if (i < PB1) {
            rnn[(j >> 9) * 1536 + 1024 + (j & 511)] = o2eb[j & 511];
        } else if (i < PB2) {
            j -= 131072;  gi[j] = gbi[j % 3072];
        } else if (i < PB3) {
            j -= 917504;  gh[j] = gbh[j % 3072];
        } else if (i < PB4) {
            j -= 1703936; tbuf[j] = f1b[j & 511];
        } else {
            j -= 1835008; out[j] = f2b[j & 4095];
        }
    }
}

// ============ split of rnn xemb region only (row-strided, float4) =========
__global__ __launch_bounds__(256)
void split_xemb(const float* __restrict__ rnn)
{
    int i = blockIdx.x * blockDim.x + threadIdx.x;      // 32768 float4 units
    if (i >= 32768) return;
    int row = i >> 7;                                    // 128 float4 per row
    int c4  = i & 127;
    size_t off = (size_t)row * 1536 + 1024 + c4 * 4;
    float4 v = *(const float4*)(rnn + off);
    __half h0 = __float2half_rn(v.x), h1 = __float2half_rn(v.y);
    __half h2 = __float2half_rn(v.z), h3 = __float2half_rn(v.w);
    __half2 hp0; hp0.x = h0; hp0.y = h1;
    __half2 hp1; hp1.x = h2; hp1.y = h3;
    __half2 lp0, lp1;
    lp0.x = __float2half_rn(v.x - __half2float(h0));
    lp0.y = __float2half_rn(v.y - __half2float(h1));
    lp1.x = __float2half_rn(v.z - __half2float(h2));
    lp1.y = __float2half_rn(v.w - __half2float(h3));
    *(__half2*)(g_bh + OFF_RNN + off)     = hp0;
    *(__half2*)(g_bh + OFF_RNN + off + 2) = hp1;
    *(__half2*)(g_bl + OFF_RNN + off)     = lp0;
    *(__half2*)(g_bl + OFF_RNN + off + 2) = lp1;
}

__global__ __launch_bounds__(256)
void f32_split_tanh(const float* __restrict__ in, __half* __restrict__ hi,
                    __half* __restrict__ lo, int n4)
{
    int i = blockIdx.x * blockDim.x + threadIdx.x;
    if (i >= n4) return;
    float4 v = ((const float4*)in)[i];
    v.x = tanhf(v.x); v.y = tanhf(v.y); v.z = tanhf(v.z); v.w = tanhf(v.w);
    __half h0 = __float2half_rn(v.x), h1 = __float2half_rn(v.y);
    __half h2 = __float2half_rn(v.z), h3 = __float2half_rn(v.w);
    __half2 hp0; hp0.x = h0; hp0.y = h1;
    __half2 hp1; hp1.x = h2; hp1.y = h3;
    __half2 lp0, lp1;
    lp0.x = __float2half_rn(v.x - __half2float(h0));
    lp0.y = __float2half_rn(v.y - __half2float(h1));
    lp1.x = __float2half_rn(v.z - __half2float(h2));
    lp1.y = __float2half_rn(v.w - __half2float(h3));
    ((__half2*)hi)[2 * i]     = hp0;
    ((__half2*)hi)[2 * i + 1] = hp1;
    ((__half2*)lo)[2 * i]     = lp0;
    ((__half2*)lo)[2 * i + 1] = lp1;
}

// ======================= 3-term split-K mma GEMM (fc2 only) ===============
#define ROWB      80
#define TILE_A_SB (128 * ROWB)
#define TILE_W_SB (64 * ROWB)
#define STAGE_SB  (2 * TILE_A_SB + 2 * TILE_W_SB)
#define GEMM_SMEM (2 * STAGE_SB + 512 + 32)

__global__ __launch_bounds__(256, 2)
void gemm64(const __half* __restrict__ Ah, const __half* __restrict__ Al,
            const __half* __restrict__ Wh, const __half* __restrict__ Wl,
            int K, int Kchunk, float* __restrict__ C, int ldc)
{
    extern __shared__ __align__(128) char smem[];
    const uint32_t sbase = (uint32_t)__cvta_generic_to_shared(smem);

    const int tid  = threadIdx.x;
    const int wid  = tid >> 5;
    const int lane = tid & 31;
    const int brow = blockIdx.y * 128;
    const int bcol = blockIdx.x * 64;
    const int k0   = blockIdx.z * Kchunk;
    const int m32  = (wid >> 1) * 32;
    const int n32w = (wid & 1) * 32;

    const int lrA = tid >> 1;
    const int cA  = (tid & 1) * 2;
    const int lrW = tid >> 2;
    const int cW  = tid & 3;
    const size_t aoff = (size_t)(brow + lrA) * K + k0;
    const size_t woff = (size_t)(bcol + lrW) * K + k0;

    auto load_stage = [&](int stage, int kk0) {
        const uint32_t sA = sbase + stage * STAGE_SB + lrA * ROWB;
        const uint32_t sW = sbase + stage * STAGE_SB + 2 * TILE_A_SB + lrW * ROWB;
        const char* pAh = (const char*)(Ah + aoff + kk0);
        const char* pAl = (const char*)(Al + aoff + kk0);
        const char* pWh = (const char*)(Wh + woff + kk0);
        const char* pWl = (const char*)(Wl + woff + kk0);
        #pragma unroll
        for (int c = cA; c < cA + 2; c++) {
            cp16(sA + c * 16, pAh + c * 16);
            cp16(sA + TILE_A_SB + c * 16, pAl + c * 16);
        }
        cp16(sW + cW * 16, pWh + cW * 16);
        cp16(sW + TILE_W_SB + cW * 16, pWl + cW * 16);
    };

    const int nk = Kchunk >> 5;

    load_stage(0, 0);
    asm volatile("cp.async.commit_group;");
    if (nk > 1) load_stage(1, 32);
    asm volatile("cp.async.commit_group;");

    float acc[2][4][4];
    #pragma unroll
    for (int i = 0; i < 2; i++)
        #pragma unroll
        for (int j = 0; j < 4; j++)
            #pragma unroll
            for (int q = 0; q < 4; q++) acc[i][j][q] = 0.f;

    const int arow_l = m32 + (lane & 15);
    const uint32_t akb = ((lane >> 4) & 1) * 16;
    const int nrow_l = n32w + (lane & 7) + ((lane >> 4) & 1) * 8;
    const uint32_t bkb = ((lane >> 3) & 1) * 16;

    for (int c = 0; c < nk; c++) {
        asm volatile("cp.async.wait_group %0;" :: "n"(1));
        __syncthreads();

        const uint32_t sb = sbase + (c & 1) * STAGE_SB;
        #pragma unroll
        for (int kk = 0; kk < 2; kk++) {
            const uint32_t kbyte = kk * 32;
            uint32_t afh[2][4], afl[2][4], bfh[4][2], bfl[4][2];
            #pragma unroll
            for (int mt = 0; mt < 2; mt++) {
                uint32_t ra = (uint32_t)((arow_l + mt * 16) * ROWB) + akb + kbyte;
                ldm4(afh[mt], sb + ra);
                ldm4(afl[mt], sb + TILE_A_SB + ra);
            }
            #pragma unroll
            for (int np = 0; np < 2; np++) {
                uint32_t rb = (uint32_t)((nrow_l + np * 16) * ROWB) + bkb + kbyte;
                uint32_t th[4], tl[4];
                ldm4(th, sb + 2 * TILE_A_SB + rb);
                ldm4(tl, sb + 2 * TILE_A_SB + TILE_W_SB + rb);
                bfh[2 * np][0] = th[0]; bfh[2 * np][1] = th[1];
                bfh[2 * np + 1][0] = th[2]; bfh[2 * np + 1][1] = th[3];
                bfl[2 * np][0] = tl[0]; bfl[2 * np][1] = tl[1];
                bfl[2 * np + 1][0] = tl[2]; bfl[2 * np + 1][1] = tl[3];
            }
            #pragma unroll
            for (int mt = 0; mt < 2; mt++)
                #pragma unroll
                for (int nt = 0; nt < 4; nt++) {
                    mma16816(acc[mt][nt], afh[mt], bfh[nt]);
                    mma16816(acc[mt][nt], afl[mt], bfh[nt]);
                    mma16816(acc[mt][nt], afh[mt], bfl[nt]);
                }
        }
        __syncthreads();

        if (c + 2 < nk) load_stage(c & 1, (c + 2) * 32);
        asm volatile("cp.async.commit_group;");
    }

    const int rloc0 = m32 + (lane >> 2);
    const int cloc0 = n32w + (lane & 3) * 2;
    #pragma unroll
    for (int mt = 0; mt < 2; mt++) {
        const int r0 = brow + rloc0 + mt * 16;
        #pragma unroll
        for (int nt = 0; nt < 4; nt++) {
            const int col = bcol + cloc0 + nt * 8;
            float* c0 = C + (size_t)r0 * ldc + col;
            float* c1 = C + (size_t)(r0 + 8) * ldc + col;
            atomicAdd(c0,     acc[mt][nt][0]);
            atomicAdd(c0 + 1, acc[mt][nt][1]);
            atomicAdd(c1,     acc[mt][nt][2]);
            atomicAdd(c1 + 1, acc[mt][nt][3]);
        }
    }
}

// ====== 2-term split-K GEMM v2: 3 stages, single sync per chunk ===========
#define STAGE2_SB (2 * TILE_A_SB + TILE_W_SB)
#define GEMM2_SMEM (3 * STAGE2_SB + 512 + 32)

__global__ __launch_bounds__(256, 2)
void gemm64b(const __half* __restrict__ Ah, const __half* __restrict__ Al,
             const __half* __restrict__ Wh,
             int K, int Kchunk, float* __restrict__ C, int ldc)
{
    extern __shared__ __align__(128) char smem[];
    const uint32_t sbase = (uint32_t)__cvta_generic_to_shared(smem);

    const int tid  = threadIdx.x;
    const int wid  = tid >> 5;
    const int lane = tid & 31;
    const int brow = blockIdx.y * 128;
    const int bcol = blockIdx.x * 64;
    const int k0   = blockIdx.z * Kchunk;
    const int m32  = (wid >> 1) * 32;
    const int n32w = (wid & 1) * 32;

    const int lrA = tid >> 1;
    const int cA  = (tid & 1) * 2;
    const int lrW = tid >> 2;
    const int cW  = tid & 3;
    const size_t aoff = (size_t)(brow + lrA) * K + k0;
    const size_t woff = (size_t)(bcol + lrW) * K + k0;

    auto load_stage = [&](int stage, int kk0) {
        const uint32_t sA = sbase + stage * STAGE2_SB + lrA * ROWB;
        const uint32_t sW = sbase + stage * STAGE2_SB + 2 * TILE_A_SB + lrW * ROWB;
        const char* pAh = (const char*)(Ah + aoff + kk0);
        const char* pAl = (const char*)(Al + aoff + kk0);
        const char* pWh = (const char*)(Wh + woff + kk0);
        #pragma unroll
        for (int c = cA; c < cA + 2; c++) {
            cp16(sA + c * 16, pAh + c * 16);
            cp16(sA + TILE_A_SB + c * 16, pAl + c * 16);
        }
        cp16(sW + cW * 16, pWh + cW * 16);
    };

    const int nk = Kchunk >> 5;

    load_stage(0, 0);
    asm volatile("cp.async.commit_group;");
    if (nk > 1) load_stage(1, 32);
    asm volatile("cp.async.commit_group;");

    float acc[2][4][4];
    #pragma unroll
    for (int i = 0; i < 2; i++)
        #pragma unroll
        for (int j = 0; j < 4; j++)
            #pragma unroll
            for (int q = 0; q < 4; q++) acc[i][j][q] = 0.f;

    const int arow_l = m32 + (lane & 15);
    const uint32_t akb = ((lane >> 4) & 1) * 16;
    const int nrow_l = n32w + (lane & 7) + ((lane >> 4) & 1) * 8;
    const uint32_t bkb = ((lane >> 3) & 1) * 16;

    int stage = 0;
    for (int c = 0; c < nk; c++) {
        asm volatile("cp.async.wait_group %0;" :: "n"(1));
        __syncthreads();

        if (c + 2 < nk) {
            int s2 = stage + 2; if (s2 >= 3) s2 -= 3;
            load_stage(s2, (c + 2) * 32);
        }
        asm volatile("cp.async.commit_group;");

        const uint32_t sb = sbase + stage * STAGE2_SB;
        #pragma unroll
        for (int kk = 0; kk < 2; kk++) {
            const uint32_t kbyte = kk * 32;
            uint32_t afh[2][4], afl[2][4], bfh[4][2];
            #pragma unroll
            for (int mt = 0; mt < 2; mt++) {
                uint32_t ra = (uint32_t)((arow_l + mt * 16) * ROWB) + akb + kbyte;
                ldm4(afh[mt], sb + ra);
                ldm4(afl[mt], sb + TILE_A_SB + ra);
            }
            #pragma unroll
            for (int np = 0; np < 2; np++) {
                uint32_t rb = (uint32_t)((nrow_l + np * 16) * ROWB) + bkb + kbyte;
                uint32_t th[4];
                ldm4(th, sb + 2 * TILE_A_SB + rb);
                bfh[2 * np][0] = th[0]; bfh[2 * np][1] = th[1];
                bfh[2 * np + 1][0] = th[2]; bfh[2 * np + 1][1] = th[3];
            }
            #pragma unroll
            for (int mt = 0; mt < 2; mt++)
                #pragma unroll
                for (int nt = 0; nt < 4; nt++) {
                    mma16816(acc[mt][nt], afh[mt], bfh[nt]);
                    mma16816(acc[mt][nt], afl[mt], bfh[nt]);
                }
        }
        if (++stage >= 3) stage = 0;
    }

    const int rloc0 = m32 + (lane >> 2);
    const int cloc0 = n32w + (lane & 3) * 2;
    #pragma unroll
    for (int mt = 0; mt < 2; mt++) {
        const int r0 = brow + rloc0 + mt * 16;
        #pragma unroll
        for (int nt = 0; nt < 4; nt++) {
            const int col = bcol + cloc0 + nt * 8;
            float* c0 = C + (size_t)r0 * ldc + col;
            float* c1 = C + (size_t)(r0 + 8) * ldc + col;
            atomicAdd(c0,     acc[mt][nt][0]);
            atomicAdd(c0 + 1, acc[mt][nt][1]);
            atomicAdd(c1,     acc[mt][nt][2]);
            atomicAdd(c1 + 1, acc[mt][nt][3]);
        }
    }
}

// ====== 2-term direct-store GEMM with 2-bias epilogue (g1), 3 stages ======
__global__ __launch_bounds__(256, 2)
void gemm64b_bias(const __half* __restrict__ Ah, const __half* __restrict__ Al,
                  const __half* __restrict__ Wh,
                  int K, float* __restrict__ C, int ldc,
                  const float* __restrict__ b1, const float* __restrict__ b2)
{
    extern __shared__ __align__(128) char smem[];
    const uint32_t sbase = (uint32_t)__cvta_generic_to_shared(smem);

    const int tid  = threadIdx.x;
    const int wid  = tid >> 5;
    const int lane = tid & 31;
    const int brow = blockIdx.y * 128;
    const int bcol = blockIdx.x * 64;
    const int m32  = (wid >> 1) * 32;
    const int n32w = (wid & 1) * 32;

    const int lrA = tid >> 1;
    const int cA  = (tid & 1) * 2;
    const int lrW = tid >> 2;
    const int cW  = tid & 3;
    const size_t aoff = (size_t)(brow + lrA) * K;
    const size_t woff = (size_t)(bcol + lrW) * K;

    auto load_stage = [&](int stage, int kk0) {
        const uint32_t sA = sbase + stage * STAGE2_SB + lrA * ROWB;
        const uint32_t sW = sbase + stage * STAGE2_SB + 2 * TILE_A_SB + lrW * ROWB;
        const char* pAh = (const char*)(Ah + aoff + kk0);
        const char* pAl = (const char*)(Al + aoff + kk0);
        const char* pWh = (const char*)(Wh + woff + kk0);
        #pragma unroll
        for (int c = cA; c < cA + 2; c++) {
            cp16(sA + c * 16, pAh + c * 16);
            cp16(sA + TILE_A_SB + c * 16, pAl + c * 16);
        }
        cp16(sW + cW * 16, pWh + cW * 16);
    };

    const int nk = K >> 5;

    load_stage(0, 0);
    asm volatile("cp.async.commit_group;");
    load_stage(1, 32);
    asm volatile("cp.async.commit_group;");

    float acc[2][4][4];
    #pragma unroll
    for (int i = 0; i < 2; i++)
        #pragma unroll
        for (int j = 0; j < 4; j++)
            #pragma unroll
            for (int q = 0; q < 4; q++) acc[i][j][q] = 0.f;

    const int arow_l = m32 + (lane & 15);
    const uint32_t akb = ((lane >> 4) & 1) * 16;
    const int nrow_l = n32w + (lane & 7) + ((lane >> 4) & 1) * 8;
    const uint32_t bkb = ((lane >> 3) & 1) * 16;

    int stage = 0;
    for (int c = 0; c < nk; c++) {
        asm volatile("cp.async.wait_group %0;" :: "n"(1));
        __syncthreads();

        if (c + 2 < nk) {
            int s2 = stage + 2; if (s2 >= 3) s2 -= 3;
            load_stage(s2, (c + 2) * 32);
        }
        asm volatile("cp.async.commit_group;");

        const uint32_t sb = sbase + stage * STAGE2_SB;
        #pragma unroll
        for (int kk = 0; kk < 2; kk++) {
            const uint32_t kbyte = kk * 32;
            uint32_t afh[2][4], afl[2][4], bfh[4][2];
            #pragma unroll
            for (int mt = 0; mt < 2; mt++) {
                uint32_t ra = (uint32_t)((arow_l + mt * 16) * ROWB) + akb + kbyte;
                ldm4(afh[mt], sb + ra);
                ldm4(afl[mt], sb + TILE_A_SB + ra);
            }
            #pragma unroll
            for (int np = 0; np < 2; np++) {
                uint32_t rb = (uint32_t)((nrow_l + np * 16) * ROWB) + bkb + kbyte;
                uint32_t th[4];
                ldm4(th, sb + 2 * TILE_A_SB + rb);
                bfh[2 * np][0] = th[0]; bfh[2 * np][1] = th[1];
                bfh[2 * np + 1][0] = th[2]; bfh[2 * np + 1][1] = th[3];
            }
            #pragma unroll
            for (int mt = 0; mt < 2; mt++)
                #pragma unroll
                for (int nt = 0; nt < 4; nt++) {
                    mma16816(acc[mt][nt], afh[mt], bfh[nt]);
                    mma16816(acc[mt][nt], afl[mt], bfh[nt]);
                }
        }
        if (++stage >= 3) stage = 0;
    }

    const int rloc0 = m32 + (lane >> 2);
    const int cloc0 = n32w + (lane & 3) * 2;
    #pragma unroll
    for (int mt = 0; mt < 2; mt++) {
        const int r0 = brow + rloc0 + mt * 16;
        #pragma unroll
        for (int nt = 0; nt < 4; nt++) {
            const int col = bcol + cloc0 + nt * 8;
            float2 bb = make_float2(b1[col] + b2[col], b1[col + 1] + b2[col + 1]);
            *(float2*)(C + (size_t)r0 * ldc + col) =
                make_float2(acc[mt][nt][0] + bb.x, acc[mt][nt][1] + bb.y);
            *(float2*)(C + (size_t)(r0 + 8) * ldc + col) =
                make_float2(acc[mt][nt][2] + bb.x, acc[mt][nt][3] + bb.y);
        }
    }
}

// ======= score GEMM v3: 128x128 tile, BK=64, 3 stages, warp 64x32 =========
#define SC_ROWB   144
#define SC_A_SB   (128 * SC_ROWB)
#define SC_W_SB   (128 * SC_ROWB)
#define SC_STAGE  (SC_A_SB + SC_W_SB)
#define SC_NST    3
#define SC_SMEM   (SC_NST * SC_STAGE + 512 + 32)

__global__ __launch_bounds__(256, 2)
void score_gemm(const __half* __restrict__ Ah, const __half* __restrict__ Wh,
                const float* __restrict__ g1, const float* __restrict__ vw,
                float* __restrict__ partial)
{
    extern __shared__ __align__(128) char smem[];
    const uint32_t sbase = (uint32_t)__cvta_generic_to_shared(smem);
    float* part_sm = (float*)(smem + SC_NST * SC_STAGE);

    const int tid  = threadIdx.x;
    const int wid  = tid >> 5;
    const int lane = tid & 31;
    const int brow = blockIdx.y * 128;
    const int bcol = blockIdx.x * 128;
    const int m64  = (wid >> 2) * 64;
    const int n32  = (wid & 3) * 32;
    const int K    = 1024;

    if (tid < 128) part_sm[tid] = 0.f;

    const int arow = tid >> 1;
    const int acb_ld = (tid & 1) * 4;
    const __half* gA = Ah + (size_t)(brow + arow) * K;
    const __half* gW = Wh + (size_t)(bcol + arow) * K;
    const uint32_t sA_ld = (uint32_t)(arow * SC_ROWB + acb_ld * 16);
    const uint32_t sW_ld = (uint32_t)(SC_A_SB + arow * SC_ROWB + acb_ld * 16);

    auto load_stage = [&](int stage, int k0) {
        const uint32_t sb = sbase + stage * SC_STAGE;
        const char* pA = (const char*)(gA + k0) + acb_ld * 16;
        const char* pW = (const char*)(gW + k0) + acb_ld * 16;
        #pragma unroll
        for (int c = 0; c < 4; c++) {
            cp16(sb + sA_ld + c * 16, pA + c * 16);
            cp16(sb + sW_ld + c * 16, pW + c * 16);
        }
    };

    const int nk = 16;

    load_stage(0, 0);
    asm volatile("cp.async.commit_group;");
    load_stage(1, 64);
    asm volatile("cp.async.commit_group;");

    float acc[4][4][4];
    #pragma unroll
    for (int i = 0; i < 4; i++)
        #pragma unroll
        for (int j = 0; j < 4; j++)
            #pragma unroll
            for (int q = 0; q < 4; q++) acc[i][j][q] = 0.f;

    const int arow_l = m64 + (lane & 15);
    const uint32_t akb = ((lane >> 4) & 1) * 16;
    const int nrow_l = n32 + (lane & 7) + ((lane >> 4) & 1) * 8;
    const uint32_t bkb = ((lane >> 3) & 1) * 16;

    int stage = 0;
    for (int c = 0; c < nk; c++) {
        asm volatile("cp.async.wait_group %0;" :: "n"(1));
        __syncthreads();

        if (c + 2 < nk) {
            int s2 = stage + 2; if (s2 >= SC_NST) s2 -= SC_NST;
            load_stage(s2, (c + 2) * 64);
        }
        asm volatile("cp.async.commit_group;");

        const uint32_t sb = sbase + stage * SC_STAGE;
        #pragma unroll
        for (int kk = 0; kk < 4; kk++) {
            const uint32_t kbyte = kk * 32;
            uint32_t bfh[4][2];
            #pragma unroll
            for (int np = 0; np < 2; np++) {
                uint32_t rb = (uint32_t)((nrow_l + np * 16) * SC_ROWB) + bkb + kbyte;
                uint32_t th[4];
                ldm4(th, sb + SC_A_SB + rb);
                bfh[2 * np][0] = th[0]; bfh[2 * np][1] = th[1];
                bfh[2 * np + 1][0] = th[2]; bfh[2 * np + 1][1] = th[3];
            }
            #pragma unroll
            for (int mt = 0; mt < 4; mt++) {
                uint32_t afh[4];
                uint32_t ra = (uint32_t)((arow_l + mt * 16) * SC_ROWB) + akb + kbyte;
                ldm4(afh, sb + ra);
                #pragma unroll
                for (int nt = 0; nt < 4; nt++)
                    mma16816(acc[mt][nt], afh, bfh[nt]);
            }
        }
        if (++stage >= SC_NST) stage = 0;
    }

    const int rloc0 = m64 + (lane >> 2);
    const int cloc0 = n32 + (lane & 3) * 2;
    const float* g1r = g1 + (size_t)blockIdx.y * 1024;
    #pragma unroll
    for (int mt = 0; mt < 4; mt++) {
        float s0 = 0.f, s1 = 0.f;
        #pragma unroll
        for (int nt = 0; nt < 4; nt++) {
            int col = bcol + cloc0 + nt * 8;
            float gw0 = g1r[col],     vw0 = vw[col];
            float gw1 = g1r[col + 1], vw1 = vw[col + 1];
            s0 += tanhf(acc[mt][nt][0] + gw0) * vw0;
            s0 += tanhf(acc[mt][nt][1] + gw1) * vw1;
            s1 += tanhf(acc[mt][nt][2] + gw0) * vw0;
            s1 += tanhf(acc[mt][nt][3] + gw1) * vw1;
        }
        atomicAdd(&part_sm[rloc0 + mt * 16], s0);
        atomicAdd(&part_sm[rloc0 + mt * 16 + 8], s1);
    }
    __syncthreads();
    if (tid < 128)
        partial[(size_t)(brow + tid) * gridDim.x + blockIdx.x] = part_sm[tid];
}

// ==== softmax + context; writes ctx directly as fp16 hi/lo splits =========
__global__ __launch_bounds__(256)
void attn_softmax_context(const float* __restrict__ part, int npart,
                          const __half* __restrict__ ench,
                          const float* __restrict__ Vb,
                          float* __restrict__ attn_out)
{
    const int b   = blockIdx.x;
    const int tid = threadIdx.x;
    __shared__ float logit[LL];

    if (tid < LL) {
        const float* pr = part + (size_t)(b * LL + tid) * npart;
        float s = Vb[0];
        for (int j = 0; j < npart; j++) s += pr[j];
        logit[tid] = s;
    }
    __syncthreads();

    if (tid < 32) {
        const int lane = tid;
        float m = -1e30f;
        for (int l = lane; l < LL; l += 32) m = fmaxf(m, logit[l]);
        #pragma unroll
        for (int o = 16; o; o >>= 1) m = fmaxf(m, __shfl_xor_sync(0xffffffffu, m, o));
        float s = 0.f;
        for (int l = lane; l < LL; l += 32) {
            float e = expf(logit[l] - m);
            logit[l] = e;
            s += e;
        }
        #pragma unroll
        for (int o = 16; o; o >>= 1) s += __shfl_xor_sync(0xffffffffu, s, o);
        float inv = 1.f / s;
        for (int l = lane; l < LL; l += 32) logit[l] *= inv;
    }
    __syncthreads();

    if (tid < LL) attn_out[b * LL + tid] = logit[tid];

    float4 acc = make_float4(0.f, 0.f, 0.f, 0.f);
    const __half2* encb = (const __half2*)(ench + (size_t)b * LL * EENC) + tid * 2;
    #pragma unroll 4
    for (int l = 0; l < LL; l++) {
        float a = logit[l];
        __half2 v0 = encb[l * (EENC / 2)];
        __half2 v1 = encb[l * (EENC / 2) + 1];
        float2 f0 = __half22float2(v0);
        float2 f1 = __half22float2(v1);
        acc.x += a * f0.x; acc.y += a * f0.y;
        acc.z += a * f1.x; acc.w += a * f1.y;
    }
    // split ctx -> bh/bl at OFF_RNN (cols 0..1023)
    size_t off = (size_t)b * 1536 + tid * 4;
    __half h0 = __float2half_rn(acc.x), h1 = __float2half_rn(acc.y);
    __half h2 = __float2half_rn(acc.z), h3 = __float2half_rn(acc.w);
    __half2 hp0; hp0.x = h0; hp0.y = h1;
    __half2 hp1; hp1.x = h2; hp1.y = h3;
    __half2 lp0, lp1;
    lp0.x = __float2half_rn(acc.x - __half2float(h0));
    lp0.y = __float2half_rn(acc.y - __half2float(h1));
    lp1.x = __float2half_rn(acc.z - __half2float(h2));
    lp1.y = __float2half_rn(acc.w - __half2float(h3));
    *(__half2*)(g_bh + OFF_RNN + off)     = hp0;
    *(__half2*)(g_bh + OFF_RNN + off + 2) = hp1;
    *(__half2*)(g_bl + OFF_RNN + off)     = lp0;
    *(__half2*)(g_bl + OFF_RNN + off + 2) = lp1;
}

// ======== GRU gates; writes hnew + fp16 hi/lo splits (fused) ==============
__global__ __launch_bounds__(256)
void gru_gate(const float* __restrict__ gi, const float* __restrict__ gh,
              const float* __restrict__ h0, float* __restrict__ hnew)
{
    const int i = blockIdx.x * blockDim.x + threadIdx.x;   // 131072, 2 elems each
    const int idx = i * 2;
    const int b = idx >> 10;
    const int d = idx & 1023;
    const float* gib = gi + (size_t)b * 3072;
    const float* ghb = gh + (size_t)b * 3072;
    float h_out[2];
    #pragma unroll
    for (int u = 0; u < 2; u++) {
        int dd = d + u;
        float r = 1.f / (1.f + expf(-(gib[dd] + ghb[dd])));
        float z = 1.f / (1.f + expf(-(gib[1024 + dd] + ghb[1024 + dd])));
        float n = tanhf(gib[2048 + dd] + r * ghb[2048 + dd]);
        h_out[u] = (1.f - z) * n + z * h0[idx + u];
    }
    *(float2*)(hnew + idx) = make_float2(h_out[0], h_out[1]);
    __half hh0 = __float2half_rn(h_out[0]);
    __half hh1 = __float2half_rn(h_out[1]);
    __half2 hp; hp.x = hh0; hp.y = hh1;
    __half2 lp;
    lp.x = __float2half_rn(h_out[0] - __half2float(hh0));
    lp.y = __float2half_rn(h_out[1] - __half2float(hh1));
    ((__half2*)(g_bh + OFF_HNEW))[i] = hp;
    ((__half2*)(g_bl + OFF_HNEW))[i] = lp;
}

// ============================ launch ======================================
extern "C" void kernel_launch(void* const* d_in, const int* in_sizes, int n_in,
                              void* d_out, int out_size)
{
    (void)in_sizes; (void)n_in; (void)out_size;

    const float* x      = (const float*)d_in[0];
    const float* hidden = (const float*)d_in[1];
    const float* enc    = (const float*)d_in[2];
    const float* W1_w   = (const float*)d_in[3];
    const float* W1_b   = (const float*)d_in[4];
    const float* W2_w   = (const float*)d_in[5];
    const float* W2_b   = (const float*)d_in[6];
    const float* V_w    = (const float*)d_in[7];
    const float* V_b    = (const float*)d_in[8];
    const float* o2e_w  = (const float*)d_in[9];
    const float* o2e_b  = (const float*)d_in[10];
    const float* gwi    = (const float*)d_in[11];
    const float* gwh    = (const float*)d_in[12];
    const float* gbi    = (const float*)d_in[13];
    const float* gbh    = (const float*)d_in[14];
    const float* f1w    = (const float*)d_in[15];
    const float* f1b    = (const float*)d_in[16];
    const float* f2w    = (const float*)d_in[17];
    const float* f2b    = (const float*)d_in[18];

    float* out  = (float*)d_out;
    float* hnew = out + (size_t)BB * VOC;
    float* attn = hnew + (size_t)BB * DDEC;

    __half* bh = nullptr;
    __half* bl = nullptr;
    float* fs = nullptr;
    cudaGetSymbolAddress((void**)&bh, g_bh);
    cudaGetSymbolAddress((void**)&bl, g_bl);
    cudaGetSymbolAddress((void**)&fs, g_f32);

    float* g1   = fs + F_G1;
    float* rnn  = fs + F_RNN;
    float* gi   = fs + F_GI;
    float* gh   = fs + F_GH;
    float* tbuf = fs + F_T;
    float* part = fs + F_PART;

    cudaFuncSetAttribute(gemm64,       cudaFuncAttributeMaxDynamicSharedMemorySize, GEMM_SMEM);
    cudaFuncSetAttribute(gemm64b,      cudaFuncAttributeMaxDynamicSharedMemorySize, GEMM2_SMEM);
    cudaFuncSetAttribute(gemm64b_bias, cudaFuncAttributeMaxDynamicSharedMemorySize, GEMM2_SMEM);
    cudaFuncSetAttribute(score_gemm,   cudaFuncAttributeMaxDynamicSharedMemorySize, SC_SMEM);

    dim3 blk(256);

    // 0) prep: all input splits + bias pre-init (one kernel)
    prep<<<PREP_TOTAL / 256, 256>>>(W1_w, W2_w, o2e_w, gwi, gwh, f1w, f2w,
                                    enc, x, hidden,
                                    rnn, gi, gh, tbuf, out,
                                    o2e_b, gbi, gbh, f1b, f2b);

    // 1) g1 = h0 @ W2^T + W2_b + W1_b  (2-term direct store)
    gemm64b_bias<<<dim3(16, 2), blk, GEMM2_SMEM>>>(
        bh + OFF_HID, bl + OFF_HID, bh + OFF_W2,
        1024, g1, 1024, W2_b, W1_b);

    // 2) score GEMM
    score_gemm<<<dim3(8, 256), blk, SC_SMEM>>>(
        bh + OFF_ENC, bh + OFF_W1, g1, V_w, part);

    // 3) x_emb += x @ out2emb^T     (2-term, splitK=8)
    gemm64b<<<dim3(8, 2, 8), blk, GEMM2_SMEM>>>(
        bh + OFF_X, bl + OFF_X, bh + OFF_O2E,
        4096, 512, rnn + 1024, 1536);

    // 4) softmax + attn out + ctx (writes fp16 splits directly)
    attn_softmax_context<<<BB, 256>>>(part, 8, bh + OFF_ENC, V_b, attn);

    // 5) gh += h0 @ gru_wh^T        (2-term, splitK=2)
    gemm64b<<<dim3(48, 2, 2), blk, GEMM2_SMEM>>>(
        bh + OFF_HID, bl + OFF_HID, bh + OFF_GWH,
        1024, 512, gh, 3072);

    // 6) xemb region of rnn -> fp16
    split_xemb<<<32768 / 256, 256>>>(rnn);

    // 7) gi += rnn_in @ gru_wi^T    (2-term, splitK=2)
    gemm64b<<<dim3(48, 2, 2), blk, GEMM2_SMEM>>>(
        bh + OFF_RNN, bl + OFF_RNN, bh + OFF_GWI,
        1536, 768, gi, 3072);

    // 8) GRU gates -> h_new (+ fused fp16 split)
    gru_gate<<<131072 / 256, 256>>>(gi, gh, hidden, hnew);

    // 9) tbuf += h_new @ fc1^T      (2-term, splitK=8)
    gemm64b<<<dim3(8, 2, 8), blk, GEMM2_SMEM>>>(
        bh + OFF_HNEW, bl + OFF_HNEW, bh + OFF_F1,
        1024, 128, tbuf, 512);

    // 10) t = tanh(tbuf) -> fp16
    f32_split_tanh<<<(131072 / 4) / 256, 256>>>(tbuf, bh + OFF_T, bl + OFF_T, 131072 / 4);

    // 11) out += t @ fc2^T          (3-term, splitK=2; direct output path)
    gemm64<<<dim3(64, 2, 2), blk, GEMM_SMEM>>>(
        bh + OFF_T, bl + OFF_T, bh + OFF_F2, bl + OFF_F2,
        512, 256, out, 4096);
}

// round 15
// speedup vs baseline: 2.1657x; 1.0490x over previous
#include <cuda_runtime.h>
#include <cuda_fp16.h>
#include <cstdint>
#include <math.h>

// Problem dims
#define BB   256
#define LL   128
#define VOC  4096
#define EENC 1024
#define DDEC 1024
#define EEMB 512

// ======================= scratch (module-load allocated) ==================
#define OFF_ENC   0ull
#define OFF_W1    (OFF_ENC + 33554432ull)
#define OFF_W2    (OFF_W1  + 1048576ull)
#define OFF_O2E   (OFF_W2  + 1048576ull)
#define OFF_GWI   (OFF_O2E + 2097152ull)
#define OFF_GWH   (OFF_GWI + 4718592ull)
#define OFF_F1    (OFF_GWH + 3145728ull)
#define OFF_F2    (OFF_F1  + 524288ull)
#define OFF_X     (OFF_F2  + 2097152ull)
#define OFF_HID   (OFF_X   + 1048576ull)
#define OFF_RNN   (OFF_HID + 262144ull)
#define OFF_HNEW  (OFF_RNN + 393216ull)
#define OFF_T     (OFF_HNEW+ 262144ull)
#define BF_TOTAL  (OFF_T   + 131072ull)

__device__ __half g_bh[BF_TOTAL];
__device__ __half g_bl[BF_TOTAL];

#define F_G1    0ull
#define F_RNN   (F_G1   + 262144ull)
#define F_GI    (F_RNN  + 393216ull)
#define F_GH    (F_GI   + 786432ull)
#define F_T     (F_GH   + 786432ull)
#define F_PART  (F_T    + 131072ull)
#define F_TOTAL (F_PART + 524288ull)

__device__ float g_f32[F_TOTAL];

// ======================= small helpers ====================================
__device__ __forceinline__ void cp16(uint32_t s, const void* g) {
    asm volatile("cp.async.cg.shared.global [%0], [%1], 16;"
                 :: "r"(s), "l"(__cvta_generic_to_global(g)));
}
__device__ __forceinline__ void ldm4(uint32_t* r, uint32_t addr) {
    asm volatile("ldmatrix.sync.aligned.m8n8.x4.shared.b16 {%0,%1,%2,%3}, [%4];"
        : "=r"(r[0]), "=r"(r[1]), "=r"(r[2]), "=r"(r[3]) : "r"(addr));
}
__device__ __forceinline__ void mma16816(float* c, const uint32_t* a, const uint32_t* b) {
    asm volatile("mma.sync.aligned.m16n8k16.row.col.f32.f16.f16.f32 "
        "{%0,%1,%2,%3}, {%4,%5,%6,%7}, {%8,%9}, {%0,%1,%2,%3};"
        : "+f"(c[0]), "+f"(c[1]), "+f"(c[2]), "+f"(c[3])
        : "r"(a[0]), "r"(a[1]), "r"(a[2]), "r"(a[3]), "r"(b[0]), "r"(b[1]));
}
__device__ __forceinline__ void do_split4(const float* __restrict__ src, int i,
                                          unsigned long long dst) {
    float4 v = ((const float4*)src)[i];
    __half h0 = __float2half_rn(v.x), h1 = __float2half_rn(v.y);
    __half h2 = __float2half_rn(v.z), h3 = __float2half_rn(v.w);
    __half2 hp0; hp0.x = h0; hp0.y = h1;
    __half2 hp1; hp1.x = h2; hp1.y = h3;
    __half2 lp0, lp1;
    lp0.x = __float2half_rn(v.x - __half2float(h0));
    lp0.y = __float2half_rn(v.y - __half2float(h1));
    lp1.x = __float2half_rn(v.z - __half2float(h2));
    lp1.y = __float2half_rn(v.w - __half2float(h3));
    ((__half2*)(g_bh + dst))[2 * i]     = hp0;
    ((__half2*)(g_bh + dst))[2 * i + 1] = hp1;
    ((__half2*)(g_bl + dst))[2 * i]     = lp0;
    ((__half2*)(g_bl + dst))[2 * i + 1] = lp1;
}
__device__ __forceinline__ void do_split4_hi(const float* __restrict__ src, int i,
                                             unsigned long long dst) {
    float4 v = ((const float4*)src)[i];
    __half2 hp0, hp1;
    hp0.x = __float2half_rn(v.x); hp0.y = __float2half_rn(v.y);
    hp1.x = __float2half_rn(v.z); hp1.y = __float2half_rn(v.w);
    ((__half2*)(g_bh + dst))[2 * i]     = hp0;
    ((__half2*)(g_bh + dst))[2 * i + 1] = hp1;
}

// ================= prep: all input splits + bias pre-init, one kernel =====
#define W4N1 262144
#define W4N2 524288
#define W4N3 1048576
#define W4N4 2228224
#define W4N5 3014656
#define W4N6 3145728
#define W4N7 3670016
#define P_ACT0 3670016
#define PA1 (P_ACT0 + 8388608)
#define PA2 (P_ACT0 + 8650752)
#define PA3 (P_ACT0 + 8716288)
#define P_BIAS0 12386304
#define PB1 (P_BIAS0 + 131072)
#define PB2 (P_BIAS0 + 917504)
#define PB3 (P_BIAS0 + 1703936)
#define PB4 (P_BIAS0 + 1835008)
#define PB5 (P_BIAS0 + 2883584)
#define PREP_TOTAL PB5

__global__ __launch_bounds__(256)
void prep(const float* __restrict__ W1, const float* __restrict__ W2,
          const float* __restrict__ o2e, const float* __restrict__ gwi,
          const float* __restrict__ gwh, const float* __restrict__ f1,
          const float* __restrict__ f2,
          const float* __restrict__ enc, const float* __restrict__ x,
          const float* __restrict__ hid,
          float* __restrict__ rnn, float* __restrict__ gi, float* __restrict__ gh,
          float* __restrict__ tbuf, float* __restrict__ out,
          const float* __restrict__ o2eb, const float* __restrict__ gbi,
          const float* __restrict__ gbh, const float* __restrict__ f1b,
          const float* __restrict__ f2b)
{
    int i = blockIdx.x * blockDim.x + threadIdx.x;
    if (i < W4N7) {
        if (i < W4N1)      do_split4_hi(W1,  i,        OFF_W1);
        else if (i < W4N2) do_split4_hi(W2,  i - W4N1, OFF_W2);
        else if (i < W4N3) do_split4_hi(o2e, i - W4N2, OFF_O2E);
        else if (i < W4N4) do_split4_hi(gwi, i - W4N3, OFF_GWI);
        else if (i < W4N5) do_split4_hi(gwh, i - W4N4, OFF_GWH);
        else if (i < W4N6) do_split4_hi(f1,  i - W4N5, OFF_F1);
        else               do_split4(f2,  i - W4N6, OFF_F2);
    } else if (i < PA3) {
        if (i < PA1)       do_split4_hi(enc, i - P_ACT0, OFF_ENC);
        else if (i < PA2)  do_split4(x,   i - PA1, OFF_X);
        else               do_split4(hid, i - PA2, OFF_HID);
    } else if (i < PB5) {
        int j = i - P_BIAS0;
        if (i < PB1) {
            rnn[(j >> 9) * 1536 + 1024 + (j & 511)] = o2eb[j & 511];
        } else if (i < PB2) {
            j -= 131072;  gi[j] = gbi[j % 3072];
        } else if (i < PB3) {
            j -= 917504;  gh[j] = gbh[j % 3072];
        } else if (i < PB4) {
            j -= 1703936; tbuf[j] = f1b[j & 511];
        } else {
            j -= 1835008; out[j] = f2b[j & 4095];
        }
    }
}

__global__ __launch_bounds__(256)
void f32_split_tanh(const float* __restrict__ in, __half* __restrict__ hi,
                    __half* __restrict__ lo, int n4)
{
    int i = blockIdx.x * blockDim.x + threadIdx.x;
    if (i >= n4) return;
    float4 v = ((const float4*)in)[i];
    v.x = tanhf(v.x); v.y = tanhf(v.y); v.z = tanhf(v.z); v.w = tanhf(v.w);
    __half h0 = __float2half_rn(v.x), h1 = __float2half_rn(v.y);
    __half h2 = __float2half_rn(v.z), h3 = __float2half_rn(v.w);
    __half2 hp0; hp0.x = h0; hp0.y = h1;
    __half2 hp1; hp1.x = h2; hp1.y = h3;
    __half2 lp0, lp1;
    lp0.x = __float2half_rn(v.x - __half2float(h0));
    lp0.y = __float2half_rn(v.y - __half2float(h1));
    lp1.x = __float2half_rn(v.z - __half2float(h2));
    lp1.y = __float2half_rn(v.w - __half2float(h3));
    ((__half2*)hi)[2 * i]     = hp0;
    ((__half2*)hi)[2 * i + 1] = hp1;
    ((__half2*)lo)[2 * i]     = lp0;
    ((__half2*)lo)[2 * i + 1] = lp1;
}

// ======================= 3-term split-K mma GEMM (fc2 only) ===============
#define ROWB      80
#define TILE_A_SB (128 * ROWB)
#define TILE_W_SB (64 * ROWB)
#define STAGE_SB  (2 * TILE_A_SB + 2 * TILE_W_SB)
#define GEMM_SMEM (2 * STAGE_SB + 512 + 32)

__global__ __launch_bounds__(256, 2)
void gemm64(const __half* __restrict__ Ah, const __half* __restrict__ Al,
            const __half* __restrict__ Wh, const __half* __restrict__ Wl,
            int K, int Kchunk, float* __restrict__ C, int ldc)
{
    extern __shared__ __align__(128) char smem[];
    const uint32_t sbase = (uint32_t)__cvta_generic_to_shared(smem);

    const int tid  = threadIdx.x;
    const int wid  = tid >> 5;
    const int lane = tid & 31;
    const int brow = blockIdx.y * 128;
    const int bcol = blockIdx.x * 64;
    const int k0   = blockIdx.z * Kchunk;
    const int m32  = (wid >> 1) * 32;
    const int n32w = (wid & 1) * 32;

    const int lrA = tid >> 1;
    const int cA  = (tid & 1) * 2;
    const int lrW = tid >> 2;
    const int cW  = tid & 3;
    const size_t aoff = (size_t)(brow + lrA) * K + k0;
    const size_t woff = (size_t)(bcol + lrW) * K + k0;

    auto load_stage = [&](int stage, int kk0) {
        const uint32_t sA = sbase + stage * STAGE_SB + lrA * ROWB;
        const uint32_t sW = sbase + stage * STAGE_SB + 2 * TILE_A_SB + lrW * ROWB;
        const char* pAh = (const char*)(Ah + aoff + kk0);
        const char* pAl = (const char*)(Al + aoff + kk0);
        const char* pWh = (const char*)(Wh + woff + kk0);
        const char* pWl = (const char*)(Wl + woff + kk0);
        #pragma unroll
        for (int c = cA; c < cA + 2; c++) {
            cp16(sA + c * 16, pAh + c * 16);
            cp16(sA + TILE_A_SB + c * 16, pAl + c * 16);
        }
        cp16(sW + cW * 16, pWh + cW * 16);
        cp16(sW + TILE_W_SB + cW * 16, pWl + cW * 16);
    };

    const int nk = Kchunk >> 5;

    load_stage(0, 0);
    asm volatile("cp.async.commit_group;");
    if (nk > 1) load_stage(1, 32);
    asm volatile("cp.async.commit_group;");

    float acc[2][4][4];
    #pragma unroll
    for (int i = 0; i < 2; i++)
        #pragma unroll
        for (int j = 0; j < 4; j++)
            #pragma unroll
            for (int q = 0; q < 4; q++) acc[i][j][q] = 0.f;

    const int arow_l = m32 + (lane & 15);
    const uint32_t akb = ((lane >> 4) & 1) * 16;
    const int nrow_l = n32w + (lane & 7) + ((lane >> 4) & 1) * 8;
    const uint32_t bkb = ((lane >> 3) & 1) * 16;

    for (int c = 0; c < nk; c++) {
        asm volatile("cp.async.wait_group %0;" :: "n"(1));
        __syncthreads();

        const uint32_t sb = sbase + (c & 1) * STAGE_SB;
        #pragma unroll
        for (int kk = 0; kk < 2; kk++) {
            const uint32_t kbyte = kk * 32;
            uint32_t afh[2][4], afl[2][4], bfh[4][2], bfl[4][2];
            #pragma unroll
            for (int mt = 0; mt < 2; mt++) {
                uint32_t ra = (uint32_t)((arow_l + mt * 16) * ROWB) + akb + kbyte;
                ldm4(afh[mt], sb + ra);
                ldm4(afl[mt], sb + TILE_A_SB + ra);
            }
            #pragma unroll
            for (int np = 0; np < 2; np++) {
                uint32_t rb = (uint32_t)((nrow_l + np * 16) * ROWB) + bkb + kbyte;
                uint32_t th[4], tl[4];
                ldm4(th, sb + 2 * TILE_A_SB + rb);
                ldm4(tl, sb + 2 * TILE_A_SB + TILE_W_SB + rb);
                bfh[2 * np][0] = th[0]; bfh[2 * np][1] = th[1];
                bfh[2 * np + 1][0] = th[2]; bfh[2 * np + 1][1] = th[3];
                bfl[2 * np][0] = tl[0]; bfl[2 * np][1] = tl[1];
                bfl[2 * np + 1][0] = tl[2]; bfl[2 * np + 1][1] = tl[3];
            }
            #pragma unroll
            for (int mt = 0; mt < 2; mt++)
                #pragma unroll
                for (int nt = 0; nt < 4; nt++) {
                    mma16816(acc[mt][nt], afh[mt], bfh[nt]);
                    mma16816(acc[mt][nt], afl[mt], bfh[nt]);
                    mma16816(acc[mt][nt], afh[mt], bfl[nt]);
                }
        }
        __syncthreads();

        if (c + 2 < nk) load_stage(c & 1, (c + 2) * 32);
        asm volatile("cp.async.commit_group;");
    }

    const int rloc0 = m32 + (lane >> 2);
    const int cloc0 = n32w + (lane & 3) * 2;
    #pragma unroll
    for (int mt = 0; mt < 2; mt++) {
        const int r0 = brow + rloc0 + mt * 16;
        #pragma unroll
        for (int nt = 0; nt < 4; nt++) {
            const int col = bcol + cloc0 + nt * 8;
            float* c0 = C + (size_t)r0 * ldc + col;
            float* c1 = C + (size_t)(r0 + 8) * ldc + col;
            atomicAdd(c0,     acc[mt][nt][0]);
            atomicAdd(c0 + 1, acc[mt][nt][1]);
            atomicAdd(c1,     acc[mt][nt][2]);
            atomicAdd(c1 + 1, acc[mt][nt][3]);
        }
    }
}

// ====== 2-term GEMM core: 3 stages, single sync; bias-store or atomic =====
#define STAGE2_SB (2 * TILE_A_SB + TILE_W_SB)
#define GEMM2_SMEM (3 * STAGE2_SB + 512 + 32)

__device__ __forceinline__ void gemm2_core(
    const __half* __restrict__ Ah, const __half* __restrict__ Al,
    const __half* __restrict__ Wh,
    int K, int Kchunk, int brow, int bcol, int k0,
    float* __restrict__ C, int ldc,
    const float* __restrict__ b1, const float* __restrict__ b2,
    uint32_t sbase)
{
    const int tid  = threadIdx.x;
    const int wid  = tid >> 5;
    const int lane = tid & 31;
    const int m32  = (wid >> 1) * 32;
    const int n32w = (wid & 1) * 32;

    const int lrA = tid >> 1;
    const int cA  = (tid & 1) * 2;
    const int lrW = tid >> 2;
    const int cW  = tid & 3;
    const size_t aoff = (size_t)(brow + lrA) * K + k0;
    const size_t woff = (size_t)(bcol + lrW) * K + k0;

    auto load_stage = [&](int stage, int kk0) {
        const uint32_t sA = sbase + stage * STAGE2_SB + lrA * ROWB;
        const uint32_t sW = sbase + stage * STAGE2_SB + 2 * TILE_A_SB + lrW * ROWB;
        const char* pAh = (const char*)(Ah + aoff + kk0);
        const char* pAl = (const char*)(Al + aoff + kk0);
        const char* pWh = (const char*)(Wh + woff + kk0);
        #pragma unroll
        for (int c = cA; c < cA + 2; c++) {
            cp16(sA + c * 16, pAh + c * 16);
            cp16(sA + TILE_A_SB + c * 16, pAl + c * 16);
        }
        cp16(sW + cW * 16, pWh + cW * 16);
    };

    const int nk = Kchunk >> 5;

    load_stage(0, 0);
    asm volatile("cp.async.commit_group;");
    if (nk > 1) load_stage(1, 32);
    asm volatile("cp.async.commit_group;");

    float acc[2][4][4];
    #pragma unroll
    for (int i = 0; i < 2; i++)
        #pragma unroll
        for (int j = 0; j < 4; j++)
            #pragma unroll
            for (int q = 0; q < 4; q++) acc[i][j][q] = 0.f;

    const int arow_l = m32 + (lane & 15);
    const uint32_t akb = ((lane >> 4) & 1) * 16;
    const int nrow_l = n32w + (lane & 7) + ((lane >> 4) & 1) * 8;
    const uint32_t bkb = ((lane >> 3) & 1) * 16;

    int stage = 0;
    for (int c = 0; c < nk; c++) {
        asm volatile("cp.async.wait_group %0;" :: "n"(1));
        __syncthreads();

        if (c + 2 < nk) {
            int s2 = stage + 2; if (s2 >= 3) s2 -= 3;
            load_stage(s2, (c + 2) * 32);
        }
        asm volatile("cp.async.commit_group;");

        const uint32_t sb = sbase + stage * STAGE2_SB;
        #pragma unroll
        for (int kk = 0; kk < 2; kk++) {
            const uint32_t kbyte = kk * 32;
            uint32_t afh[2][4], afl[2][4], bfh[4][2];
            #pragma unroll
            for (int mt = 0; mt < 2; mt++) {
                uint32_t ra = (uint32_t)((arow_l + mt * 16) * ROWB) + akb + kbyte;
                ldm4(afh[mt], sb + ra);
                ldm4(afl[mt], sb + TILE_A_SB + ra);
            }
            #pragma unroll
            for (int np = 0; np < 2; np++) {
                uint32_t rb = (uint32_t)((nrow_l + np * 16) * ROWB) + bkb + kbyte;
                uint32_t th[4];
                ldm4(th, sb + 2 * TILE_A_SB + rb);
                bfh[2 * np][0] = th[0]; bfh[2 * np][1] = th[1];
                bfh[2 * np + 1][0] = th[2]; bfh[2 * np + 1][1] = th[3];
            }
            #pragma unroll
            for (int mt = 0; mt < 2; mt++)
                #pragma unroll
                for (int nt = 0; nt < 4; nt++) {
                    mma16816(acc[mt][nt], afh[mt], bfh[nt]);
                    mma16816(acc[mt][nt], afl[mt], bfh[nt]);
                }
        }
        if (++stage >= 3) stage = 0;
    }

    const int rloc0 = m32 + (lane >> 2);
    const int cloc0 = n32w + (lane & 3) * 2;
    if (b1) {
        #pragma unroll
        for (int mt = 0; mt < 2; mt++) {
            const int r0 = brow + rloc0 + mt * 16;
            #pragma unroll
            for (int nt = 0; nt < 4; nt++) {
                const int col = bcol + cloc0 + nt * 8;
                float2 bb = make_float2(b1[col] + b2[col], b1[col + 1] + b2[col + 1]);
                *(float2*)(C + (size_t)r0 * ldc + col) =
                    make_float2(acc[mt][nt][0] + bb.x, acc[mt][nt][1] + bb.y);
                *(float2*)(C + (size_t)(r0 + 8) * ldc + col) =
                    make_float2(acc[mt][nt][2] + bb.x, acc[mt][nt][3] + bb.y);
            }
        }
    } else {
        #pragma unroll
        for (int mt = 0; mt < 2; mt++) {
            const int r0 = brow + rloc0 + mt * 16;
            #pragma unroll
            for (int nt = 0; nt < 4; nt++) {
                const int col = bcol + cloc0 + nt * 8;
                float* c0 = C + (size_t)r0 * ldc + col;
                float* c1 = C + (size_t)(r0 + 8) * ldc + col;
                atomicAdd(c0,     acc[mt][nt][0]);
                atomicAdd(c0 + 1, acc[mt][nt][1]);
                atomicAdd(c1,     acc[mt][nt][2]);
                atomicAdd(c1 + 1, acc[mt][nt][3]);
            }
        }
    }
}

// standalone 2-term split-K GEMM (gi, fc1)
__global__ __launch_bounds__(256, 2)
void gemm64b(const __half* __restrict__ Ah, const __half* __restrict__ Al,
             const __half* __restrict__ Wh,
             int K, int Kchunk, float* __restrict__ C, int ldc)
{
    extern __shared__ __align__(128) char smem[];
    const uint32_t sbase = (uint32_t)__cvta_generic_to_shared(smem);
    gemm2_core(Ah, Al, Wh, K, Kchunk,
               blockIdx.y * 128, blockIdx.x * 64, blockIdx.z * Kchunk,
               C, ldc, nullptr, nullptr, sbase);
}

// ===== fused3: g1 (32 blk, bias-store) | x_emb (128 blk) | gh (192 blk) ===
__global__ __launch_bounds__(256, 2)
void fused3(const __half* __restrict__ hidh, const __half* __restrict__ hidl,
            const __half* __restrict__ w2h,
            const __half* __restrict__ xh, const __half* __restrict__ xl,
            const __half* __restrict__ o2eh,
            const __half* __restrict__ gwhh,
            float* __restrict__ g1, float* __restrict__ rnn_xemb,
            float* __restrict__ gh,
            const float* __restrict__ w2b, const float* __restrict__ w1b)
{
    extern __shared__ __align__(128) char smem[];
    const uint32_t sbase = (uint32_t)__cvta_generic_to_shared(smem);
    const int ib = blockIdx.x;
    if (ib < 32) {
        // g1: grid (16,2), K=1024, full-K, bias-store
        int bx = ib & 15, by = ib >> 4;
        gemm2_core(hidh, hidl, w2h, 1024, 1024, by * 128, bx * 64, 0,
                   g1, 1024, w2b, w1b, sbase);
    } else if (ib < 160) {
        // x_emb: grid (8,2,8), K=4096, Kchunk=512, atomic
        int j = ib - 32;
        int bx = j & 7, by = (j >> 3) & 1, bz = j >> 4;
        gemm2_core(xh, xl, o2eh, 4096, 512, by * 128, bx * 64, bz * 512,
                   rnn_xemb, 1536, nullptr, nullptr, sbase);
    } else {
        // gh: grid (48,2,2), K=1024, Kchunk=512, atomic
        int j = ib - 160;
        int bx = j % 48, by = (j / 48) & 1, bz = j / 96;
        gemm2_core(hidh, hidl, gwhh, 1024, 512, by * 128, bx * 64, bz * 512,
                   gh, 3072, nullptr, nullptr, sbase);
    }
}

// ======= score GEMM v3: 128x128 tile, BK=64, 3 stages, warp 64x32 =========
#define SC_ROWB   144
#define SC_A_SB   (128 * SC_ROWB)
#define SC_W_SB   (128 * SC_ROWB)
#define SC_STAGE  (SC_A_SB + SC_W_SB)
#define SC_NST    3
#define SC_SMEM   (SC_NST * SC_STAGE + 512 + 32)

__global__ __launch_bounds__(256, 2)
void score_gemm(const __half* __restrict__ Ah, const __half* __restrict__ Wh,
                const float* __restrict__ g1, const float* __restrict__ vw,
                float* __restrict__ partial)
{
    extern __shared__ __align__(128) char smem[];
    const uint32_t sbase = (uint32_t)__cvta_generic_to_shared(smem);
    float* part_sm = (float*)(smem + SC_NST * SC_STAGE);

    const int tid  = threadIdx.x;
    const int wid  = tid >> 5;
    const int lane = tid & 31;
    const int brow = blockIdx.y * 128;
    const int bcol = blockIdx.x * 128;
    const int m64  = (wid >> 2) * 64;
    const int n32  = (wid & 3) * 32;
    const int K    = 1024;

    if (tid < 128) part_sm[tid] = 0.f;

    const int arow = tid >> 1;
    const int acb_ld = (tid & 1) * 4;
    const __half* gA = Ah + (size_t)(brow + arow) * K;
    const __half* gW = Wh + (size_t)(bcol + arow) * K;
    const uint32_t sA_ld = (uint32_t)(arow * SC_ROWB + acb_ld * 16);
    const uint32_t sW_ld = (uint32_t)(SC_A_SB + arow * SC_ROWB + acb_ld * 16);

    auto load_stage = [&](int stage, int k0) {
        const uint32_t sb = sbase + stage * SC_STAGE;
        const char* pA = (const char*)(gA + k0) + acb_ld * 16;
        const char* pW = (const char*)(gW + k0) + acb_ld * 16;
        #pragma unroll
        for (int c = 0; c < 4; c++) {
            cp16(sb + sA_ld + c * 16, pA + c * 16);
            cp16(sb + sW_ld + c * 16, pW + c * 16);
        }
    };

    const int nk = 16;

    load_stage(0, 0);
    asm volatile("cp.async.commit_group;");
    load_stage(1, 64);
    asm volatile("cp.async.commit_group;");

    float acc[4][4][4];
    #pragma unroll
    for (int i = 0; i < 4; i++)
        #pragma unroll
        for (int j = 0; j < 4; j++)
            #pragma unroll
            for (int q = 0; q < 4; q++) acc[i][j][q] = 0.f;

    const int arow_l = m64 + (lane & 15);
    const uint32_t akb = ((lane >> 4) & 1) * 16;
    const int nrow_l = n32 + (lane & 7) + ((lane >> 4) & 1) * 8;
    const uint32_t bkb = ((lane >> 3) & 1) * 16;

    int stage = 0;
    for (int c = 0; c < nk; c++) {
        asm volatile("cp.async.wait_group %0;" :: "n"(1));
        __syncthreads();

        if (c + 2 < nk) {
            int s2 = stage + 2; if (s2 >= SC_NST) s2 -= SC_NST;
            load_stage(s2, (c + 2) * 64);
        }
        asm volatile("cp.async.commit_group;");

        const uint32_t sb = sbase + stage * SC_STAGE;
        #pragma unroll
        for (int kk = 0; kk < 4; kk++) {
            const uint32_t kbyte = kk * 32;
            uint32_t bfh[4][2];
            #pragma unroll
            for (int np = 0; np < 2; np++) {
                uint32_t rb = (uint32_t)((nrow_l + np * 16) * SC_ROWB) + bkb + kbyte;
                uint32_t th[4];
                ldm4(th, sb + SC_A_SB + rb);
                bfh[2 * np][0] = th[0]; bfh[2 * np][1] = th[1];
                bfh[2 * np + 1][0] = th[2]; bfh[2 * np + 1][1] = th[3];
            }
            #pragma unroll
            for (int mt = 0; mt < 4; mt++) {
                uint32_t afh[4];
                uint32_t ra = (uint32_t)((arow_l + mt * 16) * SC_ROWB) + akb + kbyte;
                ldm4(afh, sb + ra);
                #pragma unroll
                for (int nt = 0; nt < 4; nt++)
                    mma16816(acc[mt][nt], afh, bfh[nt]);
            }
        }
        if (++stage >= SC_NST) stage = 0;
    }

    const int rloc0 = m64 + (lane >> 2);
    const int cloc0 = n32 + (lane & 3) * 2;
    const float* g1r = g1 + (size_t)blockIdx.y * 1024;
    #pragma unroll
    for (int mt = 0; mt < 4; mt++) {
        float s0 = 0.f, s1 = 0.f;
        #pragma unroll
        for (int nt = 0; nt < 4; nt++) {
            int col = bcol + cloc0 + nt * 8;
            float gw0 = g1r[col],     vw0 = vw[col];
            float gw1 = g1r[col + 1], vw1 = vw[col + 1];
            s0 += tanhf(acc[mt][nt][0] + gw0) * vw0;
            s0 += tanhf(acc[mt][nt][1] + gw1) * vw1;
            s1 += tanhf(acc[mt][nt][2] + gw0) * vw0;
            s1 += tanhf(acc[mt][nt][3] + gw1) * vw1;
        }
        atomicAdd(&part_sm[rloc0 + mt * 16], s0);
        atomicAdd(&part_sm[rloc0 + mt * 16 + 8], s1);
    }
    __syncthreads();
    if (tid < 128)
        partial[(size_t)(brow + tid) * gridDim.x + blockIdx.x] = part_sm[tid];
}

// ==== attn_fused: softmax+ctx (blocks 0..255) | split_xemb (256..383) =====
__global__ __launch_bounds__(256)
void attn_fused(const float* __restrict__ part, int npart,
                const __half* __restrict__ ench,
                const float* __restrict__ Vb,
                float* __restrict__ attn_out,
                const float* __restrict__ rnn)
{
    const int tid = threadIdx.x;
    if (blockIdx.x >= BB) {
        // split_xemb: 128 blocks x 256 threads, 1 float4 unit each
        int i = (blockIdx.x - BB) * 256 + tid;          // 0..32767
        int row = i >> 7;
        int c4  = i & 127;
        size_t off = (size_t)row * 1536 + 1024 + c4 * 4;
        float4 v = *(const float4*)(rnn + off);
        __half h0 = __float2half_rn(v.x), h1 = __float2half_rn(v.y);
        __half h2 = __float2half_rn(v.z), h3 = __float2half_rn(v.w);
        __half2 hp0; hp0.x = h0; hp0.y = h1;
        __half2 hp1; hp1.x = h2; hp1.y = h3;
        __half2 lp0, lp1;
        lp0.x = __float2half_rn(v.x - __half2float(h0));
        lp0.y = __float2half_rn(v.y - __half2float(h1));
        lp1.x = __float2half_rn(v.z - __half2float(h2));
        lp1.y = __float2half_rn(v.w - __half2float(h3));
        *(__half2*)(g_bh + OFF_RNN + off)     = hp0;
        *(__half2*)(g_bh + OFF_RNN + off + 2) = hp1;
        *(__half2*)(g_bl + OFF_RNN + off)     = lp0;
        *(__half2*)(g_bl + OFF_RNN + off + 2) = lp1;
        return;
    }

    const int b = blockIdx.x;
    __shared__ float logit[LL];

    if (tid < LL) {
        const float* pr = part + (size_t)(b * LL + tid) * npart;
        float s = Vb[0];
        for (int j = 0; j < npart; j++) s += pr[j];
        logit[tid] = s;
    }
    __syncthreads();

    if (tid < 32) {
        const int lane = tid;
        float m = -1e30f;
        for (int l = lane; l < LL; l += 32) m = fmaxf(m, logit[l]);
        #pragma unroll
        for (int o = 16; o; o >>= 1) m = fmaxf(m, __shfl_xor_sync(0xffffffffu, m, o));
        float s = 0.f;
        for (int l = lane; l < LL; l += 32) {
            float e = expf(logit[l] - m);
            logit[l] = e;
            s += e;
        }
        #pragma unroll
        for (int o = 16; o; o >>= 1) s += __shfl_xor_sync(0xffffffffu, s, o);
        float inv = 1.f / s;
        for (int l = lane; l < LL; l += 32) logit[l] *= inv;
    }
    __syncthreads();

    if (tid < LL) attn_out[b * LL + tid] = logit[tid];

    float4 acc = make_float4(0.f, 0.f, 0.f, 0.f);
    const __half2* encb = (const __half2*)(ench + (size_t)b * LL * EENC) + tid * 2;
    #pragma unroll 4
    for (int l = 0; l < LL; l++) {
        float a = logit[l];
        __half2 v0 = encb[l * (EENC / 2)];
        __half2 v1 = encb[l * (EENC / 2) + 1];
        float2 f0 = __half22float2(v0);
        float2 f1 = __half22float2(v1);
        acc.x += a * f0.x; acc.y += a * f0.y;
        acc.z += a * f1.x; acc.w += a * f1.y;
    }
    size_t off = (size_t)b * 1536 + tid * 4;
    __half h0 = __float2half_rn(acc.x), h1 = __float2half_rn(acc.y);
    __half h2 = __float2half_rn(acc.z), h3 = __float2half_rn(acc.w);
    __half2 hp0; hp0.x = h0; hp0.y = h1;
    __half2 hp1; hp1.x = h2; hp1.y = h3;
    __half2 lp0, lp1;
    lp0.x = __float2half_rn(acc.x - __half2float(h0));
    lp0.y = __float2half_rn(acc.y - __half2float(h1));
    lp1.x = __float2half_rn(acc.z - __half2float(h2));
    lp1.y = __float2half_rn(acc.w - __half2float(h3));
    *(__half2*)(g_bh + OFF_RNN + off)     = hp0;
    *(__half2*)(g_bh + OFF_RNN + off + 2) = hp1;
    *(__half2*)(g_bl + OFF_RNN + off)     = lp0;
    *(__half2*)(g_bl + OFF_RNN + off + 2) = lp1;
}

// ======== GRU gates; writes hnew + fp16 hi/lo splits (fused) ==============
__global__ __launch_bounds__(256)
void gru_gate(const float* __restrict__ gi, const float* __restrict__ gh,
              const float* __restrict__ h0, float* __restrict__ hnew)
{
    const int i = blockIdx.x * blockDim.x + threadIdx.x;
    const int idx = i * 2;
    const int b = idx >> 10;
    const int d = idx & 1023;
    const float* gib = gi + (size_t)b * 3072;
    const float* ghb = gh + (size_t)b * 3072;
    float h_out[2];
    #pragma unroll
    for (int u = 0; u < 2; u++) {
        int dd = d + u;
        float r = 1.f / (1.f + expf(-(gib[dd] + ghb[dd])));
        float z = 1.f / (1.f + expf(-(gib[1024 + dd] + ghb[1024 + dd])));
        float n = tanhf(gib[2048 + dd] + r * ghb[2048 + dd]);
        h_out[u] = (1.f - z) * n + z * h0[idx + u];
    }
    *(float2*)(hnew + idx) = make_float2(h_out[0], h_out[1]);
    __half hh0 = __float2half_rn(h_out[0]);
    __half hh1 = __float2half_rn(h_out[1]);
    __half2 hp; hp.x = hh0; hp.y = hh1;
    __half2 lp;
    lp.x = __float2half_rn(h_out[0] - __half2float(hh0));
    lp.y = __float2half_rn(h_out[1] - __half2float(hh1));
    ((__half2*)(g_bh + OFF_HNEW))[i] = hp;
    ((__half2*)(g_bl + OFF_HNEW))[i] = lp;
}

// ============================ launch ======================================
extern "C" void kernel_launch(void* const* d_in, const int* in_sizes, int n_in,
                              void* d_out, int out_size)
{
    (void)in_sizes; (void)n_in; (void)out_size;

    const float* x      = (const float*)d_in[0];
    const float* hidden = (const float*)d_in[1];
    const float* enc    = (const float*)d_in[2];
    const float* W1_w   = (const float*)d_in[3];
    const float* W1_b   = (const float*)d_in[4];
    const float* W2_w   = (const float*)d_in[5];
    const float* W2_b   = (const float*)d_in[6];
    const float* V_w    = (const float*)d_in[7];
    const float* V_b    = (const float*)d_in[8];
    const float* o2e_w  = (const float*)d_in[9];
    const float* o2e_b  = (const float*)d_in[10];
    const float* gwi    = (const float*)d_in[11];
    const float* gwh    = (const float*)d_in[12];
    const float* gbi    = (const float*)d_in[13];
    const float* gbh    = (const float*)d_in[14];
    const float* f1w    = (const float*)d_in[15];
    const float* f1b    = (const float*)d_in[16];
    const float* f2w    = (const float*)d_in[17];
    const float* f2b    = (const float*)d_in[18];

    float* out  = (float*)d_out;
    float* hnew = out + (size_t)BB * VOC;
    float* attn = hnew + (size_t)BB * DDEC;

    __half* bh = nullptr;
    __half* bl = nullptr;
    float* fs = nullptr;
    cudaGetSymbolAddress((void**)&bh, g_bh);
    cudaGetSymbolAddress((void**)&bl, g_bl);
    cudaGetSymbolAddress((void**)&fs, g_f32);

    float* g1   = fs + F_G1;
    float* rnn  = fs + F_RNN;
    float* gi   = fs + F_GI;
    float* gh   = fs + F_GH;
    float* tbuf = fs + F_T;
    float* part = fs + F_PART;

    cudaFuncSetAttribute(gemm64,     cudaFuncAttributeMaxDynamicSharedMemorySize, GEMM_SMEM);
    cudaFuncSetAttribute(gemm64b,    cudaFuncAttributeMaxDynamicSharedMemorySize, GEMM2_SMEM);
    cudaFuncSetAttribute(fused3,     cudaFuncAttributeMaxDynamicSharedMemorySize, GEMM2_SMEM);
    cudaFuncSetAttribute(score_gemm, cudaFuncAttributeMaxDynamicSharedMemorySize, SC_SMEM);

    dim3 blk(256);

    // 0) prep: all input splits + bias pre-init
    prep<<<PREP_TOTAL / 256, 256>>>(W1_w, W2_w, o2e_w, gwi, gwh, f1w, f2w,
                                    enc, x, hidden,
                                    rnn, gi, gh, tbuf, out,
                                    o2e_b, gbi, gbh, f1b, f2b);

    // 1) fused3: g1 | x_emb | gh  (352 blocks, one launch)
    fused3<<<352, blk, GEMM2_SMEM>>>(
        bh + OFF_HID, bl + OFF_HID, bh + OFF_W2,
        bh + OFF_X, bl + OFF_X, bh + OFF_O2E,
        bh + OFF_GWH,
        g1, rnn + 1024, gh, W2_b, W1_b);

    // 2) score GEMM
    score_gemm<<<dim3(8, 256), blk, SC_SMEM>>>(
        bh + OFF_ENC, bh + OFF_W1, g1, V_w, part);

    // 3) attn_fused: softmax+ctx | split_xemb  (384 blocks)
    attn_fused<<<BB + 128, 256>>>(part, 8, bh + OFF_ENC, V_b, attn, rnn);

    // 4) gi += rnn_in @ gru_wi^T    (2-term, splitK=2)
    gemm64b<<<dim3(48, 2, 2), blk, GEMM2_SMEM>>>(
        bh + OFF_RNN, bl + OFF_RNN, bh + OFF_GWI,
        1536, 768, gi, 3072);

    // 5) GRU gates -> h_new (+ fused fp16 split)
    gru_gate<<<131072 / 256, 256>>>(gi, gh, hidden, hnew);

    // 6) tbuf += h_new @ fc1^T      (2-term, splitK=8)
    gemm64b<<<dim3(8, 2, 8), blk, GEMM2_SMEM>>>(
        bh + OFF_HNEW, bl + OFF_HNEW, bh + OFF_F1,
        1024, 128, tbuf, 512);

    // 7) t = tanh(tbuf) -> fp16
    f32_split_tanh<<<(131072 / 4) / 256, 256>>>(tbuf, bh + OFF_T, bl + OFF_T, 131072 / 4);

    // 8) out += t @ fc2^T           (3-term, splitK=2; direct output path)
    gemm64<<<dim3(64, 2, 2), blk, GEMM_SMEM>>>(
        bh + OFF_T, bl + OFF_T, bh + OFF_F2, bl + OFF_F2,
        512, 256, out, 4096);
}

// round 16
// speedup vs baseline: 2.1851x; 1.0090x over previous
#include <cuda_runtime.h>
#include <cuda_fp16.h>
#include <cstdint>
#include <math.h>

// Problem dims
#define BB   256
#define LL   128
#define VOC  4096
#define EENC 1024
#define DDEC 1024
#define EEMB 512

// ======================= scratch (module-load allocated) ==================
#define OFF_ENC   0ull
#define OFF_W1    (OFF_ENC + 33554432ull)
#define OFF_W2    (OFF_W1  + 1048576ull)
#define OFF_O2E   (OFF_W2  + 1048576ull)
#define OFF_GWI   (OFF_O2E + 2097152ull)
#define OFF_GWH   (OFF_GWI + 4718592ull)
#define OFF_F1    (OFF_GWH + 3145728ull)
#define OFF_F2    (OFF_F1  + 524288ull)
#define OFF_X     (OFF_F2  + 2097152ull)
#define OFF_HID   (OFF_X   + 1048576ull)
#define OFF_RNN   (OFF_HID + 262144ull)
#define OFF_HNEW  (OFF_RNN + 393216ull)
#define OFF_T     (OFF_HNEW+ 262144ull)
#define BF_TOTAL  (OFF_T   + 131072ull)

__device__ __half g_bh[BF_TOTAL];
__device__ __half g_bl[BF_TOTAL];

#define F_G1    0ull
#define F_RNN   (F_G1   + 262144ull)
#define F_GI    (F_RNN  + 393216ull)
#define F_GH    (F_GI   + 786432ull)
#define F_T     (F_GH   + 786432ull)
#define F_PART  (F_T    + 131072ull)
#define F_TOTAL (F_PART + 524288ull)

__device__ float g_f32[F_TOTAL];

// ======================= small helpers ====================================
__device__ __forceinline__ void cp16(uint32_t s, const void* g) {
    asm volatile("cp.async.cg.shared.global [%0], [%1], 16;"
                 :: "r"(s), "l"(__cvta_generic_to_global(g)));
}
__device__ __forceinline__ void ldm4(uint32_t* r, uint32_t addr) {
    asm volatile("ldmatrix.sync.aligned.m8n8.x4.shared.b16 {%0,%1,%2,%3}, [%4];"
        : "=r"(r[0]), "=r"(r[1]), "=r"(r[2]), "=r"(r[3]) : "r"(addr));
}
__device__ __forceinline__ void mma16816(float* c, const uint32_t* a, const uint32_t* b) {
    asm volatile("mma.sync.aligned.m16n8k16.row.col.f32.f16.f16.f32 "
        "{%0,%1,%2,%3}, {%4,%5,%6,%7}, {%8,%9}, {%0,%1,%2,%3};"
        : "+f"(c[0]), "+f"(c[1]), "+f"(c[2]), "+f"(c[3])
        : "r"(a[0]), "r"(a[1]), "r"(a[2]), "r"(a[3]), "r"(b[0]), "r"(b[1]));
}
__device__ __forceinline__ void do_split4(const float* __restrict__ src, int i,
                                          unsigned long long dst) {
    float4 v = ((const float4*)src)[i];
    __half h0 = __float2half_rn(v.x), h1 = __float2half_rn(v.y);
    __half h2 = __float2half_rn(v.z), h3 = __float2half_rn(v.w);
    __half2 hp0; hp0.x = h0; hp0.y = h1;
    __half2 hp1; hp1.x = h2; hp1.y = h3;
    __half2 lp0, lp1;
    lp0.x = __float2half_rn(v.x - __half2float(h0));
    lp0.y = __float2half_rn(v.y - __half2float(h1));
    lp1.x = __float2half_rn(v.z - __half2float(h2));
    lp1.y = __float2half_rn(v.w - __half2float(h3));
    ((__half2*)(g_bh + dst))[2 * i]     = hp0;
    ((__half2*)(g_bh + dst))[2 * i + 1] = hp1;
    ((__half2*)(g_bl + dst))[2 * i]     = lp0;
    ((__half2*)(g_bl + dst))[2 * i + 1] = lp1;
}
__device__ __forceinline__ void do_split4_hi(const float* __restrict__ src, int i,
                                             unsigned long long dst) {
    float4 v = ((const float4*)src)[i];
    __half2 hp0, hp1;
    hp0.x = __float2half_rn(v.x); hp0.y = __float2half_rn(v.y);
    hp1.x = __float2half_rn(v.z); hp1.y = __float2half_rn(v.w);
    ((__half2*)(g_bh + dst))[2 * i]     = hp0;
    ((__half2*)(g_bh + dst))[2 * i + 1] = hp1;
}

// ================= prep: all input splits + bias pre-init, one kernel =====
#define W4N1 262144
#define W4N2 524288
#define W4N3 1048576
#define W4N4 2228224
#define W4N5 3014656
#define W4N6 3145728
#define W4N7 3670016
#define P_ACT0 3670016
#define PA1 (P_ACT0 + 8388608)
#define PA2 (P_ACT0 + 8650752)
#define PA3 (P_ACT0 + 8716288)
#define P_BIAS0 12386304
#define PB1 (P_BIAS0 + 131072)
#define PB2 (P_BIAS0 + 917504)
#define PB3 (P_BIAS0 + 1703936)
#define PB4 (P_BIAS0 + 1835008)
#define PB5 (P_BIAS0 + 2883584)
#define PREP_TOTAL PB5

__global__ __launch_bounds__(256)
void prep(const float* __restrict__ W1, const float* __restrict__ W2,
          const float* __restrict__ o2e, const float* __restrict__ gwi,
          const float* __restrict__ gwh, const float* __restrict__ f1,
          const float* __restrict__ f2,
          const float* __restrict__ enc, const float* __restrict__ x,
          const float* __restrict__ hid,
          float* __restrict__ rnn, float* __restrict__ gi, float* __restrict__ gh,
          float* __restrict__ tbuf, float* __restrict__ out,
          const float* __restrict__ o2eb, const float* __restrict__ gbi,
          const float* __restrict__ gbh, const float* __restrict__ f1b,
          const float* __restrict__ f2b)
{
    int i = blockIdx.x * blockDim.x + threadIdx.x;
    if (i < W4N7) {
        if (i < W4N1)      do_split4_hi(W1,  i,        OFF_W1);
        else if (i < W4N2) do_split4_hi(W2,  i - W4N1, OFF_W2);
        else if (i < W4N3) do_split4_hi(o2e, i - W4N2, OFF_O2E);
        else if (i < W4N4) do_split4_hi(gwi, i - W4N3, OFF_GWI);
        else if (i < W4N5) do_split4_hi(gwh, i - W4N4, OFF_GWH);
        else if (i < W4N6) do_split4_hi(f1,  i - W4N5, OFF_F1);
        else               do_split4(f2,  i - W4N6, OFF_F2);
    } else if (i < PA3) {
        if (i < PA1)       do_split4_hi(enc, i - P_ACT0, OFF_ENC);
        else if (i < PA2)  do_split4(x,   i - PA1, OFF_X);
        else               do_split4(hid, i - PA2, OFF_HID);
    } else if (i < PB5) {
        int j = i - P_BIAS0;
        if (i < PB1) {
            rnn[(j >> 9) * 1536 + 1024 + (j & 511)] = o2eb[j & 511];
        } else if (i < PB2) {
            j -= 131072;  gi[j] = gbi[j % 3072];
        } else if (i < PB3) {
            j -= 917504;  gh[j] = gbh[j % 3072];
        } else if (i < PB4) {
            j -= 1703936; tbuf[j] = f1b[j & 511];
        } else {
            j -= 1835008; out[j] = f2b[j & 4095];
        }
    }
}

__global__ __launch_bounds__(256)
void f32_split_tanh(const float* __restrict__ in, __half* __restrict__ hi,
                    __half* __restrict__ lo, int n4)
{
    int i = blockIdx.x * blockDim.x + threadIdx.x;
    if (i >= n4) return;
    float4 v = ((const float4*)in)[i];
    v.x = tanhf(v.x); v.y = tanhf(v.y); v.z = tanhf(v.z); v.w = tanhf(v.w);
    __half h0 = __float2half_rn(v.x), h1 = __float2half_rn(v.y);
    __half h2 = __float2half_rn(v.z), h3 = __float2half_rn(v.w);
    __half2 hp0; hp0.x = h0; hp0.y = h1;
    __half2 hp1; hp1.x = h2; hp1.y = h3;
    __half2 lp0, lp1;
    lp0.x = __float2half_rn(v.x - __half2float(h0));
    lp0.y = __float2half_rn(v.y - __half2float(h1));
    lp1.x = __float2half_rn(v.z - __half2float(h2));
    lp1.y = __float2half_rn(v.w - __half2float(h3));
    ((__half2*)hi)[2 * i]     = hp0;
    ((__half2*)hi)[2 * i + 1] = hp1;
    ((__half2*)lo)[2 * i]     = lp0;
    ((__half2*)lo)[2 * i + 1] = lp1;
}

// ======================= 3-term split-K mma GEMM (fc2 only) ===============
#define ROWB      80
#define TILE_A_SB (128 * ROWB)
#define TILE_W_SB (64 * ROWB)
#define STAGE_SB  (2 * TILE_A_SB + 2 * TILE_W_SB)
#define GEMM_SMEM (2 * STAGE_SB + 512 + 32)

__global__ __launch_bounds__(256, 2)
void gemm64(const __half* __restrict__ Ah, const __half* __restrict__ Al,
            const __half* __restrict__ Wh, const __half* __restrict__ Wl,
            int K, int Kchunk, float* __restrict__ C, int ldc)
{
    extern __shared__ __align__(128) char smem[];
    const uint32_t sbase = (uint32_t)__cvta_generic_to_shared(smem);

    const int tid  = threadIdx.x;
    const int wid  = tid >> 5;
    const int lane = tid & 31;
    const int brow = blockIdx.y * 128;
    const int bcol = blockIdx.x * 64;
    const int k0   = blockIdx.z * Kchunk;
    const int m32  = (wid >> 1) * 32;
    const int n32w = (wid & 1) * 32;

    const int lrA = tid >> 1;
    const int cA  = (tid & 1) * 2;
    const int lrW = tid >> 2;
    const int cW  = tid & 3;
    const size_t aoff = (size_t)(brow + lrA) * K + k0;
    const size_t woff = (size_t)(bcol + lrW) * K + k0;

    auto load_stage = [&](int stage, int kk0) {
        const uint32_t sA = sbase + stage * STAGE_SB + lrA * ROWB;
        const uint32_t sW = sbase + stage * STAGE_SB + 2 * TILE_A_SB + lrW * ROWB;
        const char* pAh = (const char*)(Ah + aoff + kk0);
        const char* pAl = (const char*)(Al + aoff + kk0);
        const char* pWh = (const char*)(Wh + woff + kk0);
        const char* pWl = (const char*)(Wl + woff + kk0);
        #pragma unroll
        for (int c = cA; c < cA + 2; c++) {
            cp16(sA + c * 16, pAh + c * 16);
            cp16(sA + TILE_A_SB + c * 16, pAl + c * 16);
        }
        cp16(sW + cW * 16, pWh + cW * 16);
        cp16(sW + TILE_W_SB + cW * 16, pWl + cW * 16);
    };

    const int nk = Kchunk >> 5;

    load_stage(0, 0);
    asm volatile("cp.async.commit_group;");
    if (nk > 1) load_stage(1, 32);
    asm volatile("cp.async.commit_group;");

    float acc[2][4][4];
    #pragma unroll
    for (int i = 0; i < 2; i++)
        #pragma unroll
        for (int j = 0; j < 4; j++)
            #pragma unroll
            for (int q = 0; q < 4; q++) acc[i][j][q] = 0.f;

    const int arow_l = m32 + (lane & 15);
    const uint32_t akb = ((lane >> 4) & 1) * 16;
    const int nrow_l = n32w + (lane & 7) + ((lane >> 4) & 1) * 8;
    const uint32_t bkb = ((lane >> 3) & 1) * 16;

    for (int c = 0; c < nk; c++) {
        asm volatile("cp.async.wait_group %0;" :: "n"(1));
        __syncthreads();

        const uint32_t sb = sbase + (c & 1) * STAGE_SB;
        #pragma unroll
        for (int kk = 0; kk < 2; kk++) {
            const uint32_t kbyte = kk * 32;
            uint32_t afh[2][4], afl[2][4], bfh[4][2], bfl[4][2];
            #pragma unroll
            for (int mt = 0; mt < 2; mt++) {
                uint32_t ra = (uint32_t)((arow_l + mt * 16) * ROWB) + akb + kbyte;
                ldm4(afh[mt], sb + ra);
                ldm4(afl[mt], sb + TILE_A_SB + ra);
            }
            #pragma unroll
            for (int np = 0; np < 2; np++) {
                uint32_t rb = (uint32_t)((nrow_l + np * 16) * ROWB) + bkb + kbyte;
                uint32_t th[4], tl[4];
                ldm4(th, sb + 2 * TILE_A_SB + rb);
                ldm4(tl, sb + 2 * TILE_A_SB + TILE_W_SB + rb);
                bfh[2 * np][0] = th[0]; bfh[2 * np][1] = th[1];
                bfh[2 * np + 1][0] = th[2]; bfh[2 * np + 1][1] = th[3];
                bfl[2 * np][0] = tl[0]; bfl[2 * np][1] = tl[1];
                bfl[2 * np + 1][0] = tl[2]; bfl[2 * np + 1][1] = tl[3];
            }
            #pragma unroll
            for (int mt = 0; mt < 2; mt++)
                #pragma unroll
                for (int nt = 0; nt < 4; nt++) {
                    mma16816(acc[mt][nt], afh[mt], bfh[nt]);
                    mma16816(acc[mt][nt], afl[mt], bfh[nt]);
                    mma16816(acc[mt][nt], afh[mt], bfl[nt]);
                }
        }
        __syncthreads();

        if (c + 2 < nk) load_stage(c & 1, (c + 2) * 32);
        asm volatile("cp.async.commit_group;");
    }

    const int rloc0 = m32 + (lane >> 2);
    const int cloc0 = n32w + (lane & 3) * 2;
    #pragma unroll
    for (int mt = 0; mt < 2; mt++) {
        const int r0 = brow + rloc0 + mt * 16;
        #pragma unroll
        for (int nt = 0; nt < 4; nt++) {
            const int col = bcol + cloc0 + nt * 8;
            float* c0 = C + (size_t)r0 * ldc + col;
            float* c1 = C + (size_t)(r0 + 8) * ldc + col;
            atomicAdd(c0,     acc[mt][nt][0]);
            atomicAdd(c0 + 1, acc[mt][nt][1]);
            atomicAdd(c1,     acc[mt][nt][2]);
            atomicAdd(c1 + 1, acc[mt][nt][3]);
        }
    }
}

// ====== 2-term GEMM core: 3 stages, single sync; bias-store or atomic =====
#define STAGE2_SB (2 * TILE_A_SB + TILE_W_SB)
#define GEMM2_SMEM (3 * STAGE2_SB + 512 + 32)

__device__ __forceinline__ void gemm2_core(
    const __half* __restrict__ Ah, const __half* __restrict__ Al,
    const __half* __restrict__ Wh,
    int K, int Kchunk, int brow, int bcol, int k0,
    float* __restrict__ C, int ldc,
    const float* __restrict__ b1, const float* __restrict__ b2,
    uint32_t sbase)
{
    const int tid  = threadIdx.x;
    const int wid  = tid >> 5;
    const int lane = tid & 31;
    const int m32  = (wid >> 1) * 32;
    const int n32w = (wid & 1) * 32;

    const int lrA = tid >> 1;
    const int cA  = (tid & 1) * 2;
    const int lrW = tid >> 2;
    const int cW  = tid & 3;
    const size_t aoff = (size_t)(brow + lrA) * K + k0;
    const size_t woff = (size_t)(bcol + lrW) * K + k0;

    auto load_stage = [&](int stage, int kk0) {
        const uint32_t sA = sbase + stage * STAGE2_SB + lrA * ROWB;
        const uint32_t sW = sbase + stage * STAGE2_SB + 2 * TILE_A_SB + lrW * ROWB;
        const char* pAh = (const char*)(Ah + aoff + kk0);
        const char* pAl = (const char*)(Al + aoff + kk0);
        const char* pWh = (const char*)(Wh + woff + kk0);
        #pragma unroll
        for (int c = cA; c < cA + 2; c++) {
            cp16(sA + c * 16, pAh + c * 16);
            cp16(sA + TILE_A_SB + c * 16, pAl + c * 16);
        }
        cp16(sW + cW * 16, pWh + cW * 16);
    };

    const int nk = Kchunk >> 5;

    load_stage(0, 0);
    asm volatile("cp.async.commit_group;");
    if (nk > 1) load_stage(1, 32);
    asm volatile("cp.async.commit_group;");

    float acc[2][4][4];
    #pragma unroll
    for (int i = 0; i < 2; i++)
        #pragma unroll
        for (int j = 0; j < 4; j++)
            #pragma unroll
            for (int q = 0; q < 4; q++) acc[i][j][q] = 0.f;

    const int arow_l = m32 + (lane & 15);
    const uint32_t akb = ((lane >> 4) & 1) * 16;
    const int nrow_l = n32w + (lane & 7) + ((lane >> 4) & 1) * 8;
    const uint32_t bkb = ((lane >> 3) & 1) * 16;

    int stage = 0;
    for (int c = 0; c < nk; c++) {
        asm volatile("cp.async.wait_group %0;" :: "n"(1));
        __syncthreads();

        if (c + 2 < nk) {
            int s2 = stage + 2; if (s2 >= 3) s2 -= 3;
            load_stage(s2, (c + 2) * 32);
        }
        asm volatile("cp.async.commit_group;");

        const uint32_t sb = sbase + stage * STAGE2_SB;
        #pragma unroll
        for (int kk = 0; kk < 2; kk++) {
            const uint32_t kbyte = kk * 32;
            uint32_t afh[2][4], afl[2][4], bfh[4][2];
            #pragma unroll
            for (int mt = 0; mt < 2; mt++) {
                uint32_t ra = (uint32_t)((arow_l + mt * 16) * ROWB) + akb + kbyte;
                ldm4(afh[mt], sb + ra);
                ldm4(afl[mt], sb + TILE_A_SB + ra);
            }
            #pragma unroll
            for (int np = 0; np < 2; np++) {
                uint32_t rb = (uint32_t)((nrow_l + np * 16) * ROWB) + bkb + kbyte;
                uint32_t th[4];
                ldm4(th, sb + 2 * TILE_A_SB + rb);
                bfh[2 * np][0] = th[0]; bfh[2 * np][1] = th[1];
                bfh[2 * np + 1][0] = th[2]; bfh[2 * np + 1][1] = th[3];
            }
            #pragma unroll
            for (int mt = 0; mt < 2; mt++)
                #pragma unroll
                for (int nt = 0; nt < 4; nt++) {
                    mma16816(acc[mt][nt], afh[mt], bfh[nt]);
                    mma16816(acc[mt][nt], afl[mt], bfh[nt]);
                }
        }
        if (++stage >= 3) stage = 0;
    }

    const int rloc0 = m32 + (lane >> 2);
    const int cloc0 = n32w + (lane & 3) * 2;
    if (b1) {
        #pragma unroll
        for (int mt = 0; mt < 2; mt++) {
            const int r0 = brow + rloc0 + mt * 16;
            #pragma unroll
            for (int nt = 0; nt < 4; nt++) {
                const int col = bcol + cloc0 + nt * 8;
                float2 bb = make_float2(b1[col] + b2[col], b1[col + 1] + b2[col + 1]);
                *(float2*)(C + (size_t)r0 * ldc + col) =
                    make_float2(acc[mt][nt][0] + bb.x, acc[mt][nt][1] + bb.y);
                *(float2*)(C + (size_t)(r0 + 8) * ldc + col) =
                    make_float2(acc[mt][nt][2] + bb.x, acc[mt][nt][3] + bb.y);
            }
        }
    } else {
        #pragma unroll
        for (int mt = 0; mt < 2; mt++) {
            const int r0 = brow + rloc0 + mt * 16;
            #pragma unroll
            for (int nt = 0; nt < 4; nt++) {
                const int col = bcol + cloc0 + nt * 8;
                float* c0 = C + (size_t)r0 * ldc + col;
                float* c1 = C + (size_t)(r0 + 8) * ldc + col;
                atomicAdd(c0,     acc[mt][nt][0]);
                atomicAdd(c0 + 1, acc[mt][nt][1]);
                atomicAdd(c1,     acc[mt][nt][2]);
                atomicAdd(c1 + 1, acc[mt][nt][3]);
            }
        }
    }
}

// standalone 2-term split-K GEMM (gi, fc1)
__global__ __launch_bounds__(256, 2)
void gemm64b(const __half* __restrict__ Ah, const __half* __restrict__ Al,
             const __half* __restrict__ Wh,
             int K, int Kchunk, float* __restrict__ C, int ldc)
{
    extern __shared__ __align__(128) char smem[];
    const uint32_t sbase = (uint32_t)__cvta_generic_to_shared(smem);
    gemm2_core(Ah, Al, Wh, K, Kchunk,
               blockIdx.y * 128, blockIdx.x * 64, blockIdx.z * Kchunk,
               C, ldc, nullptr, nullptr, sbase);
}

// g1 only (32 blocks, bias-store)
__global__ __launch_bounds__(256, 2)
void g1_gemm(const __half* __restrict__ hidh, const __half* __restrict__ hidl,
             const __half* __restrict__ w2h, float* __restrict__ g1,
             const float* __restrict__ w2b, const float* __restrict__ w1b)
{
    extern __shared__ __align__(128) char smem[];
    const uint32_t sbase = (uint32_t)__cvta_generic_to_shared(smem);
    int bx = blockIdx.x & 15, by = blockIdx.x >> 4;
    gemm2_core(hidh, hidl, w2h, 1024, 1024, by * 128, bx * 64, 0,
               g1, 1024, w2b, w1b, sbase);
}

// ======= score core: 128x128 tile, BK=64, 3 stages, warp 64x32 ============
#define SC_ROWB   144
#define SC_A_SB   (128 * SC_ROWB)
#define SC_W_SB   (128 * SC_ROWB)
#define SC_STAGE  (SC_A_SB + SC_W_SB)
#define SC_NST    3
#define SC_SMEM   (SC_NST * SC_STAGE + 512 + 32)

__device__ __forceinline__ void score_core(
    const __half* __restrict__ Ah, const __half* __restrict__ Wh,
    const float* __restrict__ g1, const float* __restrict__ vw,
    float* __restrict__ partial, int bx, int by, uint32_t sbase, char* smem)
{
    float* part_sm = (float*)(smem + SC_NST * SC_STAGE);

    const int tid  = threadIdx.x;
    const int wid  = tid >> 5;
    const int lane = tid & 31;
    const int brow = by * 128;
    const int bcol = bx * 128;
    const int m64  = (wid >> 2) * 64;
    const int n32  = (wid & 3) * 32;
    const int K    = 1024;

    if (tid < 128) part_sm[tid] = 0.f;

    const int arow = tid >> 1;
    const int acb_ld = (tid & 1) * 4;
    const __half* gA = Ah + (size_t)(brow + arow) * K;
    const __half* gW = Wh + (size_t)(bcol + arow) * K;
    const uint32_t sA_ld = (uint32_t)(arow * SC_ROWB + acb_ld * 16);
    const uint32_t sW_ld = (uint32_t)(SC_A_SB + arow * SC_ROWB + acb_ld * 16);

    auto load_stage = [&](int stage, int k0) {
        const uint32_t sb = sbase + stage * SC_STAGE;
        const char* pA = (const char*)(gA + k0) + acb_ld * 16;
        const char* pW = (const char*)(gW + k0) + acb_ld * 16;
        #pragma unroll
        for (int c = 0; c < 4; c++) {
            cp16(sb + sA_ld + c * 16, pA + c * 16);
            cp16(sb + sW_ld + c * 16, pW + c * 16);
        }
    };

    const int nk = 16;

    load_stage(0, 0);
    asm volatile("cp.async.commit_group;");
    load_stage(1, 64);
    asm volatile("cp.async.commit_group;");

    float acc[4][4][4];
    #pragma unroll
    for (int i = 0; i < 4; i++)
        #pragma unroll
        for (int j = 0; j < 4; j++)
            #pragma unroll
            for (int q = 0; q < 4; q++) acc[i][j][q] = 0.f;

    const int arow_l = m64 + (lane & 15);
    const uint32_t akb = ((lane >> 4) & 1) * 16;
    const int nrow_l = n32 + (lane & 7) + ((lane >> 4) & 1) * 8;
    const uint32_t bkb = ((lane >> 3) & 1) * 16;

    int stage = 0;
    for (int c = 0; c < nk; c++) {
        asm volatile("cp.async.wait_group %0;" :: "n"(1));
        __syncthreads();

        if (c + 2 < nk) {
            int s2 = stage + 2; if (s2 >= SC_NST) s2 -= SC_NST;
            load_stage(s2, (c + 2) * 64);
        }
        asm volatile("cp.async.commit_group;");

        const uint32_t sb = sbase + stage * SC_STAGE;
        #pragma unroll
        for (int kk = 0; kk < 4; kk++) {
            const uint32_t kbyte = kk * 32;
            uint32_t bfh[4][2];
            #pragma unroll
            for (int np = 0; np < 2; np++) {
                uint32_t rb = (uint32_t)((nrow_l + np * 16) * SC_ROWB) + bkb + kbyte;
                uint32_t th[4];
                ldm4(th, sb + SC_A_SB + rb);
                bfh[2 * np][0] = th[0]; bfh[2 * np][1] = th[1];
                bfh[2 * np + 1][0] = th[2]; bfh[2 * np + 1][1] = th[3];
            }
            #pragma unroll
            for (int mt = 0; mt < 4; mt++) {
                uint32_t afh[4];
                uint32_t ra = (uint32_t)((arow_l + mt * 16) * SC_ROWB) + akb + kbyte;
                ldm4(afh, sb + ra);
                #pragma unroll
                for (int nt = 0; nt < 4; nt++)
                    mma16816(acc[mt][nt], afh, bfh[nt]);
            }
        }
        if (++stage >= SC_NST) stage = 0;
    }

    const int rloc0 = m64 + (lane >> 2);
    const int cloc0 = n32 + (lane & 3) * 2;
    const float* g1r = g1 + (size_t)by * 1024;
    #pragma unroll
    for (int mt = 0; mt < 4; mt++) {
        float s0 = 0.f, s1 = 0.f;
        #pragma unroll
        for (int nt = 0; nt < 4; nt++) {
            int col = bcol + cloc0 + nt * 8;
            float gw0 = g1r[col],     vw0 = vw[col];
            float gw1 = g1r[col + 1], vw1 = vw[col + 1];
            s0 += tanhf(acc[mt][nt][0] + gw0) * vw0;
            s0 += tanhf(acc[mt][nt][1] + gw1) * vw1;
            s1 += tanhf(acc[mt][nt][2] + gw0) * vw0;
            s1 += tanhf(acc[mt][nt][3] + gw1) * vw1;
        }
        atomicAdd(&part_sm[rloc0 + mt * 16], s0);
        atomicAdd(&part_sm[rloc0 + mt * 16 + 8], s1);
    }
    __syncthreads();
    if (tid < 128)
        partial[(size_t)(brow + tid) * 8 + bx] = part_sm[tid];
}

// === score_plus: score (2048 blk) | x_emb (128 blk) | gh (192 blk) ========
__global__ __launch_bounds__(256, 2)
void score_plus(const __half* __restrict__ encAh, const __half* __restrict__ w1h,
                const float* __restrict__ g1, const float* __restrict__ vw,
                float* __restrict__ partial,
                const __half* __restrict__ xh, const __half* __restrict__ xl,
                const __half* __restrict__ o2eh,
                const __half* __restrict__ hidh, const __half* __restrict__ hidl,
                const __half* __restrict__ gwhh,
                float* __restrict__ rnn_xemb, float* __restrict__ gh)
{
    extern __shared__ __align__(128) char smem[];
    const uint32_t sbase = (uint32_t)__cvta_generic_to_shared(smem);
    const int ib = blockIdx.x;
    if (ib < 2048) {
        score_core(encAh, w1h, g1, vw, partial, ib & 7, ib >> 3, sbase, smem);
    } else if (ib < 2176) {
        int j = ib - 2048;
        int bx = j & 7, by = (j >> 3) & 1, bz = j >> 4;
        gemm2_core(xh, xl, o2eh, 4096, 512, by * 128, bx * 64, bz * 512,
                   rnn_xemb, 1536, nullptr, nullptr, sbase);
    } else {
        int j = ib - 2176;
        int bx = j % 48, by = (j / 48) & 1, bz = j / 96;
        gemm2_core(hidh, hidl, gwhh, 1024, 512, by * 128, bx * 64, bz * 512,
                   gh, 3072, nullptr, nullptr, sbase);
    }
}

// ==== attn_fused v2: ctx split in half-columns (512 blk) | split_xemb =====
__global__ __launch_bounds__(256)
void attn_fused(const float* __restrict__ part, int npart,
                const __half* __restrict__ ench,
                const float* __restrict__ Vb,
                float* __restrict__ attn_out,
                const float* __restrict__ rnn)
{
    const int tid = threadIdx.x;
    if (blockIdx.x >= 2 * BB) {
        // split_xemb: 128 blocks x 256 threads
        int i = (blockIdx.x - 2 * BB) * 256 + tid;
        int row = i >> 7;
        int c4  = i & 127;
        size_t off = (size_t)row * 1536 + 1024 + c4 * 4;
        float4 v = *(const float4*)(rnn + off);
        __half h0 = __float2half_rn(v.x), h1 = __float2half_rn(v.y);
        __half h2 = __float2half_rn(v.z), h3 = __float2half_rn(v.w);
        __half2 hp0; hp0.x = h0; hp0.y = h1;
        __half2 hp1; hp1.x = h2; hp1.y = h3;
        __half2 lp0, lp1;
        lp0.x = __float2half_rn(v.x - __half2float(h0));
        lp0.y = __float2half_rn(v.y - __half2float(h1));
        lp1.x = __float2half_rn(v.z - __half2float(h2));
        lp1.y = __float2half_rn(v.w - __half2float(h3));
        *(__half2*)(g_bh + OFF_RNN + off)     = hp0;
        *(__half2*)(g_bh + OFF_RNN + off + 2) = hp1;
        *(__half2*)(g_bl + OFF_RNN + off)     = lp0;
        *(__half2*)(g_bl + OFF_RNN + off + 2) = lp1;
        return;
    }

    const int b    = blockIdx.x >> 1;
    const int half = blockIdx.x & 1;
    __shared__ float logit[LL];

    if (tid < LL) {
        const float* pr = part + (size_t)(b * LL + tid) * npart;
        float s = Vb[0];
        for (int j = 0; j < npart; j++) s += pr[j];
        logit[tid] = s;
    }
    __syncthreads();

    if (tid < 32) {
        const int lane = tid;
        float m = -1e30f;
        for (int l = lane; l < LL; l += 32) m = fmaxf(m, logit[l]);
        #pragma unroll
        for (int o = 16; o; o >>= 1) m = fmaxf(m, __shfl_xor_sync(0xffffffffu, m, o));
        float s = 0.f;
        for (int l = lane; l < LL; l += 32) {
            float e = expf(logit[l] - m);
            logit[l] = e;
            s += e;
        }
        #pragma unroll
        for (int o = 16; o; o >>= 1) s += __shfl_xor_sync(0xffffffffu, s, o);
        float inv = 1.f / s;
        for (int l = lane; l < LL; l += 32) logit[l] *= inv;
    }
    __syncthreads();

    if (half == 0 && tid < LL) attn_out[b * LL + tid] = logit[tid];

    // ctx: 2 columns per thread (512 cols per block)
    float2 acc = make_float2(0.f, 0.f);
    const int colh = half * 256 + tid;              // half2 index within row
    const __half2* encb = (const __half2*)(ench + (size_t)b * LL * EENC) + colh;
    #pragma unroll 8
    for (int l = 0; l < LL; l++) {
        float a = logit[l];
        float2 f = __half22float2(encb[l * (EENC / 2)]);
        acc.x += a * f.x; acc.y += a * f.y;
    }
    size_t off = (size_t)b * 1536 + colh * 2;
    __half h0 = __float2half_rn(acc.x), h1 = __float2half_rn(acc.y);
    __half2 hp; hp.x = h0; hp.y = h1;
    __half2 lp;
    lp.x = __float2half_rn(acc.x - __half2float(h0));
    lp.y = __float2half_rn(acc.y - __half2float(h1));
    *(__half2*)(g_bh + OFF_RNN + off) = hp;
    *(__half2*)(g_bl + OFF_RNN + off) = lp;
}

// ======== GRU gates; writes hnew + fp16 hi/lo splits (fused) ==============
__global__ __launch_bounds__(256)
void gru_gate(const float* __restrict__ gi, const float* __restrict__ gh,
              const float* __restrict__ h0, float* __restrict__ hnew)
{
    const int i = blockIdx.x * blockDim.x + threadIdx.x;
    const int idx = i * 2;
    const int b = idx >> 10;
    const int d = idx & 1023;
    const float* gib = gi + (size_t)b * 3072;
    const float* ghb = gh + (size_t)b * 3072;
    float h_out[2];
    #pragma unroll
    for (int u = 0; u < 2; u++) {
        int dd = d + u;
        float r = 1.f / (1.f + expf(-(gib[dd] + ghb[dd])));
        float z = 1.f / (1.f + expf(-(gib[1024 + dd] + ghb[1024 + dd])));
        float n = tanhf(gib[2048 + dd] + r * ghb[2048 + dd]);
        h_out[u] = (1.f - z) * n + z * h0[idx + u];
    }
    *(float2*)(hnew + idx) = make_float2(h_out[0], h_out[1]);
    __half hh0 = __float2half_rn(h_out[0]);
    __half hh1 = __float2half_rn(h_out[1]);
    __half2 hp; hp.x = hh0; hp.y = hh1;
    __half2 lp;
    lp.x = __float2half_rn(h_out[0] - __half2float(hh0));
    lp.y = __float2half_rn(h_out[1] - __half2float(hh1));
    ((__half2*)(g_bh + OFF_HNEW))[i] = hp;
    ((__half2*)(g_bl + OFF_HNEW))[i] = lp;
}

// ============================ launch ======================================
extern "C" void kernel_launch(void* const* d_in, const int* in_sizes, int n_in,
                              void* d_out, int out_size)
{
    (void)in_sizes; (void)n_in; (void)out_size;

    const float* x      = (const float*)d_in[0];
    const float* hidden = (const float*)d_in[1];
    const float* enc    = (const float*)d_in[2];
    const float* W1_w   = (const float*)d_in[3];
    const float* W1_b   = (const float*)d_in[4];
    const float* W2_w   = (const float*)d_in[5];
    const float* W2_b   = (const float*)d_in[6];
    const float* V_w    = (const float*)d_in[7];
    const float* V_b    = (const float*)d_in[8];
    const float* o2e_w  = (const float*)d_in[9];
    const float* o2e_b  = (const float*)d_in[10];
    const float* gwi    = (const float*)d_in[11];
    const float* gwh    = (const float*)d_in[12];
    const float* gbi    = (const float*)d_in[13];
    const float* gbh    = (const float*)d_in[14];
    const float* f1w    = (const float*)d_in[15];
    const float* f1b    = (const float*)d_in[16];
    const float* f2w    = (const float*)d_in[17];
    const float* f2b    = (const float*)d_in[18];

    float* out  = (float*)d_out;
    float* hnew = out + (size_t)BB * VOC;
    float* attn = hnew + (size_t)BB * DDEC;

    __half* bh = nullptr;
    __half* bl = nullptr;
    float* fs = nullptr;
    cudaGetSymbolAddress((void**)&bh, g_bh);
    cudaGetSymbolAddress((void**)&bl, g_bl);
    cudaGetSymbolAddress((void**)&fs, g_f32);

    float* g1   = fs + F_G1;
    float* rnn  = fs + F_RNN;
    float* gi   = fs + F_GI;
    float* gh   = fs + F_GH;
    float* tbuf = fs + F_T;
    float* part = fs + F_PART;

    cudaFuncSetAttribute(gemm64,     cudaFuncAttributeMaxDynamicSharedMemorySize, GEMM_SMEM);
    cudaFuncSetAttribute(gemm64b,    cudaFuncAttributeMaxDynamicSharedMemorySize, GEMM2_SMEM);
    cudaFuncSetAttribute(g1_gemm,    cudaFuncAttributeMaxDynamicSharedMemorySize, GEMM2_SMEM);
    cudaFuncSetAttribute(score_plus, cudaFuncAttributeMaxDynamicSharedMemorySize, SC_SMEM);

    dim3 blk(256);

    // 0) prep: all input splits + bias pre-init
    prep<<<PREP_TOTAL / 256, 256>>>(W1_w, W2_w, o2e_w, gwi, gwh, f1w, f2w,
                                    enc, x, hidden,
                                    rnn, gi, gh, tbuf, out,
                                    o2e_b, gbi, gbh, f1b, f2b);

    // 1) g1 (needed by score)
    g1_gemm<<<32, blk, GEMM2_SMEM>>>(
        bh + OFF_HID, bl + OFF_HID, bh + OFF_W2, g1, W2_b, W1_b);

    // 2) score ⊕ x_emb ⊕ gh (2368 blocks; xemb/gh fill score's drain waves)
    score_plus<<<2368, blk, SC_SMEM>>>(
        bh + OFF_ENC, bh + OFF_W1, g1, V_w, part,
        bh + OFF_X, bl + OFF_X, bh + OFF_O2E,
        bh + OFF_HID, bl + OFF_HID, bh + OFF_GWH,
        rnn + 1024, gh);

    // 3) attn_fused v2: ctx halves (512) | split_xemb (128)
    attn_fused<<<2 * BB + 128, 256>>>(part, 8, bh + OFF_ENC, V_b, attn, rnn);

    // 4) gi += rnn_in @ gru_wi^T    (2-term, splitK=2)
    gemm64b<<<dim3(48, 2, 2), blk, GEMM2_SMEM>>>(
        bh + OFF_RNN, bl + OFF_RNN, bh + OFF_GWI,
        1536, 768, gi, 3072);

    // 5) GRU gates -> h_new (+ fused fp16 split)
    gru_gate<<<131072 / 256, 256>>>(gi, gh, hidden, hnew);

    // 6) tbuf += h_new @ fc1^T      (2-term, splitK=8)
    gemm64b<<<dim3(8, 2, 8), blk, GEMM2_SMEM>>>(
        bh + OFF_HNEW, bl + OFF_HNEW, bh + OFF_F1,
        1024, 128, tbuf, 512);

    // 7) t = tanh(tbuf) -> fp16
    f32_split_tanh<<<(131072 / 4) / 256, 256>>>(tbuf, bh + OFF_T, bl + OFF_T, 131072 / 4);

    // 8) out += t @ fc2^T           (3-term, splitK=2; direct output path)
    gemm64<<<dim3(64, 2, 2), blk, GEMM_SMEM>>>(
        bh + OFF_T, bl + OFF_T, bh + OFF_F2, bl + OFF_F2,
        512, 256, out, 4096);
}

// round 17
// speedup vs baseline: 2.2437x; 1.0268x over previous
#include <cuda_runtime.h>
#include <cuda_fp16.h>
#include <cstdint>
#include <math.h>

// Problem dims
#define BB   256
#define LL   128
#define VOC  4096
#define EENC 1024
#define DDEC 1024
#define EEMB 512

// ======================= scratch (module-load allocated) ==================
#define OFF_ENC   0ull
#define OFF_W1    (OFF_ENC + 33554432ull)
#define OFF_W2    (OFF_W1  + 1048576ull)
#define OFF_O2E   (OFF_W2  + 1048576ull)
#define OFF_GWI   (OFF_O2E + 2097152ull)
#define OFF_GWH   (OFF_GWI + 4718592ull)
#define OFF_F1    (OFF_GWH + 3145728ull)
#define OFF_F2    (OFF_F1  + 524288ull)
#define OFF_X     (OFF_F2  + 2097152ull)
#define OFF_HID   (OFF_X   + 1048576ull)
#define OFF_RNN   (OFF_HID + 262144ull)
#define OFF_HNEW  (OFF_RNN + 393216ull)
#define OFF_T     (OFF_HNEW+ 262144ull)
#define BF_TOTAL  (OFF_T   + 131072ull)

__device__ __half g_bh[BF_TOTAL];
__device__ __half g_bl[BF_TOTAL];

#define F_G1    0ull
#define F_RNN   (F_G1   + 262144ull)
#define F_GI    (F_RNN  + 393216ull)
#define F_GH    (F_GI   + 786432ull)
#define F_T     (F_GH   + 786432ull)
#define F_PART  (F_T    + 131072ull)
#define F_TOTAL (F_PART + 524288ull)

__device__ float g_f32[F_TOTAL];

// ======================= small helpers ====================================
__device__ __forceinline__ void cp16(uint32_t s, const void* g) {
    asm volatile("cp.async.cg.shared.global [%0], [%1], 16;"
                 :: "r"(s), "l"(__cvta_generic_to_global(g)));
}
__device__ __forceinline__ void ldm4(uint32_t* r, uint32_t addr) {
    asm volatile("ldmatrix.sync.aligned.m8n8.x4.shared.b16 {%0,%1,%2,%3}, [%4];"
        : "=r"(r[0]), "=r"(r[1]), "=r"(r[2]), "=r"(r[3]) : "r"(addr));
}
__device__ __forceinline__ void mma16816(float* c, const uint32_t* a, const uint32_t* b) {
    asm volatile("mma.sync.aligned.m16n8k16.row.col.f32.f16.f16.f32 "
        "{%0,%1,%2,%3}, {%4,%5,%6,%7}, {%8,%9}, {%0,%1,%2,%3};"
        : "+f"(c[0]), "+f"(c[1]), "+f"(c[2]), "+f"(c[3])
        : "r"(a[0]), "r"(a[1]), "r"(a[2]), "r"(a[3]), "r"(b[0]), "r"(b[1]));
}
// convert 4 floats -> packed 4 halves (hi) and residues (lo)
__device__ __forceinline__ uint2 cvt_hi4(float4 v) {
    __half2 a, b;
    a.x = __float2half_rn(v.x); a.y = __float2half_rn(v.y);
    b.x = __float2half_rn(v.z); b.y = __float2half_rn(v.w);
    uint2 r;
    r.x = *(uint32_t*)&a; r.y = *(uint32_t*)&b;
    return r;
}
__device__ __forceinline__ uint2 cvt_lo4(float4 v, uint2 hi) {
    __half2 ha = *(__half2*)&hi.x, hb = *(__half2*)&hi.y;
    __half2 a, b;
    a.x = __float2half_rn(v.x - __half2float(ha.x));
    a.y = __float2half_rn(v.y - __half2float(ha.y));
    b.x = __float2half_rn(v.z - __half2float(hb.x));
    b.y = __float2half_rn(v.w - __half2float(hb.y));
    uint2 r;
    r.x = *(uint32_t*)&a; r.y = *(uint32_t*)&b;
    return r;
}
// 8-float split: one 16B hi store (+16B lo store); i indexes 8-float units
__device__ __forceinline__ void do_split8(const float* __restrict__ src, int i,
                                          unsigned long long dst) {
    float4 v0 = ((const float4*)src)[2 * i];
    float4 v1 = ((const float4*)src)[2 * i + 1];
    uint2 h0 = cvt_hi4(v0), h1 = cvt_hi4(v1);
    uint2 l0 = cvt_lo4(v0, h0), l1 = cvt_lo4(v1, h1);
    uint4 hp = make_uint4(h0.x, h0.y, h1.x, h1.y);
    uint4 lp = make_uint4(l0.x, l0.y, l1.x, l1.y);
    ((uint4*)(g_bh + dst))[i] = hp;
    ((uint4*)(g_bl + dst))[i] = lp;
}
__device__ __forceinline__ void do_split8_hi(const float* __restrict__ src, int i,
                                             unsigned long long dst) {
    float4 v0 = ((const float4*)src)[2 * i];
    float4 v1 = ((const float4*)src)[2 * i + 1];
    uint2 h0 = cvt_hi4(v0), h1 = cvt_hi4(v1);
    ((uint4*)(g_bh + dst))[i] = make_uint4(h0.x, h0.y, h1.x, h1.y);
}

// ================= prep: all input splits + bias pre-init (8-float units) =
#define W8N1 131072
#define W8N2 262144
#define W8N3 524288
#define W8N4 1114112
#define W8N5 1507328
#define W8N6 1572864
#define W8N7 1835008
#define P8_ACT0 1835008
#define P8A1 (P8_ACT0 + 4194304)
#define P8A2 (P8_ACT0 + 4325376)
#define P8A3 (P8_ACT0 + 4358144)
#define P8_BIAS0 6193152
#define P8B1 (P8_BIAS0 + 131072)
#define P8B2 (P8_BIAS0 + 917504)
#define P8B3 (P8_BIAS0 + 1703936)
#define P8B4 (P8_BIAS0 + 1835008)
#define P8B5 (P8_BIAS0 + 2883584)
#define PREP_TOTAL P8B5

__global__ __launch_bounds__(256)
void prep(const float* __restrict__ W1, const float* __restrict__ W2,
          const float* __restrict__ o2e, const float* __restrict__ gwi,
          const float* __restrict__ gwh, const float* __restrict__ f1,
          const float* __restrict__ f2,
          const float* __restrict__ enc, const float* __restrict__ x,
          const float* __restrict__ hid,
          float* __restrict__ rnn, float* __restrict__ gi, float* __restrict__ gh,
          float* __restrict__ tbuf, float* __restrict__ out,
          const float* __restrict__ o2eb, const float* __restrict__ gbi,
          const float* __restrict__ gbh, const float* __restrict__ f1b,
          const float* __restrict__ f2b)
{
    int i = blockIdx.x * blockDim.x + threadIdx.x;
    if (i < W8N7) {
        if (i < W8N1)      do_split8_hi(W1,  i,        OFF_W1);
        else if (i < W8N2) do_split8_hi(W2,  i - W8N1, OFF_W2);
        else if (i < W8N3) do_split8_hi(o2e, i - W8N2, OFF_O2E);
        else if (i < W8N4) do_split8_hi(gwi, i - W8N3, OFF_GWI);
        else if (i < W8N5) do_split8_hi(gwh, i - W8N4, OFF_GWH);
        else if (i < W8N6) do_split8_hi(f1,  i - W8N5, OFF_F1);
        else               do_split8(f2,  i - W8N6, OFF_F2);
    } else if (i < P8A3) {
        if (i < P8A1)      do_split8_hi(enc, i - P8_ACT0, OFF_ENC);
        else if (i < P8A2) do_split8(x,   i - P8A1, OFF_X);
        else               do_split8(hid, i - P8A2, OFF_HID);
    } else if (i < P8B5) {
        int j = i - P8_BIAS0;
        if (i < P8B1) {
            rnn[(j >> 9) * 1536 + 1024 + (j & 511)] = o2eb[j & 511];
        } else if (i < P8B2) {
            j -= 131072;  gi[j] = gbi[j % 3072];
        } else if (i < P8B3) {
            j -= 917504;  gh[j] = gbh[j % 3072];
        } else if (i < P8B4) {
            j -= 1703936; tbuf[j] = f1b[j & 511];
        } else {
            j -= 1835008; out[j] = f2b[j & 4095];
        }
    }
}

__global__ __launch_bounds__(256)
void f32_split_tanh(const float* __restrict__ in, __half* __restrict__ hi,
                    __half* __restrict__ lo, int n4)
{
    int i = blockIdx.x * blockDim.x + threadIdx.x;
    if (i >= n4) return;
    float4 v = ((const float4*)in)[i];
    v.x = tanhf(v.x); v.y = tanhf(v.y); v.z = tanhf(v.z); v.w = tanhf(v.w);
    uint2 h = cvt_hi4(v);
    uint2 l = cvt_lo4(v, h);
    ((uint2*)hi)[i] = h;
    ((uint2*)lo)[i] = l;
}

// ======================= 3-term split-K mma GEMM (fc2 only) ===============
#define ROWB      80
#define TILE_A_SB (128 * ROWB)
#define TILE_W_SB (64 * ROWB)
#define STAGE_SB  (2 * TILE_A_SB + 2 * TILE_W_SB)
#define GEMM_SMEM (2 * STAGE_SB + 512 + 32)

__global__ __launch_bounds__(256, 2)
void gemm64(const __half* __restrict__ Ah, const __half* __restrict__ Al,
            const __half* __restrict__ Wh, const __half* __restrict__ Wl,
            int K, int Kchunk, float* __restrict__ C, int ldc)
{
    extern __shared__ __align__(128) char smem[];
    const uint32_t sbase = (uint32_t)__cvta_generic_to_shared(smem);

    const int tid  = threadIdx.x;
    const int wid  = tid >> 5;
    const int lane = tid & 31;
    const int brow = blockIdx.y * 128;
    const int bcol = blockIdx.x * 64;
    const int k0   = blockIdx.z * Kchunk;
    const int m32  = (wid >> 1) * 32;
    const int n32w = (wid & 1) * 32;

    const int lrA = tid >> 1;
    const int cA  = (tid & 1) * 2;
    const int lrW = tid >> 2;
    const int cW  = tid & 3;
    const size_t aoff = (size_t)(brow + lrA) * K + k0;
    const size_t woff = (size_t)(bcol + lrW) * K + k0;

    auto load_stage = [&](int stage, int kk0) {
        const uint32_t sA = sbase + stage * STAGE_SB + lrA * ROWB;
        const uint32_t sW = sbase + stage * STAGE_SB + 2 * TILE_A_SB + lrW * ROWB;
        const char* pAh = (const char*)(Ah + aoff + kk0);
        const char* pAl = (const char*)(Al + aoff + kk0);
        const char* pWh = (const char*)(Wh + woff + kk0);
        const char* pWl = (const char*)(Wl + woff + kk0);
        #pragma unroll
        for (int c = cA; c < cA + 2; c++) {
            cp16(sA + c * 16, pAh + c * 16);
            cp16(sA + TILE_A_SB + c * 16, pAl + c * 16);
        }
        cp16(sW + cW * 16, pWh + cW * 16);
        cp16(sW + TILE_W_SB + cW * 16, pWl + cW * 16);
    };

    const int nk = Kchunk >> 5;

    load_stage(0, 0);
    asm volatile("cp.async.commit_group;");
    if (nk > 1) load_stage(1, 32);
    asm volatile("cp.async.commit_group;");

    float acc[2][4][4];
    #pragma unroll
    for (int i = 0; i < 2; i++)
        #pragma unroll
        for (int j = 0; j < 4; j++)
            #pragma unroll
            for (int q = 0; q < 4; q++) acc[i][j][q] = 0.f;

    const int arow_l = m32 + (lane & 15);
    const uint32_t akb = ((lane >> 4) & 1) * 16;
    const int nrow_l = n32w + (lane & 7) + ((lane >> 4) & 1) * 8;
    const uint32_t bkb = ((lane >> 3) & 1) * 16;

    for (int c = 0; c < nk; c++) {
        asm volatile("cp.async.wait_group %0;" :: "n"(1));
        __syncthreads();

        const uint32_t sb = sbase + (c & 1) * STAGE_SB;
        #pragma unroll
        for (int kk = 0; kk < 2; kk++) {
            const uint32_t kbyte = kk * 32;
            uint32_t afh[2][4], afl[2][4], bfh[4][2], bfl[4][2];
            #pragma unroll
            for (int mt = 0; mt < 2; mt++) {
                uint32_t ra = (uint32_t)((arow_l + mt * 16) * ROWB) + akb + kbyte;
                ldm4(afh[mt], sb + ra);
                ldm4(afl[mt], sb + TILE_A_SB + ra);
            }
            #pragma unroll
            for (int np = 0; np < 2; np++) {
                uint32_t rb = (uint32_t)((nrow_l + np * 16) * ROWB) + bkb + kbyte;
                uint32_t th[4], tl[4];
                ldm4(th, sb + 2 * TILE_A_SB + rb);
                ldm4(tl, sb + 2 * TILE_A_SB + TILE_W_SB + rb);
                bfh[2 * np][0] = th[0]; bfh[2 * np][1] = th[1];
                bfh[2 * np + 1][0] = th[2]; bfh[2 * np + 1][1] = th[3];
                bfl[2 * np][0] = tl[0]; bfl[2 * np][1] = tl[1];
                bfl[2 * np + 1][0] = tl[2]; bfl[2 * np + 1][1] = tl[3];
            }
            #pragma unroll
            for (int mt = 0; mt < 2; mt++)
                #pragma unroll
                for (int nt = 0; nt < 4; nt++) {
                    mma16816(acc[mt][nt], afh[mt], bfh[nt]);
                    mma16816(acc[mt][nt], afl[mt], bfh[nt]);
                    mma16816(acc[mt][nt], afh[mt], bfl[nt]);
                }
        }
        __syncthreads();

        if (c + 2 < nk) load_stage(c & 1, (c + 2) * 32);
        asm volatile("cp.async.commit_group;");
    }

    const int rloc0 = m32 + (lane >> 2);
    const int cloc0 = n32w + (lane & 3) * 2;
    #pragma unroll
    for (int mt = 0; mt < 2; mt++) {
        const int r0 = brow + rloc0 + mt * 16;
        #pragma unroll
        for (int nt = 0; nt < 4; nt++) {
            const int col = bcol + cloc0 + nt * 8;
            float* c0 = C + (size_t)r0 * ldc + col;
            float* c1 = C + (size_t)(r0 + 8) * ldc + col;
            atomicAdd(c0,     acc[mt][nt][0]);
            atomicAdd(c0 + 1, acc[mt][nt][1]);
            atomicAdd(c1,     acc[mt][nt][2]);
            atomicAdd(c1 + 1, acc[mt][nt][3]);
        }
    }
}

// ====== 2-term GEMM core: 3 stages, single sync; bias-store or atomic =====
#define STAGE2_SB (2 * TILE_A_SB + TILE_W_SB)
#define GEMM2_SMEM (3 * STAGE2_SB + 512 + 32)

__device__ __forceinline__ void gemm2_core(
    const __half* __restrict__ Ah, const __half* __restrict__ Al,
    const __half* __restrict__ Wh,
    int K, int Kchunk, int brow, int bcol, int k0,
    float* __restrict__ C, int ldc,
    const float* __restrict__ b1, const float* __restrict__ b2,
    uint32_t sbase)
{
    const int tid  = threadIdx.x;
    const int wid  = tid >> 5;
    const int lane = tid & 31;
    const int m32  = (wid >> 1) * 32;
    const int n32w = (wid & 1) * 32;

    const int lrA = tid >> 1;
    const int cA  = (tid & 1) * 2;
    const int lrW = tid >> 2;
    const int cW  = tid & 3;
    const size_t aoff = (size_t)(brow + lrA) * K + k0;
    const size_t woff = (size_t)(bcol + lrW) * K + k0;

    auto load_stage = [&](int stage, int kk0) {
        const uint32_t sA = sbase + stage * STAGE2_SB + lrA * ROWB;
        const uint32_t sW = sbase + stage * STAGE2_SB + 2 * TILE_A_SB + lrW * ROWB;
        const char* pAh = (const char*)(Ah + aoff + kk0);
        const char* pAl = (const char*)(Al + aoff + kk0);
        const char* pWh = (const char*)(Wh + woff + kk0);
        #pragma unroll
        for (int c = cA; c < cA + 2; c++) {
            cp16(sA + c * 16, pAh + c * 16);
            cp16(sA + TILE_A_SB + c * 16, pAl + c * 16);
        }
        cp16(sW + cW * 16, pWh + cW * 16);
    };

    const int nk = Kchunk >> 5;

    load_stage(0, 0);
    asm volatile("cp.async.commit_group;");
    if (nk > 1) load_stage(1, 32);
    asm volatile("cp.async.commit_group;");

    float acc[2][4][4];
    #pragma unroll
    for (int i = 0; i < 2; i++)
        #pragma unroll
        for (int j = 0; j < 4; j++)
            #pragma unroll
            for (int q = 0; q < 4; q++) acc[i][j][q] = 0.f;

    const int arow_l = m32 + (lane & 15);
    const uint32_t akb = ((lane >> 4) & 1) * 16;
    const int nrow_l = n32w + (lane & 7) + ((lane >> 4) & 1) * 8;
    const uint32_t bkb = ((lane >> 3) & 1) * 16;

    int stage = 0;
    for (int c = 0; c < nk; c++) {
        asm volatile("cp.async.wait_group %0;" :: "n"(1));
        __syncthreads();

        if (c + 2 < nk) {
            int s2 = stage + 2; if (s2 >= 3) s2 -= 3;
            load_stage(s2, (c + 2) * 32);
        }
        asm volatile("cp.async.commit_group;");

        const uint32_t sb = sbase + stage * STAGE2_SB;
        #pragma unroll
        for (int kk = 0; kk < 2; kk++) {
            const uint32_t kbyte = kk * 32;
            uint32_t afh[2][4], afl[2][4], bfh[4][2];
            #pragma unroll
            for (int mt = 0; mt < 2; mt++) {
                uint32_t ra = (uint32_t)((arow_l + mt * 16) * ROWB) + akb + kbyte;
                ldm4(afh[mt], sb + ra);
                ldm4(afl[mt], sb + TILE_A_SB + ra);
            }
            #pragma unroll
            for (int np = 0; np < 2; np++) {
                uint32_t rb = (uint32_t)((nrow_l + np * 16) * ROWB) + bkb + kbyte;
                uint32_t th[4];
                ldm4(th, sb + 2 * TILE_A_SB + rb);
                bfh[2 * np][0] = th[0]; bfh[2 * np][1] = th[1];
                bfh[2 * np + 1][0] = th[2]; bfh[2 * np + 1][1] = th[3];
            }
            #pragma unroll
            for (int mt = 0; mt < 2; mt++)
                #pragma unroll
                for (int nt = 0; nt < 4; nt++) {
                    mma16816(acc[mt][nt], afh[mt], bfh[nt]);
                    mma16816(acc[mt][nt], afl[mt], bfh[nt]);
                }
        }
        if (++stage >= 3) stage = 0;
    }

    const int rloc0 = m32 + (lane >> 2);
    const int cloc0 = n32w + (lane & 3) * 2;
    if (b1) {
        #pragma unroll
        for (int mt = 0; mt < 2; mt++) {
            const int r0 = brow + rloc0 + mt * 16;
            #pragma unroll
            for (int nt = 0; nt < 4; nt++) {
                const int col = bcol + cloc0 + nt * 8;
                float2 bb = make_float2(b1[col] + b2[col], b1[col + 1] + b2[col + 1]);
                *(float2*)(C + (size_t)r0 * ldc + col) =
                    make_float2(acc[mt][nt][0] + bb.x, acc[mt][nt][1] + bb.y);
                *(float2*)(C + (size_t)(r0 + 8) * ldc + col) =
                    make_float2(acc[mt][nt][2] + bb.x, acc[mt][nt][3] + bb.y);
            }
        }
    } else {
        #pragma unroll
        for (int mt = 0; mt < 2; mt++) {
            const int r0 = brow + rloc0 + mt * 16;
            #pragma unroll
            for (int nt = 0; nt < 4; nt++) {
                const int col = bcol + cloc0 + nt * 8;
                float* c0 = C + (size_t)r0 * ldc + col;
                float* c1 = C + (size_t)(r0 + 8) * ldc + col;
                atomicAdd(c0,     acc[mt][nt][0]);
                atomicAdd(c0 + 1, acc[mt][nt][1]);
                atomicAdd(c1,     acc[mt][nt][2]);
                atomicAdd(c1 + 1, acc[mt][nt][3]);
            }
        }
    }
}

// standalone 2-term split-K GEMM (gi, fc1)
__global__ __launch_bounds__(256, 2)
void gemm64b(const __half* __restrict__ Ah, const __half* __restrict__ Al,
             const __half* __restrict__ Wh,
             int K, int Kchunk, float* __restrict__ C, int ldc)
{
    extern __shared__ __align__(128) char smem[];
    const uint32_t sbase = (uint32_t)__cvta_generic_to_shared(smem);
    gemm2_core(Ah, Al, Wh, K, Kchunk,
               blockIdx.y * 128, blockIdx.x * 64, blockIdx.z * Kchunk,
               C, ldc, nullptr, nullptr, sbase);
}

// g1 only (32 blocks, bias-store)
__global__ __launch_bounds__(256, 2)
void g1_gemm(const __half* __restrict__ hidh, const __half* __restrict__ hidl,
             const __half* __restrict__ w2h, float* __restrict__ g1,
             const float* __restrict__ w2b, const float* __restrict__ w1b)
{
    extern __shared__ __align__(128) char smem[];
    const uint32_t sbase = (uint32_t)__cvta_generic_to_shared(smem);
    int bx = blockIdx.x & 15, by = blockIdx.x >> 4;
    gemm2_core(hidh, hidl, w2h, 1024, 1024, by * 128, bx * 64, 0,
               g1, 1024, w2b, w1b, sbase);
}

// ======= score core: 128x128 tile, BK=64, 3 stages, warp 64x32 ============
#define SC_ROWB   144
#define SC_A_SB   (128 * SC_ROWB)
#define SC_W_SB   (128 * SC_ROWB)
#define SC_STAGE  (SC_A_SB + SC_W_SB)
#define SC_NST    3
#define SC_SMEM   (SC_NST * SC_STAGE + 512 + 32)

__device__ __forceinline__ void score_core(
    const __half* __restrict__ Ah, const __half* __restrict__ Wh,
    const float* __restrict__ g1, const float* __restrict__ vw,
    float* __restrict__ partial, int bx, int by, uint32_t sbase, char* smem)
{
    float* part_sm = (float*)(smem + SC_NST * SC_STAGE);

    const int tid  = threadIdx.x;
    const int wid  = tid >> 5;
    const int lane = tid & 31;
    const int brow = by * 128;
    const int bcol = bx * 128;
    const int m64  = (wid >> 2) * 64;
    const int n32  = (wid & 3) * 32;
    const int K    = 1024;

    if (tid < 128) part_sm[tid] = 0.f;

    const int arow = tid >> 1;
    const int acb_ld = (tid & 1) * 4;
    const __half* gA = Ah + (size_t)(brow + arow) * K;
    const __half* gW = Wh + (size_t)(bcol + arow) * K;
    const uint32_t sA_ld = (uint32_t)(arow * SC_ROWB + acb_ld * 16);
    const uint32_t sW_ld = (uint32_t)(SC_A_SB + arow * SC_ROWB + acb_ld * 16);

    auto load_stage = [&](int stage, int k0) {
        const uint32_t sb = sbase + stage * SC_STAGE;
        const char* pA = (const char*)(gA + k0) + acb_ld * 16;
        const char* pW = (const char*)(gW + k0) + acb_ld * 16;
        #pragma unroll
        for (int c = 0; c < 4; c++) {
            cp16(sb + sA_ld + c * 16, pA + c * 16);
            cp16(sb + sW_ld + c * 16, pW + c * 16);
        }
    };

    const int nk = 16;

    load_stage(0, 0);
    asm volatile("cp.async.commit_group;");
    load_stage(1, 64);
    asm volatile("cp.async.commit_group;");

    float acc[4][4][4];
    #pragma unroll
    for (int i = 0; i < 4; i++)
        #pragma unroll
        for (int j = 0; j < 4; j++)
            #pragma unroll
            for (int q = 0; q < 4; q++) acc[i][j][q] = 0.f;

    const int arow_l = m64 + (lane & 15);
    const uint32_t akb = ((lane >> 4) & 1) * 16;
    const int nrow_l = n32 + (lane & 7) + ((lane >> 4) & 1) * 8;
    const uint32_t bkb = ((lane >> 3) & 1) * 16;

    int stage = 0;
    for (int c = 0; c < nk; c++) {
        asm volatile("cp.async.wait_group %0;" :: "n"(1));
        __syncthreads();

        if (c + 2 < nk) {
            int s2 = stage + 2; if (s2 >= SC_NST) s2 -= SC_NST;
            load_stage(s2, (c + 2) * 64);
        }
        asm volatile("cp.async.commit_group;");

        const uint32_t sb = sbase + stage * SC_STAGE;
        #pragma unroll
        for (int kk = 0; kk < 4; kk++) {
            const uint32_t kbyte = kk * 32;
            uint32_t bfh[4][2];
            #pragma unroll
            for (int np = 0; np < 2; np++) {
                uint32_t rb = (uint32_t)((nrow_l + np * 16) * SC_ROWB) + bkb + kbyte;
                uint32_t th[4];
                ldm4(th, sb + SC_A_SB + rb);
                bfh[2 * np][0] = th[0]; bfh[2 * np][1] = th[1];
                bfh[2 * np + 1][0] = th[2]; bfh[2 * np + 1][1] = th[3];
            }
            #pragma unroll
            for (int mt = 0; mt < 4; mt++) {
                uint32_t afh[4];
                uint32_t ra = (uint32_t)((arow_l + mt * 16) * SC_ROWB) + akb + kbyte;
                ldm4(afh, sb + ra);
                #pragma unroll
                for (int nt = 0; nt < 4; nt++)
                    mma16816(acc[mt][nt], afh, bfh[nt]);
            }
        }
        if (++stage >= SC_NST) stage = 0;
    }

    const int rloc0 = m64 + (lane >> 2);
    const int cloc0 = n32 + (lane & 3) * 2;
    const float* g1r = g1 + (size_t)by * 1024;
    #pragma unroll
    for (int mt = 0; mt < 4; mt++) {
        float s0 = 0.f, s1 = 0.f;
        #pragma unroll
        for (int nt = 0; nt < 4; nt++) {
            int col = bcol + cloc0 + nt * 8;
            float gw0 = g1r[col],     vw0 = vw[col];
            float gw1 = g1r[col + 1], vw1 = vw[col + 1];
            s0 += tanhf(acc[mt][nt][0] + gw0) * vw0;
            s0 += tanhf(acc[mt][nt][1] + gw1) * vw1;
            s1 += tanhf(acc[mt][nt][2] + gw0) * vw0;
            s1 += tanhf(acc[mt][nt][3] + gw1) * vw1;
        }
        atomicAdd(&part_sm[rloc0 + mt * 16], s0);
        atomicAdd(&part_sm[rloc0 + mt * 16 + 8], s1);
    }
    __syncthreads();
    if (tid < 128)
        partial[(size_t)(brow + tid) * 8 + bx] = part_sm[tid];
}

// === score_plus: score (2048 blk) | x_emb (128 blk) | gh (192 blk) ========
__global__ __launch_bounds__(256, 2)
void score_plus(const __half* __restrict__ encAh, const __half* __restrict__ w1h,
                const float* __restrict__ g1, const float* __restrict__ vw,
                float* __restrict__ partial,
                const __half* __restrict__ xh, const __half* __restrict__ xl,
                const __half* __restrict__ o2eh,
                const __half* __restrict__ hidh, const __half* __restrict__ hidl,
                const __half* __restrict__ gwhh,
                float* __restrict__ rnn_xemb, float* __restrict__ gh)
{
    extern __shared__ __align__(128) char smem[];
    const uint32_t sbase = (uint32_t)__cvta_generic_to_shared(smem);
    const int ib = blockIdx.x;
    if (ib < 2048) {
        score_core(encAh, w1h, g1, vw, partial, ib & 7, ib >> 3, sbase, smem);
    } else if (ib < 2176) {
        int j = ib - 2048;
        int bx = j & 7, by = (j >> 3) & 1, bz = j >> 4;
        gemm2_core(xh, xl, o2eh, 4096, 512, by * 128, bx * 64, bz * 512,
                   rnn_xemb, 1536, nullptr, nullptr, sbase);
    } else {
        int j = ib - 2176;
        int bx = j % 48, by = (j / 48) & 1, bz = j / 96;
        gemm2_core(hidh, hidl, gwhh, 1024, 512, by * 128, bx * 64, bz * 512,
                   gh, 3072, nullptr, nullptr, sbase);
    }
}

// ==== attn_fused: ctx halves with batched loads (512 blk) | split_xemb ====
__global__ __launch_bounds__(256)
void attn_fused(const float* __restrict__ part, int npart,
                const __half* __restrict__ ench,
                const float* __restrict__ Vb,
                float* __restrict__ attn_out,
                const float* __restrict__ rnn)
{
    const int tid = threadIdx.x;
    if (blockIdx.x >= 2 * BB) {
        // split_xemb: 128 blocks x 256 threads
        int i = (blockIdx.x - 2 * BB) * 256 + tid;
        int row = i >> 7;
        int c4  = i & 127;
        size_t off = (size_t)row * 1536 + 1024 + c4 * 4;
        float4 v = *(const float4*)(rnn + off);
        uint2 h = cvt_hi4(v);
        uint2 l = cvt_lo4(v, h);
        *(uint2*)(g_bh + OFF_RNN + off) = h;
        *(uint2*)(g_bl + OFF_RNN + off) = l;
        return;
    }

    const int b    = blockIdx.x >> 1;
    const int half = blockIdx.x & 1;
    __shared__ float logit[LL];

    if (tid < LL) {
        const float* pr = part + (size_t)(b * LL + tid) * npart;
        float s = Vb[0];
        for (int j = 0; j < npart; j++) s += pr[j];
        logit[tid] = s;
    }
    __syncthreads();

    if (tid < 32) {
        const int lane = tid;
        float m = -1e30f;
        for (int l = lane; l < LL; l += 32) m = fmaxf(m, logit[l]);
        #pragma unroll
        for (int o = 16; o; o >>= 1) m = fmaxf(m, __shfl_xor_sync(0xffffffffu, m, o));
        float s = 0.f;
        for (int l = lane; l < LL; l += 32) {
            float e = expf(logit[l] - m);
            logit[l] = e;
            s += e;
        }
        #pragma unroll
        for (int o = 16; o; o >>= 1) s += __shfl_xor_sync(0xffffffffu, s, o);
        float inv = 1.f / s;
        for (int l = lane; l < LL; l += 32) logit[l] *= inv;
    }
    __syncthreads();

    if (half == 0 && tid < LL) attn_out[b * LL + tid] = logit[tid];

    // ctx: 2 columns/thread; 8 loads batched ahead of FMAs, 2 acc chains
    float2 acc0 = make_float2(0.f, 0.f);
    float2 acc1 = make_float2(0.f, 0.f);
    const int colh = half * 256 + tid;
    const __half2* encb = (const __half2*)(ench + (size_t)b * LL * EENC) + colh;
    #pragma unroll
    for (int l0 = 0; l0 < LL; l0 += 8) {
        __half2 v[8];
        #pragma unroll
        for (int u = 0; u < 8; u++) v[u] = encb[(l0 + u) * (EENC / 2)];
        #pragma unroll
        for (int u = 0; u < 8; u++) {
            float a = logit[l0 + u];
            float2 f = __half22float2(v[u]);
            if (u & 1) { acc1.x += a * f.x; acc1.y += a * f.y; }
            else       { acc0.x += a * f.x; acc0.y += a * f.y; }
        }
    }
    float2 acc = make_float2(acc0.x + acc1.x, acc0.y + acc1.y);
    size_t off = (size_t)b * 1536 + colh * 2;
    __half h0 = __float2half_rn(acc.x), h1 = __float2half_rn(acc.y);
    __half2 hp; hp.x = h0; hp.y = h1;
    __half2 lp;
    lp.x = __float2half_rn(acc.x - __half2float(h0));
    lp.y = __float2half_rn(acc.y - __half2float(h1));
    *(__half2*)(g_bh + OFF_RNN + off) = hp;
    *(__half2*)(g_bl + OFF_RNN + off) = lp;
}

// ======== GRU gates; 4 elems/thread; writes hnew + fp16 splits ============
__global__ __launch_bounds__(256)
void gru_gate(const float* __restrict__ gi, const float* __restrict__ gh,
              const float* __restrict__ h0, float* __restrict__ hnew)
{
    const int i = blockIdx.x * blockDim.x + threadIdx.x;   // 65536, 4 elems each
    const int idx = i * 4;
    const int b = idx >> 10;
    const int d = idx & 1023;
    const float* gib = gi + (size_t)b * 3072;
    const float* ghb = gh + (size_t)b * 3072;
    float4 ir = *(const float4*)(gib + d);
    float4 iz = *(const float4*)(gib + 1024 + d);
    float4 in_ = *(const float4*)(gib + 2048 + d);
    float4 hr = *(const float4*)(ghb + d);
    float4 hz = *(const float4*)(ghb + 1024 + d);
    float4 hn = *(const float4*)(ghb + 2048 + d);
    float4 hp0 = *(const float4*)(h0 + idx);
    float4 ho;
    {
        float r = 1.f / (1.f + expf(-(ir.x + hr.x)));
        float z = 1.f / (1.f + expf(-(iz.x + hz.x)));
        float n = tanhf(in_.x + r * hn.x);
        ho.x = (1.f - z) * n + z * hp0.x;
    }
    {
        float r = 1.f / (1.f + expf(-(ir.y + hr.y)));
        float z = 1.f / (1.f + expf(-(iz.y + hz.y)));
        float n = tanhf(in_.y + r * hn.y);
        ho.y = (1.f - z) * n + z * hp0.y;
    }
    {
        float r = 1.f / (1.f + expf(-(ir.z + hr.z)));
        float z = 1.f / (1.f + expf(-(iz.z + hz.z)));
        float n = tanhf(in_.z + r * hn.z);
        ho.z = (1.f - z) * n + z * hp0.z;
    }
    {
        float r = 1.f / (1.f + expf(-(ir.w + hr.w)));
        float z = 1.f / (1.f + expf(-(iz.w + hz.w)));
        float n = tanhf(in_.w + r * hn.w);
        ho.w = (1.f - z) * n + z * hp0.w;
    }
    *(float4*)(hnew + idx) = ho;
    uint2 h = cvt_hi4(ho);
    uint2 l = cvt_lo4(ho, h);
    ((uint2*)(g_bh + OFF_HNEW))[i] = h;
    ((uint2*)(g_bl + OFF_HNEW))[i] = l;
}

// ============================ launch ======================================
extern "C" void kernel_launch(void* const* d_in, const int* in_sizes, int n_in,
                              void* d_out, int out_size)
{
    (void)in_sizes; (void)n_in; (void)out_size;

    const float* x      = (const float*)d_in[0];
    const float* hidden = (const float*)d_in[1];
    const float* enc    = (const float*)d_in[2];
    const float* W1_w   = (const float*)d_in[3];
    const float* W1_b   = (const float*)d_in[4];
    const float* W2_w   = (const float*)d_in[5];
    const float* W2_b   = (const float*)d_in[6];
    const float* V_w    = (const float*)d_in[7];
    const float* V_b    = (const float*)d_in[8];
    const float* o2e_w  = (const float*)d_in[9];
    const float* o2e_b  = (const float*)d_in[10];
    const float* gwi    = (const float*)d_in[11];
    const float* gwh    = (const float*)d_in[12];
    const float* gbi    = (const float*)d_in[13];
    const float* gbh    = (const float*)d_in[14];
    const float* f1w    = (const float*)d_in[15];
    const float* f1b    = (const float*)d_in[16];
    const float* f2w    = (const float*)d_in[17];
    const float* f2b    = (const float*)d_in[18];

    float* out  = (float*)d_out;
    float* hnew = out + (size_t)BB * VOC;
    float* attn = hnew + (size_t)BB * DDEC;

    __half* bh = nullptr;
    __half* bl = nullptr;
    float* fs = nullptr;
    cudaGetSymbolAddress((void**)&bh, g_bh);
    cudaGetSymbolAddress((void**)&bl, g_bl);
    cudaGetSymbolAddress((void**)&fs, g_f32);

    float* g1   = fs + F_G1;
    float* rnn  = fs + F_RNN;
    float* gi   = fs + F_GI;
    float* gh   = fs + F_GH;
    float* tbuf = fs + F_T;
    float* part = fs + F_PART;

    cudaFuncSetAttribute(gemm64,     cudaFuncAttributeMaxDynamicSharedMemorySize, GEMM_SMEM);
    cudaFuncSetAttribute(gemm64b,    cudaFuncAttributeMaxDynamicSharedMemorySize, GEMM2_SMEM);
    cudaFuncSetAttribute(g1_gemm,    cudaFuncAttributeMaxDynamicSharedMemorySize, GEMM2_SMEM);
    cudaFuncSetAttribute(score_plus, cudaFuncAttributeMaxDynamicSharedMemorySize, SC_SMEM);

    dim3 blk(256);

    // 0) prep: all input splits + bias pre-init (8-float units)
    prep<<<PREP_TOTAL / 256, 256>>>(W1_w, W2_w, o2e_w, gwi, gwh, f1w, f2w,
                                    enc, x, hidden,
                                    rnn, gi, gh, tbuf, out,
                                    o2e_b, gbi, gbh, f1b, f2b);

    // 1) g1 (needed by score)
    g1_gemm<<<32, blk, GEMM2_SMEM>>>(
        bh + OFF_HID, bl + OFF_HID, bh + OFF_W2, g1, W2_b, W1_b);

    // 2) score ⊕ x_emb ⊕ gh (2368 blocks)
    score_plus<<<2368, blk, SC_SMEM>>>(
        bh + OFF_ENC, bh + OFF_W1, g1, V_w, part,
        bh + OFF_X, bl + OFF_X, bh + OFF_O2E,
        bh + OFF_HID, bl + OFF_HID, bh + OFF_GWH,
        rnn + 1024, gh);

    // 3) attn_fused: ctx halves (512) | split_xemb (128)
    attn_fused<<<2 * BB + 128, 256>>>(part, 8, bh + OFF_ENC, V_b, attn, rnn);

    // 4) gi += rnn_in @ gru_wi^T    (2-term, splitK=2)
    gemm64b<<<dim3(48, 2, 2), blk, GEMM2_SMEM>>>(
        bh + OFF_RNN, bl + OFF_RNN, bh + OFF_GWI,
        1536, 768, gi, 3072);

    // 5) GRU gates -> h_new (+ fused fp16 split; 4 elems/thread)
    gru_gate<<<65536 / 256, 256>>>(gi, gh, hidden, hnew);

    // 6) tbuf += h_new @ fc1^T      (2-term, splitK=8)
    gemm64b<<<dim3(8, 2, 8), blk, GEMM2_SMEM>>>(
        bh + OFF_HNEW, bl + OFF_HNEW, bh + OFF_F1,
        1024, 128, tbuf, 512);

    // 7) t = tanh(tbuf) -> fp16
    f32_split_tanh<<<(131072 / 4) / 256, 256>>>(tbuf, bh + OFF_T, bl + OFF_T, 131072 / 4);

    // 8) out += t @ fc2^T           (3-term, splitK=2; direct output path)
    gemm64<<<dim3(64, 2, 2), blk, GEMM_SMEM>>>(
        bh + OFF_T, bl + OFF_T, bh + OFF_F2, bl + OFF_F2,
        512, 256, out, 4096);
}